// round 3
// baseline (speedup 1.0000x reference)
#include <cuda_runtime.h>

#define BB 2
#define CC 64
#define FF 257
#define TT 500
#define TTP 512
#define DC 16
#define BN_EPS 1e-5f
#define SCALE 0.25f
#define NPIX (BB*FF*TT)
#define FTSZ (FF*TT)

typedef unsigned long long u64;

__device__ __forceinline__ u64 pk2(float lo, float hi) {
    u64 r; asm("mov.b64 %0, {%1,%2};" : "=l"(r) : "f"(lo), "f"(hi)); return r;
}
__device__ __forceinline__ void upk2(u64 v, float& lo, float& hi) {
    asm("mov.b64 {%0,%1}, %2;" : "=f"(lo), "=f"(hi) : "l"(v));
}
__device__ __forceinline__ u64 fma2(u64 a, u64 b, u64 c) {
    u64 d; asm("fma.rn.f32x2 %0, %1, %2, %3;" : "=l"(d) : "l"(a), "l"(b), "l"(c)); return d;
}
__device__ __forceinline__ u64 mul2(u64 a, u64 b) {
    u64 d; asm("mul.rn.f32x2 %0, %1, %2;" : "=l"(d) : "l"(a), "l"(b)); return d;
}

// Scratch (device globals; no allocation allowed)
__device__ float g_qf[BB*TT*FF*DC];   // [b][t][f][c]
__device__ float g_kf[BB*TT*FF*DC];   // [b][t][f][c]
__device__ float g_vv[BB*TT*FF*DC];   // [b][t][f][c]
__device__ float g_qt[BB*FF*TT*DC];   // [b][f][t][c]
__device__ float g_kt[BB*FF*TT*DC];   // [b][f][t][c]
__device__ float g_fo[BB*FF*TT*DC];   // [b][f][t][c]

// ---------------------------------------------------------------------------
// Kernel 1: fused 1x1 convs. CTA = 160 threads covering 128 pixels.
// Thread (e, pg): e = output tensor (qf,kf,vv,qt,kt), pg = 4-pixel group.
// Weights permuted in smem so each e owns 16 contiguous channels.
// ---------------------------------------------------------------------------
extern __shared__ float smc[];
__global__ __launch_bounds__(160) void asa_conv(
    const float* __restrict__ inp,
    const float* __restrict__ fw, const float* __restrict__ fb,
    const float* __restrict__ fg, const float* __restrict__ fbe,
    const float* __restrict__ fm, const float* __restrict__ fv,
    const float* __restrict__ fa,
    const float* __restrict__ tw, const float* __restrict__ tb,
    const float* __restrict__ tg, const float* __restrict__ tbe,
    const float* __restrict__ tm, const float* __restrict__ tv,
    const float* __restrict__ ta)
{
    float* ws = smc;               // [64][80]  (c-major rows of permuted outputs)
    float* xs = ws + 64*80;        // [64][128]
    float* sh = xs + 64*128;       // [80]
    float* al = sh + 80;           // [2]

    int tid = threadIdx.x;

    for (int idx = tid; idx < 80*64; idx += 160) {
        int c = idx & 63, op = idx >> 6;
        int e = op >> 4, cc = op & 15;
        float w, g, vv;
        if (e < 3) { int o = 3*cc + e;     w = fw[o*64+c]; g = fg[o]; vv = fv[o]; }
        else       { int o2 = 2*cc + (e-3); w = tw[o2*64+c]; g = tg[o2]; vv = tv[o2]; }
        ws[c*80 + op] = w * (g * rsqrtf(vv + BN_EPS));
    }
    if (tid < 80) {
        int op = tid, e = op >> 4, cc = op & 15;
        float g, vv, m, b, be;
        if (e < 3) { int o = 3*cc + e;     g=fg[o]; vv=fv[o]; m=fm[o]; b=fb[o]; be=fbe[o]; }
        else       { int o2 = 2*cc + (e-3); g=tg[o2]; vv=tv[o2]; m=tm[o2]; b=tb[o2]; be=tbe[o2]; }
        sh[op] = (b - m) * (g * rsqrtf(vv + BN_EPS)) + be;
    }
    if (tid == 0) { al[0] = fa[0]; al[1] = ta[0]; }

    int p0 = blockIdx.x * 128;
    int b0 = p0 / FTSZ;
    int bend = (p0 + 127) / FTSZ;
    if (b0 == bend && p0 + 127 < NPIX) {
        int ft0 = p0 - b0*FTSZ;
        const float* src = inp + b0*CC*FTSZ + ft0;
        for (int i = tid; i < 64*32; i += 160) {
            int c = i >> 5, l4 = i & 31;
            ((float4*)xs)[c*32 + l4] = *(const float4*)(src + c*FTSZ + l4*4);
        }
    } else {
        for (int i = tid; i < 64*128; i += 160) {
            int c = i >> 7, lp = i & 127;
            int p = p0 + lp;
            float v = 0.f;
            if (p < NPIX) {
                int b = p / FTSZ;
                int ft = p - b*FTSZ;
                v = inp[(b*CC + c)*FTSZ + ft];
            }
            xs[c*128 + lp] = v;
        }
    }
    __syncthreads();

    int e  = tid >> 5;   // 0..4 tensor
    int pg = tid & 31;   // 4-pixel group

    u64 acc[8][4];
#pragma unroll
    for (int j = 0; j < 8; j++)
#pragma unroll
        for (int x = 0; x < 4; x++) acc[j][x] = 0ull;

    const float* wbase = ws + e*16;
#pragma unroll 4
    for (int c = 0; c < 64; c++) {
        const ulonglong2* wr = (const ulonglong2*)(wbase + c*80);
        ulonglong2 wa = wr[0], wb = wr[1], wc2 = wr[2], wd = wr[3];
        float4 xv = ((const float4*)xs)[c*32 + pg];
        u64 x0 = pk2(xv.x, xv.x), x1 = pk2(xv.y, xv.y);
        u64 x2 = pk2(xv.z, xv.z), x3 = pk2(xv.w, xv.w);
        acc[0][0]=fma2(wa.x,x0,acc[0][0]); acc[0][1]=fma2(wa.x,x1,acc[0][1]);
        acc[0][2]=fma2(wa.x,x2,acc[0][2]); acc[0][3]=fma2(wa.x,x3,acc[0][3]);
        acc[1][0]=fma2(wa.y,x0,acc[1][0]); acc[1][1]=fma2(wa.y,x1,acc[1][1]);
        acc[1][2]=fma2(wa.y,x2,acc[1][2]); acc[1][3]=fma2(wa.y,x3,acc[1][3]);
        acc[2][0]=fma2(wb.x,x0,acc[2][0]); acc[2][1]=fma2(wb.x,x1,acc[2][1]);
        acc[2][2]=fma2(wb.x,x2,acc[2][2]); acc[2][3]=fma2(wb.x,x3,acc[2][3]);
        acc[3][0]=fma2(wb.y,x0,acc[3][0]); acc[3][1]=fma2(wb.y,x1,acc[3][1]);
        acc[3][2]=fma2(wb.y,x2,acc[3][2]); acc[3][3]=fma2(wb.y,x3,acc[3][3]);
        acc[4][0]=fma2(wc2.x,x0,acc[4][0]); acc[4][1]=fma2(wc2.x,x1,acc[4][1]);
        acc[4][2]=fma2(wc2.x,x2,acc[4][2]); acc[4][3]=fma2(wc2.x,x3,acc[4][3]);
        acc[5][0]=fma2(wc2.y,x0,acc[5][0]); acc[5][1]=fma2(wc2.y,x1,acc[5][1]);
        acc[5][2]=fma2(wc2.y,x2,acc[5][2]); acc[5][3]=fma2(wc2.y,x3,acc[5][3]);
        acc[6][0]=fma2(wd.x,x0,acc[6][0]); acc[6][1]=fma2(wd.x,x1,acc[6][1]);
        acc[6][2]=fma2(wd.x,x2,acc[6][2]); acc[6][3]=fma2(wd.x,x3,acc[6][3]);
        acc[7][0]=fma2(wd.y,x0,acc[7][0]); acc[7][1]=fma2(wd.y,x1,acc[7][1]);
        acc[7][2]=fma2(wd.y,x2,acc[7][2]); acc[7][3]=fma2(wd.y,x3,acc[7][3]);
    }

    float shv[16];
#pragma unroll
    for (int cc = 0; cc < 16; cc++) shv[cc] = sh[e*16 + cc];
    float alpha = (e < 3) ? al[0] : al[1];

#pragma unroll
    for (int px = 0; px < 4; px++) {
        int p = p0 + pg*4 + px;
        if (p >= NPIX) continue;
        int b = p / FTSZ;
        int ft = p - b*FTSZ;
        int f = ft / TT;
        int t = ft - f*TT;
        float y[16];
#pragma unroll
        for (int j = 0; j < 8; j++) upk2(acc[j][px], y[2*j], y[2*j+1]);
#pragma unroll
        for (int cc = 0; cc < 16; cc++) {
            float v = y[cc] + shv[cc];
            y[cc] = v >= 0.f ? v : alpha * v;
        }
        float* dst;
        if      (e == 0) dst = g_qf + ((b*TT + t)*FF + f)*DC;
        else if (e == 1) dst = g_kf + ((b*TT + t)*FF + f)*DC;
        else if (e == 2) dst = g_vv + ((b*TT + t)*FF + f)*DC;
        else if (e == 3) dst = g_qt + ((b*FF + f)*TT + t)*DC;
        else             dst = g_kt + ((b*FF + f)*TT + t)*DC;
#pragma unroll
        for (int i = 0; i < 4; i++)
            ((float4*)dst)[i] = make_float4(y[4*i], y[4*i+1], y[4*i+2], y[4*i+3]);
    }
}

// ---------------------------------------------------------------------------
__device__ __forceinline__ float dot16(const u64 q[8], const ulonglong2* kr)
{
    ulonglong2 ka = kr[0], kb = kr[1], kc = kr[2], kd = kr[3];
    u64 d0 = mul2(q[0], ka.x);
    u64 d1 = mul2(q[1], ka.y);
    d0 = fma2(q[2], kb.x, d0);
    d1 = fma2(q[3], kb.y, d1);
    d0 = fma2(q[4], kc.x, d0);
    d1 = fma2(q[5], kc.y, d1);
    d0 = fma2(q[6], kd.x, d0);
    d1 = fma2(q[7], kd.y, d1);
    float l0, h0, l1, h1;
    upk2(d0, l0, h0); upk2(d1, l1, h1);
    return (l0 + h0) + (l1 + h1);
}

__device__ __forceinline__ void pv16(u64 acc[8], u64 p2, const ulonglong2* vr)
{
    ulonglong2 v0 = vr[0], v1 = vr[1], v2 = vr[2], v3 = vr[3];
    acc[0] = fma2(p2, v0.x, acc[0]); acc[1] = fma2(p2, v0.y, acc[1]);
    acc[2] = fma2(p2, v1.x, acc[2]); acc[3] = fma2(p2, v1.y, acc[3]);
    acc[4] = fma2(p2, v2.x, acc[4]); acc[5] = fma2(p2, v2.y, acc[5]);
    acc[6] = fma2(p2, v3.x, acc[6]); acc[7] = fma2(p2, v3.y, acc[7]);
}

__device__ __forceinline__ void load_q16(const float* g, u64 q[8])
{
    const ulonglong2* qp = (const ulonglong2*)g;
    u64 s2 = pk2(SCALE, SCALE);
    ulonglong2 a = qp[0], b = qp[1], c = qp[2], d = qp[3];
    q[0]=mul2(a.x,s2); q[1]=mul2(a.y,s2); q[2]=mul2(b.x,s2); q[3]=mul2(b.y,s2);
    q[4]=mul2(c.x,s2); q[5]=mul2(c.y,s2); q[6]=mul2(d.x,s2); q[7]=mul2(d.y,s2);
}

// ---------------------------------------------------------------------------
// Kernel 2: frequency attention. One CTA per (b,t).
// ---------------------------------------------------------------------------
__global__ __launch_bounds__(160, 3) void asa_fattn()
{
    __shared__ __align__(16) float Ks[FF*DC];
    __shared__ __align__(16) float Vs[FF*DC];
    int bt = blockIdx.x;
    int b = bt / TT, t = bt % TT;
    int base = (b*TT + t)*FF*DC;
    int tid = threadIdx.x;
    for (int i = tid; i < FF*DC/4; i += 160) {
        ((float4*)Ks)[i] = ((const float4*)(g_kf + base))[i];
        ((float4*)Vs)[i] = ((const float4*)(g_vv + base))[i];
    }
    __syncthreads();
    if (tid > 128) return;

    int fA = (tid < 128) ? tid : 256;
    int fB = (tid < 128) ? tid + 128 : 256;
    bool hasB = (tid < 128);

    u64 qA[8], qB[8];
    load_q16(g_qf + base + fA*DC, qA);
    load_q16(g_qf + base + fB*DC, qB);

    float mA = -3.0e38f, lA = 0.f, mB = -3.0e38f, lB = 0.f;
    u64 accA[8], accB[8];
#pragma unroll
    for (int j = 0; j < 8; j++) { accA[j] = 0ull; accB[j] = 0ull; }

    for (int y0 = 0; y0 < 256; y0 += 8) {
        float sA[8], sB[8];
#pragma unroll
        for (int i = 0; i < 8; i++) {
            const ulonglong2* kr = (const ulonglong2*)(Ks + (y0+i)*DC);
            sA[i] = dot16(qA, kr);
            sB[i] = dot16(qB, kr);
        }
        float cmA = fmaxf(fmaxf(fmaxf(sA[0],sA[1]),fmaxf(sA[2],sA[3])),
                          fmaxf(fmaxf(sA[4],sA[5]),fmaxf(sA[6],sA[7])));
        float cmB = fmaxf(fmaxf(fmaxf(sB[0],sB[1]),fmaxf(sB[2],sB[3])),
                          fmaxf(fmaxf(sB[4],sB[5]),fmaxf(sB[6],sB[7])));
        float mnA = fmaxf(mA, cmA), mnB = fmaxf(mB, cmB);
        float corrA = __expf(mA - mnA), corrB = __expf(mB - mnB);
        mA = mnA; mB = mnB;
        u64 cA2 = pk2(corrA, corrA), cB2 = pk2(corrB, corrB);
#pragma unroll
        for (int j = 0; j < 8; j++) { accA[j] = mul2(accA[j], cA2); accB[j] = mul2(accB[j], cB2); }
        float psA = 0.f, psB = 0.f;
#pragma unroll
        for (int i = 0; i < 8; i++) {
            const ulonglong2* vr = (const ulonglong2*)(Vs + (y0+i)*DC);
            float pa = __expf(sA[i] - mnA); psA += pa;
            float pb = __expf(sB[i] - mnB); psB += pb;
            pv16(accA, pk2(pa, pa), vr);
            pv16(accB, pk2(pb, pb), vr);
        }
        lA = fmaf(lA, corrA, psA);
        lB = fmaf(lB, corrB, psB);
    }
    {
        const ulonglong2* kr = (const ulonglong2*)(Ks + 256*DC);
        const ulonglong2* vr = (const ulonglong2*)(Vs + 256*DC);
        float sA = dot16(qA, kr), sB = dot16(qB, kr);
        float mnA = fmaxf(mA, sA), mnB = fmaxf(mB, sB);
        float corrA = __expf(mA - mnA), corrB = __expf(mB - mnB);
        float pa = __expf(sA - mnA), pb = __expf(sB - mnB);
        u64 cA2 = pk2(corrA, corrA), cB2 = pk2(corrB, corrB);
#pragma unroll
        for (int j = 0; j < 8; j++) { accA[j] = mul2(accA[j], cA2); accB[j] = mul2(accB[j], cB2); }
        pv16(accA, pk2(pa, pa), vr);
        pv16(accB, pk2(pb, pb), vr);
        lA = fmaf(lA, corrA, pa);
        lB = fmaf(lB, corrB, pb);
    }
    {
        float inv = 1.f / lA;
        u64 iv = pk2(inv, inv);
        float* op = g_fo + ((b*FF + fA)*TT + t)*DC;
#pragma unroll
        for (int j = 0; j < 4; j++) {
            float x0,x1,x2,x3;
            upk2(mul2(accA[2*j],iv), x0, x1);
            upk2(mul2(accA[2*j+1],iv), x2, x3);
            ((float4*)op)[j] = make_float4(x0,x1,x2,x3);
        }
    }
    if (hasB) {
        float inv = 1.f / lB;
        u64 iv = pk2(inv, inv);
        float* op = g_fo + ((b*FF + fB)*TT + t)*DC;
#pragma unroll
        for (int j = 0; j < 4; j++) {
            float x0,x1,x2,x3;
            upk2(mul2(accB[2*j],iv), x0, x1);
            upk2(mul2(accB[2*j+1],iv), x2, x3);
            ((float4*)op)[j] = make_float4(x0,x1,x2,x3);
        }
    }
}

// ---------------------------------------------------------------------------
// Kernel 3: causal time attention + proj + residual.
// ---------------------------------------------------------------------------
__device__ __forceinline__ void proj_store2(
    const float* __restrict__ pws, const float* __restrict__ psh, float alpha,
    const float* __restrict__ inp, float* __restrict__ out,
    int b, int f, int t, const u64 acc[8], float l)
{
    u64 o2[8];
    float inv = 1.f / l;
    u64 iv = pk2(inv, inv);
#pragma unroll
    for (int j = 0; j < 8; j++) o2[j] = mul2(acc[j], iv);
    int base = b*CC*FF*TT + f*TT + t;
#pragma unroll 4
    for (int co = 0; co < 64; co++) {
        const ulonglong2* wr = (const ulonglong2*)(pws + co*16);
        ulonglong2 wa = wr[0], wb = wr[1], wc = wr[2], wd = wr[3];
        u64 d0 = mul2(wa.x, o2[0]);
        u64 d1 = mul2(wa.y, o2[1]);
        d0 = fma2(wb.x, o2[2], d0);
        d1 = fma2(wb.y, o2[3], d1);
        d0 = fma2(wc.x, o2[4], d0);
        d1 = fma2(wc.y, o2[5], d1);
        d0 = fma2(wd.x, o2[6], d0);
        d1 = fma2(wd.y, o2[7], d1);
        float l0,h0,l1,h1;
        upk2(d0,l0,h0); upk2(d1,l1,h1);
        float r = psh[co] + (l0+h0) + (l1+h1);
        r = r >= 0.f ? r : alpha * r;
        int idx = base + co*FF*TT;
        out[idx] = r + __ldg(&inp[idx]);
    }
}

extern __shared__ float sm3[];
__global__ __launch_bounds__(128, 3) void asa_tattn(
    const float* __restrict__ inp,
    const float* __restrict__ pw, const float* __restrict__ pb,
    const float* __restrict__ pg, const float* __restrict__ pbe,
    const float* __restrict__ pm, const float* __restrict__ pv,
    const float* __restrict__ pa,
    float* __restrict__ out)
{
    float* Ks  = sm3;                 // TTP*DC
    float* Vs  = sm3 + TTP*DC;        // TTP*DC
    float* pws = Vs + TTP*DC;         // 64*16
    float* psh = pws + 64*16;         // 64
    __shared__ float s_alpha;

    int bf   = blockIdx.x >> 1;
    int half = blockIdx.x & 1;
    int b = bf / FF, f = bf % FF;
    int base = bf * TT * DC;
    int tid = threadIdx.x;

    for (int i = tid; i < TTP*DC/4; i += 128) {
        float4 kk = make_float4(0,0,0,0), vv = kk;
        if (i < TT*DC/4) {
            kk = ((const float4*)(g_kt + base))[i];
            vv = ((const float4*)(g_fo + base))[i];
        }
        ((float4*)Ks)[i] = kk;
        ((float4*)Vs)[i] = vv;
    }
    for (int i = tid; i < 64*16; i += 128) {
        int o = i >> 4;
        pws[i] = pw[i] * (pg[o] * rsqrtf(pv[o] + BN_EPS));
    }
    if (tid < 64) {
        int o = tid;
        psh[o] = (pb[o] - pm[o]) * (pg[o] * rsqrtf(pv[o] + BN_EPS)) + pbe[o];
    }
    if (tid == 0) s_alpha = pa[0];
    __syncthreads();

    if (tid >= 125) return;
    float alpha = s_alpha;
    int p  = tid + half*125;
    int t1 = p;
    int t2 = TT - 1 - p;

    u64 q1[8], q2[8];
    load_q16(g_qt + base + t1*DC, q1);
    load_q16(g_qt + base + t2*DC, q2);

    float m1 = -3.0e38f, l1 = 0.f, m2 = -3.0e38f, l2 = 0.f;
    u64 a1[8], a2[8];
#pragma unroll
    for (int j = 0; j < 8; j++) { a1[j] = 0ull; a2[j] = 0ull; }

    for (int y0 = 0; y0 <= t2; y0 += 8) {
        bool doq1 = (y0 <= t1);
        float s1[8], s2[8];
#pragma unroll
        for (int i = 0; i < 8; i++) {
            int y = y0 + i;
            const ulonglong2* kr = (const ulonglong2*)(Ks + y*DC);
            float v2 = dot16(q2, kr);
            s2[i] = (y <= t2) ? v2 : -3.0e38f;
            if (doq1) {
                float v1 = dot16(q1, kr);
                s1[i] = (y <= t1) ? v1 : -3.0e38f;
            }
        }
        {
            float cm = fmaxf(fmaxf(fmaxf(s2[0],s2[1]),fmaxf(s2[2],s2[3])),
                             fmaxf(fmaxf(s2[4],s2[5]),fmaxf(s2[6],s2[7])));
            float mn = fmaxf(m2, cm);
            float corr = __expf(m2 - mn);
            m2 = mn;
            u64 c2 = pk2(corr, corr);
#pragma unroll
            for (int j = 0; j < 8; j++) a2[j] = mul2(a2[j], c2);
            float ps = 0.f;
#pragma unroll
            for (int i = 0; i < 8; i++) {
                const ulonglong2* vr = (const ulonglong2*)(Vs + (y0+i)*DC);
                float pr = __expf(s2[i] - mn); ps += pr;
                pv16(a2, pk2(pr, pr), vr);
            }
            l2 = fmaf(l2, corr, ps);
        }
        if (doq1) {
            float cm = fmaxf(fmaxf(fmaxf(s1[0],s1[1]),fmaxf(s1[2],s1[3])),
                             fmaxf(fmaxf(s1[4],s1[5]),fmaxf(s1[6],s1[7])));
            float mn = fmaxf(m1, cm);
            float corr = __expf(m1 - mn);
            m1 = mn;
            u64 c2 = pk2(corr, corr);
#pragma unroll
            for (int j = 0; j < 8; j++) a1[j] = mul2(a1[j], c2);
            float ps = 0.f;
#pragma unroll
            for (int i = 0; i < 8; i++) {
                const ulonglong2* vr = (const ulonglong2*)(Vs + (y0+i)*DC);
                float pr = __expf(s1[i] - mn); ps += pr;
                pv16(a1, pk2(pr, pr), vr);
            }
            l1 = fmaf(l1, corr, ps);
        }
    }
    proj_store2(pws, psh, alpha, inp, out, b, f, t1, a1, l1);
    proj_store2(pws, psh, alpha, inp, out, b, f, t2, a2, l2);
}

// ---------------------------------------------------------------------------
extern "C" void kernel_launch(void* const* d_in, const int* in_sizes, int n_in,
                              void* d_out, int out_size)
{
    const float* inp = (const float*)d_in[0];

    int smc_bytes = (64*80 + 64*128 + 80 + 2) * (int)sizeof(float);
    cudaFuncSetAttribute(asa_conv, cudaFuncAttributeMaxDynamicSharedMemorySize, smc_bytes);
    asa_conv<<<(NPIX + 127)/128, 160, smc_bytes>>>(
        inp,
        (const float*)d_in[1],  (const float*)d_in[2],  (const float*)d_in[3],
        (const float*)d_in[4],  (const float*)d_in[5],  (const float*)d_in[6],
        (const float*)d_in[7],
        (const float*)d_in[8],  (const float*)d_in[9],  (const float*)d_in[10],
        (const float*)d_in[11], (const float*)d_in[12], (const float*)d_in[13],
        (const float*)d_in[14]);

    asa_fattn<<<BB*TT, 160>>>();

    int smem = (TTP*DC*2 + 64*16 + 64) * (int)sizeof(float);
    cudaFuncSetAttribute(asa_tattn, cudaFuncAttributeMaxDynamicSharedMemorySize, smem);
    asa_tattn<<<BB*FF*2, 128, smem>>>(
        inp,
        (const float*)d_in[15], (const float*)d_in[16], (const float*)d_in[17],
        (const float*)d_in[18], (const float*)d_in[19], (const float*)d_in[20],
        (const float*)d_in[21],
        (float*)d_out);
}

// round 4
// speedup vs baseline: 1.5615x; 1.5615x over previous
#include <cuda_runtime.h>

#define BB 2
#define CC 64
#define FF 257
#define TT 500
#define DC 16
#define BN_EPS 1e-5f
#define SCALE 0.25f
#define NPIX (BB*FF*TT)
#define FTSZ (FF*TT)

typedef unsigned long long u64;

__device__ __forceinline__ u64 pk2(float lo, float hi) {
    u64 r; asm("mov.b64 %0, {%1,%2};" : "=l"(r) : "f"(lo), "f"(hi)); return r;
}
__device__ __forceinline__ void upk2(u64 v, float& lo, float& hi) {
    asm("mov.b64 {%0,%1}, %2;" : "=f"(lo), "=f"(hi) : "l"(v));
}
__device__ __forceinline__ u64 fma2(u64 a, u64 b, u64 c) {
    u64 d; asm("fma.rn.f32x2 %0, %1, %2, %3;" : "=l"(d) : "l"(a), "l"(b), "l"(c)); return d;
}
__device__ __forceinline__ u64 mul2(u64 a, u64 b) {
    u64 d; asm("mul.rn.f32x2 %0, %1, %2;" : "=l"(d) : "l"(a), "l"(b)); return d;
}

// Scratch (device globals; no allocation allowed)
__device__ float g_qf[BB*TT*FF*DC];   // [b][t][f][c]
__device__ float g_kf[BB*TT*FF*DC];   // [b][t][f][c]
__device__ float g_vv[BB*TT*FF*DC];   // [b][t][f][c]
__device__ float g_qt[BB*FF*TT*DC];   // [b][f][t][c]
__device__ float g_kt[BB*FF*TT*DC];   // [b][f][t][c]
__device__ float g_fo[BB*FF*TT*DC];   // [b][f][t][c]

// ---------------------------------------------------------------------------
// Kernel 1: fused 1x1 convs (unchanged from R3 — 117us, occ-improved).
// ---------------------------------------------------------------------------
extern __shared__ float smc[];
__global__ __launch_bounds__(160) void asa_conv(
    const float* __restrict__ inp,
    const float* __restrict__ fw, const float* __restrict__ fb,
    const float* __restrict__ fg, const float* __restrict__ fbe,
    const float* __restrict__ fm, const float* __restrict__ fv,
    const float* __restrict__ fa,
    const float* __restrict__ tw, const float* __restrict__ tb,
    const float* __restrict__ tg, const float* __restrict__ tbe,
    const float* __restrict__ tm, const float* __restrict__ tv,
    const float* __restrict__ ta)
{
    float* ws = smc;               // [64][80]
    float* xs = ws + 64*80;        // [64][128]
    float* sh = xs + 64*128;       // [80]
    float* al = sh + 80;           // [2]

    int tid = threadIdx.x;

    for (int idx = tid; idx < 80*64; idx += 160) {
        int c = idx & 63, op = idx >> 6;
        int e = op >> 4, cc = op & 15;
        float w, g, vv;
        if (e < 3) { int o = 3*cc + e;      w = fw[o*64+c]; g = fg[o]; vv = fv[o]; }
        else       { int o2 = 2*cc + (e-3); w = tw[o2*64+c]; g = tg[o2]; vv = tv[o2]; }
        ws[c*80 + op] = w * (g * rsqrtf(vv + BN_EPS));
    }
    if (tid < 80) {
        int op = tid, e = op >> 4, cc = op & 15;
        float g, vv, m, b, be;
        if (e < 3) { int o = 3*cc + e;      g=fg[o]; vv=fv[o]; m=fm[o]; b=fb[o]; be=fbe[o]; }
        else       { int o2 = 2*cc + (e-3); g=tg[o2]; vv=tv[o2]; m=tm[o2]; b=tb[o2]; be=tbe[o2]; }
        sh[op] = (b - m) * (g * rsqrtf(vv + BN_EPS)) + be;
    }
    if (tid == 0) { al[0] = fa[0]; al[1] = ta[0]; }

    int p0 = blockIdx.x * 128;
    int b0 = p0 / FTSZ;
    int bend = (p0 + 127) / FTSZ;
    if (b0 == bend && p0 + 127 < NPIX) {
        int ft0 = p0 - b0*FTSZ;
        const float* src = inp + b0*CC*FTSZ + ft0;
        for (int i = tid; i < 64*32; i += 160) {
            int c = i >> 5, l4 = i & 31;
            ((float4*)xs)[c*32 + l4] = *(const float4*)(src + c*FTSZ + l4*4);
        }
    } else {
        for (int i = tid; i < 64*128; i += 160) {
            int c = i >> 7, lp = i & 127;
            int p = p0 + lp;
            float v = 0.f;
            if (p < NPIX) {
                int b = p / FTSZ;
                int ft = p - b*FTSZ;
                v = inp[(b*CC + c)*FTSZ + ft];
            }
            xs[c*128 + lp] = v;
        }
    }
    __syncthreads();

    int e  = tid >> 5;
    int pg = tid & 31;

    u64 acc[8][4];
#pragma unroll
    for (int j = 0; j < 8; j++)
#pragma unroll
        for (int x = 0; x < 4; x++) acc[j][x] = 0ull;

    const float* wbase = ws + e*16;
#pragma unroll 4
    for (int c = 0; c < 64; c++) {
        const ulonglong2* wr = (const ulonglong2*)(wbase + c*80);
        ulonglong2 wa = wr[0], wb = wr[1], wc2 = wr[2], wd = wr[3];
        float4 xv = ((const float4*)xs)[c*32 + pg];
        u64 x0 = pk2(xv.x, xv.x), x1 = pk2(xv.y, xv.y);
        u64 x2 = pk2(xv.z, xv.z), x3 = pk2(xv.w, xv.w);
        acc[0][0]=fma2(wa.x,x0,acc[0][0]); acc[0][1]=fma2(wa.x,x1,acc[0][1]);
        acc[0][2]=fma2(wa.x,x2,acc[0][2]); acc[0][3]=fma2(wa.x,x3,acc[0][3]);
        acc[1][0]=fma2(wa.y,x0,acc[1][0]); acc[1][1]=fma2(wa.y,x1,acc[1][1]);
        acc[1][2]=fma2(wa.y,x2,acc[1][2]); acc[1][3]=fma2(wa.y,x3,acc[1][3]);
        acc[2][0]=fma2(wb.x,x0,acc[2][0]); acc[2][1]=fma2(wb.x,x1,acc[2][1]);
        acc[2][2]=fma2(wb.x,x2,acc[2][2]); acc[2][3]=fma2(wb.x,x3,acc[2][3]);
        acc[3][0]=fma2(wb.y,x0,acc[3][0]); acc[3][1]=fma2(wb.y,x1,acc[3][1]);
        acc[3][2]=fma2(wb.y,x2,acc[3][2]); acc[3][3]=fma2(wb.y,x3,acc[3][3]);
        acc[4][0]=fma2(wc2.x,x0,acc[4][0]); acc[4][1]=fma2(wc2.x,x1,acc[4][1]);
        acc[4][2]=fma2(wc2.x,x2,acc[4][2]); acc[4][3]=fma2(wc2.x,x3,acc[4][3]);
        acc[5][0]=fma2(wc2.y,x0,acc[5][0]); acc[5][1]=fma2(wc2.y,x1,acc[5][1]);
        acc[5][2]=fma2(wc2.y,x2,acc[5][2]); acc[5][3]=fma2(wc2.y,x3,acc[5][3]);
        acc[6][0]=fma2(wd.x,x0,acc[6][0]); acc[6][1]=fma2(wd.x,x1,acc[6][1]);
        acc[6][2]=fma2(wd.x,x2,acc[6][2]); acc[6][3]=fma2(wd.x,x3,acc[6][3]);
        acc[7][0]=fma2(wd.y,x0,acc[7][0]); acc[7][1]=fma2(wd.y,x1,acc[7][1]);
        acc[7][2]=fma2(wd.y,x2,acc[7][2]); acc[7][3]=fma2(wd.y,x3,acc[7][3]);
    }

    float shv[16];
#pragma unroll
    for (int cc = 0; cc < 16; cc++) shv[cc] = sh[e*16 + cc];
    float alpha = (e < 3) ? al[0] : al[1];

#pragma unroll
    for (int px = 0; px < 4; px++) {
        int p = p0 + pg*4 + px;
        if (p >= NPIX) continue;
        int b = p / FTSZ;
        int ft = p - b*FTSZ;
        int f = ft / TT;
        int t = ft - f*TT;
        float y[16];
#pragma unroll
        for (int j = 0; j < 8; j++) upk2(acc[j][px], y[2*j], y[2*j+1]);
#pragma unroll
        for (int cc = 0; cc < 16; cc++) {
            float v = y[cc] + shv[cc];
            y[cc] = v >= 0.f ? v : alpha * v;
        }
        float* dst;
        if      (e == 0) dst = g_qf + ((b*TT + t)*FF + f)*DC;
        else if (e == 1) dst = g_kf + ((b*TT + t)*FF + f)*DC;
        else if (e == 2) dst = g_vv + ((b*TT + t)*FF + f)*DC;
        else if (e == 3) dst = g_qt + ((b*FF + f)*TT + t)*DC;
        else             dst = g_kt + ((b*FF + f)*TT + t)*DC;
#pragma unroll
        for (int i = 0; i < 4; i++)
            ((float4*)dst)[i] = make_float4(y[4*i], y[4*i+1], y[4*i+2], y[4*i+3]);
    }
}

// ---------------------------------------------------------------------------
__device__ __forceinline__ float dot16(const u64 q[8], const ulonglong2* kr)
{
    ulonglong2 ka = kr[0], kb = kr[1], kc = kr[2], kd = kr[3];
    u64 d0 = mul2(q[0], ka.x);
    u64 d1 = mul2(q[1], ka.y);
    d0 = fma2(q[2], kb.x, d0);
    d1 = fma2(q[3], kb.y, d1);
    d0 = fma2(q[4], kc.x, d0);
    d1 = fma2(q[5], kc.y, d1);
    d0 = fma2(q[6], kd.x, d0);
    d1 = fma2(q[7], kd.y, d1);
    float l0, h0, l1, h1;
    upk2(d0, l0, h0); upk2(d1, l1, h1);
    return (l0 + h0) + (l1 + h1);
}

__device__ __forceinline__ void pv16(u64 acc[8], u64 p2, const ulonglong2* vr)
{
    ulonglong2 v0 = vr[0], v1 = vr[1], v2 = vr[2], v3 = vr[3];
    acc[0] = fma2(p2, v0.x, acc[0]); acc[1] = fma2(p2, v0.y, acc[1]);
    acc[2] = fma2(p2, v1.x, acc[2]); acc[3] = fma2(p2, v1.y, acc[3]);
    acc[4] = fma2(p2, v2.x, acc[4]); acc[5] = fma2(p2, v2.y, acc[5]);
    acc[6] = fma2(p2, v3.x, acc[6]); acc[7] = fma2(p2, v3.y, acc[7]);
}

__device__ __forceinline__ void load_q16(const float* g, u64 q[8])
{
    const ulonglong2* qp = (const ulonglong2*)g;
    u64 s2 = pk2(SCALE, SCALE);
    ulonglong2 a = qp[0], b = qp[1], c = qp[2], d = qp[3];
    q[0]=mul2(a.x,s2); q[1]=mul2(a.y,s2); q[2]=mul2(b.x,s2); q[3]=mul2(b.y,s2);
    q[4]=mul2(c.x,s2); q[5]=mul2(c.y,s2); q[6]=mul2(d.x,s2); q[7]=mul2(d.y,s2);
}

// ---------------------------------------------------------------------------
// Kernel 2: frequency attention. One CTA per (b,t), 1 query/thread,
// chunked-8 online softmax. Low regs -> high natural occupancy.
// ---------------------------------------------------------------------------
__global__ __launch_bounds__(288) void asa_fattn()
{
    __shared__ __align__(16) float Ks[FF*DC];
    __shared__ __align__(16) float Vs[FF*DC];
    int bt = blockIdx.x;
    int b = bt / TT, t = bt % TT;
    int base = (b*TT + t)*FF*DC;
    int tid = threadIdx.x;
    for (int i = tid; i < FF*DC/4; i += 288) {
        ((float4*)Ks)[i] = ((const float4*)(g_kf + base))[i];
        ((float4*)Vs)[i] = ((const float4*)(g_vv + base))[i];
    }
    __syncthreads();
    if (tid >= FF) return;
    int f = tid;

    u64 q[8];
    load_q16(g_qf + base + f*DC, q);

    float m = -3.0e38f, l = 0.f;
    u64 acc[8];
#pragma unroll
    for (int j = 0; j < 8; j++) acc[j] = 0ull;

    for (int y0 = 0; y0 < 256; y0 += 8) {
        float s[8];
#pragma unroll
        for (int i = 0; i < 8; i++)
            s[i] = dot16(q, (const ulonglong2*)(Ks + (y0+i)*DC));
        float cm = fmaxf(fmaxf(fmaxf(s[0],s[1]),fmaxf(s[2],s[3])),
                         fmaxf(fmaxf(s[4],s[5]),fmaxf(s[6],s[7])));
        float mn = fmaxf(m, cm);
        float corr = __expf(m - mn);
        m = mn;
        u64 c2 = pk2(corr, corr);
#pragma unroll
        for (int j = 0; j < 8; j++) acc[j] = mul2(acc[j], c2);
        float ps = 0.f;
#pragma unroll
        for (int i = 0; i < 8; i++) {
            float pr = __expf(s[i] - mn); ps += pr;
            pv16(acc, pk2(pr, pr), (const ulonglong2*)(Vs + (y0+i)*DC));
        }
        l = fmaf(l, corr, ps);
    }
    { // tail y = 256
        float s = dot16(q, (const ulonglong2*)(Ks + 256*DC));
        float mn = fmaxf(m, s);
        float corr = __expf(m - mn);
        float pr = __expf(s - mn);
        u64 c2 = pk2(corr, corr);
#pragma unroll
        for (int j = 0; j < 8; j++) acc[j] = mul2(acc[j], c2);
        pv16(acc, pk2(pr, pr), (const ulonglong2*)(Vs + 256*DC));
        l = fmaf(l, corr, pr);
    }
    float inv = 1.f / l;
    u64 iv = pk2(inv, inv);
    float* op = g_fo + ((b*FF + f)*TT + t)*DC;
#pragma unroll
    for (int j = 0; j < 4; j++) {
        float x0,x1,x2,x3;
        upk2(mul2(acc[2*j],iv), x0, x1);
        upk2(mul2(acc[2*j+1],iv), x2, x3);
        ((float4*)op)[j] = make_float4(x0,x1,x2,x3);
    }
}

// ---------------------------------------------------------------------------
// Kernel 3: causal time attention + proj + residual.
// 2 CTAs per (b,f): half h owns queries t in [h*250, h*250+250).
// 1 query/thread; half=0 loads only 256 K/V rows.
// ---------------------------------------------------------------------------
extern __shared__ float sm3[];
__global__ __launch_bounds__(256) void asa_tattn(
    const float* __restrict__ inp,
    const float* __restrict__ pw, const float* __restrict__ pb,
    const float* __restrict__ pg, const float* __restrict__ pbe,
    const float* __restrict__ pm, const float* __restrict__ pv,
    const float* __restrict__ pa,
    float* __restrict__ out)
{
    float* Ks  = sm3;                 // 512*DC
    float* Vs  = sm3 + 512*DC;        // 512*DC
    float* pws = Vs + 512*DC;         // 64*16
    float* psh = pws + 64*16;         // 64
    __shared__ float s_alpha;

    int bf   = blockIdx.x >> 1;
    int half = blockIdx.x & 1;
    int b = bf / FF, f = bf % FF;
    int base = bf * TT * DC;
    int tid = threadIdx.x;

    int nrows = half ? 512 : 256;   // rows of K/V needed by this half
    for (int i = tid; i < nrows*DC/4; i += 256) {
        float4 kk = make_float4(0,0,0,0), vv = kk;
        if (i < TT*DC/4) {
            kk = ((const float4*)(g_kt + base))[i];
            vv = ((const float4*)(g_fo + base))[i];
        }
        ((float4*)Ks)[i] = kk;
        ((float4*)Vs)[i] = vv;
    }
    for (int i = tid; i < 64*16; i += 256) {
        int o = i >> 4;
        pws[i] = pw[i] * (pg[o] * rsqrtf(pv[o] + BN_EPS));
    }
    if (tid < 64) {
        int o = tid;
        psh[o] = (pb[o] - pm[o]) * (pg[o] * rsqrtf(pv[o] + BN_EPS)) + pbe[o];
    }
    if (tid == 0) s_alpha = pa[0];
    __syncthreads();

    if (tid >= 250) return;
    int t = half*250 + tid;

    u64 q[8];
    load_q16(g_qt + base + t*DC, q);

    float m = -3.0e38f, l = 0.f;
    u64 acc[8];
#pragma unroll
    for (int j = 0; j < 8; j++) acc[j] = 0ull;

    for (int y0 = 0; y0 <= t; y0 += 8) {
        float s[8];
#pragma unroll
        for (int i = 0; i < 8; i++) {
            int y = y0 + i;
            float v = dot16(q, (const ulonglong2*)(Ks + y*DC));
            s[i] = (y <= t) ? v : -3.0e38f;
        }
        float cm = fmaxf(fmaxf(fmaxf(s[0],s[1]),fmaxf(s[2],s[3])),
                         fmaxf(fmaxf(s[4],s[5]),fmaxf(s[6],s[7])));
        float mn = fmaxf(m, cm);
        float corr = __expf(m - mn);
        m = mn;
        u64 c2 = pk2(corr, corr);
#pragma unroll
        for (int j = 0; j < 8; j++) acc[j] = mul2(acc[j], c2);
        float ps = 0.f;
#pragma unroll
        for (int i = 0; i < 8; i++) {
            float pr = __expf(s[i] - mn); ps += pr;
            pv16(acc, pk2(pr, pr), (const ulonglong2*)(Vs + (y0+i)*DC));
        }
        l = fmaf(l, corr, ps);
    }

    // proj + PReLU + residual
    float alpha = s_alpha;
    u64 o2[8];
    float inv = 1.f / l;
    u64 iv = pk2(inv, inv);
#pragma unroll
    for (int j = 0; j < 8; j++) o2[j] = mul2(acc[j], iv);
    int obase = b*CC*FF*TT + f*TT + t;
#pragma unroll 4
    for (int co = 0; co < 64; co++) {
        const ulonglong2* wr = (const ulonglong2*)(pws + co*16);
        ulonglong2 wa = wr[0], wb = wr[1], wc = wr[2], wd = wr[3];
        u64 d0 = mul2(wa.x, o2[0]);
        u64 d1 = mul2(wa.y, o2[1]);
        d0 = fma2(wb.x, o2[2], d0);
        d1 = fma2(wb.y, o2[3], d1);
        d0 = fma2(wc.x, o2[4], d0);
        d1 = fma2(wc.y, o2[5], d1);
        d0 = fma2(wd.x, o2[6], d0);
        d1 = fma2(wd.y, o2[7], d1);
        float l0,h0,l1,h1;
        upk2(d0,l0,h0); upk2(d1,l1,h1);
        float r = psh[co] + (l0+h0) + (l1+h1);
        r = r >= 0.f ? r : alpha * r;
        int idx = obase + co*FF*TT;
        out[idx] = r + __ldg(&inp[idx]);
    }
}

// ---------------------------------------------------------------------------
extern "C" void kernel_launch(void* const* d_in, const int* in_sizes, int n_in,
                              void* d_out, int out_size)
{
    const float* inp = (const float*)d_in[0];

    int smc_bytes = (64*80 + 64*128 + 80 + 2) * (int)sizeof(float);
    cudaFuncSetAttribute(asa_conv, cudaFuncAttributeMaxDynamicSharedMemorySize, smc_bytes);
    asa_conv<<<(NPIX + 127)/128, 160, smc_bytes>>>(
        inp,
        (const float*)d_in[1],  (const float*)d_in[2],  (const float*)d_in[3],
        (const float*)d_in[4],  (const float*)d_in[5],  (const float*)d_in[6],
        (const float*)d_in[7],
        (const float*)d_in[8],  (const float*)d_in[9],  (const float*)d_in[10],
        (const float*)d_in[11], (const float*)d_in[12], (const float*)d_in[13],
        (const float*)d_in[14]);

    asa_fattn<<<BB*TT, 288>>>();

    int smem = (512*DC*2 + 64*16 + 64) * (int)sizeof(float);
    cudaFuncSetAttribute(asa_tattn, cudaFuncAttributeMaxDynamicSharedMemorySize, smem);
    asa_tattn<<<BB*FF*2, 256, smem>>>(
        inp,
        (const float*)d_in[15], (const float*)d_in[16], (const float*)d_in[17],
        (const float*)d_in[18], (const float*)d_in[19], (const float*)d_in[20],
        (const float*)d_in[21],
        (float*)d_out);
}

// round 5
// speedup vs baseline: 1.7842x; 1.1426x over previous
#include <cuda_runtime.h>

#define BB 2
#define CC 64
#define FF 257
#define TT 500
#define DC 16
#define BN_EPS 1e-5f
#define SCALE 0.25f
#define NPIX (BB*FF*TT)
#define FTSZ (FF*TT)

typedef unsigned long long u64;

__device__ __forceinline__ u64 pk2(float lo, float hi) {
    u64 r; asm("mov.b64 %0, {%1,%2};" : "=l"(r) : "f"(lo), "f"(hi)); return r;
}
__device__ __forceinline__ void upk2(u64 v, float& lo, float& hi) {
    asm("mov.b64 {%0,%1}, %2;" : "=f"(lo), "=f"(hi) : "l"(v));
}
__device__ __forceinline__ u64 fma2(u64 a, u64 b, u64 c) {
    u64 d; asm("fma.rn.f32x2 %0, %1, %2, %3;" : "=l"(d) : "l"(a), "l"(b), "l"(c)); return d;
}
__device__ __forceinline__ u64 mul2(u64 a, u64 b) {
    u64 d; asm("mul.rn.f32x2 %0, %1, %2;" : "=l"(d) : "l"(a), "l"(b)); return d;
}
__device__ __forceinline__ unsigned cvt_tf32(float x) {
    unsigned r; asm("cvt.rna.tf32.f32 %0, %1;" : "=r"(r) : "f"(x)); return r;
}
__device__ __forceinline__ void mma_tf32(
    float& d0, float& d1, float& d2, float& d3,
    unsigned a0, unsigned a1, unsigned a2, unsigned a3,
    unsigned b0, unsigned b1)
{
    asm("mma.sync.aligned.m16n8k8.row.col.f32.tf32.tf32.f32 "
        "{%0,%1,%2,%3},{%4,%5,%6,%7},{%8,%9},{%0,%1,%2,%3};"
        : "+f"(d0), "+f"(d1), "+f"(d2), "+f"(d3)
        : "r"(a0), "r"(a1), "r"(a2), "r"(a3), "r"(b0), "r"(b1));
}

// Scratch (device globals; no allocation allowed)
__device__ float g_qf[BB*TT*FF*DC];   // [b][t][f][c]
__device__ float g_kf[BB*TT*FF*DC];   // [b][t][f][c]
__device__ float g_vv[BB*TT*FF*DC];   // [b][t][f][c]
__device__ float g_qt[BB*FF*TT*DC];   // [b][f][t][c]
__device__ float g_kt[BB*FF*TT*DC];   // [b][f][t][c]
__device__ float g_fo[BB*FF*TT*DC];   // [b][f][t][c]

// ---------------------------------------------------------------------------
// Kernel 1: fused 1x1 convs (unchanged from R3/R4).
// ---------------------------------------------------------------------------
extern __shared__ float smc[];
__global__ __launch_bounds__(160) void asa_conv(
    const float* __restrict__ inp,
    const float* __restrict__ fw, const float* __restrict__ fb,
    const float* __restrict__ fg, const float* __restrict__ fbe,
    const float* __restrict__ fm, const float* __restrict__ fv,
    const float* __restrict__ fa,
    const float* __restrict__ tw, const float* __restrict__ tb,
    const float* __restrict__ tg, const float* __restrict__ tbe,
    const float* __restrict__ tm, const float* __restrict__ tv,
    const float* __restrict__ ta)
{
    float* ws = smc;               // [64][80]
    float* xs = ws + 64*80;        // [64][128]
    float* sh = xs + 64*128;       // [80]
    float* al = sh + 80;           // [2]

    int tid = threadIdx.x;

    for (int idx = tid; idx < 80*64; idx += 160) {
        int c = idx & 63, op = idx >> 6;
        int e = op >> 4, cc = op & 15;
        float w, g, vv;
        if (e < 3) { int o = 3*cc + e;      w = fw[o*64+c]; g = fg[o]; vv = fv[o]; }
        else       { int o2 = 2*cc + (e-3); w = tw[o2*64+c]; g = tg[o2]; vv = tv[o2]; }
        ws[c*80 + op] = w * (g * rsqrtf(vv + BN_EPS));
    }
    if (tid < 80) {
        int op = tid, e = op >> 4, cc = op & 15;
        float g, vv, m, b, be;
        if (e < 3) { int o = 3*cc + e;      g=fg[o]; vv=fv[o]; m=fm[o]; b=fb[o]; be=fbe[o]; }
        else       { int o2 = 2*cc + (e-3); g=tg[o2]; vv=tv[o2]; m=tm[o2]; b=tb[o2]; be=tbe[o2]; }
        sh[op] = (b - m) * (g * rsqrtf(vv + BN_EPS)) + be;
    }
    if (tid == 0) { al[0] = fa[0]; al[1] = ta[0]; }

    int p0 = blockIdx.x * 128;
    int b0 = p0 / FTSZ;
    int bend = (p0 + 127) / FTSZ;
    if (b0 == bend && p0 + 127 < NPIX) {
        int ft0 = p0 - b0*FTSZ;
        const float* src = inp + b0*CC*FTSZ + ft0;
        for (int i = tid; i < 64*32; i += 160) {
            int c = i >> 5, l4 = i & 31;
            ((float4*)xs)[c*32 + l4] = *(const float4*)(src + c*FTSZ + l4*4);
        }
    } else {
        for (int i = tid; i < 64*128; i += 160) {
            int c = i >> 7, lp = i & 127;
            int p = p0 + lp;
            float v = 0.f;
            if (p < NPIX) {
                int b = p / FTSZ;
                int ft = p - b*FTSZ;
                v = inp[(b*CC + c)*FTSZ + ft];
            }
            xs[c*128 + lp] = v;
        }
    }
    __syncthreads();

    int e  = tid >> 5;
    int pg = tid & 31;

    u64 acc[8][4];
#pragma unroll
    for (int j = 0; j < 8; j++)
#pragma unroll
        for (int x = 0; x < 4; x++) acc[j][x] = 0ull;

    const float* wbase = ws + e*16;
#pragma unroll 4
    for (int c = 0; c < 64; c++) {
        const ulonglong2* wr = (const ulonglong2*)(wbase + c*80);
        ulonglong2 wa = wr[0], wb = wr[1], wc2 = wr[2], wd = wr[3];
        float4 xv = ((const float4*)xs)[c*32 + pg];
        u64 x0 = pk2(xv.x, xv.x), x1 = pk2(xv.y, xv.y);
        u64 x2 = pk2(xv.z, xv.z), x3 = pk2(xv.w, xv.w);
        acc[0][0]=fma2(wa.x,x0,acc[0][0]); acc[0][1]=fma2(wa.x,x1,acc[0][1]);
        acc[0][2]=fma2(wa.x,x2,acc[0][2]); acc[0][3]=fma2(wa.x,x3,acc[0][3]);
        acc[1][0]=fma2(wa.y,x0,acc[1][0]); acc[1][1]=fma2(wa.y,x1,acc[1][1]);
        acc[1][2]=fma2(wa.y,x2,acc[1][2]); acc[1][3]=fma2(wa.y,x3,acc[1][3]);
        acc[2][0]=fma2(wb.x,x0,acc[2][0]); acc[2][1]=fma2(wb.x,x1,acc[2][1]);
        acc[2][2]=fma2(wb.x,x2,acc[2][2]); acc[2][3]=fma2(wb.x,x3,acc[2][3]);
        acc[3][0]=fma2(wb.y,x0,acc[3][0]); acc[3][1]=fma2(wb.y,x1,acc[3][1]);
        acc[3][2]=fma2(wb.y,x2,acc[3][2]); acc[3][3]=fma2(wb.y,x3,acc[3][3]);
        acc[4][0]=fma2(wc2.x,x0,acc[4][0]); acc[4][1]=fma2(wc2.x,x1,acc[4][1]);
        acc[4][2]=fma2(wc2.x,x2,acc[4][2]); acc[4][3]=fma2(wc2.x,x3,acc[4][3]);
        acc[5][0]=fma2(wc2.y,x0,acc[5][0]); acc[5][1]=fma2(wc2.y,x1,acc[5][1]);
        acc[5][2]=fma2(wc2.y,x2,acc[5][2]); acc[5][3]=fma2(wc2.y,x3,acc[5][3]);
        acc[6][0]=fma2(wd.x,x0,acc[6][0]); acc[6][1]=fma2(wd.x,x1,acc[6][1]);
        acc[6][2]=fma2(wd.x,x2,acc[6][2]); acc[6][3]=fma2(wd.x,x3,acc[6][3]);
        acc[7][0]=fma2(wd.y,x0,acc[7][0]); acc[7][1]=fma2(wd.y,x1,acc[7][1]);
        acc[7][2]=fma2(wd.y,x2,acc[7][2]); acc[7][3]=fma2(wd.y,x3,acc[7][3]);
    }

    float shv[16];
#pragma unroll
    for (int cc = 0; cc < 16; cc++) shv[cc] = sh[e*16 + cc];
    float alpha = (e < 3) ? al[0] : al[1];

#pragma unroll
    for (int px = 0; px < 4; px++) {
        int p = p0 + pg*4 + px;
        if (p >= NPIX) continue;
        int b = p / FTSZ;
        int ft = p - b*FTSZ;
        int f = ft / TT;
        int t = ft - f*TT;
        float y[16];
#pragma unroll
        for (int j = 0; j < 8; j++) upk2(acc[j][px], y[2*j], y[2*j+1]);
#pragma unroll
        for (int cc = 0; cc < 16; cc++) {
            float v = y[cc] + shv[cc];
            y[cc] = v >= 0.f ? v : alpha * v;
        }
        float* dst;
        if      (e == 0) dst = g_qf + ((b*TT + t)*FF + f)*DC;
        else if (e == 1) dst = g_kf + ((b*TT + t)*FF + f)*DC;
        else if (e == 2) dst = g_vv + ((b*TT + t)*FF + f)*DC;
        else if (e == 3) dst = g_qt + ((b*FF + f)*TT + t)*DC;
        else             dst = g_kt + ((b*FF + f)*TT + t)*DC;
#pragma unroll
        for (int i = 0; i < 4; i++)
            ((float4*)dst)[i] = make_float4(y[4*i], y[4*i+1], y[4*i+2], y[4*i+3]);
    }
}

// ---------------------------------------------------------------------------
// Kernel 2: frequency attention via tf32 mma.sync flash tiles.
// One CTA per (b,t), 9 warps. Warp tile = 16 queries; keys 0..256 in 33
// blocks of 8 (block 32 masked). K smem stride 20, V stride 24 (bank-free
// B-fragment loads).
// ---------------------------------------------------------------------------
#define KSTR 20
#define VSTR 24
__global__ __launch_bounds__(288) void asa_fattn()
{
    __shared__ float Ks[264*KSTR];
    __shared__ float Vs[264*VSTR];
    int bt = blockIdx.x;
    int b = bt / TT, t = bt % TT;
    int base = (b*TT + t)*FF*DC;
    int tid = threadIdx.x;

    // fill + tf32-convert K, V (rows >= FF zeroed)
    for (int i = tid; i < 264*4; i += 288) {
        int row = i >> 2, j4 = (i & 3) * 4;
        uint4 ku = make_uint4(0,0,0,0), vu = ku;
        if (row < FF) {
            float4 kk = *(const float4*)(g_kf + base + row*DC + j4);
            float4 vv = *(const float4*)(g_vv + base + row*DC + j4);
            ku.x = cvt_tf32(kk.x); ku.y = cvt_tf32(kk.y);
            ku.z = cvt_tf32(kk.z); ku.w = cvt_tf32(kk.w);
            vu.x = cvt_tf32(vv.x); vu.y = cvt_tf32(vv.y);
            vu.z = cvt_tf32(vv.z); vu.w = cvt_tf32(vv.w);
        }
        *(uint4*)(Ks + row*KSTR + j4) = ku;
        *(uint4*)(Vs + row*VSTR + j4) = vu;
    }
    __syncthreads();

    int warp = tid >> 5, lane = tid & 31;
    int g = lane >> 2, tig = lane & 3;
    int qsel = lane & ~3;
    int src1 = qsel | (tig >> 1);
    int src2 = src1 + 2;

    for (int tile = warp; tile < 17; tile += 9) {
        int fr0 = min(tile*16 + g, FF-1);
        int fr1 = min(tile*16 + g + 8, FF-1);
        const float* q0p = g_qf + base + fr0*DC;
        const float* q1p = g_qf + base + fr1*DC;
        unsigned qa[2][4];
#pragma unroll
        for (int ks = 0; ks < 2; ks++) {
            qa[ks][0] = cvt_tf32(q0p[ks*8 + tig]     * SCALE);
            qa[ks][1] = cvt_tf32(q1p[ks*8 + tig]     * SCALE);
            qa[ks][2] = cvt_tf32(q0p[ks*8 + tig + 4] * SCALE);
            qa[ks][3] = cvt_tf32(q1p[ks*8 + tig + 4] * SCALE);
        }
        float m0 = -3.0e38f, m1 = -3.0e38f, l0 = 0.f, l1 = 0.f;
        float oA[4] = {0,0,0,0}, oB[4] = {0,0,0,0};

        for (int kb = 0; kb < 33; kb++) {
            int krow = (kb*8 + g)*KSTR;
            unsigned k0 = __float_as_uint(Ks[krow + tig]);
            unsigned k1 = __float_as_uint(Ks[krow + tig + 4]);
            unsigned k2 = __float_as_uint(Ks[krow + tig + 8]);
            unsigned k3 = __float_as_uint(Ks[krow + tig + 12]);
            float s0 = 0.f, s1 = 0.f, s2 = 0.f, s3 = 0.f;
            mma_tf32(s0,s1,s2,s3, qa[0][0],qa[0][1],qa[0][2],qa[0][3], k0,k1);
            mma_tf32(s0,s1,s2,s3, qa[1][0],qa[1][1],qa[1][2],qa[1][3], k2,k3);
            if (kb == 32) {
                if (tig > 0) { s0 = -3.0e38f; s2 = -3.0e38f; }
                s1 = -3.0e38f; s3 = -3.0e38f;
            }
            float cm0 = fmaxf(s0, s1), cm1 = fmaxf(s2, s3);
            cm0 = fmaxf(cm0, __shfl_xor_sync(0xffffffffu, cm0, 1));
            cm0 = fmaxf(cm0, __shfl_xor_sync(0xffffffffu, cm0, 2));
            cm1 = fmaxf(cm1, __shfl_xor_sync(0xffffffffu, cm1, 1));
            cm1 = fmaxf(cm1, __shfl_xor_sync(0xffffffffu, cm1, 2));
            float mn0 = fmaxf(m0, cm0), mn1 = fmaxf(m1, cm1);
            float c0 = __expf(m0 - mn0), c1 = __expf(m1 - mn1);
            m0 = mn0; m1 = mn1;
            float p0 = __expf(s0 - mn0), p1 = __expf(s1 - mn0);
            float p2 = __expf(s2 - mn1), p3 = __expf(s3 - mn1);
            float ps0 = p0 + p1, ps1 = p2 + p3;
            ps0 += __shfl_xor_sync(0xffffffffu, ps0, 1);
            ps0 += __shfl_xor_sync(0xffffffffu, ps0, 2);
            ps1 += __shfl_xor_sync(0xffffffffu, ps1, 1);
            ps1 += __shfl_xor_sync(0xffffffffu, ps1, 2);
            l0 = l0*c0 + ps0; l1 = l1*c1 + ps1;
            oA[0] *= c0; oA[1] *= c0; oA[2] *= c1; oA[3] *= c1;
            oB[0] *= c0; oB[1] *= c0; oB[2] *= c1; oB[3] *= c1;
            // redistribute P (D-frag cols {2c,2c+1}) into A-frag cols {c,c+4}
            unsigned u0 = cvt_tf32(p0), u1 = cvt_tf32(p1);
            unsigned u2 = cvt_tf32(p2), u3 = cvt_tf32(p3);
            unsigned x0 = __shfl_sync(0xffffffffu, u0, src1);
            unsigned x1 = __shfl_sync(0xffffffffu, u1, src1);
            unsigned pa0 = (tig & 1) ? x1 : x0;
            unsigned y0 = __shfl_sync(0xffffffffu, u2, src1);
            unsigned y1 = __shfl_sync(0xffffffffu, u3, src1);
            unsigned pa1 = (tig & 1) ? y1 : y0;
            x0 = __shfl_sync(0xffffffffu, u0, src2);
            x1 = __shfl_sync(0xffffffffu, u1, src2);
            unsigned pa2 = (tig & 1) ? x1 : x0;
            y0 = __shfl_sync(0xffffffffu, u2, src2);
            y1 = __shfl_sync(0xffffffffu, u3, src2);
            unsigned pa3 = (tig & 1) ? y1 : y0;

            int vr0 = (kb*8 + tig)*VSTR, vr1 = (kb*8 + tig + 4)*VSTR;
            unsigned v0 = __float_as_uint(Vs[vr0 + g]);
            unsigned v1 = __float_as_uint(Vs[vr1 + g]);
            unsigned v2 = __float_as_uint(Vs[vr0 + g + 8]);
            unsigned v3 = __float_as_uint(Vs[vr1 + g + 8]);
            mma_tf32(oA[0],oA[1],oA[2],oA[3], pa0,pa1,pa2,pa3, v0,v1);
            mma_tf32(oB[0],oB[1],oB[2],oB[3], pa0,pa1,pa2,pa3, v2,v3);
        }
        float inv0 = 1.f / l0, inv1 = 1.f / l1;
        int f0 = tile*16 + g, f1 = f0 + 8;
        if (f0 < FF) {
            float* op = g_fo + ((b*FF + f0)*TT + t)*DC;
            *(float2*)(op + 2*tig)     = make_float2(oA[0]*inv0, oA[1]*inv0);
            *(float2*)(op + 8 + 2*tig) = make_float2(oB[0]*inv0, oB[1]*inv0);
        }
        if (f1 < FF) {
            float* op = g_fo + ((b*FF + f1)*TT + t)*DC;
            *(float2*)(op + 2*tig)     = make_float2(oA[2]*inv1, oA[3]*inv1);
            *(float2*)(op + 8 + 2*tig) = make_float2(oB[2]*inv1, oB[3]*inv1);
        }
    }
}

// ---------------------------------------------------------------------------
__device__ __forceinline__ float dot16(const u64 q[8], const ulonglong2* kr)
{
    ulonglong2 ka = kr[0], kb = kr[1], kc = kr[2], kd = kr[3];
    u64 d0 = mul2(q[0], ka.x);
    u64 d1 = mul2(q[1], ka.y);
    d0 = fma2(q[2], kb.x, d0);
    d1 = fma2(q[3], kb.y, d1);
    d0 = fma2(q[4], kc.x, d0);
    d1 = fma2(q[5], kc.y, d1);
    d0 = fma2(q[6], kd.x, d0);
    d1 = fma2(q[7], kd.y, d1);
    float l0, h0, l1, h1;
    upk2(d0, l0, h0); upk2(d1, l1, h1);
    return (l0 + h0) + (l1 + h1);
}

__device__ __forceinline__ void pv16(u64 acc[8], u64 p2, const ulonglong2* vr)
{
    ulonglong2 v0 = vr[0], v1 = vr[1], v2 = vr[2], v3 = vr[3];
    acc[0] = fma2(p2, v0.x, acc[0]); acc[1] = fma2(p2, v0.y, acc[1]);
    acc[2] = fma2(p2, v1.x, acc[2]); acc[3] = fma2(p2, v1.y, acc[3]);
    acc[4] = fma2(p2, v2.x, acc[4]); acc[5] = fma2(p2, v2.y, acc[5]);
    acc[6] = fma2(p2, v3.x, acc[6]); acc[7] = fma2(p2, v3.y, acc[7]);
}

__device__ __forceinline__ void load_q16(const float* g, u64 q[8])
{
    const ulonglong2* qp = (const ulonglong2*)g;
    u64 s2 = pk2(SCALE, SCALE);
    ulonglong2 a = qp[0], b = qp[1], c = qp[2], d = qp[3];
    q[0]=mul2(a.x,s2); q[1]=mul2(a.y,s2); q[2]=mul2(b.x,s2); q[3]=mul2(b.y,s2);
    q[4]=mul2(c.x,s2); q[5]=mul2(c.y,s2); q[6]=mul2(d.x,s2); q[7]=mul2(d.y,s2);
}

// ---------------------------------------------------------------------------
// Kernel 3: causal time attention + proj + residual (unchanged from R4).
// ---------------------------------------------------------------------------
extern __shared__ float sm3[];
__global__ __launch_bounds__(256) void asa_tattn(
    const float* __restrict__ inp,
    const float* __restrict__ pw, const float* __restrict__ pb,
    const float* __restrict__ pg, const float* __restrict__ pbe,
    const float* __restrict__ pm, const float* __restrict__ pv,
    const float* __restrict__ pa,
    float* __restrict__ out)
{
    float* Ks  = sm3;                 // 512*DC
    float* Vs  = sm3 + 512*DC;        // 512*DC
    float* pws = Vs + 512*DC;         // 64*16
    float* psh = pws + 64*16;         // 64
    __shared__ float s_alpha;

    int bf   = blockIdx.x >> 1;
    int half = blockIdx.x & 1;
    int b = bf / FF, f = bf % FF;
    int base = bf * TT * DC;
    int tid = threadIdx.x;

    int nrows = half ? 512 : 256;
    for (int i = tid; i < nrows*DC/4; i += 256) {
        float4 kk = make_float4(0,0,0,0), vv = kk;
        if (i < TT*DC/4) {
            kk = ((const float4*)(g_kt + base))[i];
            vv = ((const float4*)(g_fo + base))[i];
        }
        ((float4*)Ks)[i] = kk;
        ((float4*)Vs)[i] = vv;
    }
    for (int i = tid; i < 64*16; i += 256) {
        int o = i >> 4;
        pws[i] = pw[i] * (pg[o] * rsqrtf(pv[o] + BN_EPS));
    }
    if (tid < 64) {
        int o = tid;
        psh[o] = (pb[o] - pm[o]) * (pg[o] * rsqrtf(pv[o] + BN_EPS)) + pbe[o];
    }
    if (tid == 0) s_alpha = pa[0];
    __syncthreads();

    if (tid >= 250) return;
    int t = half*250 + tid;

    u64 q[8];
    load_q16(g_qt + base + t*DC, q);

    float m = -3.0e38f, l = 0.f;
    u64 acc[8];
#pragma unroll
    for (int j = 0; j < 8; j++) acc[j] = 0ull;

    for (int y0 = 0; y0 <= t; y0 += 8) {
        float s[8];
#pragma unroll
        for (int i = 0; i < 8; i++) {
            int y = y0 + i;
            float v = dot16(q, (const ulonglong2*)(Ks + y*DC));
            s[i] = (y <= t) ? v : -3.0e38f;
        }
        float cm = fmaxf(fmaxf(fmaxf(s[0],s[1]),fmaxf(s[2],s[3])),
                         fmaxf(fmaxf(s[4],s[5]),fmaxf(s[6],s[7])));
        float mn = fmaxf(m, cm);
        float corr = __expf(m - mn);
        m = mn;
        u64 c2 = pk2(corr, corr);
#pragma unroll
        for (int j = 0; j < 8; j++) acc[j] = mul2(acc[j], c2);
        float ps = 0.f;
#pragma unroll
        for (int i = 0; i < 8; i++) {
            float pr = __expf(s[i] - mn); ps += pr;
            pv16(acc, pk2(pr, pr), (const ulonglong2*)(Vs + (y0+i)*DC));
        }
        l = fmaf(l, corr, ps);
    }

    float alpha = s_alpha;
    u64 o2[8];
    float inv = 1.f / l;
    u64 iv = pk2(inv, inv);
#pragma unroll
    for (int j = 0; j < 8; j++) o2[j] = mul2(acc[j], iv);
    int obase = b*CC*FF*TT + f*TT + t;
#pragma unroll 4
    for (int co = 0; co < 64; co++) {
        const ulonglong2* wr = (const ulonglong2*)(pws + co*16);
        ulonglong2 wa = wr[0], wb = wr[1], wc = wr[2], wd = wr[3];
        u64 d0 = mul2(wa.x, o2[0]);
        u64 d1 = mul2(wa.y, o2[1]);
        d0 = fma2(wb.x, o2[2], d0);
        d1 = fma2(wb.y, o2[3], d1);
        d0 = fma2(wc.x, o2[4], d0);
        d1 = fma2(wc.y, o2[5], d1);
        d0 = fma2(wd.x, o2[6], d0);
        d1 = fma2(wd.y, o2[7], d1);
        float l0,h0,l1,h1;
        upk2(d0,l0,h0); upk2(d1,l1,h1);
        float r = psh[co] + (l0+h0) + (l1+h1);
        r = r >= 0.f ? r : alpha * r;
        int idx = obase + co*FF*TT;
        out[idx] = r + __ldg(&inp[idx]);
    }
}

// ---------------------------------------------------------------------------
extern "C" void kernel_launch(void* const* d_in, const int* in_sizes, int n_in,
                              void* d_out, int out_size)
{
    const float* inp = (const float*)d_in[0];

    int smc_bytes = (64*80 + 64*128 + 80 + 2) * (int)sizeof(float);
    cudaFuncSetAttribute(asa_conv, cudaFuncAttributeMaxDynamicSharedMemorySize, smc_bytes);
    asa_conv<<<(NPIX + 127)/128, 160, smc_bytes>>>(
        inp,
        (const float*)d_in[1],  (const float*)d_in[2],  (const float*)d_in[3],
        (const float*)d_in[4],  (const float*)d_in[5],  (const float*)d_in[6],
        (const float*)d_in[7],
        (const float*)d_in[8],  (const float*)d_in[9],  (const float*)d_in[10],
        (const float*)d_in[11], (const float*)d_in[12], (const float*)d_in[13],
        (const float*)d_in[14]);

    asa_fattn<<<BB*TT, 288>>>();

    int smem = (512*DC*2 + 64*16 + 64) * (int)sizeof(float);
    cudaFuncSetAttribute(asa_tattn, cudaFuncAttributeMaxDynamicSharedMemorySize, smem);
    asa_tattn<<<BB*FF*2, 256, smem>>>(
        inp,
        (const float*)d_in[15], (const float*)d_in[16], (const float*)d_in[17],
        (const float*)d_in[18], (const float*)d_in[19], (const float*)d_in[20],
        (const float*)d_in[21],
        (float*)d_out);
}

// round 6
// speedup vs baseline: 2.1322x; 1.1951x over previous
#include <cuda_runtime.h>

#define BB 2
#define CC 64
#define FF 257
#define TT 500
#define DC 16
#define BN_EPS 1e-5f
#define SCALE 0.25f
#define NPIX (BB*FF*TT)
#define FTSZ (FF*TT)

typedef unsigned long long u64;

__device__ __forceinline__ u64 pk2(float lo, float hi) {
    u64 r; asm("mov.b64 %0, {%1,%2};" : "=l"(r) : "f"(lo), "f"(hi)); return r;
}
__device__ __forceinline__ void upk2(u64 v, float& lo, float& hi) {
    asm("mov.b64 {%0,%1}, %2;" : "=f"(lo), "=f"(hi) : "l"(v));
}
__device__ __forceinline__ u64 fma2(u64 a, u64 b, u64 c) {
    u64 d; asm("fma.rn.f32x2 %0, %1, %2, %3;" : "=l"(d) : "l"(a), "l"(b), "l"(c)); return d;
}
__device__ __forceinline__ u64 mul2(u64 a, u64 b) {
    u64 d; asm("mul.rn.f32x2 %0, %1, %2;" : "=l"(d) : "l"(a), "l"(b)); return d;
}
__device__ __forceinline__ unsigned cvt_tf32(float x) {
    unsigned r; asm("cvt.rna.tf32.f32 %0, %1;" : "=r"(r) : "f"(x)); return r;
}
__device__ __forceinline__ void mma_tf32(
    float& d0, float& d1, float& d2, float& d3,
    unsigned a0, unsigned a1, unsigned a2, unsigned a3,
    unsigned b0, unsigned b1)
{
    asm("mma.sync.aligned.m16n8k8.row.col.f32.tf32.tf32.f32 "
        "{%0,%1,%2,%3},{%4,%5,%6,%7},{%8,%9},{%0,%1,%2,%3};"
        : "+f"(d0), "+f"(d1), "+f"(d2), "+f"(d3)
        : "r"(a0), "r"(a1), "r"(a2), "r"(a3), "r"(b0), "r"(b1));
}

// Scratch (device globals; no allocation allowed)
__device__ float g_qf[BB*TT*FF*DC];   // [b][t][f][c]
__device__ float g_kf[BB*TT*FF*DC];   // [b][t][f][c]
__device__ float g_vv[BB*TT*FF*DC];   // [b][t][f][c]
__device__ float g_qt[BB*FF*TT*DC];   // [b][f][t][c]
__device__ float g_kt[BB*FF*TT*DC];   // [b][f][t][c]
__device__ float g_fo[BB*FF*TT*DC];   // [b][f][t][c]

// ---------------------------------------------------------------------------
// Kernel 1: fused 1x1 convs (unchanged).
// ---------------------------------------------------------------------------
extern __shared__ float smc[];
__global__ __launch_bounds__(160) void asa_conv(
    const float* __restrict__ inp,
    const float* __restrict__ fw, const float* __restrict__ fb,
    const float* __restrict__ fg, const float* __restrict__ fbe,
    const float* __restrict__ fm, const float* __restrict__ fv,
    const float* __restrict__ fa,
    const float* __restrict__ tw, const float* __restrict__ tb,
    const float* __restrict__ tg, const float* __restrict__ tbe,
    const float* __restrict__ tm, const float* __restrict__ tv,
    const float* __restrict__ ta)
{
    float* ws = smc;               // [64][80]
    float* xs = ws + 64*80;        // [64][128]
    float* sh = xs + 64*128;       // [80]
    float* al = sh + 80;           // [2]

    int tid = threadIdx.x;

    for (int idx = tid; idx < 80*64; idx += 160) {
        int c = idx & 63, op = idx >> 6;
        int e = op >> 4, cc = op & 15;
        float w, g, vv;
        if (e < 3) { int o = 3*cc + e;      w = fw[o*64+c]; g = fg[o]; vv = fv[o]; }
        else       { int o2 = 2*cc + (e-3); w = tw[o2*64+c]; g = tg[o2]; vv = tv[o2]; }
        ws[c*80 + op] = w * (g * rsqrtf(vv + BN_EPS));
    }
    if (tid < 80) {
        int op = tid, e = op >> 4, cc = op & 15;
        float g, vv, m, b, be;
        if (e < 3) { int o = 3*cc + e;      g=fg[o]; vv=fv[o]; m=fm[o]; b=fb[o]; be=fbe[o]; }
        else       { int o2 = 2*cc + (e-3); g=tg[o2]; vv=tv[o2]; m=tm[o2]; b=tb[o2]; be=tbe[o2]; }
        sh[op] = (b - m) * (g * rsqrtf(vv + BN_EPS)) + be;
    }
    if (tid == 0) { al[0] = fa[0]; al[1] = ta[0]; }

    int p0 = blockIdx.x * 128;
    int b0 = p0 / FTSZ;
    int bend = (p0 + 127) / FTSZ;
    if (b0 == bend && p0 + 127 < NPIX) {
        int ft0 = p0 - b0*FTSZ;
        const float* src = inp + b0*CC*FTSZ + ft0;
        for (int i = tid; i < 64*32; i += 160) {
            int c = i >> 5, l4 = i & 31;
            ((float4*)xs)[c*32 + l4] = *(const float4*)(src + c*FTSZ + l4*4);
        }
    } else {
        for (int i = tid; i < 64*128; i += 160) {
            int c = i >> 7, lp = i & 127;
            int p = p0 + lp;
            float v = 0.f;
            if (p < NPIX) {
                int b = p / FTSZ;
                int ft = p - b*FTSZ;
                v = inp[(b*CC + c)*FTSZ + ft];
            }
            xs[c*128 + lp] = v;
        }
    }
    __syncthreads();

    int e  = tid >> 5;
    int pg = tid & 31;

    u64 acc[8][4];
#pragma unroll
    for (int j = 0; j < 8; j++)
#pragma unroll
        for (int x = 0; x < 4; x++) acc[j][x] = 0ull;

    const float* wbase = ws + e*16;
#pragma unroll 4
    for (int c = 0; c < 64; c++) {
        const ulonglong2* wr = (const ulonglong2*)(wbase + c*80);
        ulonglong2 wa = wr[0], wb = wr[1], wc2 = wr[2], wd = wr[3];
        float4 xv = ((const float4*)xs)[c*32 + pg];
        u64 x0 = pk2(xv.x, xv.x), x1 = pk2(xv.y, xv.y);
        u64 x2 = pk2(xv.z, xv.z), x3 = pk2(xv.w, xv.w);
        acc[0][0]=fma2(wa.x,x0,acc[0][0]); acc[0][1]=fma2(wa.x,x1,acc[0][1]);
        acc[0][2]=fma2(wa.x,x2,acc[0][2]); acc[0][3]=fma2(wa.x,x3,acc[0][3]);
        acc[1][0]=fma2(wa.y,x0,acc[1][0]); acc[1][1]=fma2(wa.y,x1,acc[1][1]);
        acc[1][2]=fma2(wa.y,x2,acc[1][2]); acc[1][3]=fma2(wa.y,x3,acc[1][3]);
        acc[2][0]=fma2(wb.x,x0,acc[2][0]); acc[2][1]=fma2(wb.x,x1,acc[2][1]);
        acc[2][2]=fma2(wb.x,x2,acc[2][2]); acc[2][3]=fma2(wb.x,x3,acc[2][3]);
        acc[3][0]=fma2(wb.y,x0,acc[3][0]); acc[3][1]=fma2(wb.y,x1,acc[3][1]);
        acc[3][2]=fma2(wb.y,x2,acc[3][2]); acc[3][3]=fma2(wb.y,x3,acc[3][3]);
        acc[4][0]=fma2(wc2.x,x0,acc[4][0]); acc[4][1]=fma2(wc2.x,x1,acc[4][1]);
        acc[4][2]=fma2(wc2.x,x2,acc[4][2]); acc[4][3]=fma2(wc2.x,x3,acc[4][3]);
        acc[5][0]=fma2(wc2.y,x0,acc[5][0]); acc[5][1]=fma2(wc2.y,x1,acc[5][1]);
        acc[5][2]=fma2(wc2.y,x2,acc[5][2]); acc[5][3]=fma2(wc2.y,x3,acc[5][3]);
        acc[6][0]=fma2(wd.x,x0,acc[6][0]); acc[6][1]=fma2(wd.x,x1,acc[6][1]);
        acc[6][2]=fma2(wd.x,x2,acc[6][2]); acc[6][3]=fma2(wd.x,x3,acc[6][3]);
        acc[7][0]=fma2(wd.y,x0,acc[7][0]); acc[7][1]=fma2(wd.y,x1,acc[7][1]);
        acc[7][2]=fma2(wd.y,x2,acc[7][2]); acc[7][3]=fma2(wd.y,x3,acc[7][3]);
    }

    float shv[16];
#pragma unroll
    for (int cc = 0; cc < 16; cc++) shv[cc] = sh[e*16 + cc];
    float alpha = (e < 3) ? al[0] : al[1];

#pragma unroll
    for (int px = 0; px < 4; px++) {
        int p = p0 + pg*4 + px;
        if (p >= NPIX) continue;
        int b = p / FTSZ;
        int ft = p - b*FTSZ;
        int f = ft / TT;
        int t = ft - f*TT;
        float y[16];
#pragma unroll
        for (int j = 0; j < 8; j++) upk2(acc[j][px], y[2*j], y[2*j+1]);
#pragma unroll
        for (int cc = 0; cc < 16; cc++) {
            float v = y[cc] + shv[cc];
            y[cc] = v >= 0.f ? v : alpha * v;
        }
        float* dst;
        if      (e == 0) dst = g_qf + ((b*TT + t)*FF + f)*DC;
        else if (e == 1) dst = g_kf + ((b*TT + t)*FF + f)*DC;
        else if (e == 2) dst = g_vv + ((b*TT + t)*FF + f)*DC;
        else if (e == 3) dst = g_qt + ((b*FF + f)*TT + t)*DC;
        else             dst = g_kt + ((b*FF + f)*TT + t)*DC;
#pragma unroll
        for (int i = 0; i < 4; i++)
            ((float4*)dst)[i] = make_float4(y[4*i], y[4*i+1], y[4*i+2], y[4*i+3]);
    }
}

// ---------------------------------------------------------------------------
// Kernel 2: frequency attention via tf32 mma (unchanged from R5).
// ---------------------------------------------------------------------------
#define KSTR 20
#define VSTR 24
__global__ __launch_bounds__(288) void asa_fattn()
{
    __shared__ float Ks[264*KSTR];
    __shared__ float Vs[264*VSTR];
    int bt = blockIdx.x;
    int b = bt / TT, t = bt % TT;
    int base = (b*TT + t)*FF*DC;
    int tid = threadIdx.x;

    for (int i = tid; i < 264*4; i += 288) {
        int row = i >> 2, j4 = (i & 3) * 4;
        uint4 ku = make_uint4(0,0,0,0), vu = ku;
        if (row < FF) {
            float4 kk = *(const float4*)(g_kf + base + row*DC + j4);
            float4 vv = *(const float4*)(g_vv + base + row*DC + j4);
            ku.x = cvt_tf32(kk.x); ku.y = cvt_tf32(kk.y);
            ku.z = cvt_tf32(kk.z); ku.w = cvt_tf32(kk.w);
            vu.x = cvt_tf32(vv.x); vu.y = cvt_tf32(vv.y);
            vu.z = cvt_tf32(vv.z); vu.w = cvt_tf32(vv.w);
        }
        *(uint4*)(Ks + row*KSTR + j4) = ku;
        *(uint4*)(Vs + row*VSTR + j4) = vu;
    }
    __syncthreads();

    int warp = tid >> 5, lane = tid & 31;
    int g = lane >> 2, tig = lane & 3;
    int qsel = lane & ~3;
    int src1 = qsel | (tig >> 1);
    int src2 = src1 + 2;

    for (int tile = warp; tile < 17; tile += 9) {
        int fr0 = min(tile*16 + g, FF-1);
        int fr1 = min(tile*16 + g + 8, FF-1);
        const float* q0p = g_qf + base + fr0*DC;
        const float* q1p = g_qf + base + fr1*DC;
        unsigned qa[2][4];
#pragma unroll
        for (int ks = 0; ks < 2; ks++) {
            qa[ks][0] = cvt_tf32(q0p[ks*8 + tig]     * SCALE);
            qa[ks][1] = cvt_tf32(q1p[ks*8 + tig]     * SCALE);
            qa[ks][2] = cvt_tf32(q0p[ks*8 + tig + 4] * SCALE);
            qa[ks][3] = cvt_tf32(q1p[ks*8 + tig + 4] * SCALE);
        }
        float m0 = -3.0e38f, m1 = -3.0e38f, l0 = 0.f, l1 = 0.f;
        float oA[4] = {0,0,0,0}, oB[4] = {0,0,0,0};

        for (int kb = 0; kb < 33; kb++) {
            int krow = (kb*8 + g)*KSTR;
            unsigned k0 = __float_as_uint(Ks[krow + tig]);
            unsigned k1 = __float_as_uint(Ks[krow + tig + 4]);
            unsigned k2 = __float_as_uint(Ks[krow + tig + 8]);
            unsigned k3 = __float_as_uint(Ks[krow + tig + 12]);
            float s0 = 0.f, s1 = 0.f, s2 = 0.f, s3 = 0.f;
            mma_tf32(s0,s1,s2,s3, qa[0][0],qa[0][1],qa[0][2],qa[0][3], k0,k1);
            mma_tf32(s0,s1,s2,s3, qa[1][0],qa[1][1],qa[1][2],qa[1][3], k2,k3);
            if (kb == 32) {
                if (tig > 0) { s0 = -3.0e38f; s2 = -3.0e38f; }
                s1 = -3.0e38f; s3 = -3.0e38f;
            }
            float cm0 = fmaxf(s0, s1), cm1 = fmaxf(s2, s3);
            cm0 = fmaxf(cm0, __shfl_xor_sync(0xffffffffu, cm0, 1));
            cm0 = fmaxf(cm0, __shfl_xor_sync(0xffffffffu, cm0, 2));
            cm1 = fmaxf(cm1, __shfl_xor_sync(0xffffffffu, cm1, 1));
            cm1 = fmaxf(cm1, __shfl_xor_sync(0xffffffffu, cm1, 2));
            float mn0 = fmaxf(m0, cm0), mn1 = fmaxf(m1, cm1);
            float c0 = __expf(m0 - mn0), c1 = __expf(m1 - mn1);
            m0 = mn0; m1 = mn1;
            float p0 = __expf(s0 - mn0), p1 = __expf(s1 - mn0);
            float p2 = __expf(s2 - mn1), p3 = __expf(s3 - mn1);
            float ps0 = p0 + p1, ps1 = p2 + p3;
            ps0 += __shfl_xor_sync(0xffffffffu, ps0, 1);
            ps0 += __shfl_xor_sync(0xffffffffu, ps0, 2);
            ps1 += __shfl_xor_sync(0xffffffffu, ps1, 1);
            ps1 += __shfl_xor_sync(0xffffffffu, ps1, 2);
            l0 = l0*c0 + ps0; l1 = l1*c1 + ps1;
            oA[0] *= c0; oA[1] *= c0; oA[2] *= c1; oA[3] *= c1;
            oB[0] *= c0; oB[1] *= c0; oB[2] *= c1; oB[3] *= c1;
            unsigned u0 = cvt_tf32(p0), u1 = cvt_tf32(p1);
            unsigned u2 = cvt_tf32(p2), u3 = cvt_tf32(p3);
            unsigned x0 = __shfl_sync(0xffffffffu, u0, src1);
            unsigned x1 = __shfl_sync(0xffffffffu, u1, src1);
            unsigned pa0 = (tig & 1) ? x1 : x0;
            unsigned y0 = __shfl_sync(0xffffffffu, u2, src1);
            unsigned y1 = __shfl_sync(0xffffffffu, u3, src1);
            unsigned pa1 = (tig & 1) ? y1 : y0;
            x0 = __shfl_sync(0xffffffffu, u0, src2);
            x1 = __shfl_sync(0xffffffffu, u1, src2);
            unsigned pa2 = (tig & 1) ? x1 : x0;
            y0 = __shfl_sync(0xffffffffu, u2, src2);
            y1 = __shfl_sync(0xffffffffu, u3, src2);
            unsigned pa3 = (tig & 1) ? y1 : y0;

            int vr0 = (kb*8 + tig)*VSTR, vr1 = (kb*8 + tig + 4)*VSTR;
            unsigned v0 = __float_as_uint(Vs[vr0 + g]);
            unsigned v1 = __float_as_uint(Vs[vr1 + g]);
            unsigned v2 = __float_as_uint(Vs[vr0 + g + 8]);
            unsigned v3 = __float_as_uint(Vs[vr1 + g + 8]);
            mma_tf32(oA[0],oA[1],oA[2],oA[3], pa0,pa1,pa2,pa3, v0,v1);
            mma_tf32(oB[0],oB[1],oB[2],oB[3], pa0,pa1,pa2,pa3, v2,v3);
        }
        float inv0 = 1.f / l0, inv1 = 1.f / l1;
        int f0 = tile*16 + g, f1 = f0 + 8;
        if (f0 < FF) {
            float* op = g_fo + ((b*FF + f0)*TT + t)*DC;
            *(float2*)(op + 2*tig)     = make_float2(oA[0]*inv0, oA[1]*inv0);
            *(float2*)(op + 8 + 2*tig) = make_float2(oB[0]*inv0, oB[1]*inv0);
        }
        if (f1 < FF) {
            float* op = g_fo + ((b*FF + f1)*TT + t)*DC;
            *(float2*)(op + 2*tig)     = make_float2(oA[2]*inv1, oA[3]*inv1);
            *(float2*)(op + 8 + 2*tig) = make_float2(oB[2]*inv1, oB[3]*inv1);
        }
    }
}

// ---------------------------------------------------------------------------
// Kernel 3: causal time attention via tf32 mma + proj + residual.
// One CTA per (b,f), 8 warps. Warp takes tiles {w, 15-w, 16+w, 31-w}
// (exactly 132 key-blocks each). Diagonal blocks masked per element.
// ---------------------------------------------------------------------------
extern __shared__ float sm3[];
__global__ __launch_bounds__(256) void asa_tattn(
    const float* __restrict__ inp,
    const float* __restrict__ pw, const float* __restrict__ pb,
    const float* __restrict__ pg, const float* __restrict__ pbe,
    const float* __restrict__ pm, const float* __restrict__ pv,
    const float* __restrict__ pa,
    float* __restrict__ out)
{
    float* Ks   = sm3;                    // 512*KSTR
    float* Vs   = Ks + 512*KSTR;          // 512*VSTR
    float* pws  = Vs + 512*VSTR;          // 64*16
    float* psh  = pws + 64*16;            // 64
    float* obuf = psh + 64;               // 8 warps * 16*17
    __shared__ float s_alpha;

    int bf = blockIdx.x;
    int b = bf / FF, f = bf % FF;
    int base = bf * TT * DC;
    int tid = threadIdx.x;

    for (int i = tid; i < 512*4; i += 256) {
        int row = i >> 2, j4 = (i & 3) * 4;
        uint4 ku = make_uint4(0,0,0,0), vu = ku;
        if (row < TT) {
            float4 kk = *(const float4*)(g_kt + base + row*DC + j4);
            float4 vv = *(const float4*)(g_fo + base + row*DC + j4);
            ku.x = cvt_tf32(kk.x); ku.y = cvt_tf32(kk.y);
            ku.z = cvt_tf32(kk.z); ku.w = cvt_tf32(kk.w);
            vu.x = cvt_tf32(vv.x); vu.y = cvt_tf32(vv.y);
            vu.z = cvt_tf32(vv.z); vu.w = cvt_tf32(vv.w);
        }
        *(uint4*)(Ks + row*KSTR + j4) = ku;
        *(uint4*)(Vs + row*VSTR + j4) = vu;
    }
    for (int i = tid; i < 64*16; i += 256) {
        int o = i >> 4;
        pws[i] = pw[i] * (pg[o] * rsqrtf(pv[o] + BN_EPS));
    }
    if (tid < 64) {
        int o = tid;
        psh[o] = (pb[o] - pm[o]) * (pg[o] * rsqrtf(pv[o] + BN_EPS)) + pbe[o];
    }
    if (tid == 0) s_alpha = pa[0];
    __syncthreads();

    int warp = tid >> 5, lane = tid & 31;
    int g = lane >> 2, tig = lane & 3;
    int qsel = lane & ~3;
    int src1 = qsel | (tig >> 1);
    int src2 = src1 + 2;
    float alpha = s_alpha;
    float* ob = obuf + warp * (16*17);

    int tiles[4] = { warp, 15 - warp, 16 + warp, 31 - warp };

#pragma unroll
    for (int ti = 0; ti < 4; ti++) {
        int tile = tiles[ti];
        int qt0 = tile * 16;
        int ta = qt0 + g;          // query t of rows g (may exceed TT-1 on tail)
        int tb = qt0 + g + 8;
        int tr0 = min(ta, TT-1), tr1 = min(tb, TT-1);
        const float* q0p = g_qt + base + tr0*DC;
        const float* q1p = g_qt + base + tr1*DC;
        unsigned qa[2][4];
#pragma unroll
        for (int ks = 0; ks < 2; ks++) {
            qa[ks][0] = cvt_tf32(q0p[ks*8 + tig]     * SCALE);
            qa[ks][1] = cvt_tf32(q1p[ks*8 + tig]     * SCALE);
            qa[ks][2] = cvt_tf32(q0p[ks*8 + tig + 4] * SCALE);
            qa[ks][3] = cvt_tf32(q1p[ks*8 + tig + 4] * SCALE);
        }
        float m0 = -3.0e38f, m1 = -3.0e38f, l0 = 0.f, l1 = 0.f;
        float oA[4] = {0,0,0,0}, oB[4] = {0,0,0,0};

        int kbmax = (qt0 + 15) >> 3;   // inclusive
        for (int kb = 0; kb <= kbmax; kb++) {
            int krow = (kb*8 + g)*KSTR;
            unsigned k0 = __float_as_uint(Ks[krow + tig]);
            unsigned k1 = __float_as_uint(Ks[krow + tig + 4]);
            unsigned k2 = __float_as_uint(Ks[krow + tig + 8]);
            unsigned k3 = __float_as_uint(Ks[krow + tig + 12]);
            float s0 = 0.f, s1 = 0.f, s2 = 0.f, s3 = 0.f;
            mma_tf32(s0,s1,s2,s3, qa[0][0],qa[0][1],qa[0][2],qa[0][3], k0,k1);
            mma_tf32(s0,s1,s2,s3, qa[1][0],qa[1][1],qa[1][2],qa[1][3], k2,k3);
            if (kb*8 + 7 > qt0) {      // diagonal / tail masking
                int y0 = kb*8 + 2*tig, y1 = y0 + 1;
                if (y0 > ta) s0 = -3.0e38f;
                if (y1 > ta) s1 = -3.0e38f;
                if (y0 > tb) s2 = -3.0e38f;
                if (y1 > tb) s3 = -3.0e38f;
            }
            float cm0 = fmaxf(s0, s1), cm1 = fmaxf(s2, s3);
            cm0 = fmaxf(cm0, __shfl_xor_sync(0xffffffffu, cm0, 1));
            cm0 = fmaxf(cm0, __shfl_xor_sync(0xffffffffu, cm0, 2));
            cm1 = fmaxf(cm1, __shfl_xor_sync(0xffffffffu, cm1, 1));
            cm1 = fmaxf(cm1, __shfl_xor_sync(0xffffffffu, cm1, 2));
            float mn0 = fmaxf(m0, cm0), mn1 = fmaxf(m1, cm1);
            float c0 = __expf(m0 - mn0), c1 = __expf(m1 - mn1);
            m0 = mn0; m1 = mn1;
            float p0 = __expf(s0 - mn0), p1 = __expf(s1 - mn0);
            float p2 = __expf(s2 - mn1), p3 = __expf(s3 - mn1);
            float ps0 = p0 + p1, ps1 = p2 + p3;
            ps0 += __shfl_xor_sync(0xffffffffu, ps0, 1);
            ps0 += __shfl_xor_sync(0xffffffffu, ps0, 2);
            ps1 += __shfl_xor_sync(0xffffffffu, ps1, 1);
            ps1 += __shfl_xor_sync(0xffffffffu, ps1, 2);
            l0 = l0*c0 + ps0; l1 = l1*c1 + ps1;
            oA[0] *= c0; oA[1] *= c0; oA[2] *= c1; oA[3] *= c1;
            oB[0] *= c0; oB[1] *= c0; oB[2] *= c1; oB[3] *= c1;
            unsigned u0 = cvt_tf32(p0), u1 = cvt_tf32(p1);
            unsigned u2 = cvt_tf32(p2), u3 = cvt_tf32(p3);
            unsigned x0 = __shfl_sync(0xffffffffu, u0, src1);
            unsigned x1 = __shfl_sync(0xffffffffu, u1, src1);
            unsigned pa0 = (tig & 1) ? x1 : x0;
            unsigned y0s = __shfl_sync(0xffffffffu, u2, src1);
            unsigned y1s = __shfl_sync(0xffffffffu, u3, src1);
            unsigned pa1 = (tig & 1) ? y1s : y0s;
            x0 = __shfl_sync(0xffffffffu, u0, src2);
            x1 = __shfl_sync(0xffffffffu, u1, src2);
            unsigned pa2 = (tig & 1) ? x1 : x0;
            y0s = __shfl_sync(0xffffffffu, u2, src2);
            y1s = __shfl_sync(0xffffffffu, u3, src2);
            unsigned pa3 = (tig & 1) ? y1s : y0s;

            int vr0 = (kb*8 + tig)*VSTR, vr1 = (kb*8 + tig + 4)*VSTR;
            unsigned v0 = __float_as_uint(Vs[vr0 + g]);
            unsigned v1 = __float_as_uint(Vs[vr1 + g]);
            unsigned v2 = __float_as_uint(Vs[vr0 + g + 8]);
            unsigned v3 = __float_as_uint(Vs[vr1 + g + 8]);
            mma_tf32(oA[0],oA[1],oA[2],oA[3], pa0,pa1,pa2,pa3, v0,v1);
            mma_tf32(oB[0],oB[1],oB[2],oB[3], pa0,pa1,pa2,pa3, v2,v3);
        }
        // stage normalized o into smem tile [16 queries][16 dc] (stride 17)
        float inv0 = 1.f / l0, inv1 = 1.f / l1;
        ob[g*17 + 2*tig]          = oA[0]*inv0;
        ob[g*17 + 2*tig + 1]      = oA[1]*inv0;
        ob[g*17 + 8 + 2*tig]      = oB[0]*inv0;
        ob[g*17 + 8 + 2*tig + 1]  = oB[1]*inv0;
        ob[(g+8)*17 + 2*tig]         = oA[2]*inv1;
        ob[(g+8)*17 + 2*tig + 1]     = oA[3]*inv1;
        ob[(g+8)*17 + 8 + 2*tig]     = oB[2]*inv1;
        ob[(g+8)*17 + 8 + 2*tig + 1] = oB[3]*inv1;
        __syncwarp();

        // proj + PReLU + residual: lane -> query (lane&15), channel half (lane>>4)
        int qi = lane & 15;
        int t = qt0 + qi;
        if (t < TT) {
            const float* orow = ob + qi*17;
            u64 o2[8];
#pragma unroll
            for (int j = 0; j < 8; j++) o2[j] = pk2(orow[2*j], orow[2*j+1]);
            int c0 = (lane >> 4) * 32;
            int obase = b*CC*FTSZ + f*TT + t;
#pragma unroll 4
            for (int j = 0; j < 32; j++) {
                int co = c0 + j;
                const ulonglong2* wr = (const ulonglong2*)(pws + co*16);
                ulonglong2 wa = wr[0], wb = wr[1], wc = wr[2], wd = wr[3];
                u64 d0 = mul2(wa.x, o2[0]);
                u64 d1 = mul2(wa.y, o2[1]);
                d0 = fma2(wb.x, o2[2], d0);
                d1 = fma2(wb.y, o2[3], d1);
                d0 = fma2(wc.x, o2[4], d0);
                d1 = fma2(wc.y, o2[5], d1);
                d0 = fma2(wd.x, o2[6], d0);
                d1 = fma2(wd.y, o2[7], d1);
                float lo0,hi0,lo1,hi1;
                upk2(d0,lo0,hi0); upk2(d1,lo1,hi1);
                float r = psh[co] + (lo0+hi0) + (lo1+hi1);
                r = r >= 0.f ? r : alpha * r;
                int idx = obase + co*FTSZ;
                out[idx] = r + __ldg(&inp[idx]);
            }
        }
        __syncwarp();
    }
}

// ---------------------------------------------------------------------------
extern "C" void kernel_launch(void* const* d_in, const int* in_sizes, int n_in,
                              void* d_out, int out_size)
{
    const float* inp = (const float*)d_in[0];

    int smc_bytes = (64*80 + 64*128 + 80 + 2) * (int)sizeof(float);
    cudaFuncSetAttribute(asa_conv, cudaFuncAttributeMaxDynamicSharedMemorySize, smc_bytes);
    asa_conv<<<(NPIX + 127)/128, 160, smc_bytes>>>(
        inp,
        (const float*)d_in[1],  (const float*)d_in[2],  (const float*)d_in[3],
        (const float*)d_in[4],  (const float*)d_in[5],  (const float*)d_in[6],
        (const float*)d_in[7],
        (const float*)d_in[8],  (const float*)d_in[9],  (const float*)d_in[10],
        (const float*)d_in[11], (const float*)d_in[12], (const float*)d_in[13],
        (const float*)d_in[14]);

    asa_fattn<<<BB*TT, 288>>>();

    int sm3_bytes = (512*KSTR + 512*VSTR + 64*16 + 64 + 8*16*17) * (int)sizeof(float);
    cudaFuncSetAttribute(asa_tattn, cudaFuncAttributeMaxDynamicSharedMemorySize, sm3_bytes);
    asa_tattn<<<BB*FF, 256, sm3_bytes>>>(
        inp,
        (const float*)d_in[15], (const float*)d_in[16], (const float*)d_in[17],
        (const float*)d_in[18], (const float*)d_in[19], (const float*)d_in[20],
        (const float*)d_in[21],
        (float*)d_out);
}

// round 7
// speedup vs baseline: 2.3579x; 1.1058x over previous
#include <cuda_runtime.h>

#define BB 2
#define CC 64
#define FF 257
#define TT 500
#define DC 16
#define BN_EPS 1e-5f
#define SCALE 0.25f
#define NPIX (BB*FF*TT)
#define FTSZ (FF*TT)

typedef unsigned long long u64;

__device__ __forceinline__ u64 pk2(float lo, float hi) {
    u64 r; asm("mov.b64 %0, {%1,%2};" : "=l"(r) : "f"(lo), "f"(hi)); return r;
}
__device__ __forceinline__ void upk2(u64 v, float& lo, float& hi) {
    asm("mov.b64 {%0,%1}, %2;" : "=f"(lo), "=f"(hi) : "l"(v));
}
__device__ __forceinline__ u64 fma2(u64 a, u64 b, u64 c) {
    u64 d; asm("fma.rn.f32x2 %0, %1, %2, %3;" : "=l"(d) : "l"(a), "l"(b), "l"(c)); return d;
}
__device__ __forceinline__ u64 mul2(u64 a, u64 b) {
    u64 d; asm("mul.rn.f32x2 %0, %1, %2;" : "=l"(d) : "l"(a), "l"(b)); return d;
}
__device__ __forceinline__ unsigned cvt_tf32(float x) {
    unsigned r; asm("cvt.rna.tf32.f32 %0, %1;" : "=r"(r) : "f"(x)); return r;
}
__device__ __forceinline__ void mma_tf32(
    float& d0, float& d1, float& d2, float& d3,
    unsigned a0, unsigned a1, unsigned a2, unsigned a3,
    unsigned b0, unsigned b1)
{
    asm("mma.sync.aligned.m16n8k8.row.col.f32.tf32.tf32.f32 "
        "{%0,%1,%2,%3},{%4,%5,%6,%7},{%8,%9},{%0,%1,%2,%3};"
        : "+f"(d0), "+f"(d1), "+f"(d2), "+f"(d3)
        : "r"(a0), "r"(a1), "r"(a2), "r"(a3), "r"(b0), "r"(b1));
}

// Scratch (device globals; no allocation allowed)
__device__ float g_qf[BB*TT*FF*DC];   // [b][t][f][c]
__device__ float g_kf[BB*TT*FF*DC];   // [b][t][f][c]
__device__ float g_vv[BB*TT*FF*DC];   // [b][t][f][c]
__device__ float g_qt[BB*FF*TT*DC];   // [b][f][t][c]
__device__ float g_kt[BB*FF*TT*DC];   // [b][f][t][c]
__device__ float g_fo[BB*FF*TT*DC];   // [b][f][t][c]

// ---------------------------------------------------------------------------
// Kernel 1: fused 1x1 convs (unchanged).
// ---------------------------------------------------------------------------
extern __shared__ float smc[];
__global__ __launch_bounds__(160) void asa_conv(
    const float* __restrict__ inp,
    const float* __restrict__ fw, const float* __restrict__ fb,
    const float* __restrict__ fg, const float* __restrict__ fbe,
    const float* __restrict__ fm, const float* __restrict__ fv,
    const float* __restrict__ fa,
    const float* __restrict__ tw, const float* __restrict__ tb,
    const float* __restrict__ tg, const float* __restrict__ tbe,
    const float* __restrict__ tm, const float* __restrict__ tv,
    const float* __restrict__ ta)
{
    float* ws = smc;               // [64][80]
    float* xs = ws + 64*80;        // [64][128]
    float* sh = xs + 64*128;       // [80]
    float* al = sh + 80;           // [2]

    int tid = threadIdx.x;

    for (int idx = tid; idx < 80*64; idx += 160) {
        int c = idx & 63, op = idx >> 6;
        int e = op >> 4, cc = op & 15;
        float w, g, vv;
        if (e < 3) { int o = 3*cc + e;      w = fw[o*64+c]; g = fg[o]; vv = fv[o]; }
        else       { int o2 = 2*cc + (e-3); w = tw[o2*64+c]; g = tg[o2]; vv = tv[o2]; }
        ws[c*80 + op] = w * (g * rsqrtf(vv + BN_EPS));
    }
    if (tid < 80) {
        int op = tid, e = op >> 4, cc = op & 15;
        float g, vv, m, b, be;
        if (e < 3) { int o = 3*cc + e;      g=fg[o]; vv=fv[o]; m=fm[o]; b=fb[o]; be=fbe[o]; }
        else       { int o2 = 2*cc + (e-3); g=tg[o2]; vv=tv[o2]; m=tm[o2]; b=tb[o2]; be=tbe[o2]; }
        sh[op] = (b - m) * (g * rsqrtf(vv + BN_EPS)) + be;
    }
    if (tid == 0) { al[0] = fa[0]; al[1] = ta[0]; }

    int p0 = blockIdx.x * 128;
    int b0 = p0 / FTSZ;
    int bend = (p0 + 127) / FTSZ;
    if (b0 == bend && p0 + 127 < NPIX) {
        int ft0 = p0 - b0*FTSZ;
        const float* src = inp + b0*CC*FTSZ + ft0;
        for (int i = tid; i < 64*32; i += 160) {
            int c = i >> 5, l4 = i & 31;
            ((float4*)xs)[c*32 + l4] = *(const float4*)(src + c*FTSZ + l4*4);
        }
    } else {
        for (int i = tid; i < 64*128; i += 160) {
            int c = i >> 7, lp = i & 127;
            int p = p0 + lp;
            float v = 0.f;
            if (p < NPIX) {
                int b = p / FTSZ;
                int ft = p - b*FTSZ;
                v = inp[(b*CC + c)*FTSZ + ft];
            }
            xs[c*128 + lp] = v;
        }
    }
    __syncthreads();

    int e  = tid >> 5;
    int pg = tid & 31;

    u64 acc[8][4];
#pragma unroll
    for (int j = 0; j < 8; j++)
#pragma unroll
        for (int x = 0; x < 4; x++) acc[j][x] = 0ull;

    const float* wbase = ws + e*16;
#pragma unroll 4
    for (int c = 0; c < 64; c++) {
        const ulonglong2* wr = (const ulonglong2*)(wbase + c*80);
        ulonglong2 wa = wr[0], wb = wr[1], wc2 = wr[2], wd = wr[3];
        float4 xv = ((const float4*)xs)[c*32 + pg];
        u64 x0 = pk2(xv.x, xv.x), x1 = pk2(xv.y, xv.y);
        u64 x2 = pk2(xv.z, xv.z), x3 = pk2(xv.w, xv.w);
        acc[0][0]=fma2(wa.x,x0,acc[0][0]); acc[0][1]=fma2(wa.x,x1,acc[0][1]);
        acc[0][2]=fma2(wa.x,x2,acc[0][2]); acc[0][3]=fma2(wa.x,x3,acc[0][3]);
        acc[1][0]=fma2(wa.y,x0,acc[1][0]); acc[1][1]=fma2(wa.y,x1,acc[1][1]);
        acc[1][2]=fma2(wa.y,x2,acc[1][2]); acc[1][3]=fma2(wa.y,x3,acc[1][3]);
        acc[2][0]=fma2(wb.x,x0,acc[2][0]); acc[2][1]=fma2(wb.x,x1,acc[2][1]);
        acc[2][2]=fma2(wb.x,x2,acc[2][2]); acc[2][3]=fma2(wb.x,x3,acc[2][3]);
        acc[3][0]=fma2(wb.y,x0,acc[3][0]); acc[3][1]=fma2(wb.y,x1,acc[3][1]);
        acc[3][2]=fma2(wb.y,x2,acc[3][2]); acc[3][3]=fma2(wb.y,x3,acc[3][3]);
        acc[4][0]=fma2(wc2.x,x0,acc[4][0]); acc[4][1]=fma2(wc2.x,x1,acc[4][1]);
        acc[4][2]=fma2(wc2.x,x2,acc[4][2]); acc[4][3]=fma2(wc2.x,x3,acc[4][3]);
        acc[5][0]=fma2(wc2.y,x0,acc[5][0]); acc[5][1]=fma2(wc2.y,x1,acc[5][1]);
        acc[5][2]=fma2(wc2.y,x2,acc[5][2]); acc[5][3]=fma2(wc2.y,x3,acc[5][3]);
        acc[6][0]=fma2(wd.x,x0,acc[6][0]); acc[6][1]=fma2(wd.x,x1,acc[6][1]);
        acc[6][2]=fma2(wd.x,x2,acc[6][2]); acc[6][3]=fma2(wd.x,x3,acc[6][3]);
        acc[7][0]=fma2(wd.y,x0,acc[7][0]); acc[7][1]=fma2(wd.y,x1,acc[7][1]);
        acc[7][2]=fma2(wd.y,x2,acc[7][2]); acc[7][3]=fma2(wd.y,x3,acc[7][3]);
    }

    float shv[16];
#pragma unroll
    for (int cc = 0; cc < 16; cc++) shv[cc] = sh[e*16 + cc];
    float alpha = (e < 3) ? al[0] : al[1];

#pragma unroll
    for (int px = 0; px < 4; px++) {
        int p = p0 + pg*4 + px;
        if (p >= NPIX) continue;
        int b = p / FTSZ;
        int ft = p - b*FTSZ;
        int f = ft / TT;
        int t = ft - f*TT;
        float y[16];
#pragma unroll
        for (int j = 0; j < 8; j++) upk2(acc[j][px], y[2*j], y[2*j+1]);
#pragma unroll
        for (int cc = 0; cc < 16; cc++) {
            float v = y[cc] + shv[cc];
            y[cc] = v >= 0.f ? v : alpha * v;
        }
        float* dst;
        if      (e == 0) dst = g_qf + ((b*TT + t)*FF + f)*DC;
        else if (e == 1) dst = g_kf + ((b*TT + t)*FF + f)*DC;
        else if (e == 2) dst = g_vv + ((b*TT + t)*FF + f)*DC;
        else if (e == 3) dst = g_qt + ((b*FF + f)*TT + t)*DC;
        else             dst = g_kt + ((b*FF + f)*TT + t)*DC;
#pragma unroll
        for (int i = 0; i < 4; i++)
            ((float4*)dst)[i] = make_float4(y[4*i], y[4*i+1], y[4*i+2], y[4*i+3]);
    }
}

// ---------------------------------------------------------------------------
// Shared warp-level helpers for attention (tf32 MMA path).
// ---------------------------------------------------------------------------
#define KSTR 20
#define VSTR 24

// Redistribute D-fragment P values (u0..u3: rows g/g+8, cols 2tig,2tig+1)
// into A-fragment registers (cols tig, tig+4).
__device__ __forceinline__ void redistribute_p(
    unsigned u0, unsigned u1, unsigned u2, unsigned u3,
    int src1, int src2, int tig,
    unsigned& pa0, unsigned& pa1, unsigned& pa2, unsigned& pa3)
{
    unsigned x0 = __shfl_sync(0xffffffffu, u0, src1);
    unsigned x1 = __shfl_sync(0xffffffffu, u1, src1);
    pa0 = (tig & 1) ? x1 : x0;
    unsigned y0 = __shfl_sync(0xffffffffu, u2, src1);
    unsigned y1 = __shfl_sync(0xffffffffu, u3, src1);
    pa1 = (tig & 1) ? y1 : y0;
    x0 = __shfl_sync(0xffffffffu, u0, src2);
    x1 = __shfl_sync(0xffffffffu, u1, src2);
    pa2 = (tig & 1) ? x1 : x0;
    y0 = __shfl_sync(0xffffffffu, u2, src2);
    y1 = __shfl_sync(0xffffffffu, u3, src2);
    pa3 = (tig & 1) ? y1 : y0;
}

// ---------------------------------------------------------------------------
// Kernel 2: frequency attention via tf32 mma, 16-key double blocks.
// ---------------------------------------------------------------------------
__global__ __launch_bounds__(288) void asa_fattn()
{
    __shared__ float Ks[264*KSTR];
    __shared__ float Vs[264*VSTR];
    int bt = blockIdx.x;
    int b = bt / TT, t = bt % TT;
    int base = (b*TT + t)*FF*DC;
    int tid = threadIdx.x;

    for (int i = tid; i < 264*4; i += 288) {
        int row = i >> 2, j4 = (i & 3) * 4;
        uint4 ku = make_uint4(0,0,0,0), vu = ku;
        if (row < FF) {
            float4 kk = *(const float4*)(g_kf + base + row*DC + j4);
            float4 vv = *(const float4*)(g_vv + base + row*DC + j4);
            ku.x = cvt_tf32(kk.x); ku.y = cvt_tf32(kk.y);
            ku.z = cvt_tf32(kk.z); ku.w = cvt_tf32(kk.w);
            vu.x = cvt_tf32(vv.x); vu.y = cvt_tf32(vv.y);
            vu.z = cvt_tf32(vv.z); vu.w = cvt_tf32(vv.w);
        }
        *(uint4*)(Ks + row*KSTR + j4) = ku;
        *(uint4*)(Vs + row*VSTR + j4) = vu;
    }
    __syncthreads();

    int warp = tid >> 5, lane = tid & 31;
    int g = lane >> 2, tig = lane & 3;
    int qsel = lane & ~3;
    int src1 = qsel | (tig >> 1);
    int src2 = src1 + 2;

    for (int tile = warp; tile < 17; tile += 9) {
        int fr0 = min(tile*16 + g, FF-1);
        int fr1 = min(tile*16 + g + 8, FF-1);
        const float* q0p = g_qf + base + fr0*DC;
        const float* q1p = g_qf + base + fr1*DC;
        unsigned qa[2][4];
#pragma unroll
        for (int ks = 0; ks < 2; ks++) {
            qa[ks][0] = cvt_tf32(q0p[ks*8 + tig]     * SCALE);
            qa[ks][1] = cvt_tf32(q1p[ks*8 + tig]     * SCALE);
            qa[ks][2] = cvt_tf32(q0p[ks*8 + tig + 4] * SCALE);
            qa[ks][3] = cvt_tf32(q1p[ks*8 + tig + 4] * SCALE);
        }
        float m0 = -3.0e38f, m1 = -3.0e38f, l0 = 0.f, l1 = 0.f;
        float oA[4] = {0,0,0,0}, oB[4] = {0,0,0,0};

        // 16 double-blocks (keys 0..255)
        for (int kb = 0; kb < 16; kb++) {
            int krA = (kb*16 + g)*KSTR;
            int krB = (kb*16 + 8 + g)*KSTR;
            unsigned k0 = __float_as_uint(Ks[krA + tig]);
            unsigned k1 = __float_as_uint(Ks[krA + tig + 4]);
            unsigned k2 = __float_as_uint(Ks[krA + tig + 8]);
            unsigned k3 = __float_as_uint(Ks[krA + tig + 12]);
            unsigned k4 = __float_as_uint(Ks[krB + tig]);
            unsigned k5 = __float_as_uint(Ks[krB + tig + 4]);
            unsigned k6 = __float_as_uint(Ks[krB + tig + 8]);
            unsigned k7 = __float_as_uint(Ks[krB + tig + 12]);
            float s0=0.f,s1=0.f,s2=0.f,s3=0.f, s4=0.f,s5=0.f,s6=0.f,s7=0.f;
            mma_tf32(s0,s1,s2,s3, qa[0][0],qa[0][1],qa[0][2],qa[0][3], k0,k1);
            mma_tf32(s0,s1,s2,s3, qa[1][0],qa[1][1],qa[1][2],qa[1][3], k2,k3);
            mma_tf32(s4,s5,s6,s7, qa[0][0],qa[0][1],qa[0][2],qa[0][3], k4,k5);
            mma_tf32(s4,s5,s6,s7, qa[1][0],qa[1][1],qa[1][2],qa[1][3], k6,k7);

            float cm0 = fmaxf(fmaxf(s0,s1), fmaxf(s4,s5));
            float cm1 = fmaxf(fmaxf(s2,s3), fmaxf(s6,s7));
            cm0 = fmaxf(cm0, __shfl_xor_sync(0xffffffffu, cm0, 1));
            cm0 = fmaxf(cm0, __shfl_xor_sync(0xffffffffu, cm0, 2));
            cm1 = fmaxf(cm1, __shfl_xor_sync(0xffffffffu, cm1, 1));
            cm1 = fmaxf(cm1, __shfl_xor_sync(0xffffffffu, cm1, 2));
            float mn0 = fmaxf(m0, cm0), mn1 = fmaxf(m1, cm1);
            float c0 = __expf(m0 - mn0), c1 = __expf(m1 - mn1);
            m0 = mn0; m1 = mn1;
            float p0 = __expf(s0 - mn0), p1 = __expf(s1 - mn0);
            float p2 = __expf(s2 - mn1), p3 = __expf(s3 - mn1);
            float p4 = __expf(s4 - mn0), p5 = __expf(s5 - mn0);
            float p6 = __expf(s6 - mn1), p7 = __expf(s7 - mn1);
            float ps0 = (p0 + p1) + (p4 + p5);
            float ps1 = (p2 + p3) + (p6 + p7);
            ps0 += __shfl_xor_sync(0xffffffffu, ps0, 1);
            ps0 += __shfl_xor_sync(0xffffffffu, ps0, 2);
            ps1 += __shfl_xor_sync(0xffffffffu, ps1, 1);
            ps1 += __shfl_xor_sync(0xffffffffu, ps1, 2);
            l0 = l0*c0 + ps0; l1 = l1*c1 + ps1;
            oA[0] *= c0; oA[1] *= c0; oA[2] *= c1; oA[3] *= c1;
            oB[0] *= c0; oB[1] *= c0; oB[2] *= c1; oB[3] *= c1;

            unsigned paA0,paA1,paA2,paA3, paB0,paB1,paB2,paB3;
            redistribute_p(cvt_tf32(p0),cvt_tf32(p1),cvt_tf32(p2),cvt_tf32(p3),
                           src1,src2,tig, paA0,paA1,paA2,paA3);
            redistribute_p(cvt_tf32(p4),cvt_tf32(p5),cvt_tf32(p6),cvt_tf32(p7),
                           src1,src2,tig, paB0,paB1,paB2,paB3);

            int vrA0 = (kb*16 + tig)*VSTR,      vrA1 = (kb*16 + tig + 4)*VSTR;
            int vrB0 = (kb*16 + 8 + tig)*VSTR,  vrB1 = (kb*16 + 12 + tig)*VSTR;
            unsigned vA0 = __float_as_uint(Vs[vrA0 + g]);
            unsigned vA1 = __float_as_uint(Vs[vrA1 + g]);
            unsigned vA2 = __float_as_uint(Vs[vrA0 + g + 8]);
            unsigned vA3 = __float_as_uint(Vs[vrA1 + g + 8]);
            unsigned vB0 = __float_as_uint(Vs[vrB0 + g]);
            unsigned vB1 = __float_as_uint(Vs[vrB1 + g]);
            unsigned vB2 = __float_as_uint(Vs[vrB0 + g + 8]);
            unsigned vB3 = __float_as_uint(Vs[vrB1 + g + 8]);
            mma_tf32(oA[0],oA[1],oA[2],oA[3], paA0,paA1,paA2,paA3, vA0,vA1);
            mma_tf32(oA[0],oA[1],oA[2],oA[3], paB0,paB1,paB2,paB3, vB0,vB1);
            mma_tf32(oB[0],oB[1],oB[2],oB[3], paA0,paA1,paA2,paA3, vA2,vA3);
            mma_tf32(oB[0],oB[1],oB[2],oB[3], paB0,paB1,paB2,paB3, vB2,vB3);
        }
        // tail single block: key 256 (cols >0 masked)
        {
            int krow = (256 + g)*KSTR;
            unsigned k0 = __float_as_uint(Ks[krow + tig]);
            unsigned k1 = __float_as_uint(Ks[krow + tig + 4]);
            unsigned k2 = __float_as_uint(Ks[krow + tig + 8]);
            unsigned k3 = __float_as_uint(Ks[krow + tig + 12]);
            float s0=0.f,s1=0.f,s2=0.f,s3=0.f;
            mma_tf32(s0,s1,s2,s3, qa[0][0],qa[0][1],qa[0][2],qa[0][3], k0,k1);
            mma_tf32(s0,s1,s2,s3, qa[1][0],qa[1][1],qa[1][2],qa[1][3], k2,k3);
            if (tig > 0) { s0 = -3.0e38f; s2 = -3.0e38f; }
            s1 = -3.0e38f; s3 = -3.0e38f;
            float cm0 = fmaxf(s0, s1), cm1 = fmaxf(s2, s3);
            cm0 = fmaxf(cm0, __shfl_xor_sync(0xffffffffu, cm0, 1));
            cm0 = fmaxf(cm0, __shfl_xor_sync(0xffffffffu, cm0, 2));
            cm1 = fmaxf(cm1, __shfl_xor_sync(0xffffffffu, cm1, 1));
            cm1 = fmaxf(cm1, __shfl_xor_sync(0xffffffffu, cm1, 2));
            float mn0 = fmaxf(m0, cm0), mn1 = fmaxf(m1, cm1);
            float c0 = __expf(m0 - mn0), c1 = __expf(m1 - mn1);
            m0 = mn0; m1 = mn1;
            float p0 = __expf(s0 - mn0), p1 = __expf(s1 - mn0);
            float p2 = __expf(s2 - mn1), p3 = __expf(s3 - mn1);
            float ps0 = p0 + p1, ps1 = p2 + p3;
            ps0 += __shfl_xor_sync(0xffffffffu, ps0, 1);
            ps0 += __shfl_xor_sync(0xffffffffu, ps0, 2);
            ps1 += __shfl_xor_sync(0xffffffffu, ps1, 1);
            ps1 += __shfl_xor_sync(0xffffffffu, ps1, 2);
            l0 = l0*c0 + ps0; l1 = l1*c1 + ps1;
            oA[0] *= c0; oA[1] *= c0; oA[2] *= c1; oA[3] *= c1;
            oB[0] *= c0; oB[1] *= c0; oB[2] *= c1; oB[3] *= c1;
            unsigned pa0,pa1,pa2,pa3;
            redistribute_p(cvt_tf32(p0),cvt_tf32(p1),cvt_tf32(p2),cvt_tf32(p3),
                           src1,src2,tig, pa0,pa1,pa2,pa3);
            int vr0 = (256 + tig)*VSTR, vr1 = (256 + tig + 4)*VSTR;
            unsigned v0 = __float_as_uint(Vs[vr0 + g]);
            unsigned v1 = __float_as_uint(Vs[vr1 + g]);
            unsigned v2 = __float_as_uint(Vs[vr0 + g + 8]);
            unsigned v3 = __float_as_uint(Vs[vr1 + g + 8]);
            mma_tf32(oA[0],oA[1],oA[2],oA[3], pa0,pa1,pa2,pa3, v0,v1);
            mma_tf32(oB[0],oB[1],oB[2],oB[3], pa0,pa1,pa2,pa3, v2,v3);
        }
        float inv0 = 1.f / l0, inv1 = 1.f / l1;
        int f0 = tile*16 + g, f1 = f0 + 8;
        if (f0 < FF) {
            float* op = g_fo + ((b*FF + f0)*TT + t)*DC;
            *(float2*)(op + 2*tig)     = make_float2(oA[0]*inv0, oA[1]*inv0);
            *(float2*)(op + 8 + 2*tig) = make_float2(oB[0]*inv0, oB[1]*inv0);
        }
        if (f1 < FF) {
            float* op = g_fo + ((b*FF + f1)*TT + t)*DC;
            *(float2*)(op + 2*tig)     = make_float2(oA[2]*inv1, oA[3]*inv1);
            *(float2*)(op + 8 + 2*tig) = make_float2(oB[2]*inv1, oB[3]*inv1);
        }
    }
}

// ---------------------------------------------------------------------------
// Kernel 3: causal time attention via tf32 mma (16-key double blocks) +
// proj + residual. Warp tiles {w, 15-w, 16+w, 31-w} -> 66 double-blocks each.
// ---------------------------------------------------------------------------
extern __shared__ float sm3[];
__global__ __launch_bounds__(256) void asa_tattn(
    const float* __restrict__ inp,
    const float* __restrict__ pw, const float* __restrict__ pb,
    const float* __restrict__ pg, const float* __restrict__ pbe,
    const float* __restrict__ pm, const float* __restrict__ pv,
    const float* __restrict__ pa,
    float* __restrict__ out)
{
    float* Ks   = sm3;                    // 512*KSTR
    float* Vs   = Ks + 512*KSTR;          // 512*VSTR
    float* pws  = Vs + 512*VSTR;          // 64*16
    float* psh  = pws + 64*16;            // 64
    float* obuf = psh + 64;               // 8 warps * 16*17
    __shared__ float s_alpha;

    int bf = blockIdx.x;
    int b = bf / FF, f = bf % FF;
    int base = bf * TT * DC;
    int tid = threadIdx.x;

    for (int i = tid; i < 512*4; i += 256) {
        int row = i >> 2, j4 = (i & 3) * 4;
        uint4 ku = make_uint4(0,0,0,0), vu = ku;
        if (row < TT) {
            float4 kk = *(const float4*)(g_kt + base + row*DC + j4);
            float4 vv = *(const float4*)(g_fo + base + row*DC + j4);
            ku.x = cvt_tf32(kk.x); ku.y = cvt_tf32(kk.y);
            ku.z = cvt_tf32(kk.z); ku.w = cvt_tf32(kk.w);
            vu.x = cvt_tf32(vv.x); vu.y = cvt_tf32(vv.y);
            vu.z = cvt_tf32(vv.z); vu.w = cvt_tf32(vv.w);
        }
        *(uint4*)(Ks + row*KSTR + j4) = ku;
        *(uint4*)(Vs + row*VSTR + j4) = vu;
    }
    for (int i = tid; i < 64*16; i += 256) {
        int o = i >> 4;
        pws[i] = pw[i] * (pg[o] * rsqrtf(pv[o] + BN_EPS));
    }
    if (tid < 64) {
        int o = tid;
        psh[o] = (pb[o] - pm[o]) * (pg[o] * rsqrtf(pv[o] + BN_EPS)) + pbe[o];
    }
    if (tid == 0) s_alpha = pa[0];
    __syncthreads();

    int warp = tid >> 5, lane = tid & 31;
    int g = lane >> 2, tig = lane & 3;
    int qsel = lane & ~3;
    int src1 = qsel | (tig >> 1);
    int src2 = src1 + 2;
    float alpha = s_alpha;
    float* ob = obuf + warp * (16*17);

    int tiles[4] = { warp, 15 - warp, 16 + warp, 31 - warp };

#pragma unroll
    for (int ti = 0; ti < 4; ti++) {
        int tile = tiles[ti];
        int qt0 = tile * 16;
        int ta = qt0 + g;
        int tb = qt0 + g + 8;
        int tr0 = min(ta, TT-1), tr1 = min(tb, TT-1);
        const float* q0p = g_qt + base + tr0*DC;
        const float* q1p = g_qt + base + tr1*DC;
        unsigned qa[2][4];
#pragma unroll
        for (int ks = 0; ks < 2; ks++) {
            qa[ks][0] = cvt_tf32(q0p[ks*8 + tig]     * SCALE);
            qa[ks][1] = cvt_tf32(q1p[ks*8 + tig]     * SCALE);
            qa[ks][2] = cvt_tf32(q0p[ks*8 + tig + 4] * SCALE);
            qa[ks][3] = cvt_tf32(q1p[ks*8 + tig + 4] * SCALE);
        }
        float m0 = -3.0e38f, m1 = -3.0e38f, l0 = 0.f, l1 = 0.f;
        float oA[4] = {0,0,0,0}, oB[4] = {0,0,0,0};

        // double-blocks 0..tile (16 keys each); diagonal (kb==tile) masked
        for (int kb = 0; kb <= tile; kb++) {
            int krA = (kb*16 + g)*KSTR;
            int krB = (kb*16 + 8 + g)*KSTR;
            unsigned k0 = __float_as_uint(Ks[krA + tig]);
            unsigned k1 = __float_as_uint(Ks[krA + tig + 4]);
            unsigned k2 = __float_as_uint(Ks[krA + tig + 8]);
            unsigned k3 = __float_as_uint(Ks[krA + tig + 12]);
            unsigned k4 = __float_as_uint(Ks[krB + tig]);
            unsigned k5 = __float_as_uint(Ks[krB + tig + 4]);
            unsigned k6 = __float_as_uint(Ks[krB + tig + 8]);
            unsigned k7 = __float_as_uint(Ks[krB + tig + 12]);
            float s0=0.f,s1=0.f,s2=0.f,s3=0.f, s4=0.f,s5=0.f,s6=0.f,s7=0.f;
            mma_tf32(s0,s1,s2,s3, qa[0][0],qa[0][1],qa[0][2],qa[0][3], k0,k1);
            mma_tf32(s0,s1,s2,s3, qa[1][0],qa[1][1],qa[1][2],qa[1][3], k2,k3);
            mma_tf32(s4,s5,s6,s7, qa[0][0],qa[0][1],qa[0][2],qa[0][3], k4,k5);
            mma_tf32(s4,s5,s6,s7, qa[1][0],qa[1][1],qa[1][2],qa[1][3], k6,k7);
            if (kb == tile) {   // diagonal 16x16 block: causal mask
                int yA0 = kb*16 + 2*tig, yA1 = yA0 + 1;
                int yB0 = yA0 + 8,       yB1 = yA1 + 8;
                if (yA0 > ta) s0 = -3.0e38f;
                if (yA1 > ta) s1 = -3.0e38f;
                if (yA0 > tb) s2 = -3.0e38f;
                if (yA1 > tb) s3 = -3.0e38f;
                if (yB0 > ta) s4 = -3.0e38f;
                if (yB1 > ta) s5 = -3.0e38f;
                if (yB0 > tb) s6 = -3.0e38f;
                if (yB1 > tb) s7 = -3.0e38f;
            }
            float cm0 = fmaxf(fmaxf(s0,s1), fmaxf(s4,s5));
            float cm1 = fmaxf(fmaxf(s2,s3), fmaxf(s6,s7));
            cm0 = fmaxf(cm0, __shfl_xor_sync(0xffffffffu, cm0, 1));
            cm0 = fmaxf(cm0, __shfl_xor_sync(0xffffffffu, cm0, 2));
            cm1 = fmaxf(cm1, __shfl_xor_sync(0xffffffffu, cm1, 1));
            cm1 = fmaxf(cm1, __shfl_xor_sync(0xffffffffu, cm1, 2));
            float mn0 = fmaxf(m0, cm0), mn1 = fmaxf(m1, cm1);
            float c0 = __expf(m0 - mn0), c1 = __expf(m1 - mn1);
            m0 = mn0; m1 = mn1;
            float p0 = __expf(s0 - mn0), p1 = __expf(s1 - mn0);
            float p2 = __expf(s2 - mn1), p3 = __expf(s3 - mn1);
            float p4 = __expf(s4 - mn0), p5 = __expf(s5 - mn0);
            float p6 = __expf(s6 - mn1), p7 = __expf(s7 - mn1);
            float ps0 = (p0 + p1) + (p4 + p5);
            float ps1 = (p2 + p3) + (p6 + p7);
            ps0 += __shfl_xor_sync(0xffffffffu, ps0, 1);
            ps0 += __shfl_xor_sync(0xffffffffu, ps0, 2);
            ps1 += __shfl_xor_sync(0xffffffffu, ps1, 1);
            ps1 += __shfl_xor_sync(0xffffffffu, ps1, 2);
            l0 = l0*c0 + ps0; l1 = l1*c1 + ps1;
            oA[0] *= c0; oA[1] *= c0; oA[2] *= c1; oA[3] *= c1;
            oB[0] *= c0; oB[1] *= c0; oB[2] *= c1; oB[3] *= c1;

            unsigned paA0,paA1,paA2,paA3, paB0,paB1,paB2,paB3;
            redistribute_p(cvt_tf32(p0),cvt_tf32(p1),cvt_tf32(p2),cvt_tf32(p3),
                           src1,src2,tig, paA0,paA1,paA2,paA3);
            redistribute_p(cvt_tf32(p4),cvt_tf32(p5),cvt_tf32(p6),cvt_tf32(p7),
                           src1,src2,tig, paB0,paB1,paB2,paB3);

            int vrA0 = (kb*16 + tig)*VSTR,      vrA1 = (kb*16 + tig + 4)*VSTR;
            int vrB0 = (kb*16 + 8 + tig)*VSTR,  vrB1 = (kb*16 + 12 + tig)*VSTR;
            unsigned vA0 = __float_as_uint(Vs[vrA0 + g]);
            unsigned vA1 = __float_as_uint(Vs[vrA1 + g]);
            unsigned vA2 = __float_as_uint(Vs[vrA0 + g + 8]);
            unsigned vA3 = __float_as_uint(Vs[vrA1 + g + 8]);
            unsigned vB0 = __float_as_uint(Vs[vrB0 + g]);
            unsigned vB1 = __float_as_uint(Vs[vrB1 + g]);
            unsigned vB2 = __float_as_uint(Vs[vrB0 + g + 8]);
            unsigned vB3 = __float_as_uint(Vs[vrB1 + g + 8]);
            mma_tf32(oA[0],oA[1],oA[2],oA[3], paA0,paA1,paA2,paA3, vA0,vA1);
            mma_tf32(oA[0],oA[1],oA[2],oA[3], paB0,paB1,paB2,paB3, vB0,vB1);
            mma_tf32(oB[0],oB[1],oB[2],oB[3], paA0,paA1,paA2,paA3, vA2,vA3);
            mma_tf32(oB[0],oB[1],oB[2],oB[3], paB0,paB1,paB2,paB3, vB2,vB3);
        }
        // stage normalized o into smem tile [16 queries][16 dc] (stride 17)
        float inv0 = 1.f / l0, inv1 = 1.f / l1;
        ob[g*17 + 2*tig]          = oA[0]*inv0;
        ob[g*17 + 2*tig + 1]      = oA[1]*inv0;
        ob[g*17 + 8 + 2*tig]      = oB[0]*inv0;
        ob[g*17 + 8 + 2*tig + 1]  = oB[1]*inv0;
        ob[(g+8)*17 + 2*tig]         = oA[2]*inv1;
        ob[(g+8)*17 + 2*tig + 1]     = oA[3]*inv1;
        ob[(g+8)*17 + 8 + 2*tig]     = oB[2]*inv1;
        ob[(g+8)*17 + 8 + 2*tig + 1] = oB[3]*inv1;
        __syncwarp();

        int qi = lane & 15;
        int t = qt0 + qi;
        if (t < TT) {
            const float* orow = ob + qi*17;
            u64 o2[8];
#pragma unroll
            for (int j = 0; j < 8; j++) o2[j] = pk2(orow[2*j], orow[2*j+1]);
            int c0 = (lane >> 4) * 32;
            int obase = b*CC*FTSZ + f*TT + t;
#pragma unroll 4
            for (int j = 0; j < 32; j++) {
                int co = c0 + j;
                const ulonglong2* wr = (const ulonglong2*)(pws + co*16);
                ulonglong2 wa = wr[0], wb = wr[1], wc = wr[2], wd = wr[3];
                u64 d0 = mul2(wa.x, o2[0]);
                u64 d1 = mul2(wa.y, o2[1]);
                d0 = fma2(wb.x, o2[2], d0);
                d1 = fma2(wb.y, o2[3], d1);
                d0 = fma2(wc.x, o2[4], d0);
                d1 = fma2(wc.y, o2[5], d1);
                d0 = fma2(wd.x, o2[6], d0);
                d1 = fma2(wd.y, o2[7], d1);
                float lo0,hi0,lo1,hi1;
                upk2(d0,lo0,hi0); upk2(d1,lo1,hi1);
                float r = psh[co] + (lo0+hi0) + (lo1+hi1);
                r = r >= 0.f ? r : alpha * r;
                int idx = obase + co*FTSZ;
                out[idx] = r + __ldg(&inp[idx]);
            }
        }
        __syncwarp();
    }
}

// ---------------------------------------------------------------------------
extern "C" void kernel_launch(void* const* d_in, const int* in_sizes, int n_in,
                              void* d_out, int out_size)
{
    const float* inp = (const float*)d_in[0];

    int smc_bytes = (64*80 + 64*128 + 80 + 2) * (int)sizeof(float);
    cudaFuncSetAttribute(asa_conv, cudaFuncAttributeMaxDynamicSharedMemorySize, smc_bytes);
    asa_conv<<<(NPIX + 127)/128, 160, smc_bytes>>>(
        inp,
        (const float*)d_in[1],  (const float*)d_in[2],  (const float*)d_in[3],
        (const float*)d_in[4],  (const float*)d_in[5],  (const float*)d_in[6],
        (const float*)d_in[7],
        (const float*)d_in[8],  (const float*)d_in[9],  (const float*)d_in[10],
        (const float*)d_in[11], (const float*)d_in[12], (const float*)d_in[13],
        (const float*)d_in[14]);

    asa_fattn<<<BB*TT, 288>>>();

    int sm3_bytes = (512*KSTR + 512*VSTR + 64*16 + 64 + 8*16*17) * (int)sizeof(float);
    cudaFuncSetAttribute(asa_tattn, cudaFuncAttributeMaxDynamicSharedMemorySize, sm3_bytes);
    asa_tattn<<<BB*FF, 256, sm3_bytes>>>(
        inp,
        (const float*)d_in[15], (const float*)d_in[16], (const float*)d_in[17],
        (const float*)d_in[18], (const float*)d_in[19], (const float*)d_in[20],
        (const float*)d_in[21],
        (float*)d_out);
}

// round 8
// speedup vs baseline: 2.4446x; 1.0367x over previous
#include <cuda_runtime.h>

#define BB 2
#define CC 64
#define FF 257
#define TT 500
#define DC 16
#define BN_EPS 1e-5f
#define SCALE 0.25f
#define NPIX (BB*FF*TT)
#define FTSZ (FF*TT)

typedef unsigned long long u64;

__device__ __forceinline__ u64 pk2(float lo, float hi) {
    u64 r; asm("mov.b64 %0, {%1,%2};" : "=l"(r) : "f"(lo), "f"(hi)); return r;
}
__device__ __forceinline__ void upk2(u64 v, float& lo, float& hi) {
    asm("mov.b64 {%0,%1}, %2;" : "=f"(lo), "=f"(hi) : "l"(v));
}
__device__ __forceinline__ u64 fma2(u64 a, u64 b, u64 c) {
    u64 d; asm("fma.rn.f32x2 %0, %1, %2, %3;" : "=l"(d) : "l"(a), "l"(b), "l"(c)); return d;
}
__device__ __forceinline__ u64 mul2(u64 a, u64 b) {
    u64 d; asm("mul.rn.f32x2 %0, %1, %2;" : "=l"(d) : "l"(a), "l"(b)); return d;
}
__device__ __forceinline__ unsigned cvt_tf32(float x) {
    unsigned r; asm("cvt.rna.tf32.f32 %0, %1;" : "=r"(r) : "f"(x)); return r;
}
__device__ __forceinline__ void mma_tf32(
    float& d0, float& d1, float& d2, float& d3,
    unsigned a0, unsigned a1, unsigned a2, unsigned a3,
    unsigned b0, unsigned b1)
{
    asm("mma.sync.aligned.m16n8k8.row.col.f32.tf32.tf32.f32 "
        "{%0,%1,%2,%3},{%4,%5,%6,%7},{%8,%9},{%0,%1,%2,%3};"
        : "+f"(d0), "+f"(d1), "+f"(d2), "+f"(d3)
        : "r"(a0), "r"(a1), "r"(a2), "r"(a3), "r"(b0), "r"(b1));
}

// Scratch (device globals; no allocation allowed)
__device__ float g_qf[BB*TT*FF*DC];   // [b][t][f][c]
__device__ float g_kf[BB*TT*FF*DC];   // [b][t][f][c]
__device__ float g_vv[BB*TT*FF*DC];   // [b][t][f][c]
__device__ float g_qt[BB*FF*TT*DC];   // [b][f][t][c]
__device__ float g_kt[BB*FF*TT*DC];   // [b][f][t][c]
__device__ float g_fo[BB*FF*TT*DC];   // [b][f][t][c]

// ---------------------------------------------------------------------------
// Kernel 1: fused 1x1 convs via tf32 MMA.
// CTA = 128 pixels, 4 warps. D[px][out80] = X[px][64ch] * W[64][80].
// X smem [ch][px] stride 136; W smem [ch][op] stride 88 (op = e*16+cc
// permuted); accumulators staged to smem [px][84] then BN+PReLU+scatter.
// ---------------------------------------------------------------------------
#define PSTR 136
#define WSTR 88
#define OSTR 84

extern __shared__ float smc[];
__global__ __launch_bounds__(128) void asa_conv(
    const float* __restrict__ inp,
    const float* __restrict__ fw, const float* __restrict__ fb,
    const float* __restrict__ fg, const float* __restrict__ fbe,
    const float* __restrict__ fm, const float* __restrict__ fv,
    const float* __restrict__ fa,
    const float* __restrict__ tw, const float* __restrict__ tb,
    const float* __restrict__ tg, const float* __restrict__ tbe,
    const float* __restrict__ tm, const float* __restrict__ tv,
    const float* __restrict__ ta)
{
    float* un = smc;                   // union: X [64][PSTR] -> staging [128][OSTR]
    float* ws = smc + 128*OSTR;        // [64][WSTR]
    float* sh = ws + 64*WSTR;          // [80]
    float* al = sh + 80;               // [2]

    int tid = threadIdx.x;

    // weights (BN scale folded, tf32), permuted op = e*16 + cc
    for (int idx = tid; idx < 80*64; idx += 128) {
        int c = idx & 63, op = idx >> 6;
        int e = op >> 4, cc = op & 15;
        float w, g, vv;
        if (e < 3) { int o = 3*cc + e;      w = fw[o*64+c]; g = fg[o]; vv = fv[o]; }
        else       { int o2 = 2*cc + (e-3); w = tw[o2*64+c]; g = tg[o2]; vv = tv[o2]; }
        ws[c*WSTR + op] = __uint_as_float(cvt_tf32(w * (g * rsqrtf(vv + BN_EPS))));
    }
    if (tid < 80) {
        int op = tid, e = op >> 4, cc = op & 15;
        float g, vv, m, b, be;
        if (e < 3) { int o = 3*cc + e;      g=fg[o]; vv=fv[o]; m=fm[o]; b=fb[o]; be=fbe[o]; }
        else       { int o2 = 2*cc + (e-3); g=tg[o2]; vv=tv[o2]; m=tm[o2]; b=tb[o2]; be=tbe[o2]; }
        sh[op] = (b - m) * (g * rsqrtf(vv + BN_EPS)) + be;
    }
    if (tid == 0) { al[0] = fa[0]; al[1] = ta[0]; }

    // X fill: [ch][px] tf32, stride PSTR
    int p0 = blockIdx.x * 128;
    int b0 = p0 / FTSZ;
    int bend = (p0 + 127) / FTSZ;
    if (b0 == bend && p0 + 127 < NPIX) {
        int ft0 = p0 - b0*FTSZ;
        const float* src = inp + b0*CC*FTSZ + ft0;
        for (int i = tid; i < 64*32; i += 128) {
            int c = i >> 5, l4 = i & 31;
            float4 v = *(const float4*)(src + c*FTSZ + l4*4);
            uint4 u;
            u.x = cvt_tf32(v.x); u.y = cvt_tf32(v.y);
            u.z = cvt_tf32(v.z); u.w = cvt_tf32(v.w);
            *(uint4*)(un + c*PSTR + l4*4) = u;
        }
    } else {
        for (int i = tid; i < 64*128; i += 128) {
            int c = i >> 7, lp = i & 127;
            int p = p0 + lp;
            float v = 0.f;
            if (p < NPIX) {
                int b = p / FTSZ;
                int ft = p - b*FTSZ;
                v = inp[(b*CC + c)*FTSZ + ft];
            }
            un[c*PSTR + lp] = __uint_as_float(cvt_tf32(v));
        }
    }
    __syncthreads();

    int warp = tid >> 5, lane = tid & 31;
    int g = lane >> 2, tig = lane & 3;
    int pxA = warp*32, pxB = warp*32 + 16;

    float accA[10][4], accB[10][4];
#pragma unroll
    for (int nt = 0; nt < 10; nt++)
#pragma unroll
        for (int j = 0; j < 4; j++) { accA[nt][j] = 0.f; accB[nt][j] = 0.f; }

#pragma unroll
    for (int k = 0; k < 8; k++) {
        int r0 = (8*k + tig)*PSTR, r1 = (8*k + tig + 4)*PSTR;
        unsigned aA0 = __float_as_uint(un[r0 + pxA + g]);
        unsigned aA1 = __float_as_uint(un[r0 + pxA + g + 8]);
        unsigned aA2 = __float_as_uint(un[r1 + pxA + g]);
        unsigned aA3 = __float_as_uint(un[r1 + pxA + g + 8]);
        unsigned aB0 = __float_as_uint(un[r0 + pxB + g]);
        unsigned aB1 = __float_as_uint(un[r0 + pxB + g + 8]);
        unsigned aB2 = __float_as_uint(un[r1 + pxB + g]);
        unsigned aB3 = __float_as_uint(un[r1 + pxB + g + 8]);
        int w0 = (8*k + tig)*WSTR + g, w1 = (8*k + tig + 4)*WSTR + g;
#pragma unroll
        for (int nt = 0; nt < 10; nt++) {
            unsigned bb0 = __float_as_uint(ws[w0 + nt*8]);
            unsigned bb1 = __float_as_uint(ws[w1 + nt*8]);
            mma_tf32(accA[nt][0], accA[nt][1], accA[nt][2], accA[nt][3],
                     aA0, aA1, aA2, aA3, bb0, bb1);
            mma_tf32(accB[nt][0], accB[nt][1], accB[nt][2], accB[nt][3],
                     aB0, aB1, aB2, aB3, bb0, bb1);
        }
    }
    __syncthreads();   // all warps done reading X

    // stage accumulators to smem [px][OSTR]
#pragma unroll
    for (int nt = 0; nt < 10; nt++) {
        *(float2*)(un + (pxA+g)*OSTR + nt*8 + 2*tig)     = make_float2(accA[nt][0], accA[nt][1]);
        *(float2*)(un + (pxA+g+8)*OSTR + nt*8 + 2*tig)   = make_float2(accA[nt][2], accA[nt][3]);
        *(float2*)(un + (pxB+g)*OSTR + nt*8 + 2*tig)     = make_float2(accB[nt][0], accB[nt][1]);
        *(float2*)(un + (pxB+g+8)*OSTR + nt*8 + 2*tig)   = make_float2(accB[nt][2], accB[nt][3]);
    }
    __syncthreads();

    // epilogue: thread = pixel; BN shift + PReLU + scatter (same as before)
    int p = p0 + tid;
    if (p < NPIX) {
        int b = p / FTSZ;
        int ft = p - b*FTSZ;
        int f = ft / TT;
        int t = ft - f*TT;
        const float* row = un + tid*OSTR;
        float a0v = al[0], a1v = al[1];
#pragma unroll
        for (int e = 0; e < 5; e++) {
            float alpha = (e < 3) ? a0v : a1v;
            float y[16];
            float4 r0 = *(const float4*)(row + e*16);
            float4 r1 = *(const float4*)(row + e*16 + 4);
            float4 r2 = *(const float4*)(row + e*16 + 8);
            float4 r3 = *(const float4*)(row + e*16 + 12);
            y[0]=r0.x; y[1]=r0.y; y[2]=r0.z; y[3]=r0.w;
            y[4]=r1.x; y[5]=r1.y; y[6]=r1.z; y[7]=r1.w;
            y[8]=r2.x; y[9]=r2.y; y[10]=r2.z; y[11]=r2.w;
            y[12]=r3.x; y[13]=r3.y; y[14]=r3.z; y[15]=r3.w;
#pragma unroll
            for (int cc = 0; cc < 16; cc++) {
                float v = y[cc] + sh[e*16 + cc];
                y[cc] = v >= 0.f ? v : alpha * v;
            }
            float* dst;
            if      (e == 0) dst = g_qf + ((b*TT + t)*FF + f)*DC;
            else if (e == 1) dst = g_kf + ((b*TT + t)*FF + f)*DC;
            else if (e == 2) dst = g_vv + ((b*TT + t)*FF + f)*DC;
            else if (e == 3) dst = g_qt + ((b*FF + f)*TT + t)*DC;
            else             dst = g_kt + ((b*FF + f)*TT + t)*DC;
#pragma unroll
            for (int i = 0; i < 4; i++)
                ((float4*)dst)[i] = make_float4(y[4*i], y[4*i+1], y[4*i+2], y[4*i+3]);
        }
    }
}

// ---------------------------------------------------------------------------
// Shared warp-level helpers for attention (tf32 MMA path).
// ---------------------------------------------------------------------------
#define KSTR 20
#define VSTR 24

__device__ __forceinline__ void redistribute_p(
    unsigned u0, unsigned u1, unsigned u2, unsigned u3,
    int src1, int src2, int tig,
    unsigned& pa0, unsigned& pa1, unsigned& pa2, unsigned& pa3)
{
    unsigned x0 = __shfl_sync(0xffffffffu, u0, src1);
    unsigned x1 = __shfl_sync(0xffffffffu, u1, src1);
    pa0 = (tig & 1) ? x1 : x0;
    unsigned y0 = __shfl_sync(0xffffffffu, u2, src1);
    unsigned y1 = __shfl_sync(0xffffffffu, u3, src1);
    pa1 = (tig & 1) ? y1 : y0;
    x0 = __shfl_sync(0xffffffffu, u0, src2);
    x1 = __shfl_sync(0xffffffffu, u1, src2);
    pa2 = (tig & 1) ? x1 : x0;
    y0 = __shfl_sync(0xffffffffu, u2, src2);
    y1 = __shfl_sync(0xffffffffu, u3, src2);
    pa3 = (tig & 1) ? y1 : y0;
}

// ---------------------------------------------------------------------------
// Kernel 2: frequency attention via tf32 mma, 16-key double blocks.
// ---------------------------------------------------------------------------
__global__ __launch_bounds__(288) void asa_fattn()
{
    __shared__ float Ks[264*KSTR];
    __shared__ float Vs[264*VSTR];
    int bt = blockIdx.x;
    int b = bt / TT, t = bt % TT;
    int base = (b*TT + t)*FF*DC;
    int tid = threadIdx.x;

    for (int i = tid; i < 264*4; i += 288) {
        int row = i >> 2, j4 = (i & 3) * 4;
        uint4 ku = make_uint4(0,0,0,0), vu = ku;
        if (row < FF) {
            float4 kk = *(const float4*)(g_kf + base + row*DC + j4);
            float4 vv = *(const float4*)(g_vv + base + row*DC + j4);
            ku.x = cvt_tf32(kk.x); ku.y = cvt_tf32(kk.y);
            ku.z = cvt_tf32(kk.z); ku.w = cvt_tf32(kk.w);
            vu.x = cvt_tf32(vv.x); vu.y = cvt_tf32(vv.y);
            vu.z = cvt_tf32(vv.z); vu.w = cvt_tf32(vv.w);
        }
        *(uint4*)(Ks + row*KSTR + j4) = ku;
        *(uint4*)(Vs + row*VSTR + j4) = vu;
    }
    __syncthreads();

    int warp = tid >> 5, lane = tid & 31;
    int g = lane >> 2, tig = lane & 3;
    int qsel = lane & ~3;
    int src1 = qsel | (tig >> 1);
    int src2 = src1 + 2;

    for (int tile = warp; tile < 17; tile += 9) {
        int fr0 = min(tile*16 + g, FF-1);
        int fr1 = min(tile*16 + g + 8, FF-1);
        const float* q0p = g_qf + base + fr0*DC;
        const float* q1p = g_qf + base + fr1*DC;
        unsigned qa[2][4];
#pragma unroll
        for (int ks = 0; ks < 2; ks++) {
            qa[ks][0] = cvt_tf32(q0p[ks*8 + tig]     * SCALE);
            qa[ks][1] = cvt_tf32(q1p[ks*8 + tig]     * SCALE);
            qa[ks][2] = cvt_tf32(q0p[ks*8 + tig + 4] * SCALE);
            qa[ks][3] = cvt_tf32(q1p[ks*8 + tig + 4] * SCALE);
        }
        float m0 = -3.0e38f, m1 = -3.0e38f, l0 = 0.f, l1 = 0.f;
        float oA[4] = {0,0,0,0}, oB[4] = {0,0,0,0};

        for (int kb = 0; kb < 16; kb++) {
            int krA = (kb*16 + g)*KSTR;
            int krB = (kb*16 + 8 + g)*KSTR;
            unsigned k0 = __float_as_uint(Ks[krA + tig]);
            unsigned k1 = __float_as_uint(Ks[krA + tig + 4]);
            unsigned k2 = __float_as_uint(Ks[krA + tig + 8]);
            unsigned k3 = __float_as_uint(Ks[krA + tig + 12]);
            unsigned k4 = __float_as_uint(Ks[krB + tig]);
            unsigned k5 = __float_as_uint(Ks[krB + tig + 4]);
            unsigned k6 = __float_as_uint(Ks[krB + tig + 8]);
            unsigned k7 = __float_as_uint(Ks[krB + tig + 12]);
            float s0=0.f,s1=0.f,s2=0.f,s3=0.f, s4=0.f,s5=0.f,s6=0.f,s7=0.f;
            mma_tf32(s0,s1,s2,s3, qa[0][0],qa[0][1],qa[0][2],qa[0][3], k0,k1);
            mma_tf32(s0,s1,s2,s3, qa[1][0],qa[1][1],qa[1][2],qa[1][3], k2,k3);
            mma_tf32(s4,s5,s6,s7, qa[0][0],qa[0][1],qa[0][2],qa[0][3], k4,k5);
            mma_tf32(s4,s5,s6,s7, qa[1][0],qa[1][1],qa[1][2],qa[1][3], k6,k7);

            float cm0 = fmaxf(fmaxf(s0,s1), fmaxf(s4,s5));
            float cm1 = fmaxf(fmaxf(s2,s3), fmaxf(s6,s7));
            cm0 = fmaxf(cm0, __shfl_xor_sync(0xffffffffu, cm0, 1));
            cm0 = fmaxf(cm0, __shfl_xor_sync(0xffffffffu, cm0, 2));
            cm1 = fmaxf(cm1, __shfl_xor_sync(0xffffffffu, cm1, 1));
            cm1 = fmaxf(cm1, __shfl_xor_sync(0xffffffffu, cm1, 2));
            float mn0 = fmaxf(m0, cm0), mn1 = fmaxf(m1, cm1);
            float c0 = __expf(m0 - mn0), c1 = __expf(m1 - mn1);
            m0 = mn0; m1 = mn1;
            float p0 = __expf(s0 - mn0), p1 = __expf(s1 - mn0);
            float p2 = __expf(s2 - mn1), p3 = __expf(s3 - mn1);
            float p4 = __expf(s4 - mn0), p5 = __expf(s5 - mn0);
            float p6 = __expf(s6 - mn1), p7 = __expf(s7 - mn1);
            float ps0 = (p0 + p1) + (p4 + p5);
            float ps1 = (p2 + p3) + (p6 + p7);
            ps0 += __shfl_xor_sync(0xffffffffu, ps0, 1);
            ps0 += __shfl_xor_sync(0xffffffffu, ps0, 2);
            ps1 += __shfl_xor_sync(0xffffffffu, ps1, 1);
            ps1 += __shfl_xor_sync(0xffffffffu, ps1, 2);
            l0 = l0*c0 + ps0; l1 = l1*c1 + ps1;
            oA[0] *= c0; oA[1] *= c0; oA[2] *= c1; oA[3] *= c1;
            oB[0] *= c0; oB[1] *= c0; oB[2] *= c1; oB[3] *= c1;

            unsigned paA0,paA1,paA2,paA3, paB0,paB1,paB2,paB3;
            redistribute_p(cvt_tf32(p0),cvt_tf32(p1),cvt_tf32(p2),cvt_tf32(p3),
                           src1,src2,tig, paA0,paA1,paA2,paA3);
            redistribute_p(cvt_tf32(p4),cvt_tf32(p5),cvt_tf32(p6),cvt_tf32(p7),
                           src1,src2,tig, paB0,paB1,paB2,paB3);

            int vrA0 = (kb*16 + tig)*VSTR,      vrA1 = (kb*16 + tig + 4)*VSTR;
            int vrB0 = (kb*16 + 8 + tig)*VSTR,  vrB1 = (kb*16 + 12 + tig)*VSTR;
            unsigned vA0 = __float_as_uint(Vs[vrA0 + g]);
            unsigned vA1 = __float_as_uint(Vs[vrA1 + g]);
            unsigned vA2 = __float_as_uint(Vs[vrA0 + g + 8]);
            unsigned vA3 = __float_as_uint(Vs[vrA1 + g + 8]);
            unsigned vB0 = __float_as_uint(Vs[vrB0 + g]);
            unsigned vB1 = __float_as_uint(Vs[vrB1 + g]);
            unsigned vB2 = __float_as_uint(Vs[vrB0 + g + 8]);
            unsigned vB3 = __float_as_uint(Vs[vrB1 + g + 8]);
            mma_tf32(oA[0],oA[1],oA[2],oA[3], paA0,paA1,paA2,paA3, vA0,vA1);
            mma_tf32(oA[0],oA[1],oA[2],oA[3], paB0,paB1,paB2,paB3, vB0,vB1);
            mma_tf32(oB[0],oB[1],oB[2],oB[3], paA0,paA1,paA2,paA3, vA2,vA3);
            mma_tf32(oB[0],oB[1],oB[2],oB[3], paB0,paB1,paB2,paB3, vB2,vB3);
        }
        // tail single block: key 256 (cols >0 masked)
        {
            int krow = (256 + g)*KSTR;
            unsigned k0 = __float_as_uint(Ks[krow + tig]);
            unsigned k1 = __float_as_uint(Ks[krow + tig + 4]);
            unsigned k2 = __float_as_uint(Ks[krow + tig + 8]);
            unsigned k3 = __float_as_uint(Ks[krow + tig + 12]);
            float s0=0.f,s1=0.f,s2=0.f,s3=0.f;
            mma_tf32(s0,s1,s2,s3, qa[0][0],qa[0][1],qa[0][2],qa[0][3], k0,k1);
            mma_tf32(s0,s1,s2,s3, qa[1][0],qa[1][1],qa[1][2],qa[1][3], k2,k3);
            if (tig > 0) { s0 = -3.0e38f; s2 = -3.0e38f; }
            s1 = -3.0e38f; s3 = -3.0e38f;
            float cm0 = fmaxf(s0, s1), cm1 = fmaxf(s2, s3);
            cm0 = fmaxf(cm0, __shfl_xor_sync(0xffffffffu, cm0, 1));
            cm0 = fmaxf(cm0, __shfl_xor_sync(0xffffffffu, cm0, 2));
            cm1 = fmaxf(cm1, __shfl_xor_sync(0xffffffffu, cm1, 1));
            cm1 = fmaxf(cm1, __shfl_xor_sync(0xffffffffu, cm1, 2));
            float mn0 = fmaxf(m0, cm0), mn1 = fmaxf(m1, cm1);
            float c0 = __expf(m0 - mn0), c1 = __expf(m1 - mn1);
            m0 = mn0; m1 = mn1;
            float p0 = __expf(s0 - mn0), p1 = __expf(s1 - mn0);
            float p2 = __expf(s2 - mn1), p3 = __expf(s3 - mn1);
            float ps0 = p0 + p1, ps1 = p2 + p3;
            ps0 += __shfl_xor_sync(0xffffffffu, ps0, 1);
            ps0 += __shfl_xor_sync(0xffffffffu, ps0, 2);
            ps1 += __shfl_xor_sync(0xffffffffu, ps1, 1);
            ps1 += __shfl_xor_sync(0xffffffffu, ps1, 2);
            l0 = l0*c0 + ps0; l1 = l1*c1 + ps1;
            oA[0] *= c0; oA[1] *= c0; oA[2] *= c1; oA[3] *= c1;
            oB[0] *= c0; oB[1] *= c0; oB[2] *= c1; oB[3] *= c1;
            unsigned pa0,pa1,pa2,pa3;
            redistribute_p(cvt_tf32(p0),cvt_tf32(p1),cvt_tf32(p2),cvt_tf32(p3),
                           src1,src2,tig, pa0,pa1,pa2,pa3);
            int vr0 = (256 + tig)*VSTR, vr1 = (256 + tig + 4)*VSTR;
            unsigned v0 = __float_as_uint(Vs[vr0 + g]);
            unsigned v1 = __float_as_uint(Vs[vr1 + g]);
            unsigned v2 = __float_as_uint(Vs[vr0 + g + 8]);
            unsigned v3 = __float_as_uint(Vs[vr1 + g + 8]);
            mma_tf32(oA[0],oA[1],oA[2],oA[3], pa0,pa1,pa2,pa3, v0,v1);
            mma_tf32(oB[0],oB[1],oB[2],oB[3], pa0,pa1,pa2,pa3, v2,v3);
        }
        float inv0 = 1.f / l0, inv1 = 1.f / l1;
        int f0 = tile*16 + g, f1 = f0 + 8;
        if (f0 < FF) {
            float* op = g_fo + ((b*FF + f0)*TT + t)*DC;
            *(float2*)(op + 2*tig)     = make_float2(oA[0]*inv0, oA[1]*inv0);
            *(float2*)(op + 8 + 2*tig) = make_float2(oB[0]*inv0, oB[1]*inv0);
        }
        if (f1 < FF) {
            float* op = g_fo + ((b*FF + f1)*TT + t)*DC;
            *(float2*)(op + 2*tig)     = make_float2(oA[2]*inv1, oA[3]*inv1);
            *(float2*)(op + 8 + 2*tig) = make_float2(oB[2]*inv1, oB[3]*inv1);
        }
    }
}

// ---------------------------------------------------------------------------
// Kernel 3: causal time attention via tf32 mma (16-key double blocks) +
// proj + residual. Warp tiles {w, 15-w, 16+w, 31-w} -> 66 double-blocks each.
// ---------------------------------------------------------------------------
extern __shared__ float sm3[];
__global__ __launch_bounds__(256) void asa_tattn(
    const float* __restrict__ inp,
    const float* __restrict__ pw, const float* __restrict__ pb,
    const float* __restrict__ pg, const float* __restrict__ pbe,
    const float* __restrict__ pm, const float* __restrict__ pv,
    const float* __restrict__ pa,
    float* __restrict__ out)
{
    float* Ks   = sm3;                    // 512*KSTR
    float* Vs   = Ks + 512*KSTR;          // 512*VSTR
    float* pws  = Vs + 512*VSTR;          // 64*16
    float* psh  = pws + 64*16;            // 64
    float* obuf = psh + 64;               // 8 warps * 16*17
    __shared__ float s_alpha;

    int bf = blockIdx.x;
    int b = bf / FF, f = bf % FF;
    int base = bf * TT * DC;
    int tid = threadIdx.x;

    for (int i = tid; i < 512*4; i += 256) {
        int row = i >> 2, j4 = (i & 3) * 4;
        uint4 ku = make_uint4(0,0,0,0), vu = ku;
        if (row < TT) {
            float4 kk = *(const float4*)(g_kt + base + row*DC + j4);
            float4 vv = *(const float4*)(g_fo + base + row*DC + j4);
            ku.x = cvt_tf32(kk.x); ku.y = cvt_tf32(kk.y);
            ku.z = cvt_tf32(kk.z); ku.w = cvt_tf32(kk.w);
            vu.x = cvt_tf32(vv.x); vu.y = cvt_tf32(vv.y);
            vu.z = cvt_tf32(vv.z); vu.w = cvt_tf32(vv.w);
        }
        *(uint4*)(Ks + row*KSTR + j4) = ku;
        *(uint4*)(Vs + row*VSTR + j4) = vu;
    }
    for (int i = tid; i < 64*16; i += 256) {
        int o = i >> 4;
        pws[i] = pw[i] * (pg[o] * rsqrtf(pv[o] + BN_EPS));
    }
    if (tid < 64) {
        int o = tid;
        psh[o] = (pb[o] - pm[o]) * (pg[o] * rsqrtf(pv[o] + BN_EPS)) + pbe[o];
    }
    if (tid == 0) s_alpha = pa[0];
    __syncthreads();

    int warp = tid >> 5, lane = tid & 31;
    int g = lane >> 2, tig = lane & 3;
    int qsel = lane & ~3;
    int src1 = qsel | (tig >> 1);
    int src2 = src1 + 2;
    float alpha = s_alpha;
    float* ob = obuf + warp * (16*17);

    int tiles[4] = { warp, 15 - warp, 16 + warp, 31 - warp };

#pragma unroll
    for (int ti = 0; ti < 4; ti++) {
        int tile = tiles[ti];
        int qt0 = tile * 16;
        int ta = qt0 + g;
        int tb = qt0 + g + 8;
        int tr0 = min(ta, TT-1), tr1 = min(tb, TT-1);
        const float* q0p = g_qt + base + tr0*DC;
        const float* q1p = g_qt + base + tr1*DC;
        unsigned qa[2][4];
#pragma unroll
        for (int ks = 0; ks < 2; ks++) {
            qa[ks][0] = cvt_tf32(q0p[ks*8 + tig]     * SCALE);
            qa[ks][1] = cvt_tf32(q1p[ks*8 + tig]     * SCALE);
            qa[ks][2] = cvt_tf32(q0p[ks*8 + tig + 4] * SCALE);
            qa[ks][3] = cvt_tf32(q1p[ks*8 + tig + 4] * SCALE);
        }
        float m0 = -3.0e38f, m1 = -3.0e38f, l0 = 0.f, l1 = 0.f;
        float oA[4] = {0,0,0,0}, oB[4] = {0,0,0,0};

        for (int kb = 0; kb <= tile; kb++) {
            int krA = (kb*16 + g)*KSTR;
            int krB = (kb*16 + 8 + g)*KSTR;
            unsigned k0 = __float_as_uint(Ks[krA + tig]);
            unsigned k1 = __float_as_uint(Ks[krA + tig + 4]);
            unsigned k2 = __float_as_uint(Ks[krA + tig + 8]);
            unsigned k3 = __float_as_uint(Ks[krA + tig + 12]);
            unsigned k4 = __float_as_uint(Ks[krB + tig]);
            unsigned k5 = __float_as_uint(Ks[krB + tig + 4]);
            unsigned k6 = __float_as_uint(Ks[krB + tig + 8]);
            unsigned k7 = __float_as_uint(Ks[krB + tig + 12]);
            float s0=0.f,s1=0.f,s2=0.f,s3=0.f, s4=0.f,s5=0.f,s6=0.f,s7=0.f;
            mma_tf32(s0,s1,s2,s3, qa[0][0],qa[0][1],qa[0][2],qa[0][3], k0,k1);
            mma_tf32(s0,s1,s2,s3, qa[1][0],qa[1][1],qa[1][2],qa[1][3], k2,k3);
            mma_tf32(s4,s5,s6,s7, qa[0][0],qa[0][1],qa[0][2],qa[0][3], k4,k5);
            mma_tf32(s4,s5,s6,s7, qa[1][0],qa[1][1],qa[1][2],qa[1][3], k6,k7);
            if (kb == tile) {
                int yA0 = kb*16 + 2*tig, yA1 = yA0 + 1;
                int yB0 = yA0 + 8,       yB1 = yA1 + 8;
                if (yA0 > ta) s0 = -3.0e38f;
                if (yA1 > ta) s1 = -3.0e38f;
                if (yA0 > tb) s2 = -3.0e38f;
                if (yA1 > tb) s3 = -3.0e38f;
                if (yB0 > ta) s4 = -3.0e38f;
                if (yB1 > ta) s5 = -3.0e38f;
                if (yB0 > tb) s6 = -3.0e38f;
                if (yB1 > tb) s7 = -3.0e38f;
            }
            float cm0 = fmaxf(fmaxf(s0,s1), fmaxf(s4,s5));
            float cm1 = fmaxf(fmaxf(s2,s3), fmaxf(s6,s7));
            cm0 = fmaxf(cm0, __shfl_xor_sync(0xffffffffu, cm0, 1));
            cm0 = fmaxf(cm0, __shfl_xor_sync(0xffffffffu, cm0, 2));
            cm1 = fmaxf(cm1, __shfl_xor_sync(0xffffffffu, cm1, 1));
            cm1 = fmaxf(cm1, __shfl_xor_sync(0xffffffffu, cm1, 2));
            float mn0 = fmaxf(m0, cm0), mn1 = fmaxf(m1, cm1);
            float c0 = __expf(m0 - mn0), c1 = __expf(m1 - mn1);
            m0 = mn0; m1 = mn1;
            float p0 = __expf(s0 - mn0), p1 = __expf(s1 - mn0);
            float p2 = __expf(s2 - mn1), p3 = __expf(s3 - mn1);
            float p4 = __expf(s4 - mn0), p5 = __expf(s5 - mn0);
            float p6 = __expf(s6 - mn1), p7 = __expf(s7 - mn1);
            float ps0 = (p0 + p1) + (p4 + p5);
            float ps1 = (p2 + p3) + (p6 + p7);
            ps0 += __shfl_xor_sync(0xffffffffu, ps0, 1);
            ps0 += __shfl_xor_sync(0xffffffffu, ps0, 2);
            ps1 += __shfl_xor_sync(0xffffffffu, ps1, 1);
            ps1 += __shfl_xor_sync(0xffffffffu, ps1, 2);
            l0 = l0*c0 + ps0; l1 = l1*c1 + ps1;
            oA[0] *= c0; oA[1] *= c0; oA[2] *= c1; oA[3] *= c1;
            oB[0] *= c0; oB[1] *= c0; oB[2] *= c1; oB[3] *= c1;

            unsigned paA0,paA1,paA2,paA3, paB0,paB1,paB2,paB3;
            redistribute_p(cvt_tf32(p0),cvt_tf32(p1),cvt_tf32(p2),cvt_tf32(p3),
                           src1,src2,tig, paA0,paA1,paA2,paA3);
            redistribute_p(cvt_tf32(p4),cvt_tf32(p5),cvt_tf32(p6),cvt_tf32(p7),
                           src1,src2,tig, paB0,paB1,paB2,paB3);

            int vrA0 = (kb*16 + tig)*VSTR,      vrA1 = (kb*16 + tig + 4)*VSTR;
            int vrB0 = (kb*16 + 8 + tig)*VSTR,  vrB1 = (kb*16 + 12 + tig)*VSTR;
            unsigned vA0 = __float_as_uint(Vs[vrA0 + g]);
            unsigned vA1 = __float_as_uint(Vs[vrA1 + g]);
            unsigned vA2 = __float_as_uint(Vs[vrA0 + g + 8]);
            unsigned vA3 = __float_as_uint(Vs[vrA1 + g + 8]);
            unsigned vB0 = __float_as_uint(Vs[vrB0 + g]);
            unsigned vB1 = __float_as_uint(Vs[vrB1 + g]);
            unsigned vB2 = __float_as_uint(Vs[vrB0 + g + 8]);
            unsigned vB3 = __float_as_uint(Vs[vrB1 + g + 8]);
            mma_tf32(oA[0],oA[1],oA[2],oA[3], paA0,paA1,paA2,paA3, vA0,vA1);
            mma_tf32(oA[0],oA[1],oA[2],oA[3], paB0,paB1,paB2,paB3, vB0,vB1);
            mma_tf32(oB[0],oB[1],oB[2],oB[3], paA0,paA1,paA2,paA3, vA2,vA3);
            mma_tf32(oB[0],oB[1],oB[2],oB[3], paB0,paB1,paB2,paB3, vB2,vB3);
        }
        float inv0 = 1.f / l0, inv1 = 1.f / l1;
        ob[g*17 + 2*tig]          = oA[0]*inv0;
        ob[g*17 + 2*tig + 1]      = oA[1]*inv0;
        ob[g*17 + 8 + 2*tig]      = oB[0]*inv0;
        ob[g*17 + 8 + 2*tig + 1]  = oB[1]*inv0;
        ob[(g+8)*17 + 2*tig]         = oA[2]*inv1;
        ob[(g+8)*17 + 2*tig + 1]     = oA[3]*inv1;
        ob[(g+8)*17 + 8 + 2*tig]     = oB[2]*inv1;
        ob[(g+8)*17 + 8 + 2*tig + 1] = oB[3]*inv1;
        __syncwarp();

        int qi = lane & 15;
        int t = qt0 + qi;
        if (t < TT) {
            const float* orow = ob + qi*17;
            u64 o2[8];
#pragma unroll
            for (int j = 0; j < 8; j++) o2[j] = pk2(orow[2*j], orow[2*j+1]);
            int c0 = (lane >> 4) * 32;
            int obase = b*CC*FTSZ + f*TT + t;
#pragma unroll 4
            for (int j = 0; j < 32; j++) {
                int co = c0 + j;
                const ulonglong2* wr = (const ulonglong2*)(pws + co*16);
                ulonglong2 wa = wr[0], wb = wr[1], wc = wr[2], wd = wr[3];
                u64 d0 = mul2(wa.x, o2[0]);
                u64 d1 = mul2(wa.y, o2[1]);
                d0 = fma2(wb.x, o2[2], d0);
                d1 = fma2(wb.y, o2[3], d1);
                d0 = fma2(wc.x, o2[4], d0);
                d1 = fma2(wc.y, o2[5], d1);
                d0 = fma2(wd.x, o2[6], d0);
                d1 = fma2(wd.y, o2[7], d1);
                float lo0,hi0,lo1,hi1;
                upk2(d0,lo0,hi0); upk2(d1,lo1,hi1);
                float r = psh[co] + (lo0+hi0) + (lo1+hi1);
                r = r >= 0.f ? r : alpha * r;
                int idx = obase + co*FTSZ;
                out[idx] = r + __ldg(&inp[idx]);
            }
        }
        __syncwarp();
    }
}

// ---------------------------------------------------------------------------
extern "C" void kernel_launch(void* const* d_in, const int* in_sizes, int n_in,
                              void* d_out, int out_size)
{
    const float* inp = (const float*)d_in[0];

    int smc_bytes = (128*OSTR + 64*WSTR + 80 + 2) * (int)sizeof(float);
    cudaFuncSetAttribute(asa_conv, cudaFuncAttributeMaxDynamicSharedMemorySize, smc_bytes);
    asa_conv<<<(NPIX + 127)/128, 128, smc_bytes>>>(
        inp,
        (const float*)d_in[1],  (const float*)d_in[2],  (const float*)d_in[3],
        (const float*)d_in[4],  (const float*)d_in[5],  (const float*)d_in[6],
        (const float*)d_in[7],
        (const float*)d_in[8],  (const float*)d_in[9],  (const float*)d_in[10],
        (const float*)d_in[11], (const float*)d_in[12], (const float*)d_in[13],
        (const float*)d_in[14]);

    asa_fattn<<<BB*TT, 288>>>();

    int sm3_bytes = (512*KSTR + 512*VSTR + 64*16 + 64 + 8*16*17) * (int)sizeof(float);
    cudaFuncSetAttribute(asa_tattn, cudaFuncAttributeMaxDynamicSharedMemorySize, sm3_bytes);
    asa_tattn<<<BB*FF, 256, sm3_bytes>>>(
        inp,
        (const float*)d_in[15], (const float*)d_in[16], (const float*)d_in[17],
        (const float*)d_in[18], (const float*)d_in[19], (const float*)d_in[20],
        (const float*)d_in[21],
        (float*)d_out);
}

// round 9
// speedup vs baseline: 2.5661x; 1.0497x over previous
#include <cuda_runtime.h>

#define BB 2
#define CC 64
#define FF 257
#define TT 500
#define DC 16
#define BN_EPS 1e-5f
#define SCALE 0.25f
#define NPIX (BB*FF*TT)
#define FTSZ (FF*TT)

typedef unsigned long long u64;

__device__ __forceinline__ u64 pk2(float lo, float hi) {
    u64 r; asm("mov.b64 %0, {%1,%2};" : "=l"(r) : "f"(lo), "f"(hi)); return r;
}
__device__ __forceinline__ void upk2(u64 v, float& lo, float& hi) {
    asm("mov.b64 {%0,%1}, %2;" : "=f"(lo), "=f"(hi) : "l"(v));
}
__device__ __forceinline__ u64 fma2(u64 a, u64 b, u64 c) {
    u64 d; asm("fma.rn.f32x2 %0, %1, %2, %3;" : "=l"(d) : "l"(a), "l"(b), "l"(c)); return d;
}
__device__ __forceinline__ u64 mul2(u64 a, u64 b) {
    u64 d; asm("mul.rn.f32x2 %0, %1, %2;" : "=l"(d) : "l"(a), "l"(b)); return d;
}
__device__ __forceinline__ unsigned cvt_tf32(float x) {
    unsigned r; asm("cvt.rna.tf32.f32 %0, %1;" : "=r"(r) : "f"(x)); return r;
}
__device__ __forceinline__ void mma_tf32(
    float& d0, float& d1, float& d2, float& d3,
    unsigned a0, unsigned a1, unsigned a2, unsigned a3,
    unsigned b0, unsigned b1)
{
    asm("mma.sync.aligned.m16n8k8.row.col.f32.tf32.tf32.f32 "
        "{%0,%1,%2,%3},{%4,%5,%6,%7},{%8,%9},{%0,%1,%2,%3};"
        : "+f"(d0), "+f"(d1), "+f"(d2), "+f"(d3)
        : "r"(a0), "r"(a1), "r"(a2), "r"(a3), "r"(b0), "r"(b1));
}

// Scratch (device globals; no allocation allowed)
__device__ float g_qf[BB*TT*FF*DC];   // [b][t][f][c]
__device__ float g_kf[BB*TT*FF*DC];   // [b][t][f][c]
__device__ float g_vv[BB*TT*FF*DC];   // [b][t][f][c]
__device__ float g_qt[BB*FF*TT*DC];   // [b][f][t][c]
__device__ float g_kt[BB*FF*TT*DC];   // [b][f][t][c]
__device__ float g_fo[BB*FF*TT*DC];   // [b][f][t][c]

// ---------------------------------------------------------------------------
// Kernel 1: fused 1x1 convs via tf32 MMA, direct fragment stores.
// CTA = 128 pixels, 4 warps. X smem [64][136]; W smem [64][88].
// D fragments -> BN+PReLU in registers -> float2 global scatter.
// ---------------------------------------------------------------------------
#define PSTR 136
#define WSTR 88

extern __shared__ float smc[];
__global__ __launch_bounds__(128) void asa_conv(
    const float* __restrict__ inp,
    const float* __restrict__ fw, const float* __restrict__ fb,
    const float* __restrict__ fg, const float* __restrict__ fbe,
    const float* __restrict__ fm, const float* __restrict__ fv,
    const float* __restrict__ fa,
    const float* __restrict__ tw, const float* __restrict__ tb,
    const float* __restrict__ tg, const float* __restrict__ tbe,
    const float* __restrict__ tm, const float* __restrict__ tv,
    const float* __restrict__ ta)
{
    float* xs = smc;                   // [64][PSTR]
    float* ws = smc + 64*PSTR;         // [64][WSTR]
    float* sh = ws + 64*WSTR;          // [80]
    float* al = sh + 80;               // [2]

    int tid = threadIdx.x;

    // weights (BN scale folded, tf32), permuted op = e*16 + cc
    for (int idx = tid; idx < 80*64; idx += 128) {
        int c = idx & 63, op = idx >> 6;
        int e = op >> 4, cc = op & 15;
        float w, g, vv;
        if (e < 3) { int o = 3*cc + e;      w = fw[o*64+c]; g = fg[o]; vv = fv[o]; }
        else       { int o2 = 2*cc + (e-3); w = tw[o2*64+c]; g = tg[o2]; vv = tv[o2]; }
        ws[c*WSTR + op] = __uint_as_float(cvt_tf32(w * (g * rsqrtf(vv + BN_EPS))));
    }
    if (tid < 80) {
        int op = tid, e = op >> 4, cc = op & 15;
        float g, vv, m, b, be;
        if (e < 3) { int o = 3*cc + e;      g=fg[o]; vv=fv[o]; m=fm[o]; b=fb[o]; be=fbe[o]; }
        else       { int o2 = 2*cc + (e-3); g=tg[o2]; vv=tv[o2]; m=tm[o2]; b=tb[o2]; be=tbe[o2]; }
        sh[op] = (b - m) * (g * rsqrtf(vv + BN_EPS)) + be;
    }
    if (tid == 0) { al[0] = fa[0]; al[1] = ta[0]; }

    // X fill: [ch][px] tf32, stride PSTR
    int p0 = blockIdx.x * 128;
    int b0 = p0 / FTSZ;
    int bend = (p0 + 127) / FTSZ;
    if (b0 == bend && p0 + 127 < NPIX) {
        int ft0 = p0 - b0*FTSZ;
        const float* src = inp + b0*CC*FTSZ + ft0;
        for (int i = tid; i < 64*32; i += 128) {
            int c = i >> 5, l4 = i & 31;
            float4 v = *(const float4*)(src + c*FTSZ + l4*4);
            uint4 u;
            u.x = cvt_tf32(v.x); u.y = cvt_tf32(v.y);
            u.z = cvt_tf32(v.z); u.w = cvt_tf32(v.w);
            *(uint4*)(xs + c*PSTR + l4*4) = u;
        }
    } else {
        for (int i = tid; i < 64*128; i += 128) {
            int c = i >> 7, lp = i & 127;
            int p = p0 + lp;
            float v = 0.f;
            if (p < NPIX) {
                int b = p / FTSZ;
                int ft = p - b*FTSZ;
                v = inp[(b*CC + c)*FTSZ + ft];
            }
            xs[c*PSTR + lp] = __uint_as_float(cvt_tf32(v));
        }
    }
    __syncthreads();

    int warp = tid >> 5, lane = tid & 31;
    int g = lane >> 2, tig = lane & 3;
    int pxA = warp*32, pxB = warp*32 + 16;

    float accA[10][4], accB[10][4];
#pragma unroll
    for (int nt = 0; nt < 10; nt++)
#pragma unroll
        for (int j = 0; j < 4; j++) { accA[nt][j] = 0.f; accB[nt][j] = 0.f; }

#pragma unroll
    for (int k = 0; k < 8; k++) {
        int r0 = (8*k + tig)*PSTR, r1 = (8*k + tig + 4)*PSTR;
        unsigned aA0 = __float_as_uint(xs[r0 + pxA + g]);
        unsigned aA1 = __float_as_uint(xs[r0 + pxA + g + 8]);
        unsigned aA2 = __float_as_uint(xs[r1 + pxA + g]);
        unsigned aA3 = __float_as_uint(xs[r1 + pxA + g + 8]);
        unsigned aB0 = __float_as_uint(xs[r0 + pxB + g]);
        unsigned aB1 = __float_as_uint(xs[r0 + pxB + g + 8]);
        unsigned aB2 = __float_as_uint(xs[r1 + pxB + g]);
        unsigned aB3 = __float_as_uint(xs[r1 + pxB + g + 8]);
        int w0 = (8*k + tig)*WSTR + g, w1 = (8*k + tig + 4)*WSTR + g;
#pragma unroll
        for (int nt = 0; nt < 10; nt++) {
            unsigned bb0 = __float_as_uint(ws[w0 + nt*8]);
            unsigned bb1 = __float_as_uint(ws[w1 + nt*8]);
            mma_tf32(accA[nt][0], accA[nt][1], accA[nt][2], accA[nt][3],
                     aA0, aA1, aA2, aA3, bb0, bb1);
            mma_tf32(accB[nt][0], accB[nt][1], accB[nt][2], accB[nt][3],
                     aB0, aB1, aB2, aB3, bb0, bb1);
        }
    }

    // direct epilogue: BN shift + PReLU in registers, float2 scatter
    float sh0[10], sh1[10];
#pragma unroll
    for (int nt = 0; nt < 10; nt++) {
        sh0[nt] = sh[nt*8 + 2*tig];
        sh1[nt] = sh[nt*8 + 2*tig + 1];
    }
    float a0v = al[0], a1v = al[1];

#pragma unroll
    for (int r = 0; r < 4; r++) {
        int px  = (r < 2 ? pxA : pxB) + g + (r & 1) * 8;
        int off = (r & 1) * 2;     // 0 -> d0/d1, 2 -> d2/d3
        int p = p0 + px;
        if (p >= NPIX) continue;
        int b = p / FTSZ;
        int ft = p - b*FTSZ;
        int f = ft / TT;
        int t = ft - f*TT;
        int fidx = ((b*TT + t)*FF + f)*DC;
        int tidx = ((b*FF + f)*TT + t)*DC;
        float* dsts[5];
        dsts[0] = g_qf + fidx;
        dsts[1] = g_kf + fidx;
        dsts[2] = g_vv + fidx;
        dsts[3] = g_qt + tidx;
        dsts[4] = g_kt + tidx;
        const float (*ac)[4] = (r < 2) ? accA : accB;
#pragma unroll
        for (int nt = 0; nt < 10; nt++) {
            int e = nt >> 1;
            float alpha = (e < 3) ? a0v : a1v;
            float v0 = ac[nt][off]     + sh0[nt];
            float v1 = ac[nt][off + 1] + sh1[nt];
            v0 = v0 >= 0.f ? v0 : alpha * v0;
            v1 = v1 >= 0.f ? v1 : alpha * v1;
            *(float2*)(dsts[e] + (nt & 1)*8 + 2*tig) = make_float2(v0, v1);
        }
    }
}

// ---------------------------------------------------------------------------
// Shared warp-level helpers for attention (tf32 MMA path).
// ---------------------------------------------------------------------------
#define KSTR 20
#define VSTR 24

__device__ __forceinline__ void redistribute_p(
    unsigned u0, unsigned u1, unsigned u2, unsigned u3,
    int src1, int src2, int tig,
    unsigned& pa0, unsigned& pa1, unsigned& pa2, unsigned& pa3)
{
    unsigned x0 = __shfl_sync(0xffffffffu, u0, src1);
    unsigned x1 = __shfl_sync(0xffffffffu, u1, src1);
    pa0 = (tig & 1) ? x1 : x0;
    unsigned y0 = __shfl_sync(0xffffffffu, u2, src1);
    unsigned y1 = __shfl_sync(0xffffffffu, u3, src1);
    pa1 = (tig & 1) ? y1 : y0;
    x0 = __shfl_sync(0xffffffffu, u0, src2);
    x1 = __shfl_sync(0xffffffffu, u1, src2);
    pa2 = (tig & 1) ? x1 : x0;
    y0 = __shfl_sync(0xffffffffu, u2, src2);
    y1 = __shfl_sync(0xffffffffu, u3, src2);
    pa3 = (tig & 1) ? y1 : y0;
}

// ---------------------------------------------------------------------------
// Kernel 2: frequency attention via tf32 mma, 16-key double blocks.
// ---------------------------------------------------------------------------
__global__ __launch_bounds__(288) void asa_fattn()
{
    __shared__ float Ks[264*KSTR];
    __shared__ float Vs[264*VSTR];
    int bt = blockIdx.x;
    int b = bt / TT, t = bt % TT;
    int base = (b*TT + t)*FF*DC;
    int tid = threadIdx.x;

    for (int i = tid; i < 264*4; i += 288) {
        int row = i >> 2, j4 = (i & 3) * 4;
        uint4 ku = make_uint4(0,0,0,0), vu = ku;
        if (row < FF) {
            float4 kk = *(const float4*)(g_kf + base + row*DC + j4);
            float4 vv = *(const float4*)(g_vv + base + row*DC + j4);
            ku.x = cvt_tf32(kk.x); ku.y = cvt_tf32(kk.y);
            ku.z = cvt_tf32(kk.z); ku.w = cvt_tf32(kk.w);
            vu.x = cvt_tf32(vv.x); vu.y = cvt_tf32(vv.y);
            vu.z = cvt_tf32(vv.z); vu.w = cvt_tf32(vv.w);
        }
        *(uint4*)(Ks + row*KSTR + j4) = ku;
        *(uint4*)(Vs + row*VSTR + j4) = vu;
    }
    __syncthreads();

    int warp = tid >> 5, lane = tid & 31;
    int g = lane >> 2, tig = lane & 3;
    int qsel = lane & ~3;
    int src1 = qsel | (tig >> 1);
    int src2 = src1 + 2;

    for (int tile = warp; tile < 17; tile += 9) {
        int fr0 = min(tile*16 + g, FF-1);
        int fr1 = min(tile*16 + g + 8, FF-1);
        const float* q0p = g_qf + base + fr0*DC;
        const float* q1p = g_qf + base + fr1*DC;
        unsigned qa[2][4];
#pragma unroll
        for (int ks = 0; ks < 2; ks++) {
            qa[ks][0] = cvt_tf32(q0p[ks*8 + tig]     * SCALE);
            qa[ks][1] = cvt_tf32(q1p[ks*8 + tig]     * SCALE);
            qa[ks][2] = cvt_tf32(q0p[ks*8 + tig + 4] * SCALE);
            qa[ks][3] = cvt_tf32(q1p[ks*8 + tig + 4] * SCALE);
        }
        float m0 = -3.0e38f, m1 = -3.0e38f, l0 = 0.f, l1 = 0.f;
        float oA[4] = {0,0,0,0}, oB[4] = {0,0,0,0};

        for (int kb = 0; kb < 16; kb++) {
            int krA = (kb*16 + g)*KSTR;
            int krB = (kb*16 + 8 + g)*KSTR;
            unsigned k0 = __float_as_uint(Ks[krA + tig]);
            unsigned k1 = __float_as_uint(Ks[krA + tig + 4]);
            unsigned k2 = __float_as_uint(Ks[krA + tig + 8]);
            unsigned k3 = __float_as_uint(Ks[krA + tig + 12]);
            unsigned k4 = __float_as_uint(Ks[krB + tig]);
            unsigned k5 = __float_as_uint(Ks[krB + tig + 4]);
            unsigned k6 = __float_as_uint(Ks[krB + tig + 8]);
            unsigned k7 = __float_as_uint(Ks[krB + tig + 12]);
            float s0=0.f,s1=0.f,s2=0.f,s3=0.f, s4=0.f,s5=0.f,s6=0.f,s7=0.f;
            mma_tf32(s0,s1,s2,s3, qa[0][0],qa[0][1],qa[0][2],qa[0][3], k0,k1);
            mma_tf32(s0,s1,s2,s3, qa[1][0],qa[1][1],qa[1][2],qa[1][3], k2,k3);
            mma_tf32(s4,s5,s6,s7, qa[0][0],qa[0][1],qa[0][2],qa[0][3], k4,k5);
            mma_tf32(s4,s5,s6,s7, qa[1][0],qa[1][1],qa[1][2],qa[1][3], k6,k7);

            float cm0 = fmaxf(fmaxf(s0,s1), fmaxf(s4,s5));
            float cm1 = fmaxf(fmaxf(s2,s3), fmaxf(s6,s7));
            cm0 = fmaxf(cm0, __shfl_xor_sync(0xffffffffu, cm0, 1));
            cm0 = fmaxf(cm0, __shfl_xor_sync(0xffffffffu, cm0, 2));
            cm1 = fmaxf(cm1, __shfl_xor_sync(0xffffffffu, cm1, 1));
            cm1 = fmaxf(cm1, __shfl_xor_sync(0xffffffffu, cm1, 2));
            float mn0 = fmaxf(m0, cm0), mn1 = fmaxf(m1, cm1);
            float c0 = __expf(m0 - mn0), c1 = __expf(m1 - mn1);
            m0 = mn0; m1 = mn1;
            float p0 = __expf(s0 - mn0), p1 = __expf(s1 - mn0);
            float p2 = __expf(s2 - mn1), p3 = __expf(s3 - mn1);
            float p4 = __expf(s4 - mn0), p5 = __expf(s5 - mn0);
            float p6 = __expf(s6 - mn1), p7 = __expf(s7 - mn1);
            float ps0 = (p0 + p1) + (p4 + p5);
            float ps1 = (p2 + p3) + (p6 + p7);
            ps0 += __shfl_xor_sync(0xffffffffu, ps0, 1);
            ps0 += __shfl_xor_sync(0xffffffffu, ps0, 2);
            ps1 += __shfl_xor_sync(0xffffffffu, ps1, 1);
            ps1 += __shfl_xor_sync(0xffffffffu, ps1, 2);
            l0 = l0*c0 + ps0; l1 = l1*c1 + ps1;
            oA[0] *= c0; oA[1] *= c0; oA[2] *= c1; oA[3] *= c1;
            oB[0] *= c0; oB[1] *= c0; oB[2] *= c1; oB[3] *= c1;

            unsigned paA0,paA1,paA2,paA3, paB0,paB1,paB2,paB3;
            redistribute_p(cvt_tf32(p0),cvt_tf32(p1),cvt_tf32(p2),cvt_tf32(p3),
                           src1,src2,tig, paA0,paA1,paA2,paA3);
            redistribute_p(cvt_tf32(p4),cvt_tf32(p5),cvt_tf32(p6),cvt_tf32(p7),
                           src1,src2,tig, paB0,paB1,paB2,paB3);

            int vrA0 = (kb*16 + tig)*VSTR,      vrA1 = (kb*16 + tig + 4)*VSTR;
            int vrB0 = (kb*16 + 8 + tig)*VSTR,  vrB1 = (kb*16 + 12 + tig)*VSTR;
            unsigned vA0 = __float_as_uint(Vs[vrA0 + g]);
            unsigned vA1 = __float_as_uint(Vs[vrA1 + g]);
            unsigned vA2 = __float_as_uint(Vs[vrA0 + g + 8]);
            unsigned vA3 = __float_as_uint(Vs[vrA1 + g + 8]);
            unsigned vB0 = __float_as_uint(Vs[vrB0 + g]);
            unsigned vB1 = __float_as_uint(Vs[vrB1 + g]);
            unsigned vB2 = __float_as_uint(Vs[vrB0 + g + 8]);
            unsigned vB3 = __float_as_uint(Vs[vrB1 + g + 8]);
            mma_tf32(oA[0],oA[1],oA[2],oA[3], paA0,paA1,paA2,paA3, vA0,vA1);
            mma_tf32(oA[0],oA[1],oA[2],oA[3], paB0,paB1,paB2,paB3, vB0,vB1);
            mma_tf32(oB[0],oB[1],oB[2],oB[3], paA0,paA1,paA2,paA3, vA2,vA3);
            mma_tf32(oB[0],oB[1],oB[2],oB[3], paB0,paB1,paB2,paB3, vB2,vB3);
        }
        // tail single block: key 256 (cols >0 masked)
        {
            int krow = (256 + g)*KSTR;
            unsigned k0 = __float_as_uint(Ks[krow + tig]);
            unsigned k1 = __float_as_uint(Ks[krow + tig + 4]);
            unsigned k2 = __float_as_uint(Ks[krow + tig + 8]);
            unsigned k3 = __float_as_uint(Ks[krow + tig + 12]);
            float s0=0.f,s1=0.f,s2=0.f,s3=0.f;
            mma_tf32(s0,s1,s2,s3, qa[0][0],qa[0][1],qa[0][2],qa[0][3], k0,k1);
            mma_tf32(s0,s1,s2,s3, qa[1][0],qa[1][1],qa[1][2],qa[1][3], k2,k3);
            if (tig > 0) { s0 = -3.0e38f; s2 = -3.0e38f; }
            s1 = -3.0e38f; s3 = -3.0e38f;
            float cm0 = fmaxf(s0, s1), cm1 = fmaxf(s2, s3);
            cm0 = fmaxf(cm0, __shfl_xor_sync(0xffffffffu, cm0, 1));
            cm0 = fmaxf(cm0, __shfl_xor_sync(0xffffffffu, cm0, 2));
            cm1 = fmaxf(cm1, __shfl_xor_sync(0xffffffffu, cm1, 1));
            cm1 = fmaxf(cm1, __shfl_xor_sync(0xffffffffu, cm1, 2));
            float mn0 = fmaxf(m0, cm0), mn1 = fmaxf(m1, cm1);
            float c0 = __expf(m0 - mn0), c1 = __expf(m1 - mn1);
            m0 = mn0; m1 = mn1;
            float p0 = __expf(s0 - mn0), p1 = __expf(s1 - mn0);
            float p2 = __expf(s2 - mn1), p3 = __expf(s3 - mn1);
            float ps0 = p0 + p1, ps1 = p2 + p3;
            ps0 += __shfl_xor_sync(0xffffffffu, ps0, 1);
            ps0 += __shfl_xor_sync(0xffffffffu, ps0, 2);
            ps1 += __shfl_xor_sync(0xffffffffu, ps1, 1);
            ps1 += __shfl_xor_sync(0xffffffffu, ps1, 2);
            l0 = l0*c0 + ps0; l1 = l1*c1 + ps1;
            oA[0] *= c0; oA[1] *= c0; oA[2] *= c1; oA[3] *= c1;
            oB[0] *= c0; oB[1] *= c0; oB[2] *= c1; oB[3] *= c1;
            unsigned pa0,pa1,pa2,pa3;
            redistribute_p(cvt_tf32(p0),cvt_tf32(p1),cvt_tf32(p2),cvt_tf32(p3),
                           src1,src2,tig, pa0,pa1,pa2,pa3);
            int vr0 = (256 + tig)*VSTR, vr1 = (256 + tig + 4)*VSTR;
            unsigned v0 = __float_as_uint(Vs[vr0 + g]);
            unsigned v1 = __float_as_uint(Vs[vr1 + g]);
            unsigned v2 = __float_as_uint(Vs[vr0 + g + 8]);
            unsigned v3 = __float_as_uint(Vs[vr1 + g + 8]);
            mma_tf32(oA[0],oA[1],oA[2],oA[3], pa0,pa1,pa2,pa3, v0,v1);
            mma_tf32(oB[0],oB[1],oB[2],oB[3], pa0,pa1,pa2,pa3, v2,v3);
        }
        float inv0 = 1.f / l0, inv1 = 1.f / l1;
        int f0 = tile*16 + g, f1 = f0 + 8;
        if (f0 < FF) {
            float* op = g_fo + ((b*FF + f0)*TT + t)*DC;
            *(float2*)(op + 2*tig)     = make_float2(oA[0]*inv0, oA[1]*inv0);
            *(float2*)(op + 8 + 2*tig) = make_float2(oB[0]*inv0, oB[1]*inv0);
        }
        if (f1 < FF) {
            float* op = g_fo + ((b*FF + f1)*TT + t)*DC;
            *(float2*)(op + 2*tig)     = make_float2(oA[2]*inv1, oA[3]*inv1);
            *(float2*)(op + 8 + 2*tig) = make_float2(oB[2]*inv1, oB[3]*inv1);
        }
    }
}

// ---------------------------------------------------------------------------
// Kernel 3: causal time attention via tf32 mma (16-key double blocks) +
// proj + residual. Warp tiles {w, 15-w, 16+w, 31-w} -> 66 double-blocks each.
// ---------------------------------------------------------------------------
extern __shared__ float sm3[];
__global__ __launch_bounds__(256) void asa_tattn(
    const float* __restrict__ inp,
    const float* __restrict__ pw, const float* __restrict__ pb,
    const float* __restrict__ pg, const float* __restrict__ pbe,
    const float* __restrict__ pm, const float* __restrict__ pv,
    const float* __restrict__ pa,
    float* __restrict__ out)
{
    float* Ks   = sm3;                    // 512*KSTR
    float* Vs   = Ks + 512*KSTR;          // 512*VSTR
    float* pws  = Vs + 512*VSTR;          // 64*16
    float* psh  = pws + 64*16;            // 64
    float* obuf = psh + 64;               // 8 warps * 16*17
    __shared__ float s_alpha;

    int bf = blockIdx.x;
    int b = bf / FF, f = bf % FF;
    int base = bf * TT * DC;
    int tid = threadIdx.x;

    for (int i = tid; i < 512*4; i += 256) {
        int row = i >> 2, j4 = (i & 3) * 4;
        uint4 ku = make_uint4(0,0,0,0), vu = ku;
        if (row < TT) {
            float4 kk = *(const float4*)(g_kt + base + row*DC + j4);
            float4 vv = *(const float4*)(g_fo + base + row*DC + j4);
            ku.x = cvt_tf32(kk.x); ku.y = cvt_tf32(kk.y);
            ku.z = cvt_tf32(kk.z); ku.w = cvt_tf32(kk.w);
            vu.x = cvt_tf32(vv.x); vu.y = cvt_tf32(vv.y);
            vu.z = cvt_tf32(vv.z); vu.w = cvt_tf32(vv.w);
        }
        *(uint4*)(Ks + row*KSTR + j4) = ku;
        *(uint4*)(Vs + row*VSTR + j4) = vu;
    }
    for (int i = tid; i < 64*16; i += 256) {
        int o = i >> 4;
        pws[i] = pw[i] * (pg[o] * rsqrtf(pv[o] + BN_EPS));
    }
    if (tid < 64) {
        int o = tid;
        psh[o] = (pb[o] - pm[o]) * (pg[o] * rsqrtf(pv[o] + BN_EPS)) + pbe[o];
    }
    if (tid == 0) s_alpha = pa[0];
    __syncthreads();

    int warp = tid >> 5, lane = tid & 31;
    int g = lane >> 2, tig = lane & 3;
    int qsel = lane & ~3;
    int src1 = qsel | (tig >> 1);
    int src2 = src1 + 2;
    float alpha = s_alpha;
    float* ob = obuf + warp * (16*17);

    int tiles[4] = { warp, 15 - warp, 16 + warp, 31 - warp };

#pragma unroll
    for (int ti = 0; ti < 4; ti++) {
        int tile = tiles[ti];
        int qt0 = tile * 16;
        int ta = qt0 + g;
        int tb = qt0 + g + 8;
        int tr0 = min(ta, TT-1), tr1 = min(tb, TT-1);
        const float* q0p = g_qt + base + tr0*DC;
        const float* q1p = g_qt + base + tr1*DC;
        unsigned qa[2][4];
#pragma unroll
        for (int ks = 0; ks < 2; ks++) {
            qa[ks][0] = cvt_tf32(q0p[ks*8 + tig]     * SCALE);
            qa[ks][1] = cvt_tf32(q1p[ks*8 + tig]     * SCALE);
            qa[ks][2] = cvt_tf32(q0p[ks*8 + tig + 4] * SCALE);
            qa[ks][3] = cvt_tf32(q1p[ks*8 + tig + 4] * SCALE);
        }
        float m0 = -3.0e38f, m1 = -3.0e38f, l0 = 0.f, l1 = 0.f;
        float oA[4] = {0,0,0,0}, oB[4] = {0,0,0,0};

        for (int kb = 0; kb <= tile; kb++) {
            int krA = (kb*16 + g)*KSTR;
            int krB = (kb*16 + 8 + g)*KSTR;
            unsigned k0 = __float_as_uint(Ks[krA + tig]);
            unsigned k1 = __float_as_uint(Ks[krA + tig + 4]);
            unsigned k2 = __float_as_uint(Ks[krA + tig + 8]);
            unsigned k3 = __float_as_uint(Ks[krA + tig + 12]);
            unsigned k4 = __float_as_uint(Ks[krB + tig]);
            unsigned k5 = __float_as_uint(Ks[krB + tig + 4]);
            unsigned k6 = __float_as_uint(Ks[krB + tig + 8]);
            unsigned k7 = __float_as_uint(Ks[krB + tig + 12]);
            float s0=0.f,s1=0.f,s2=0.f,s3=0.f, s4=0.f,s5=0.f,s6=0.f,s7=0.f;
            mma_tf32(s0,s1,s2,s3, qa[0][0],qa[0][1],qa[0][2],qa[0][3], k0,k1);
            mma_tf32(s0,s1,s2,s3, qa[1][0],qa[1][1],qa[1][2],qa[1][3], k2,k3);
            mma_tf32(s4,s5,s6,s7, qa[0][0],qa[0][1],qa[0][2],qa[0][3], k4,k5);
            mma_tf32(s4,s5,s6,s7, qa[1][0],qa[1][1],qa[1][2],qa[1][3], k6,k7);
            if (kb == tile) {
                int yA0 = kb*16 + 2*tig, yA1 = yA0 + 1;
                int yB0 = yA0 + 8,       yB1 = yA1 + 8;
                if (yA0 > ta) s0 = -3.0e38f;
                if (yA1 > ta) s1 = -3.0e38f;
                if (yA0 > tb) s2 = -3.0e38f;
                if (yA1 > tb) s3 = -3.0e38f;
                if (yB0 > ta) s4 = -3.0e38f;
                if (yB1 > ta) s5 = -3.0e38f;
                if (yB0 > tb) s6 = -3.0e38f;
                if (yB1 > tb) s7 = -3.0e38f;
            }
            float cm0 = fmaxf(fmaxf(s0,s1), fmaxf(s4,s5));
            float cm1 = fmaxf(fmaxf(s2,s3), fmaxf(s6,s7));
            cm0 = fmaxf(cm0, __shfl_xor_sync(0xffffffffu, cm0, 1));
            cm0 = fmaxf(cm0, __shfl_xor_sync(0xffffffffu, cm0, 2));
            cm1 = fmaxf(cm1, __shfl_xor_sync(0xffffffffu, cm1, 1));
            cm1 = fmaxf(cm1, __shfl_xor_sync(0xffffffffu, cm1, 2));
            float mn0 = fmaxf(m0, cm0), mn1 = fmaxf(m1, cm1);
            float c0 = __expf(m0 - mn0), c1 = __expf(m1 - mn1);
            m0 = mn0; m1 = mn1;
            float p0 = __expf(s0 - mn0), p1 = __expf(s1 - mn0);
            float p2 = __expf(s2 - mn1), p3 = __expf(s3 - mn1);
            float p4 = __expf(s4 - mn0), p5 = __expf(s5 - mn0);
            float p6 = __expf(s6 - mn1), p7 = __expf(s7 - mn1);
            float ps0 = (p0 + p1) + (p4 + p5);
            float ps1 = (p2 + p3) + (p6 + p7);
            ps0 += __shfl_xor_sync(0xffffffffu, ps0, 1);
            ps0 += __shfl_xor_sync(0xffffffffu, ps0, 2);
            ps1 += __shfl_xor_sync(0xffffffffu, ps1, 1);
            ps1 += __shfl_xor_sync(0xffffffffu, ps1, 2);
            l0 = l0*c0 + ps0; l1 = l1*c1 + ps1;
            oA[0] *= c0; oA[1] *= c0; oA[2] *= c1; oA[3] *= c1;
            oB[0] *= c0; oB[1] *= c0; oB[2] *= c1; oB[3] *= c1;

            unsigned paA0,paA1,paA2,paA3, paB0,paB1,paB2,paB3;
            redistribute_p(cvt_tf32(p0),cvt_tf32(p1),cvt_tf32(p2),cvt_tf32(p3),
                           src1,src2,tig, paA0,paA1,paA2,paA3);
            redistribute_p(cvt_tf32(p4),cvt_tf32(p5),cvt_tf32(p6),cvt_tf32(p7),
                           src1,src2,tig, paB0,paB1,paB2,paB3);

            int vrA0 = (kb*16 + tig)*VSTR,      vrA1 = (kb*16 + tig + 4)*VSTR;
            int vrB0 = (kb*16 + 8 + tig)*VSTR,  vrB1 = (kb*16 + 12 + tig)*VSTR;
            unsigned vA0 = __float_as_uint(Vs[vrA0 + g]);
            unsigned vA1 = __float_as_uint(Vs[vrA1 + g]);
            unsigned vA2 = __float_as_uint(Vs[vrA0 + g + 8]);
            unsigned vA3 = __float_as_uint(Vs[vrA1 + g + 8]);
            unsigned vB0 = __float_as_uint(Vs[vrB0 + g]);
            unsigned vB1 = __float_as_uint(Vs[vrB1 + g]);
            unsigned vB2 = __float_as_uint(Vs[vrB0 + g + 8]);
            unsigned vB3 = __float_as_uint(Vs[vrB1 + g + 8]);
            mma_tf32(oA[0],oA[1],oA[2],oA[3], paA0,paA1,paA2,paA3, vA0,vA1);
            mma_tf32(oA[0],oA[1],oA[2],oA[3], paB0,paB1,paB2,paB3, vB0,vB1);
            mma_tf32(oB[0],oB[1],oB[2],oB[3], paA0,paA1,paA2,paA3, vA2,vA3);
            mma_tf32(oB[0],oB[1],oB[2],oB[3], paB0,paB1,paB2,paB3, vB2,vB3);
        }
        float inv0 = 1.f / l0, inv1 = 1.f / l1;
        ob[g*17 + 2*tig]          = oA[0]*inv0;
        ob[g*17 + 2*tig + 1]      = oA[1]*inv0;
        ob[g*17 + 8 + 2*tig]      = oB[0]*inv0;
        ob[g*17 + 8 + 2*tig + 1]  = oB[1]*inv0;
        ob[(g+8)*17 + 2*tig]         = oA[2]*inv1;
        ob[(g+8)*17 + 2*tig + 1]     = oA[3]*inv1;
        ob[(g+8)*17 + 8 + 2*tig]     = oB[2]*inv1;
        ob[(g+8)*17 + 8 + 2*tig + 1] = oB[3]*inv1;
        __syncwarp();

        int qi = lane & 15;
        int t = qt0 + qi;
        if (t < TT) {
            const float* orow = ob + qi*17;
            u64 o2[8];
#pragma unroll
            for (int j = 0; j < 8; j++) o2[j] = pk2(orow[2*j], orow[2*j+1]);
            int c0 = (lane >> 4) * 32;
            int obase = b*CC*FTSZ + f*TT + t;
#pragma unroll 4
            for (int j = 0; j < 32; j++) {
                int co = c0 + j;
                const ulonglong2* wr = (const ulonglong2*)(pws + co*16);
                ulonglong2 wa = wr[0], wb = wr[1], wc = wr[2], wd = wr[3];
                u64 d0 = mul2(wa.x, o2[0]);
                u64 d1 = mul2(wa.y, o2[1]);
                d0 = fma2(wb.x, o2[2], d0);
                d1 = fma2(wb.y, o2[3], d1);
                d0 = fma2(wc.x, o2[4], d0);
                d1 = fma2(wc.y, o2[5], d1);
                d0 = fma2(wd.x, o2[6], d0);
                d1 = fma2(wd.y, o2[7], d1);
                float lo0,hi0,lo1,hi1;
                upk2(d0,lo0,hi0); upk2(d1,lo1,hi1);
                float r = psh[co] + (lo0+hi0) + (lo1+hi1);
                r = r >= 0.f ? r : alpha * r;
                int idx = obase + co*FTSZ;
                out[idx] = r + __ldg(&inp[idx]);
            }
        }
        __syncwarp();
    }
}

// ---------------------------------------------------------------------------
extern "C" void kernel_launch(void* const* d_in, const int* in_sizes, int n_in,
                              void* d_out, int out_size)
{
    const float* inp = (const float*)d_in[0];

    int smc_bytes = (64*PSTR + 64*WSTR + 80 + 2) * (int)sizeof(float);
    cudaFuncSetAttribute(asa_conv, cudaFuncAttributeMaxDynamicSharedMemorySize, smc_bytes);
    asa_conv<<<(NPIX + 127)/128, 128, smc_bytes>>>(
        inp,
        (const float*)d_in[1],  (const float*)d_in[2],  (const float*)d_in[3],
        (const float*)d_in[4],  (const float*)d_in[5],  (const float*)d_in[6],
        (const float*)d_in[7],
        (const float*)d_in[8],  (const float*)d_in[9],  (const float*)d_in[10],
        (const float*)d_in[11], (const float*)d_in[12], (const float*)d_in[13],
        (const float*)d_in[14]);

    asa_fattn<<<BB*TT, 288>>>();

    int sm3_bytes = (512*KSTR + 512*VSTR + 64*16 + 64 + 8*16*17) * (int)sizeof(float);
    cudaFuncSetAttribute(asa_tattn, cudaFuncAttributeMaxDynamicSharedMemorySize, sm3_bytes);
    asa_tattn<<<BB*FF, 256, sm3_bytes>>>(
        inp,
        (const float*)d_in[15], (const float*)d_in[16], (const float*)d_in[17],
        (const float*)d_in[18], (const float*)d_in[19], (const float*)d_in[20],
        (const float*)d_in[21],
        (float*)d_out);
}

// round 10
// speedup vs baseline: 2.7440x; 1.0693x over previous
#include <cuda_runtime.h>

#define BB 2
#define CC 64
#define FF 257
#define TT 500
#define DC 16
#define BN_EPS 1e-5f
#define SCALE2 0.36067376022224085f   /* 0.25 * log2(e) */
#define NPIX (BB*FF*TT)
#define FTSZ (FF*TT)

typedef unsigned long long u64;

__device__ __forceinline__ u64 pk2(float lo, float hi) {
    u64 r; asm("mov.b64 %0, {%1,%2};" : "=l"(r) : "f"(lo), "f"(hi)); return r;
}
__device__ __forceinline__ void upk2(u64 v, float& lo, float& hi) {
    asm("mov.b64 {%0,%1}, %2;" : "=f"(lo), "=f"(hi) : "l"(v));
}
__device__ __forceinline__ u64 fma2(u64 a, u64 b, u64 c) {
    u64 d; asm("fma.rn.f32x2 %0, %1, %2, %3;" : "=l"(d) : "l"(a), "l"(b), "l"(c)); return d;
}
__device__ __forceinline__ u64 mul2(u64 a, u64 b) {
    u64 d; asm("mul.rn.f32x2 %0, %1, %2;" : "=l"(d) : "l"(a), "l"(b)); return d;
}
__device__ __forceinline__ unsigned cvt_tf32(float x) {
    unsigned r; asm("cvt.rna.tf32.f32 %0, %1;" : "=r"(r) : "f"(x)); return r;
}
__device__ __forceinline__ void mma_tf32(
    float& d0, float& d1, float& d2, float& d3,
    unsigned a0, unsigned a1, unsigned a2, unsigned a3,
    unsigned b0, unsigned b1)
{
    asm("mma.sync.aligned.m16n8k8.row.col.f32.tf32.tf32.f32 "
        "{%0,%1,%2,%3},{%4,%5,%6,%7},{%8,%9},{%0,%1,%2,%3};"
        : "+f"(d0), "+f"(d1), "+f"(d2), "+f"(d3)
        : "r"(a0), "r"(a1), "r"(a2), "r"(a3), "r"(b0), "r"(b1));
}

// Scratch (device globals; no allocation allowed)
__device__ float g_qf[BB*TT*FF*DC];   // [b][t][f][c]
__device__ float g_kf[BB*TT*FF*DC];   // [b][t][f][c]
__device__ float g_vv[BB*TT*FF*DC];   // [b][t][f][c]
__device__ float g_qt[BB*FF*TT*DC];   // [b][f][t][c]
__device__ float g_kt[BB*FF*TT*DC];   // [b][f][t][c]
__device__ float g_fo[BB*FF*TT*DC];   // [b][f][t][c]

// ---------------------------------------------------------------------------
// Kernel 1: fused 1x1 convs via tf32 MMA, 8 warps per 128-px tile,
// direct fragment stores.
// ---------------------------------------------------------------------------
#define PSTR 136
#define WSTR 88

extern __shared__ float smc[];
__global__ __launch_bounds__(256) void asa_conv(
    const float* __restrict__ inp,
    const float* __restrict__ fw, const float* __restrict__ fb,
    const float* __restrict__ fg, const float* __restrict__ fbe,
    const float* __restrict__ fm, const float* __restrict__ fv,
    const float* __restrict__ fa,
    const float* __restrict__ tw, const float* __restrict__ tb,
    const float* __restrict__ tg, const float* __restrict__ tbe,
    const float* __restrict__ tm, const float* __restrict__ tv,
    const float* __restrict__ ta)
{
    float* xs = smc;                   // [64][PSTR]
    float* ws = smc + 64*PSTR;         // [64][WSTR]
    float* sh = ws + 64*WSTR;          // [80]
    float* al = sh + 80;               // [2]

    int tid = threadIdx.x;

    // weights (BN scale folded, tf32), permuted op = e*16 + cc
    for (int idx = tid; idx < 80*64; idx += 256) {
        int c = idx & 63, op = idx >> 6;
        int e = op >> 4, cc = op & 15;
        float w, g, vv;
        if (e < 3) { int o = 3*cc + e;      w = fw[o*64+c]; g = fg[o]; vv = fv[o]; }
        else       { int o2 = 2*cc + (e-3); w = tw[o2*64+c]; g = tg[o2]; vv = tv[o2]; }
        ws[c*WSTR + op] = __uint_as_float(cvt_tf32(w * (g * rsqrtf(vv + BN_EPS))));
    }
    if (tid < 80) {
        int op = tid, e = op >> 4, cc = op & 15;
        float g, vv, m, b, be;
        if (e < 3) { int o = 3*cc + e;      g=fg[o]; vv=fv[o]; m=fm[o]; b=fb[o]; be=fbe[o]; }
        else       { int o2 = 2*cc + (e-3); g=tg[o2]; vv=tv[o2]; m=tm[o2]; b=tb[o2]; be=tbe[o2]; }
        sh[op] = (b - m) * (g * rsqrtf(vv + BN_EPS)) + be;
    }
    if (tid == 0) { al[0] = fa[0]; al[1] = ta[0]; }

    // X fill: [ch][px] tf32, stride PSTR
    int p0 = blockIdx.x * 128;
    int b0 = p0 / FTSZ;
    int bend = (p0 + 127) / FTSZ;
    if (b0 == bend && p0 + 127 < NPIX) {
        int ft0 = p0 - b0*FTSZ;
        const float* src = inp + b0*CC*FTSZ + ft0;
        for (int i = tid; i < 64*32; i += 256) {
            int c = i >> 5, l4 = i & 31;
            float4 v = *(const float4*)(src + c*FTSZ + l4*4);
            uint4 u;
            u.x = cvt_tf32(v.x); u.y = cvt_tf32(v.y);
            u.z = cvt_tf32(v.z); u.w = cvt_tf32(v.w);
            *(uint4*)(xs + c*PSTR + l4*4) = u;
        }
    } else {
        for (int i = tid; i < 64*128; i += 256) {
            int c = i >> 7, lp = i & 127;
            int p = p0 + lp;
            float v = 0.f;
            if (p < NPIX) {
                int b = p / FTSZ;
                int ft = p - b*FTSZ;
                v = inp[(b*CC + c)*FTSZ + ft];
            }
            xs[c*PSTR + lp] = __uint_as_float(cvt_tf32(v));
        }
    }
    __syncthreads();

    int warp = tid >> 5, lane = tid & 31;
    int g = lane >> 2, tig = lane & 3;
    int px0 = warp*16;                 // one m16 tile per warp

    float acc[10][4];
#pragma unroll
    for (int nt = 0; nt < 10; nt++)
#pragma unroll
        for (int j = 0; j < 4; j++) acc[nt][j] = 0.f;

#pragma unroll
    for (int k = 0; k < 8; k++) {
        int r0 = (8*k + tig)*PSTR, r1 = (8*k + tig + 4)*PSTR;
        unsigned a0 = __float_as_uint(xs[r0 + px0 + g]);
        unsigned a1 = __float_as_uint(xs[r0 + px0 + g + 8]);
        unsigned a2 = __float_as_uint(xs[r1 + px0 + g]);
        unsigned a3 = __float_as_uint(xs[r1 + px0 + g + 8]);
        int w0 = (8*k + tig)*WSTR + g, w1 = (8*k + tig + 4)*WSTR + g;
#pragma unroll
        for (int nt = 0; nt < 10; nt++) {
            unsigned bb0 = __float_as_uint(ws[w0 + nt*8]);
            unsigned bb1 = __float_as_uint(ws[w1 + nt*8]);
            mma_tf32(acc[nt][0], acc[nt][1], acc[nt][2], acc[nt][3],
                     a0, a1, a2, a3, bb0, bb1);
        }
    }

    // direct epilogue: BN shift + PReLU in registers, float2 scatter
    float sh0[10], sh1[10];
#pragma unroll
    for (int nt = 0; nt < 10; nt++) {
        sh0[nt] = sh[nt*8 + 2*tig];
        sh1[nt] = sh[nt*8 + 2*tig + 1];
    }
    float a0v = al[0], a1v = al[1];

#pragma unroll
    for (int r = 0; r < 2; r++) {
        int px  = px0 + g + r*8;
        int off = r * 2;
        int p = p0 + px;
        if (p >= NPIX) continue;
        int b = p / FTSZ;
        int ft = p - b*FTSZ;
        int f = ft / TT;
        int t = ft - f*TT;
        int fidx = ((b*TT + t)*FF + f)*DC;
        int tidx = ((b*FF + f)*TT + t)*DC;
        float* dsts[5];
        dsts[0] = g_qf + fidx;
        dsts[1] = g_kf + fidx;
        dsts[2] = g_vv + fidx;
        dsts[3] = g_qt + tidx;
        dsts[4] = g_kt + tidx;
#pragma unroll
        for (int nt = 0; nt < 10; nt++) {
            int e = nt >> 1;
            float alpha = (e < 3) ? a0v : a1v;
            float v0 = acc[nt][off]     + sh0[nt];
            float v1 = acc[nt][off + 1] + sh1[nt];
            v0 = v0 >= 0.f ? v0 : alpha * v0;
            v1 = v1 >= 0.f ? v1 : alpha * v1;
            *(float2*)(dsts[e] + (nt & 1)*8 + 2*tig) = make_float2(v0, v1);
        }
    }
}

// ---------------------------------------------------------------------------
// Shared warp-level helpers for attention (tf32 MMA path).
// ---------------------------------------------------------------------------
#define KSTR 20
#define VSTR 24

__device__ __forceinline__ void redistribute_p(
    unsigned u0, unsigned u1, unsigned u2, unsigned u3,
    int src1, int src2, int tig,
    unsigned& pa0, unsigned& pa1, unsigned& pa2, unsigned& pa3)
{
    unsigned x0 = __shfl_sync(0xffffffffu, u0, src1);
    unsigned x1 = __shfl_sync(0xffffffffu, u1, src1);
    pa0 = (tig & 1) ? x1 : x0;
    unsigned y0 = __shfl_sync(0xffffffffu, u2, src1);
    unsigned y1 = __shfl_sync(0xffffffffu, u3, src1);
    pa1 = (tig & 1) ? y1 : y0;
    x0 = __shfl_sync(0xffffffffu, u0, src2);
    x1 = __shfl_sync(0xffffffffu, u1, src2);
    pa2 = (tig & 1) ? x1 : x0;
    y0 = __shfl_sync(0xffffffffu, u2, src2);
    y1 = __shfl_sync(0xffffffffu, u3, src2);
    pa3 = (tig & 1) ? y1 : y0;
}

// ---------------------------------------------------------------------------
// Kernel 2: frequency attention via tf32 mma, 16-key double blocks,
// exp2-domain softmax (log2e folded into q scale).
// ---------------------------------------------------------------------------
__global__ __launch_bounds__(288) void asa_fattn()
{
    __shared__ float Ks[264*KSTR];
    __shared__ float Vs[264*VSTR];
    int bt = blockIdx.x;
    int b = bt / TT, t = bt % TT;
    int base = (b*TT + t)*FF*DC;
    int tid = threadIdx.x;

    for (int i = tid; i < 264*4; i += 288) {
        int row = i >> 2, j4 = (i & 3) * 4;
        uint4 ku = make_uint4(0,0,0,0), vu = ku;
        if (row < FF) {
            float4 kk = *(const float4*)(g_kf + base + row*DC + j4);
            float4 vv = *(const float4*)(g_vv + base + row*DC + j4);
            ku.x = cvt_tf32(kk.x); ku.y = cvt_tf32(kk.y);
            ku.z = cvt_tf32(kk.z); ku.w = cvt_tf32(kk.w);
            vu.x = cvt_tf32(vv.x); vu.y = cvt_tf32(vv.y);
            vu.z = cvt_tf32(vv.z); vu.w = cvt_tf32(vv.w);
        }
        *(uint4*)(Ks + row*KSTR + j4) = ku;
        *(uint4*)(Vs + row*VSTR + j4) = vu;
    }
    __syncthreads();

    int warp = tid >> 5, lane = tid & 31;
    int g = lane >> 2, tig = lane & 3;
    int qsel = lane & ~3;
    int src1 = qsel | (tig >> 1);
    int src2 = src1 + 2;

    for (int tile = warp; tile < 17; tile += 9) {
        int fr0 = min(tile*16 + g, FF-1);
        int fr1 = min(tile*16 + g + 8, FF-1);
        const float* q0p = g_qf + base + fr0*DC;
        const float* q1p = g_qf + base + fr1*DC;
        unsigned qa[2][4];
#pragma unroll
        for (int ks = 0; ks < 2; ks++) {
            qa[ks][0] = cvt_tf32(q0p[ks*8 + tig]     * SCALE2);
            qa[ks][1] = cvt_tf32(q1p[ks*8 + tig]     * SCALE2);
            qa[ks][2] = cvt_tf32(q0p[ks*8 + tig + 4] * SCALE2);
            qa[ks][3] = cvt_tf32(q1p[ks*8 + tig + 4] * SCALE2);
        }
        float m0 = -3.0e38f, m1 = -3.0e38f, l0 = 0.f, l1 = 0.f;
        float oA[4] = {0,0,0,0}, oB[4] = {0,0,0,0};

        for (int kb = 0; kb < 16; kb++) {
            int krA = (kb*16 + g)*KSTR;
            int krB = (kb*16 + 8 + g)*KSTR;
            unsigned k0 = __float_as_uint(Ks[krA + tig]);
            unsigned k1 = __float_as_uint(Ks[krA + tig + 4]);
            unsigned k2 = __float_as_uint(Ks[krA + tig + 8]);
            unsigned k3 = __float_as_uint(Ks[krA + tig + 12]);
            unsigned k4 = __float_as_uint(Ks[krB + tig]);
            unsigned k5 = __float_as_uint(Ks[krB + tig + 4]);
            unsigned k6 = __float_as_uint(Ks[krB + tig + 8]);
            unsigned k7 = __float_as_uint(Ks[krB + tig + 12]);
            float s0=0.f,s1=0.f,s2=0.f,s3=0.f, s4=0.f,s5=0.f,s6=0.f,s7=0.f;
            mma_tf32(s0,s1,s2,s3, qa[0][0],qa[0][1],qa[0][2],qa[0][3], k0,k1);
            mma_tf32(s0,s1,s2,s3, qa[1][0],qa[1][1],qa[1][2],qa[1][3], k2,k3);
            mma_tf32(s4,s5,s6,s7, qa[0][0],qa[0][1],qa[0][2],qa[0][3], k4,k5);
            mma_tf32(s4,s5,s6,s7, qa[1][0],qa[1][1],qa[1][2],qa[1][3], k6,k7);

            float cm0 = fmaxf(fmaxf(s0,s1), fmaxf(s4,s5));
            float cm1 = fmaxf(fmaxf(s2,s3), fmaxf(s6,s7));
            cm0 = fmaxf(cm0, __shfl_xor_sync(0xffffffffu, cm0, 1));
            cm0 = fmaxf(cm0, __shfl_xor_sync(0xffffffffu, cm0, 2));
            cm1 = fmaxf(cm1, __shfl_xor_sync(0xffffffffu, cm1, 1));
            cm1 = fmaxf(cm1, __shfl_xor_sync(0xffffffffu, cm1, 2));
            float mn0 = fmaxf(m0, cm0), mn1 = fmaxf(m1, cm1);
            float c0 = exp2f(m0 - mn0), c1 = exp2f(m1 - mn1);
            m0 = mn0; m1 = mn1;
            float p0 = exp2f(s0 - mn0), p1 = exp2f(s1 - mn0);
            float p2 = exp2f(s2 - mn1), p3 = exp2f(s3 - mn1);
            float p4 = exp2f(s4 - mn0), p5 = exp2f(s5 - mn0);
            float p6 = exp2f(s6 - mn1), p7 = exp2f(s7 - mn1);
            float ps0 = (p0 + p1) + (p4 + p5);
            float ps1 = (p2 + p3) + (p6 + p7);
            ps0 += __shfl_xor_sync(0xffffffffu, ps0, 1);
            ps0 += __shfl_xor_sync(0xffffffffu, ps0, 2);
            ps1 += __shfl_xor_sync(0xffffffffu, ps1, 1);
            ps1 += __shfl_xor_sync(0xffffffffu, ps1, 2);
            l0 = l0*c0 + ps0; l1 = l1*c1 + ps1;
            oA[0] *= c0; oA[1] *= c0; oA[2] *= c1; oA[3] *= c1;
            oB[0] *= c0; oB[1] *= c0; oB[2] *= c1; oB[3] *= c1;

            unsigned paA0,paA1,paA2,paA3, paB0,paB1,paB2,paB3;
            redistribute_p(cvt_tf32(p0),cvt_tf32(p1),cvt_tf32(p2),cvt_tf32(p3),
                           src1,src2,tig, paA0,paA1,paA2,paA3);
            redistribute_p(cvt_tf32(p4),cvt_tf32(p5),cvt_tf32(p6),cvt_tf32(p7),
                           src1,src2,tig, paB0,paB1,paB2,paB3);

            int vrA0 = (kb*16 + tig)*VSTR,      vrA1 = (kb*16 + tig + 4)*VSTR;
            int vrB0 = (kb*16 + 8 + tig)*VSTR,  vrB1 = (kb*16 + 12 + tig)*VSTR;
            unsigned vA0 = __float_as_uint(Vs[vrA0 + g]);
            unsigned vA1 = __float_as_uint(Vs[vrA1 + g]);
            unsigned vA2 = __float_as_uint(Vs[vrA0 + g + 8]);
            unsigned vA3 = __float_as_uint(Vs[vrA1 + g + 8]);
            unsigned vB0 = __float_as_uint(Vs[vrB0 + g]);
            unsigned vB1 = __float_as_uint(Vs[vrB1 + g]);
            unsigned vB2 = __float_as_uint(Vs[vrB0 + g + 8]);
            unsigned vB3 = __float_as_uint(Vs[vrB1 + g + 8]);
            mma_tf32(oA[0],oA[1],oA[2],oA[3], paA0,paA1,paA2,paA3, vA0,vA1);
            mma_tf32(oA[0],oA[1],oA[2],oA[3], paB0,paB1,paB2,paB3, vB0,vB1);
            mma_tf32(oB[0],oB[1],oB[2],oB[3], paA0,paA1,paA2,paA3, vA2,vA3);
            mma_tf32(oB[0],oB[1],oB[2],oB[3], paB0,paB1,paB2,paB3, vB2,vB3);
        }
        // tail single block: key 256 (cols >0 masked)
        {
            int krow = (256 + g)*KSTR;
            unsigned k0 = __float_as_uint(Ks[krow + tig]);
            unsigned k1 = __float_as_uint(Ks[krow + tig + 4]);
            unsigned k2 = __float_as_uint(Ks[krow + tig + 8]);
            unsigned k3 = __float_as_uint(Ks[krow + tig + 12]);
            float s0=0.f,s1=0.f,s2=0.f,s3=0.f;
            mma_tf32(s0,s1,s2,s3, qa[0][0],qa[0][1],qa[0][2],qa[0][3], k0,k1);
            mma_tf32(s0,s1,s2,s3, qa[1][0],qa[1][1],qa[1][2],qa[1][3], k2,k3);
            if (tig > 0) { s0 = -3.0e38f; s2 = -3.0e38f; }
            s1 = -3.0e38f; s3 = -3.0e38f;
            float cm0 = fmaxf(s0, s1), cm1 = fmaxf(s2, s3);
            cm0 = fmaxf(cm0, __shfl_xor_sync(0xffffffffu, cm0, 1));
            cm0 = fmaxf(cm0, __shfl_xor_sync(0xffffffffu, cm0, 2));
            cm1 = fmaxf(cm1, __shfl_xor_sync(0xffffffffu, cm1, 1));
            cm1 = fmaxf(cm1, __shfl_xor_sync(0xffffffffu, cm1, 2));
            float mn0 = fmaxf(m0, cm0), mn1 = fmaxf(m1, cm1);
            float c0 = exp2f(m0 - mn0), c1 = exp2f(m1 - mn1);
            m0 = mn0; m1 = mn1;
            float p0 = exp2f(s0 - mn0), p1 = exp2f(s1 - mn0);
            float p2 = exp2f(s2 - mn1), p3 = exp2f(s3 - mn1);
            float ps0 = p0 + p1, ps1 = p2 + p3;
            ps0 += __shfl_xor_sync(0xffffffffu, ps0, 1);
            ps0 += __shfl_xor_sync(0xffffffffu, ps0, 2);
            ps1 += __shfl_xor_sync(0xffffffffu, ps1, 1);
            ps1 += __shfl_xor_sync(0xffffffffu, ps1, 2);
            l0 = l0*c0 + ps0; l1 = l1*c1 + ps1;
            oA[0] *= c0; oA[1] *= c0; oA[2] *= c1; oA[3] *= c1;
            oB[0] *= c0; oB[1] *= c0; oB[2] *= c1; oB[3] *= c1;
            unsigned pa0,pa1,pa2,pa3;
            redistribute_p(cvt_tf32(p0),cvt_tf32(p1),cvt_tf32(p2),cvt_tf32(p3),
                           src1,src2,tig, pa0,pa1,pa2,pa3);
            int vr0 = (256 + tig)*VSTR, vr1 = (256 + tig + 4)*VSTR;
            unsigned v0 = __float_as_uint(Vs[vr0 + g]);
            unsigned v1 = __float_as_uint(Vs[vr1 + g]);
            unsigned v2 = __float_as_uint(Vs[vr0 + g + 8]);
            unsigned v3 = __float_as_uint(Vs[vr1 + g + 8]);
            mma_tf32(oA[0],oA[1],oA[2],oA[3], pa0,pa1,pa2,pa3, v0,v1);
            mma_tf32(oB[0],oB[1],oB[2],oB[3], pa0,pa1,pa2,pa3, v2,v3);
        }
        float inv0 = 1.f / l0, inv1 = 1.f / l1;
        int f0 = tile*16 + g, f1 = f0 + 8;
        if (f0 < FF) {
            float* op = g_fo + ((b*FF + f0)*TT + t)*DC;
            *(float2*)(op + 2*tig)     = make_float2(oA[0]*inv0, oA[1]*inv0);
            *(float2*)(op + 8 + 2*tig) = make_float2(oB[0]*inv0, oB[1]*inv0);
        }
        if (f1 < FF) {
            float* op = g_fo + ((b*FF + f1)*TT + t)*DC;
            *(float2*)(op + 2*tig)     = make_float2(oA[2]*inv1, oA[3]*inv1);
            *(float2*)(op + 8 + 2*tig) = make_float2(oB[2]*inv1, oB[3]*inv1);
        }
    }
}

// ---------------------------------------------------------------------------
// Kernel 3: causal time attention via tf32 mma (16-key double blocks,
// exp2-domain softmax) + proj + residual.
// ---------------------------------------------------------------------------
extern __shared__ float sm3[];
__global__ __launch_bounds__(256) void asa_tattn(
    const float* __restrict__ inp,
    const float* __restrict__ pw, const float* __restrict__ pb,
    const float* __restrict__ pg, const float* __restrict__ pbe,
    const float* __restrict__ pm, const float* __restrict__ pv,
    const float* __restrict__ pa,
    float* __restrict__ out)
{
    float* Ks   = sm3;                    // 512*KSTR
    float* Vs   = Ks + 512*KSTR;          // 512*VSTR
    float* pws  = Vs + 512*VSTR;          // 64*16
    float* psh  = pws + 64*16;            // 64
    float* obuf = psh + 64;               // 8 warps * 16*17
    __shared__ float s_alpha;

    int bf = blockIdx.x;
    int b = bf / FF, f = bf % FF;
    int base = bf * TT * DC;
    int tid = threadIdx.x;

    for (int i = tid; i < 512*4; i += 256) {
        int row = i >> 2, j4 = (i & 3) * 4;
        uint4 ku = make_uint4(0,0,0,0), vu = ku;
        if (row < TT) {
            float4 kk = *(const float4*)(g_kt + base + row*DC + j4);
            float4 vv = *(const float4*)(g_fo + base + row*DC + j4);
            ku.x = cvt_tf32(kk.x); ku.y = cvt_tf32(kk.y);
            ku.z = cvt_tf32(kk.z); ku.w = cvt_tf32(kk.w);
            vu.x = cvt_tf32(vv.x); vu.y = cvt_tf32(vv.y);
            vu.z = cvt_tf32(vv.z); vu.w = cvt_tf32(vv.w);
        }
        *(uint4*)(Ks + row*KSTR + j4) = ku;
        *(uint4*)(Vs + row*VSTR + j4) = vu;
    }
    for (int i = tid; i < 64*16; i += 256) {
        int o = i >> 4;
        pws[i] = pw[i] * (pg[o] * rsqrtf(pv[o] + BN_EPS));
    }
    if (tid < 64) {
        int o = tid;
        psh[o] = (pb[o] - pm[o]) * (pg[o] * rsqrtf(pv[o] + BN_EPS)) + pbe[o];
    }
    if (tid == 0) s_alpha = pa[0];
    __syncthreads();

    int warp = tid >> 5, lane = tid & 31;
    int g = lane >> 2, tig = lane & 3;
    int qsel = lane & ~3;
    int src1 = qsel | (tig >> 1);
    int src2 = src1 + 2;
    float alpha = s_alpha;
    float* ob = obuf + warp * (16*17);

    int tiles[4] = { warp, 15 - warp, 16 + warp, 31 - warp };

#pragma unroll
    for (int ti = 0; ti < 4; ti++) {
        int tile = tiles[ti];
        int qt0 = tile * 16;
        int ta = qt0 + g;
        int tb = qt0 + g + 8;
        int tr0 = min(ta, TT-1), tr1 = min(tb, TT-1);
        const float* q0p = g_qt + base + tr0*DC;
        const float* q1p = g_qt + base + tr1*DC;
        unsigned qa[2][4];
#pragma unroll
        for (int ks = 0; ks < 2; ks++) {
            qa[ks][0] = cvt_tf32(q0p[ks*8 + tig]     * SCALE2);
            qa[ks][1] = cvt_tf32(q1p[ks*8 + tig]     * SCALE2);
            qa[ks][2] = cvt_tf32(q0p[ks*8 + tig + 4] * SCALE2);
            qa[ks][3] = cvt_tf32(q1p[ks*8 + tig + 4] * SCALE2);
        }
        float m0 = -3.0e38f, m1 = -3.0e38f, l0 = 0.f, l1 = 0.f;
        float oA[4] = {0,0,0,0}, oB[4] = {0,0,0,0};

        for (int kb = 0; kb <= tile; kb++) {
            int krA = (kb*16 + g)*KSTR;
            int krB = (kb*16 + 8 + g)*KSTR;
            unsigned k0 = __float_as_uint(Ks[krA + tig]);
            unsigned k1 = __float_as_uint(Ks[krA + tig + 4]);
            unsigned k2 = __float_as_uint(Ks[krA + tig + 8]);
            unsigned k3 = __float_as_uint(Ks[krA + tig + 12]);
            unsigned k4 = __float_as_uint(Ks[krB + tig]);
            unsigned k5 = __float_as_uint(Ks[krB + tig + 4]);
            unsigned k6 = __float_as_uint(Ks[krB + tig + 8]);
            unsigned k7 = __float_as_uint(Ks[krB + tig + 12]);
            float s0=0.f,s1=0.f,s2=0.f,s3=0.f, s4=0.f,s5=0.f,s6=0.f,s7=0.f;
            mma_tf32(s0,s1,s2,s3, qa[0][0],qa[0][1],qa[0][2],qa[0][3], k0,k1);
            mma_tf32(s0,s1,s2,s3, qa[1][0],qa[1][1],qa[1][2],qa[1][3], k2,k3);
            mma_tf32(s4,s5,s6,s7, qa[0][0],qa[0][1],qa[0][2],qa[0][3], k4,k5);
            mma_tf32(s4,s5,s6,s7, qa[1][0],qa[1][1],qa[1][2],qa[1][3], k6,k7);
            if (kb == tile) {
                int yA0 = kb*16 + 2*tig, yA1 = yA0 + 1;
                int yB0 = yA0 + 8,       yB1 = yA1 + 8;
                if (yA0 > ta) s0 = -3.0e38f;
                if (yA1 > ta) s1 = -3.0e38f;
                if (yA0 > tb) s2 = -3.0e38f;
                if (yA1 > tb) s3 = -3.0e38f;
                if (yB0 > ta) s4 = -3.0e38f;
                if (yB1 > ta) s5 = -3.0e38f;
                if (yB0 > tb) s6 = -3.0e38f;
                if (yB1 > tb) s7 = -3.0e38f;
            }
            float cm0 = fmaxf(fmaxf(s0,s1), fmaxf(s4,s5));
            float cm1 = fmaxf(fmaxf(s2,s3), fmaxf(s6,s7));
            cm0 = fmaxf(cm0, __shfl_xor_sync(0xffffffffu, cm0, 1));
            cm0 = fmaxf(cm0, __shfl_xor_sync(0xffffffffu, cm0, 2));
            cm1 = fmaxf(cm1, __shfl_xor_sync(0xffffffffu, cm1, 1));
            cm1 = fmaxf(cm1, __shfl_xor_sync(0xffffffffu, cm1, 2));
            float mn0 = fmaxf(m0, cm0), mn1 = fmaxf(m1, cm1);
            float c0 = exp2f(m0 - mn0), c1 = exp2f(m1 - mn1);
            m0 = mn0; m1 = mn1;
            float p0 = exp2f(s0 - mn0), p1 = exp2f(s1 - mn0);
            float p2 = exp2f(s2 - mn1), p3 = exp2f(s3 - mn1);
            float p4 = exp2f(s4 - mn0), p5 = exp2f(s5 - mn0);
            float p6 = exp2f(s6 - mn1), p7 = exp2f(s7 - mn1);
            float ps0 = (p0 + p1) + (p4 + p5);
            float ps1 = (p2 + p3) + (p6 + p7);
            ps0 += __shfl_xor_sync(0xffffffffu, ps0, 1);
            ps0 += __shfl_xor_sync(0xffffffffu, ps0, 2);
            ps1 += __shfl_xor_sync(0xffffffffu, ps1, 1);
            ps1 += __shfl_xor_sync(0xffffffffu, ps1, 2);
            l0 = l0*c0 + ps0; l1 = l1*c1 + ps1;
            oA[0] *= c0; oA[1] *= c0; oA[2] *= c1; oA[3] *= c1;
            oB[0] *= c0; oB[1] *= c0; oB[2] *= c1; oB[3] *= c1;

            unsigned paA0,paA1,paA2,paA3, paB0,paB1,paB2,paB3;
            redistribute_p(cvt_tf32(p0),cvt_tf32(p1),cvt_tf32(p2),cvt_tf32(p3),
                           src1,src2,tig, paA0,paA1,paA2,paA3);
            redistribute_p(cvt_tf32(p4),cvt_tf32(p5),cvt_tf32(p6),cvt_tf32(p7),
                           src1,src2,tig, paB0,paB1,paB2,paB3);

            int vrA0 = (kb*16 + tig)*VSTR,      vrA1 = (kb*16 + tig + 4)*VSTR;
            int vrB0 = (kb*16 + 8 + tig)*VSTR,  vrB1 = (kb*16 + 12 + tig)*VSTR;
            unsigned vA0 = __float_as_uint(Vs[vrA0 + g]);
            unsigned vA1 = __float_as_uint(Vs[vrA1 + g]);
            unsigned vA2 = __float_as_uint(Vs[vrA0 + g + 8]);
            unsigned vA3 = __float_as_uint(Vs[vrA1 + g + 8]);
            unsigned vB0 = __float_as_uint(Vs[vrB0 + g]);
            unsigned vB1 = __float_as_uint(Vs[vrB1 + g]);
            unsigned vB2 = __float_as_uint(Vs[vrB0 + g + 8]);
            unsigned vB3 = __float_as_uint(Vs[vrB1 + g + 8]);
            mma_tf32(oA[0],oA[1],oA[2],oA[3], paA0,paA1,paA2,paA3, vA0,vA1);
            mma_tf32(oA[0],oA[1],oA[2],oA[3], paB0,paB1,paB2,paB3, vB0,vB1);
            mma_tf32(oB[0],oB[1],oB[2],oB[3], paA0,paA1,paA2,paA3, vA2,vA3);
            mma_tf32(oB[0],oB[1],oB[2],oB[3], paB0,paB1,paB2,paB3, vB2,vB3);
        }
        float inv0 = 1.f / l0, inv1 = 1.f / l1;
        ob[g*17 + 2*tig]          = oA[0]*inv0;
        ob[g*17 + 2*tig + 1]      = oA[1]*inv0;
        ob[g*17 + 8 + 2*tig]      = oB[0]*inv0;
        ob[g*17 + 8 + 2*tig + 1]  = oB[1]*inv0;
        ob[(g+8)*17 + 2*tig]         = oA[2]*inv1;
        ob[(g+8)*17 + 2*tig + 1]     = oA[3]*inv1;
        ob[(g+8)*17 + 8 + 2*tig]     = oB[2]*inv1;
        ob[(g+8)*17 + 8 + 2*tig + 1] = oB[3]*inv1;
        __syncwarp();

        int qi = lane & 15;
        int t = qt0 + qi;
        if (t < TT) {
            const float* orow = ob + qi*17;
            u64 o2[8];
#pragma unroll
            for (int j = 0; j < 8; j++) o2[j] = pk2(orow[2*j], orow[2*j+1]);
            int c0 = (lane >> 4) * 32;
            int obase = b*CC*FTSZ + f*TT + t;
#pragma unroll 4
            for (int j = 0; j < 32; j++) {
                int co = c0 + j;
                const ulonglong2* wr = (const ulonglong2*)(pws + co*16);
                ulonglong2 wa = wr[0], wb = wr[1], wc = wr[2], wd = wr[3];
                u64 d0 = mul2(wa.x, o2[0]);
                u64 d1 = mul2(wa.y, o2[1]);
                d0 = fma2(wb.x, o2[2], d0);
                d1 = fma2(wb.y, o2[3], d1);
                d0 = fma2(wc.x, o2[4], d0);
                d1 = fma2(wc.y, o2[5], d1);
                d0 = fma2(wd.x, o2[6], d0);
                d1 = fma2(wd.y, o2[7], d1);
                float lo0,hi0,lo1,hi1;
                upk2(d0,lo0,hi0); upk2(d1,lo1,hi1);
                float r = psh[co] + (lo0+hi0) + (lo1+hi1);
                r = r >= 0.f ? r : alpha * r;
                int idx = obase + co*FTSZ;
                out[idx] = r + __ldg(&inp[idx]);
            }
        }
        __syncwarp();
    }
}

// ---------------------------------------------------------------------------
extern "C" void kernel_launch(void* const* d_in, const int* in_sizes, int n_in,
                              void* d_out, int out_size)
{
    const float* inp = (const float*)d_in[0];

    int smc_bytes = (64*PSTR + 64*WSTR + 80 + 2) * (int)sizeof(float);
    cudaFuncSetAttribute(asa_conv, cudaFuncAttributeMaxDynamicSharedMemorySize, smc_bytes);
    asa_conv<<<(NPIX + 127)/128, 256, smc_bytes>>>(
        inp,
        (const float*)d_in[1],  (const float*)d_in[2],  (const float*)d_in[3],
        (const float*)d_in[4],  (const float*)d_in[5],  (const float*)d_in[6],
        (const float*)d_in[7],
        (const float*)d_in[8],  (const float*)d_in[9],  (const float*)d_in[10],
        (const float*)d_in[11], (const float*)d_in[12], (const float*)d_in[13],
        (const float*)d_in[14]);

    asa_fattn<<<BB*TT, 288>>>();

    int sm3_bytes = (512*KSTR + 512*VSTR + 64*16 + 64 + 8*16*17) * (int)sizeof(float);
    cudaFuncSetAttribute(asa_tattn, cudaFuncAttributeMaxDynamicSharedMemorySize, sm3_bytes);
    asa_tattn<<<BB*FF, 256, sm3_bytes>>>(
        inp,
        (const float*)d_in[15], (const float*)d_in[16], (const float*)d_in[17],
        (const float*)d_in[18], (const float*)d_in[19], (const float*)d_in[20],
        (const float*)d_in[21],
        (float*)d_out);
}

// round 11
// speedup vs baseline: 3.0632x; 1.1163x over previous
#include <cuda_runtime.h>

#define BB 2
#define CC 64
#define FF 257
#define TT 500
#define DC 16
#define BN_EPS 1e-5f
#define SCALE2 0.36067376022224085f   /* 0.25 * log2(e) */
#define NPIX (BB*FF*TT)
#define FTSZ (FF*TT)

typedef unsigned long long u64;

__device__ __forceinline__ u64 pk2(float lo, float hi) {
    u64 r; asm("mov.b64 %0, {%1,%2};" : "=l"(r) : "f"(lo), "f"(hi)); return r;
}
__device__ __forceinline__ void upk2(u64 v, float& lo, float& hi) {
    asm("mov.b64 {%0,%1}, %2;" : "=f"(lo), "=f"(hi) : "l"(v));
}
__device__ __forceinline__ u64 fma2(u64 a, u64 b, u64 c) {
    u64 d; asm("fma.rn.f32x2 %0, %1, %2, %3;" : "=l"(d) : "l"(a), "l"(b), "l"(c)); return d;
}
__device__ __forceinline__ u64 mul2(u64 a, u64 b) {
    u64 d; asm("mul.rn.f32x2 %0, %1, %2;" : "=l"(d) : "l"(a), "l"(b)); return d;
}
__device__ __forceinline__ unsigned cvt_tf32(float x) {
    unsigned r; asm("cvt.rna.tf32.f32 %0, %1;" : "=r"(r) : "f"(x)); return r;
}
__device__ __forceinline__ void mma_tf32(
    float& d0, float& d1, float& d2, float& d3,
    unsigned a0, unsigned a1, unsigned a2, unsigned a3,
    unsigned b0, unsigned b1)
{
    asm("mma.sync.aligned.m16n8k8.row.col.f32.tf32.tf32.f32 "
        "{%0,%1,%2,%3},{%4,%5,%6,%7},{%8,%9},{%0,%1,%2,%3};"
        : "+f"(d0), "+f"(d1), "+f"(d2), "+f"(d3)
        : "r"(a0), "r"(a1), "r"(a2), "r"(a3), "r"(b0), "r"(b1));
}

// Scratch (device globals; no allocation allowed)
__device__ float g_qf[BB*TT*FF*DC];   // [b][t][f][c]
__device__ float g_kf[BB*TT*FF*DC];   // [b][t][f][c]
__device__ float g_vv[BB*TT*FF*DC];   // [b][t][f][c]
__device__ float g_qt[BB*FF*TT*DC];   // [b][f][t][c]
__device__ float g_kt[BB*FF*TT*DC];   // [b][f][t][c]
__device__ float g_fo[BB*FF*TT*DC];   // [b][f][t][c]

// ---------------------------------------------------------------------------
// Kernel 1: fused 1x1 convs via tf32 MMA (unchanged from R10).
// ---------------------------------------------------------------------------
#define PSTR 136
#define WSTR 88

extern __shared__ float smc[];
__global__ __launch_bounds__(256) void asa_conv(
    const float* __restrict__ inp,
    const float* __restrict__ fw, const float* __restrict__ fb,
    const float* __restrict__ fg, const float* __restrict__ fbe,
    const float* __restrict__ fm, const float* __restrict__ fv,
    const float* __restrict__ fa,
    const float* __restrict__ tw, const float* __restrict__ tb,
    const float* __restrict__ tg, const float* __restrict__ tbe,
    const float* __restrict__ tm, const float* __restrict__ tv,
    const float* __restrict__ ta)
{
    float* xs = smc;                   // [64][PSTR]
    float* ws = smc + 64*PSTR;         // [64][WSTR]
    float* sh = ws + 64*WSTR;          // [80]
    float* al = sh + 80;               // [2]

    int tid = threadIdx.x;

    for (int idx = tid; idx < 80*64; idx += 256) {
        int c = idx & 63, op = idx >> 6;
        int e = op >> 4, cc = op & 15;
        float w, g, vv;
        if (e < 3) { int o = 3*cc + e;      w = fw[o*64+c]; g = fg[o]; vv = fv[o]; }
        else       { int o2 = 2*cc + (e-3); w = tw[o2*64+c]; g = tg[o2]; vv = tv[o2]; }
        ws[c*WSTR + op] = __uint_as_float(cvt_tf32(w * (g * rsqrtf(vv + BN_EPS))));
    }
    if (tid < 80) {
        int op = tid, e = op >> 4, cc = op & 15;
        float g, vv, m, b, be;
        if (e < 3) { int o = 3*cc + e;      g=fg[o]; vv=fv[o]; m=fm[o]; b=fb[o]; be=fbe[o]; }
        else       { int o2 = 2*cc + (e-3); g=tg[o2]; vv=tv[o2]; m=tm[o2]; b=tb[o2]; be=tbe[o2]; }
        sh[op] = (b - m) * (g * rsqrtf(vv + BN_EPS)) + be;
    }
    if (tid == 0) { al[0] = fa[0]; al[1] = ta[0]; }

    int p0 = blockIdx.x * 128;
    int b0 = p0 / FTSZ;
    int bend = (p0 + 127) / FTSZ;
    if (b0 == bend && p0 + 127 < NPIX) {
        int ft0 = p0 - b0*FTSZ;
        const float* src = inp + b0*CC*FTSZ + ft0;
        for (int i = tid; i < 64*32; i += 256) {
            int c = i >> 5, l4 = i & 31;
            float4 v = *(const float4*)(src + c*FTSZ + l4*4);
            uint4 u;
            u.x = cvt_tf32(v.x); u.y = cvt_tf32(v.y);
            u.z = cvt_tf32(v.z); u.w = cvt_tf32(v.w);
            *(uint4*)(xs + c*PSTR + l4*4) = u;
        }
    } else {
        for (int i = tid; i < 64*128; i += 256) {
            int c = i >> 7, lp = i & 127;
            int p = p0 + lp;
            float v = 0.f;
            if (p < NPIX) {
                int b = p / FTSZ;
                int ft = p - b*FTSZ;
                v = inp[(b*CC + c)*FTSZ + ft];
            }
            xs[c*PSTR + lp] = __uint_as_float(cvt_tf32(v));
        }
    }
    __syncthreads();

    int warp = tid >> 5, lane = tid & 31;
    int g = lane >> 2, tig = lane & 3;
    int px0 = warp*16;

    float acc[10][4];
#pragma unroll
    for (int nt = 0; nt < 10; nt++)
#pragma unroll
        for (int j = 0; j < 4; j++) acc[nt][j] = 0.f;

#pragma unroll
    for (int k = 0; k < 8; k++) {
        int r0 = (8*k + tig)*PSTR, r1 = (8*k + tig + 4)*PSTR;
        unsigned a0 = __float_as_uint(xs[r0 + px0 + g]);
        unsigned a1 = __float_as_uint(xs[r0 + px0 + g + 8]);
        unsigned a2 = __float_as_uint(xs[r1 + px0 + g]);
        unsigned a3 = __float_as_uint(xs[r1 + px0 + g + 8]);
        int w0 = (8*k + tig)*WSTR + g, w1 = (8*k + tig + 4)*WSTR + g;
#pragma unroll
        for (int nt = 0; nt < 10; nt++) {
            unsigned bb0 = __float_as_uint(ws[w0 + nt*8]);
            unsigned bb1 = __float_as_uint(ws[w1 + nt*8]);
            mma_tf32(acc[nt][0], acc[nt][1], acc[nt][2], acc[nt][3],
                     a0, a1, a2, a3, bb0, bb1);
        }
    }

    float sh0[10], sh1[10];
#pragma unroll
    for (int nt = 0; nt < 10; nt++) {
        sh0[nt] = sh[nt*8 + 2*tig];
        sh1[nt] = sh[nt*8 + 2*tig + 1];
    }
    float a0v = al[0], a1v = al[1];

#pragma unroll
    for (int r = 0; r < 2; r++) {
        int px  = px0 + g + r*8;
        int off = r * 2;
        int p = p0 + px;
        if (p >= NPIX) continue;
        int b = p / FTSZ;
        int ft = p - b*FTSZ;
        int f = ft / TT;
        int t = ft - f*TT;
        int fidx = ((b*TT + t)*FF + f)*DC;
        int tidx = ((b*FF + f)*TT + t)*DC;
        float* dsts[5];
        dsts[0] = g_qf + fidx;
        dsts[1] = g_kf + fidx;
        dsts[2] = g_vv + fidx;
        dsts[3] = g_qt + tidx;
        dsts[4] = g_kt + tidx;
#pragma unroll
        for (int nt = 0; nt < 10; nt++) {
            int e = nt >> 1;
            float alpha = (e < 3) ? a0v : a1v;
            float v0 = acc[nt][off]     + sh0[nt];
            float v1 = acc[nt][off + 1] + sh1[nt];
            v0 = v0 >= 0.f ? v0 : alpha * v0;
            v1 = v1 >= 0.f ? v1 : alpha * v1;
            *(float2*)(dsts[e] + (nt & 1)*8 + 2*tig) = make_float2(v0, v1);
        }
    }
}

// ---------------------------------------------------------------------------
// Shared warp-level helpers for attention (tf32 MMA path).
// ---------------------------------------------------------------------------
#define KSTR 20
#define VSTR 24

__device__ __forceinline__ void redistribute_p(
    unsigned u0, unsigned u1, unsigned u2, unsigned u3,
    int src1, int src2, int tig,
    unsigned& pa0, unsigned& pa1, unsigned& pa2, unsigned& pa3)
{
    unsigned x0 = __shfl_sync(0xffffffffu, u0, src1);
    unsigned x1 = __shfl_sync(0xffffffffu, u1, src1);
    pa0 = (tig & 1) ? x1 : x0;
    unsigned y0 = __shfl_sync(0xffffffffu, u2, src1);
    unsigned y1 = __shfl_sync(0xffffffffu, u3, src1);
    pa1 = (tig & 1) ? y1 : y0;
    x0 = __shfl_sync(0xffffffffu, u0, src2);
    x1 = __shfl_sync(0xffffffffu, u1, src2);
    pa2 = (tig & 1) ? x1 : x0;
    y0 = __shfl_sync(0xffffffffu, u2, src2);
    y1 = __shfl_sync(0xffffffffu, u3, src2);
    pa3 = (tig & 1) ? y1 : y0;
}

// ---------------------------------------------------------------------------
// Kernel 2: frequency attention via tf32 mma, 16-key double blocks,
// 17 warps (one tile per warp), exp2-domain softmax.
// ---------------------------------------------------------------------------
__global__ __launch_bounds__(544) void asa_fattn()
{
    __shared__ float Ks[264*KSTR];
    __shared__ float Vs[264*VSTR];
    int bt = blockIdx.x;
    int b = bt / TT, t = bt % TT;
    int base = (b*TT + t)*FF*DC;
    int tid = threadIdx.x;

    for (int i = tid; i < 264*4; i += 544) {
        int row = i >> 2, j4 = (i & 3) * 4;
        uint4 ku = make_uint4(0,0,0,0), vu = ku;
        if (row < FF) {
            float4 kk = *(const float4*)(g_kf + base + row*DC + j4);
            float4 vv = *(const float4*)(g_vv + base + row*DC + j4);
            ku.x = cvt_tf32(kk.x); ku.y = cvt_tf32(kk.y);
            ku.z = cvt_tf32(kk.z); ku.w = cvt_tf32(kk.w);
            vu.x = cvt_tf32(vv.x); vu.y = cvt_tf32(vv.y);
            vu.z = cvt_tf32(vv.z); vu.w = cvt_tf32(vv.w);
        }
        *(uint4*)(Ks + row*KSTR + j4) = ku;
        *(uint4*)(Vs + row*VSTR + j4) = vu;
    }
    __syncthreads();

    int warp = tid >> 5, lane = tid & 31;
    int g = lane >> 2, tig = lane & 3;
    int qsel = lane & ~3;
    int src1 = qsel | (tig >> 1);
    int src2 = src1 + 2;

    {
        int tile = warp;   // 17 warps, one 16-query tile each
        int fr0 = min(tile*16 + g, FF-1);
        int fr1 = min(tile*16 + g + 8, FF-1);
        const float* q0p = g_qf + base + fr0*DC;
        const float* q1p = g_qf + base + fr1*DC;
        unsigned qa[2][4];
#pragma unroll
        for (int ks = 0; ks < 2; ks++) {
            qa[ks][0] = cvt_tf32(q0p[ks*8 + tig]     * SCALE2);
            qa[ks][1] = cvt_tf32(q1p[ks*8 + tig]     * SCALE2);
            qa[ks][2] = cvt_tf32(q0p[ks*8 + tig + 4] * SCALE2);
            qa[ks][3] = cvt_tf32(q1p[ks*8 + tig + 4] * SCALE2);
        }
        float m0 = -3.0e38f, m1 = -3.0e38f, l0 = 0.f, l1 = 0.f;
        float oA[4] = {0,0,0,0}, oB[4] = {0,0,0,0};

        for (int kb = 0; kb < 16; kb++) {
            int krA = (kb*16 + g)*KSTR;
            int krB = (kb*16 + 8 + g)*KSTR;
            unsigned k0 = __float_as_uint(Ks[krA + tig]);
            unsigned k1 = __float_as_uint(Ks[krA + tig + 4]);
            unsigned k2 = __float_as_uint(Ks[krA + tig + 8]);
            unsigned k3 = __float_as_uint(Ks[krA + tig + 12]);
            unsigned k4 = __float_as_uint(Ks[krB + tig]);
            unsigned k5 = __float_as_uint(Ks[krB + tig + 4]);
            unsigned k6 = __float_as_uint(Ks[krB + tig + 8]);
            unsigned k7 = __float_as_uint(Ks[krB + tig + 12]);
            float s0=0.f,s1=0.f,s2=0.f,s3=0.f, s4=0.f,s5=0.f,s6=0.f,s7=0.f;
            mma_tf32(s0,s1,s2,s3, qa[0][0],qa[0][1],qa[0][2],qa[0][3], k0,k1);
            mma_tf32(s0,s1,s2,s3, qa[1][0],qa[1][1],qa[1][2],qa[1][3], k2,k3);
            mma_tf32(s4,s5,s6,s7, qa[0][0],qa[0][1],qa[0][2],qa[0][3], k4,k5);
            mma_tf32(s4,s5,s6,s7, qa[1][0],qa[1][1],qa[1][2],qa[1][3], k6,k7);

            float cm0 = fmaxf(fmaxf(s0,s1), fmaxf(s4,s5));
            float cm1 = fmaxf(fmaxf(s2,s3), fmaxf(s6,s7));
            cm0 = fmaxf(cm0, __shfl_xor_sync(0xffffffffu, cm0, 1));
            cm0 = fmaxf(cm0, __shfl_xor_sync(0xffffffffu, cm0, 2));
            cm1 = fmaxf(cm1, __shfl_xor_sync(0xffffffffu, cm1, 1));
            cm1 = fmaxf(cm1, __shfl_xor_sync(0xffffffffu, cm1, 2));
            float mn0 = fmaxf(m0, cm0), mn1 = fmaxf(m1, cm1);
            float c0 = exp2f(m0 - mn0), c1 = exp2f(m1 - mn1);
            m0 = mn0; m1 = mn1;
            float p0 = exp2f(s0 - mn0), p1 = exp2f(s1 - mn0);
            float p2 = exp2f(s2 - mn1), p3 = exp2f(s3 - mn1);
            float p4 = exp2f(s4 - mn0), p5 = exp2f(s5 - mn0);
            float p6 = exp2f(s6 - mn1), p7 = exp2f(s7 - mn1);
            float ps0 = (p0 + p1) + (p4 + p5);
            float ps1 = (p2 + p3) + (p6 + p7);
            ps0 += __shfl_xor_sync(0xffffffffu, ps0, 1);
            ps0 += __shfl_xor_sync(0xffffffffu, ps0, 2);
            ps1 += __shfl_xor_sync(0xffffffffu, ps1, 1);
            ps1 += __shfl_xor_sync(0xffffffffu, ps1, 2);
            l0 = l0*c0 + ps0; l1 = l1*c1 + ps1;
            oA[0] *= c0; oA[1] *= c0; oA[2] *= c1; oA[3] *= c1;
            oB[0] *= c0; oB[1] *= c0; oB[2] *= c1; oB[3] *= c1;

            unsigned paA0,paA1,paA2,paA3, paB0,paB1,paB2,paB3;
            redistribute_p(cvt_tf32(p0),cvt_tf32(p1),cvt_tf32(p2),cvt_tf32(p3),
                           src1,src2,tig, paA0,paA1,paA2,paA3);
            redistribute_p(cvt_tf32(p4),cvt_tf32(p5),cvt_tf32(p6),cvt_tf32(p7),
                           src1,src2,tig, paB0,paB1,paB2,paB3);

            int vrA0 = (kb*16 + tig)*VSTR,      vrA1 = (kb*16 + tig + 4)*VSTR;
            int vrB0 = (kb*16 + 8 + tig)*VSTR,  vrB1 = (kb*16 + 12 + tig)*VSTR;
            unsigned vA0 = __float_as_uint(Vs[vrA0 + g]);
            unsigned vA1 = __float_as_uint(Vs[vrA1 + g]);
            unsigned vA2 = __float_as_uint(Vs[vrA0 + g + 8]);
            unsigned vA3 = __float_as_uint(Vs[vrA1 + g + 8]);
            unsigned vB0 = __float_as_uint(Vs[vrB0 + g]);
            unsigned vB1 = __float_as_uint(Vs[vrB1 + g]);
            unsigned vB2 = __float_as_uint(Vs[vrB0 + g + 8]);
            unsigned vB3 = __float_as_uint(Vs[vrB1 + g + 8]);
            mma_tf32(oA[0],oA[1],oA[2],oA[3], paA0,paA1,paA2,paA3, vA0,vA1);
            mma_tf32(oA[0],oA[1],oA[2],oA[3], paB0,paB1,paB2,paB3, vB0,vB1);
            mma_tf32(oB[0],oB[1],oB[2],oB[3], paA0,paA1,paA2,paA3, vA2,vA3);
            mma_tf32(oB[0],oB[1],oB[2],oB[3], paB0,paB1,paB2,paB3, vB2,vB3);
        }
        // tail single block: key 256 (cols >0 masked)
        {
            int krow = (256 + g)*KSTR;
            unsigned k0 = __float_as_uint(Ks[krow + tig]);
            unsigned k1 = __float_as_uint(Ks[krow + tig + 4]);
            unsigned k2 = __float_as_uint(Ks[krow + tig + 8]);
            unsigned k3 = __float_as_uint(Ks[krow + tig + 12]);
            float s0=0.f,s1=0.f,s2=0.f,s3=0.f;
            mma_tf32(s0,s1,s2,s3, qa[0][0],qa[0][1],qa[0][2],qa[0][3], k0,k1);
            mma_tf32(s0,s1,s2,s3, qa[1][0],qa[1][1],qa[1][2],qa[1][3], k2,k3);
            if (tig > 0) { s0 = -3.0e38f; s2 = -3.0e38f; }
            s1 = -3.0e38f; s3 = -3.0e38f;
            float cm0 = fmaxf(s0, s1), cm1 = fmaxf(s2, s3);
            cm0 = fmaxf(cm0, __shfl_xor_sync(0xffffffffu, cm0, 1));
            cm0 = fmaxf(cm0, __shfl_xor_sync(0xffffffffu, cm0, 2));
            cm1 = fmaxf(cm1, __shfl_xor_sync(0xffffffffu, cm1, 1));
            cm1 = fmaxf(cm1, __shfl_xor_sync(0xffffffffu, cm1, 2));
            float mn0 = fmaxf(m0, cm0), mn1 = fmaxf(m1, cm1);
            float c0 = exp2f(m0 - mn0), c1 = exp2f(m1 - mn1);
            m0 = mn0; m1 = mn1;
            float p0 = exp2f(s0 - mn0), p1 = exp2f(s1 - mn0);
            float p2 = exp2f(s2 - mn1), p3 = exp2f(s3 - mn1);
            float ps0 = p0 + p1, ps1 = p2 + p3;
            ps0 += __shfl_xor_sync(0xffffffffu, ps0, 1);
            ps0 += __shfl_xor_sync(0xffffffffu, ps0, 2);
            ps1 += __shfl_xor_sync(0xffffffffu, ps1, 1);
            ps1 += __shfl_xor_sync(0xffffffffu, ps1, 2);
            l0 = l0*c0 + ps0; l1 = l1*c1 + ps1;
            oA[0] *= c0; oA[1] *= c0; oA[2] *= c1; oA[3] *= c1;
            oB[0] *= c0; oB[1] *= c0; oB[2] *= c1; oB[3] *= c1;
            unsigned pa0,pa1,pa2,pa3;
            redistribute_p(cvt_tf32(p0),cvt_tf32(p1),cvt_tf32(p2),cvt_tf32(p3),
                           src1,src2,tig, pa0,pa1,pa2,pa3);
            int vr0 = (256 + tig)*VSTR, vr1 = (256 + tig + 4)*VSTR;
            unsigned v0 = __float_as_uint(Vs[vr0 + g]);
            unsigned v1 = __float_as_uint(Vs[vr1 + g]);
            unsigned v2 = __float_as_uint(Vs[vr0 + g + 8]);
            unsigned v3 = __float_as_uint(Vs[vr1 + g + 8]);
            mma_tf32(oA[0],oA[1],oA[2],oA[3], pa0,pa1,pa2,pa3, v0,v1);
            mma_tf32(oB[0],oB[1],oB[2],oB[3], pa0,pa1,pa2,pa3, v2,v3);
        }
        float inv0 = 1.f / l0, inv1 = 1.f / l1;
        int f0 = tile*16 + g, f1 = f0 + 8;
        if (f0 < FF) {
            float* op = g_fo + ((b*FF + f0)*TT + t)*DC;
            *(float2*)(op + 2*tig)     = make_float2(oA[0]*inv0, oA[1]*inv0);
            *(float2*)(op + 8 + 2*tig) = make_float2(oB[0]*inv0, oB[1]*inv0);
        }
        if (f1 < FF) {
            float* op = g_fo + ((b*FF + f1)*TT + t)*DC;
            *(float2*)(op + 2*tig)     = make_float2(oA[2]*inv1, oA[3]*inv1);
            *(float2*)(op + 8 + 2*tig) = make_float2(oB[2]*inv1, oB[3]*inv1);
        }
    }
}

// ---------------------------------------------------------------------------
// Kernel 3: causal time attention via tf32 mma, 16 warps x 2 tiles
// {w, 31-w} (exactly 33 double-blocks each) + proj + residual.
// ---------------------------------------------------------------------------
extern __shared__ float sm3[];
__global__ __launch_bounds__(512) void asa_tattn(
    const float* __restrict__ inp,
    const float* __restrict__ pw, const float* __restrict__ pb,
    const float* __restrict__ pg, const float* __restrict__ pbe,
    const float* __restrict__ pm, const float* __restrict__ pv,
    const float* __restrict__ pa,
    float* __restrict__ out)
{
    float* Ks   = sm3;                    // 512*KSTR
    float* Vs   = Ks + 512*KSTR;          // 512*VSTR
    float* pws  = Vs + 512*VSTR;          // 64*16
    float* psh  = pws + 64*16;            // 64
    float* obuf = psh + 64;               // 16 warps * 16*17
    __shared__ float s_alpha;

    int bf = blockIdx.x;
    int b = bf / FF, f = bf % FF;
    int base = bf * TT * DC;
    int tid = threadIdx.x;

    for (int i = tid; i < 512*4; i += 512) {
        int row = i >> 2, j4 = (i & 3) * 4;
        uint4 ku = make_uint4(0,0,0,0), vu = ku;
        if (row < TT) {
            float4 kk = *(const float4*)(g_kt + base + row*DC + j4);
            float4 vv = *(const float4*)(g_fo + base + row*DC + j4);
            ku.x = cvt_tf32(kk.x); ku.y = cvt_tf32(kk.y);
            ku.z = cvt_tf32(kk.z); ku.w = cvt_tf32(kk.w);
            vu.x = cvt_tf32(vv.x); vu.y = cvt_tf32(vv.y);
            vu.z = cvt_tf32(vv.z); vu.w = cvt_tf32(vv.w);
        }
        *(uint4*)(Ks + row*KSTR + j4) = ku;
        *(uint4*)(Vs + row*VSTR + j4) = vu;
    }
    for (int i = tid; i < 64*16; i += 512) {
        int o = i >> 4;
        pws[i] = pw[i] * (pg[o] * rsqrtf(pv[o] + BN_EPS));
    }
    if (tid < 64) {
        int o = tid;
        psh[o] = (pb[o] - pm[o]) * (pg[o] * rsqrtf(pv[o] + BN_EPS)) + pbe[o];
    }
    if (tid == 0) s_alpha = pa[0];
    __syncthreads();

    int warp = tid >> 5, lane = tid & 31;
    int g = lane >> 2, tig = lane & 3;
    int qsel = lane & ~3;
    int src1 = qsel | (tig >> 1);
    int src2 = src1 + 2;
    float alpha = s_alpha;
    float* ob = obuf + warp * (16*17);

    int tiles[2] = { warp, 31 - warp };

#pragma unroll
    for (int ti = 0; ti < 2; ti++) {
        int tile = tiles[ti];
        int qt0 = tile * 16;
        int ta = qt0 + g;
        int tb = qt0 + g + 8;
        int tr0 = min(ta, TT-1), tr1 = min(tb, TT-1);
        const float* q0p = g_qt + base + tr0*DC;
        const float* q1p = g_qt + base + tr1*DC;
        unsigned qa[2][4];
#pragma unroll
        for (int ks = 0; ks < 2; ks++) {
            qa[ks][0] = cvt_tf32(q0p[ks*8 + tig]     * SCALE2);
            qa[ks][1] = cvt_tf32(q1p[ks*8 + tig]     * SCALE2);
            qa[ks][2] = cvt_tf32(q0p[ks*8 + tig + 4] * SCALE2);
            qa[ks][3] = cvt_tf32(q1p[ks*8 + tig + 4] * SCALE2);
        }
        float m0 = -3.0e38f, m1 = -3.0e38f, l0 = 0.f, l1 = 0.f;
        float oA[4] = {0,0,0,0}, oB[4] = {0,0,0,0};

        for (int kb = 0; kb <= tile; kb++) {
            int krA = (kb*16 + g)*KSTR;
            int krB = (kb*16 + 8 + g)*KSTR;
            unsigned k0 = __float_as_uint(Ks[krA + tig]);
            unsigned k1 = __float_as_uint(Ks[krA + tig + 4]);
            unsigned k2 = __float_as_uint(Ks[krA + tig + 8]);
            unsigned k3 = __float_as_uint(Ks[krA + tig + 12]);
            unsigned k4 = __float_as_uint(Ks[krB + tig]);
            unsigned k5 = __float_as_uint(Ks[krB + tig + 4]);
            unsigned k6 = __float_as_uint(Ks[krB + tig + 8]);
            unsigned k7 = __float_as_uint(Ks[krB + tig + 12]);
            float s0=0.f,s1=0.f,s2=0.f,s3=0.f, s4=0.f,s5=0.f,s6=0.f,s7=0.f;
            mma_tf32(s0,s1,s2,s3, qa[0][0],qa[0][1],qa[0][2],qa[0][3], k0,k1);
            mma_tf32(s0,s1,s2,s3, qa[1][0],qa[1][1],qa[1][2],qa[1][3], k2,k3);
            mma_tf32(s4,s5,s6,s7, qa[0][0],qa[0][1],qa[0][2],qa[0][3], k4,k5);
            mma_tf32(s4,s5,s6,s7, qa[1][0],qa[1][1],qa[1][2],qa[1][3], k6,k7);
            if (kb == tile) {
                int yA0 = kb*16 + 2*tig, yA1 = yA0 + 1;
                int yB0 = yA0 + 8,       yB1 = yA1 + 8;
                if (yA0 > ta) s0 = -3.0e38f;
                if (yA1 > ta) s1 = -3.0e38f;
                if (yA0 > tb) s2 = -3.0e38f;
                if (yA1 > tb) s3 = -3.0e38f;
                if (yB0 > ta) s4 = -3.0e38f;
                if (yB1 > ta) s5 = -3.0e38f;
                if (yB0 > tb) s6 = -3.0e38f;
                if (yB1 > tb) s7 = -3.0e38f;
            }
            float cm0 = fmaxf(fmaxf(s0,s1), fmaxf(s4,s5));
            float cm1 = fmaxf(fmaxf(s2,s3), fmaxf(s6,s7));
            cm0 = fmaxf(cm0, __shfl_xor_sync(0xffffffffu, cm0, 1));
            cm0 = fmaxf(cm0, __shfl_xor_sync(0xffffffffu, cm0, 2));
            cm1 = fmaxf(cm1, __shfl_xor_sync(0xffffffffu, cm1, 1));
            cm1 = fmaxf(cm1, __shfl_xor_sync(0xffffffffu, cm1, 2));
            float mn0 = fmaxf(m0, cm0), mn1 = fmaxf(m1, cm1);
            float c0 = exp2f(m0 - mn0), c1 = exp2f(m1 - mn1);
            m0 = mn0; m1 = mn1;
            float p0 = exp2f(s0 - mn0), p1 = exp2f(s1 - mn0);
            float p2 = exp2f(s2 - mn1), p3 = exp2f(s3 - mn1);
            float p4 = exp2f(s4 - mn0), p5 = exp2f(s5 - mn0);
            float p6 = exp2f(s6 - mn1), p7 = exp2f(s7 - mn1);
            float ps0 = (p0 + p1) + (p4 + p5);
            float ps1 = (p2 + p3) + (p6 + p7);
            ps0 += __shfl_xor_sync(0xffffffffu, ps0, 1);
            ps0 += __shfl_xor_sync(0xffffffffu, ps0, 2);
            ps1 += __shfl_xor_sync(0xffffffffu, ps1, 1);
            ps1 += __shfl_xor_sync(0xffffffffu, ps1, 2);
            l0 = l0*c0 + ps0; l1 = l1*c1 + ps1;
            oA[0] *= c0; oA[1] *= c0; oA[2] *= c1; oA[3] *= c1;
            oB[0] *= c0; oB[1] *= c0; oB[2] *= c1; oB[3] *= c1;

            unsigned paA0,paA1,paA2,paA3, paB0,paB1,paB2,paB3;
            redistribute_p(cvt_tf32(p0),cvt_tf32(p1),cvt_tf32(p2),cvt_tf32(p3),
                           src1,src2,tig, paA0,paA1,paA2,paA3);
            redistribute_p(cvt_tf32(p4),cvt_tf32(p5),cvt_tf32(p6),cvt_tf32(p7),
                           src1,src2,tig, paB0,paB1,paB2,paB3);

            int vrA0 = (kb*16 + tig)*VSTR,      vrA1 = (kb*16 + tig + 4)*VSTR;
            int vrB0 = (kb*16 + 8 + tig)*VSTR,  vrB1 = (kb*16 + 12 + tig)*VSTR;
            unsigned vA0 = __float_as_uint(Vs[vrA0 + g]);
            unsigned vA1 = __float_as_uint(Vs[vrA1 + g]);
            unsigned vA2 = __float_as_uint(Vs[vrA0 + g + 8]);
            unsigned vA3 = __float_as_uint(Vs[vrA1 + g + 8]);
            unsigned vB0 = __float_as_uint(Vs[vrB0 + g]);
            unsigned vB1 = __float_as_uint(Vs[vrB1 + g]);
            unsigned vB2 = __float_as_uint(Vs[vrB0 + g + 8]);
            unsigned vB3 = __float_as_uint(Vs[vrB1 + g + 8]);
            mma_tf32(oA[0],oA[1],oA[2],oA[3], paA0,paA1,paA2,paA3, vA0,vA1);
            mma_tf32(oA[0],oA[1],oA[2],oA[3], paB0,paB1,paB2,paB3, vB0,vB1);
            mma_tf32(oB[0],oB[1],oB[2],oB[3], paA0,paA1,paA2,paA3, vA2,vA3);
            mma_tf32(oB[0],oB[1],oB[2],oB[3], paB0,paB1,paB2,paB3, vB2,vB3);
        }
        float inv0 = 1.f / l0, inv1 = 1.f / l1;
        ob[g*17 + 2*tig]          = oA[0]*inv0;
        ob[g*17 + 2*tig + 1]      = oA[1]*inv0;
        ob[g*17 + 8 + 2*tig]      = oB[0]*inv0;
        ob[g*17 + 8 + 2*tig + 1]  = oB[1]*inv0;
        ob[(g+8)*17 + 2*tig]         = oA[2]*inv1;
        ob[(g+8)*17 + 2*tig + 1]     = oA[3]*inv1;
        ob[(g+8)*17 + 8 + 2*tig]     = oB[2]*inv1;
        ob[(g+8)*17 + 8 + 2*tig + 1] = oB[3]*inv1;
        __syncwarp();

        int qi = lane & 15;
        int t = qt0 + qi;
        if (t < TT) {
            const float* orow = ob + qi*17;
            u64 o2[8];
#pragma unroll
            for (int j = 0; j < 8; j++) o2[j] = pk2(orow[2*j], orow[2*j+1]);
            int c0 = (lane >> 4) * 32;
            int obase = b*CC*FTSZ + f*TT + t;
#pragma unroll 4
            for (int j = 0; j < 32; j++) {
                int co = c0 + j;
                const ulonglong2* wr = (const ulonglong2*)(pws + co*16);
                ulonglong2 wa = wr[0], wb = wr[1], wc = wr[2], wd = wr[3];
                u64 d0 = mul2(wa.x, o2[0]);
                u64 d1 = mul2(wa.y, o2[1]);
                d0 = fma2(wb.x, o2[2], d0);
                d1 = fma2(wb.y, o2[3], d1);
                d0 = fma2(wc.x, o2[4], d0);
                d1 = fma2(wc.y, o2[5], d1);
                d0 = fma2(wd.x, o2[6], d0);
                d1 = fma2(wd.y, o2[7], d1);
                float lo0,hi0,lo1,hi1;
                upk2(d0,lo0,hi0); upk2(d1,lo1,hi1);
                float r = psh[co] + (lo0+hi0) + (lo1+hi1);
                r = r >= 0.f ? r : alpha * r;
                int idx = obase + co*FTSZ;
                out[idx] = r + __ldg(&inp[idx]);
            }
        }
        __syncwarp();
    }
}

// ---------------------------------------------------------------------------
extern "C" void kernel_launch(void* const* d_in, const int* in_sizes, int n_in,
                              void* d_out, int out_size)
{
    const float* inp = (const float*)d_in[0];

    int smc_bytes = (64*PSTR + 64*WSTR + 80 + 2) * (int)sizeof(float);
    cudaFuncSetAttribute(asa_conv, cudaFuncAttributeMaxDynamicSharedMemorySize, smc_bytes);
    asa_conv<<<(NPIX + 127)/128, 256, smc_bytes>>>(
        inp,
        (const float*)d_in[1],  (const float*)d_in[2],  (const float*)d_in[3],
        (const float*)d_in[4],  (const float*)d_in[5],  (const float*)d_in[6],
        (const float*)d_in[7],
        (const float*)d_in[8],  (const float*)d_in[9],  (const float*)d_in[10],
        (const float*)d_in[11], (const float*)d_in[12], (const float*)d_in[13],
        (const float*)d_in[14]);

    asa_fattn<<<BB*TT, 544>>>();

    int sm3_bytes = (512*KSTR + 512*VSTR + 64*16 + 64 + 16*16*17) * (int)sizeof(float);
    cudaFuncSetAttribute(asa_tattn, cudaFuncAttributeMaxDynamicSharedMemorySize, sm3_bytes);
    asa_tattn<<<BB*FF, 512, sm3_bytes>>>(
        inp,
        (const float*)d_in[15], (const float*)d_in[16], (const float*)d_in[17],
        (const float*)d_in[18], (const float*)d_in[19], (const float*)d_in[20],
        (const float*)d_in[21],
        (float*)d_out);
}

// round 12
// speedup vs baseline: 3.3355x; 1.0889x over previous
#include <cuda_runtime.h>

#define BB 2
#define CC 64
#define FF 257
#define TT 500
#define DC 16
#define BN_EPS 1e-5f
#define SCALE2 0.36067376022224085f   /* 0.25 * log2(e) */
#define NPIX (BB*FF*TT)
#define FTSZ (FF*TT)

typedef unsigned long long u64;

__device__ __forceinline__ u64 pk2(float lo, float hi) {
    u64 r; asm("mov.b64 %0, {%1,%2};" : "=l"(r) : "f"(lo), "f"(hi)); return r;
}
__device__ __forceinline__ void upk2(u64 v, float& lo, float& hi) {
    asm("mov.b64 {%0,%1}, %2;" : "=f"(lo), "=f"(hi) : "l"(v));
}
__device__ __forceinline__ u64 fma2(u64 a, u64 b, u64 c) {
    u64 d; asm("fma.rn.f32x2 %0, %1, %2, %3;" : "=l"(d) : "l"(a), "l"(b), "l"(c)); return d;
}
__device__ __forceinline__ u64 mul2(u64 a, u64 b) {
    u64 d; asm("mul.rn.f32x2 %0, %1, %2;" : "=l"(d) : "l"(a), "l"(b)); return d;
}
__device__ __forceinline__ void mma_tf32(
    float& d0, float& d1, float& d2, float& d3,
    unsigned a0, unsigned a1, unsigned a2, unsigned a3,
    unsigned b0, unsigned b1)
{
    asm("mma.sync.aligned.m16n8k8.row.col.f32.tf32.tf32.f32 "
        "{%0,%1,%2,%3},{%4,%5,%6,%7},{%8,%9},{%0,%1,%2,%3};"
        : "+f"(d0), "+f"(d1), "+f"(d2), "+f"(d3)
        : "r"(a0), "r"(a1), "r"(a2), "r"(a3), "r"(b0), "r"(b1));
}
__device__ __forceinline__ void cp16(void* dst, const void* src) {
    unsigned d = (unsigned)__cvta_generic_to_shared(dst);
    asm volatile("cp.async.ca.shared.global [%0], [%1], 16;" :: "r"(d), "l"(src));
}
#define CP_WAIT() asm volatile("cp.async.commit_group;\ncp.async.wait_group 0;" ::: "memory")

// Scratch (device globals; no allocation allowed)
__device__ float g_qf[BB*TT*FF*DC];   // [b][t][f][c]
__device__ float g_kf[BB*TT*FF*DC];   // [b][t][f][c]
__device__ float g_vv[BB*TT*FF*DC];   // [b][t][f][c]
__device__ float g_qt[BB*FF*TT*DC];   // [b][f][t][c]
__device__ float g_kt[BB*FF*TT*DC];   // [b][f][t][c]
__device__ float g_fo[BB*FF*TT*DC];   // [b][f][t][c]

// ---------------------------------------------------------------------------
// Kernel 1: fused 1x1 convs via tf32 MMA (cp.async fill, no cvt).
// ---------------------------------------------------------------------------
#define PSTR 136
#define WSTR 88

extern __shared__ float smc[];
__global__ __launch_bounds__(256) void asa_conv(
    const float* __restrict__ inp,
    const float* __restrict__ fw, const float* __restrict__ fb,
    const float* __restrict__ fg, const float* __restrict__ fbe,
    const float* __restrict__ fm, const float* __restrict__ fv,
    const float* __restrict__ fa,
    const float* __restrict__ tw, const float* __restrict__ tb,
    const float* __restrict__ tg, const float* __restrict__ tbe,
    const float* __restrict__ tm, const float* __restrict__ tv,
    const float* __restrict__ ta)
{
    float* xs = smc;                   // [64][PSTR]
    float* ws = smc + 64*PSTR;         // [64][WSTR]
    float* sh = ws + 64*WSTR;          // [80]
    float* al = sh + 80;               // [2]

    int tid = threadIdx.x;

    for (int idx = tid; idx < 80*64; idx += 256) {
        int c = idx & 63, op = idx >> 6;
        int e = op >> 4, cc = op & 15;
        float w, g, vv;
        if (e < 3) { int o = 3*cc + e;      w = fw[o*64+c]; g = fg[o]; vv = fv[o]; }
        else       { int o2 = 2*cc + (e-3); w = tw[o2*64+c]; g = tg[o2]; vv = tv[o2]; }
        ws[c*WSTR + op] = w * (g * rsqrtf(vv + BN_EPS));
    }
    if (tid < 80) {
        int op = tid, e = op >> 4, cc = op & 15;
        float g, vv, m, b, be;
        if (e < 3) { int o = 3*cc + e;      g=fg[o]; vv=fv[o]; m=fm[o]; b=fb[o]; be=fbe[o]; }
        else       { int o2 = 2*cc + (e-3); g=tg[o2]; vv=tv[o2]; m=tm[o2]; b=tb[o2]; be=tbe[o2]; }
        sh[op] = (b - m) * (g * rsqrtf(vv + BN_EPS)) + be;
    }
    if (tid == 0) { al[0] = fa[0]; al[1] = ta[0]; }

    int p0 = blockIdx.x * 128;
    int b0 = p0 / FTSZ;
    int bend = (p0 + 127) / FTSZ;
    if (b0 == bend && p0 + 127 < NPIX) {
        int ft0 = p0 - b0*FTSZ;
        const float* src = inp + b0*CC*FTSZ + ft0;
        for (int i = tid; i < 64*32; i += 256) {
            int c = i >> 5, l4 = i & 31;
            cp16(xs + c*PSTR + l4*4, src + c*FTSZ + l4*4);
        }
        CP_WAIT();
    } else {
        for (int i = tid; i < 64*128; i += 256) {
            int c = i >> 7, lp = i & 127;
            int p = p0 + lp;
            float v = 0.f;
            if (p < NPIX) {
                int b = p / FTSZ;
                int ft = p - b*FTSZ;
                v = inp[(b*CC + c)*FTSZ + ft];
            }
            xs[c*PSTR + lp] = v;
        }
    }
    __syncthreads();

    int warp = tid >> 5, lane = tid & 31;
    int g = lane >> 2, tig = lane & 3;
    int px0 = warp*16;

    float acc[10][4];
#pragma unroll
    for (int nt = 0; nt < 10; nt++)
#pragma unroll
        for (int j = 0; j < 4; j++) acc[nt][j] = 0.f;

#pragma unroll
    for (int k = 0; k < 8; k++) {
        int r0 = (8*k + tig)*PSTR, r1 = (8*k + tig + 4)*PSTR;
        unsigned a0 = __float_as_uint(xs[r0 + px0 + g]);
        unsigned a1 = __float_as_uint(xs[r0 + px0 + g + 8]);
        unsigned a2 = __float_as_uint(xs[r1 + px0 + g]);
        unsigned a3 = __float_as_uint(xs[r1 + px0 + g + 8]);
        int w0 = (8*k + tig)*WSTR + g, w1 = (8*k + tig + 4)*WSTR + g;
#pragma unroll
        for (int nt = 0; nt < 10; nt++) {
            unsigned bb0 = __float_as_uint(ws[w0 + nt*8]);
            unsigned bb1 = __float_as_uint(ws[w1 + nt*8]);
            mma_tf32(acc[nt][0], acc[nt][1], acc[nt][2], acc[nt][3],
                     a0, a1, a2, a3, bb0, bb1);
        }
    }

    float sh0[10], sh1[10];
#pragma unroll
    for (int nt = 0; nt < 10; nt++) {
        sh0[nt] = sh[nt*8 + 2*tig];
        sh1[nt] = sh[nt*8 + 2*tig + 1];
    }
    float a0v = al[0], a1v = al[1];

#pragma unroll
    for (int r = 0; r < 2; r++) {
        int px  = px0 + g + r*8;
        int off = r * 2;
        int p = p0 + px;
        if (p >= NPIX) continue;
        int b = p / FTSZ;
        int ft = p - b*FTSZ;
        int f = ft / TT;
        int t = ft - f*TT;
        int fidx = ((b*TT + t)*FF + f)*DC;
        int tidx = ((b*FF + f)*TT + t)*DC;
        float* dsts[5];
        dsts[0] = g_qf + fidx;
        dsts[1] = g_kf + fidx;
        dsts[2] = g_vv + fidx;
        dsts[3] = g_qt + tidx;
        dsts[4] = g_kt + tidx;
#pragma unroll
        for (int nt = 0; nt < 10; nt++) {
            int e = nt >> 1;
            float alpha = (e < 3) ? a0v : a1v;
            float v0 = acc[nt][off]     + sh0[nt];
            float v1 = acc[nt][off + 1] + sh1[nt];
            v0 = v0 >= 0.f ? v0 : alpha * v0;
            v1 = v1 >= 0.f ? v1 : alpha * v1;
            *(float2*)(dsts[e] + (nt & 1)*8 + 2*tig) = make_float2(v0, v1);
        }
    }
}

// ---------------------------------------------------------------------------
// Shared warp-level helpers for attention (tf32 MMA path).
// ---------------------------------------------------------------------------
#define KSTR 20
#define VSTR 24

__device__ __forceinline__ void redistribute_p(
    unsigned u0, unsigned u1, unsigned u2, unsigned u3,
    int src1, int src2, int tig,
    unsigned& pa0, unsigned& pa1, unsigned& pa2, unsigned& pa3)
{
    unsigned x0 = __shfl_sync(0xffffffffu, u0, src1);
    unsigned x1 = __shfl_sync(0xffffffffu, u1, src1);
    pa0 = (tig & 1) ? x1 : x0;
    unsigned y0 = __shfl_sync(0xffffffffu, u2, src1);
    unsigned y1 = __shfl_sync(0xffffffffu, u3, src1);
    pa1 = (tig & 1) ? y1 : y0;
    x0 = __shfl_sync(0xffffffffu, u0, src2);
    x1 = __shfl_sync(0xffffffffu, u1, src2);
    pa2 = (tig & 1) ? x1 : x0;
    y0 = __shfl_sync(0xffffffffu, u2, src2);
    y1 = __shfl_sync(0xffffffffu, u3, src2);
    pa3 = (tig & 1) ? y1 : y0;
}

// ---------------------------------------------------------------------------
// Kernel 2: frequency attention via tf32 mma, 17 warps, cp.async fill,
// no-cvt tf32 passthrough, exp2-domain softmax.
// ---------------------------------------------------------------------------
__global__ __launch_bounds__(544) void asa_fattn()
{
    __shared__ float Ks[264*KSTR];
    __shared__ float Vs[264*VSTR];
    int bt = blockIdx.x;
    int b = bt / TT, t = bt % TT;
    int base = (b*TT + t)*FF*DC;
    int tid = threadIdx.x;

    for (int i = tid; i < 264*4; i += 544) {
        int row = i >> 2, j4e = (i & 3) * 4;
        if (row < FF) {
            cp16(Ks + row*KSTR + j4e, g_kf + base + row*DC + j4e);
            cp16(Vs + row*VSTR + j4e, g_vv + base + row*DC + j4e);
        } else {
            uint4 z = make_uint4(0,0,0,0);
            *(uint4*)(Ks + row*KSTR + j4e) = z;
            *(uint4*)(Vs + row*VSTR + j4e) = z;
        }
    }
    CP_WAIT();
    __syncthreads();

    int warp = tid >> 5, lane = tid & 31;
    int g = lane >> 2, tig = lane & 3;
    int qsel = lane & ~3;
    int src1 = qsel | (tig >> 1);
    int src2 = src1 + 2;

    {
        int tile = warp;   // 17 warps, one 16-query tile each
        int fr0 = min(tile*16 + g, FF-1);
        int fr1 = min(tile*16 + g + 8, FF-1);
        const float* q0p = g_qf + base + fr0*DC;
        const float* q1p = g_qf + base + fr1*DC;
        unsigned qa[2][4];
#pragma unroll
        for (int ks = 0; ks < 2; ks++) {
            qa[ks][0] = __float_as_uint(q0p[ks*8 + tig]     * SCALE2);
            qa[ks][1] = __float_as_uint(q1p[ks*8 + tig]     * SCALE2);
            qa[ks][2] = __float_as_uint(q0p[ks*8 + tig + 4] * SCALE2);
            qa[ks][3] = __float_as_uint(q1p[ks*8 + tig + 4] * SCALE2);
        }
        float m0 = -3.0e38f, m1 = -3.0e38f, l0 = 0.f, l1 = 0.f;
        float oA[4] = {0,0,0,0}, oB[4] = {0,0,0,0};

        for (int kb = 0; kb < 16; kb++) {
            int krA = (kb*16 + g)*KSTR;
            int krB = (kb*16 + 8 + g)*KSTR;
            unsigned k0 = __float_as_uint(Ks[krA + tig]);
            unsigned k1 = __float_as_uint(Ks[krA + tig + 4]);
            unsigned k2 = __float_as_uint(Ks[krA + tig + 8]);
            unsigned k3 = __float_as_uint(Ks[krA + tig + 12]);
            unsigned k4 = __float_as_uint(Ks[krB + tig]);
            unsigned k5 = __float_as_uint(Ks[krB + tig + 4]);
            unsigned k6 = __float_as_uint(Ks[krB + tig + 8]);
            unsigned k7 = __float_as_uint(Ks[krB + tig + 12]);
            float s0=0.f,s1=0.f,s2=0.f,s3=0.f, s4=0.f,s5=0.f,s6=0.f,s7=0.f;
            mma_tf32(s0,s1,s2,s3, qa[0][0],qa[0][1],qa[0][2],qa[0][3], k0,k1);
            mma_tf32(s0,s1,s2,s3, qa[1][0],qa[1][1],qa[1][2],qa[1][3], k2,k3);
            mma_tf32(s4,s5,s6,s7, qa[0][0],qa[0][1],qa[0][2],qa[0][3], k4,k5);
            mma_tf32(s4,s5,s6,s7, qa[1][0],qa[1][1],qa[1][2],qa[1][3], k6,k7);

            float cm0 = fmaxf(fmaxf(s0,s1), fmaxf(s4,s5));
            float cm1 = fmaxf(fmaxf(s2,s3), fmaxf(s6,s7));
            cm0 = fmaxf(cm0, __shfl_xor_sync(0xffffffffu, cm0, 1));
            cm0 = fmaxf(cm0, __shfl_xor_sync(0xffffffffu, cm0, 2));
            cm1 = fmaxf(cm1, __shfl_xor_sync(0xffffffffu, cm1, 1));
            cm1 = fmaxf(cm1, __shfl_xor_sync(0xffffffffu, cm1, 2));
            float mn0 = fmaxf(m0, cm0), mn1 = fmaxf(m1, cm1);
            float c0 = exp2f(m0 - mn0), c1 = exp2f(m1 - mn1);
            m0 = mn0; m1 = mn1;
            float p0 = exp2f(s0 - mn0), p1 = exp2f(s1 - mn0);
            float p2 = exp2f(s2 - mn1), p3 = exp2f(s3 - mn1);
            float p4 = exp2f(s4 - mn0), p5 = exp2f(s5 - mn0);
            float p6 = exp2f(s6 - mn1), p7 = exp2f(s7 - mn1);
            float ps0 = (p0 + p1) + (p4 + p5);
            float ps1 = (p2 + p3) + (p6 + p7);
            ps0 += __shfl_xor_sync(0xffffffffu, ps0, 1);
            ps0 += __shfl_xor_sync(0xffffffffu, ps0, 2);
            ps1 += __shfl_xor_sync(0xffffffffu, ps1, 1);
            ps1 += __shfl_xor_sync(0xffffffffu, ps1, 2);
            l0 = l0*c0 + ps0; l1 = l1*c1 + ps1;
            oA[0] *= c0; oA[1] *= c0; oA[2] *= c1; oA[3] *= c1;
            oB[0] *= c0; oB[1] *= c0; oB[2] *= c1; oB[3] *= c1;

            unsigned paA0,paA1,paA2,paA3, paB0,paB1,paB2,paB3;
            redistribute_p(__float_as_uint(p0),__float_as_uint(p1),
                           __float_as_uint(p2),__float_as_uint(p3),
                           src1,src2,tig, paA0,paA1,paA2,paA3);
            redistribute_p(__float_as_uint(p4),__float_as_uint(p5),
                           __float_as_uint(p6),__float_as_uint(p7),
                           src1,src2,tig, paB0,paB1,paB2,paB3);

            int vrA0 = (kb*16 + tig)*VSTR,      vrA1 = (kb*16 + tig + 4)*VSTR;
            int vrB0 = (kb*16 + 8 + tig)*VSTR,  vrB1 = (kb*16 + 12 + tig)*VSTR;
            unsigned vA0 = __float_as_uint(Vs[vrA0 + g]);
            unsigned vA1 = __float_as_uint(Vs[vrA1 + g]);
            unsigned vA2 = __float_as_uint(Vs[vrA0 + g + 8]);
            unsigned vA3 = __float_as_uint(Vs[vrA1 + g + 8]);
            unsigned vB0 = __float_as_uint(Vs[vrB0 + g]);
            unsigned vB1 = __float_as_uint(Vs[vrB1 + g]);
            unsigned vB2 = __float_as_uint(Vs[vrB0 + g + 8]);
            unsigned vB3 = __float_as_uint(Vs[vrB1 + g + 8]);
            mma_tf32(oA[0],oA[1],oA[2],oA[3], paA0,paA1,paA2,paA3, vA0,vA1);
            mma_tf32(oA[0],oA[1],oA[2],oA[3], paB0,paB1,paB2,paB3, vB0,vB1);
            mma_tf32(oB[0],oB[1],oB[2],oB[3], paA0,paA1,paA2,paA3, vA2,vA3);
            mma_tf32(oB[0],oB[1],oB[2],oB[3], paB0,paB1,paB2,paB3, vB2,vB3);
        }
        // tail single block: key 256 (cols >0 masked)
        {
            int krow = (256 + g)*KSTR;
            unsigned k0 = __float_as_uint(Ks[krow + tig]);
            unsigned k1 = __float_as_uint(Ks[krow + tig + 4]);
            unsigned k2 = __float_as_uint(Ks[krow + tig + 8]);
            unsigned k3 = __float_as_uint(Ks[krow + tig + 12]);
            float s0=0.f,s1=0.f,s2=0.f,s3=0.f;
            mma_tf32(s0,s1,s2,s3, qa[0][0],qa[0][1],qa[0][2],qa[0][3], k0,k1);
            mma_tf32(s0,s1,s2,s3, qa[1][0],qa[1][1],qa[1][2],qa[1][3], k2,k3);
            if (tig > 0) { s0 = -3.0e38f; s2 = -3.0e38f; }
            s1 = -3.0e38f; s3 = -3.0e38f;
            float cm0 = fmaxf(s0, s1), cm1 = fmaxf(s2, s3);
            cm0 = fmaxf(cm0, __shfl_xor_sync(0xffffffffu, cm0, 1));
            cm0 = fmaxf(cm0, __shfl_xor_sync(0xffffffffu, cm0, 2));
            cm1 = fmaxf(cm1, __shfl_xor_sync(0xffffffffu, cm1, 1));
            cm1 = fmaxf(cm1, __shfl_xor_sync(0xffffffffu, cm1, 2));
            float mn0 = fmaxf(m0, cm0), mn1 = fmaxf(m1, cm1);
            float c0 = exp2f(m0 - mn0), c1 = exp2f(m1 - mn1);
            m0 = mn0; m1 = mn1;
            float p0 = exp2f(s0 - mn0), p1 = exp2f(s1 - mn0);
            float p2 = exp2f(s2 - mn1), p3 = exp2f(s3 - mn1);
            float ps0 = p0 + p1, ps1 = p2 + p3;
            ps0 += __shfl_xor_sync(0xffffffffu, ps0, 1);
            ps0 += __shfl_xor_sync(0xffffffffu, ps0, 2);
            ps1 += __shfl_xor_sync(0xffffffffu, ps1, 1);
            ps1 += __shfl_xor_sync(0xffffffffu, ps1, 2);
            l0 = l0*c0 + ps0; l1 = l1*c1 + ps1;
            oA[0] *= c0; oA[1] *= c0; oA[2] *= c1; oA[3] *= c1;
            oB[0] *= c0; oB[1] *= c0; oB[2] *= c1; oB[3] *= c1;
            unsigned pa0,pa1,pa2,pa3;
            redistribute_p(__float_as_uint(p0),__float_as_uint(p1),
                           __float_as_uint(p2),__float_as_uint(p3),
                           src1,src2,tig, pa0,pa1,pa2,pa3);
            int vr0 = (256 + tig)*VSTR, vr1 = (256 + tig + 4)*VSTR;
            unsigned v0 = __float_as_uint(Vs[vr0 + g]);
            unsigned v1 = __float_as_uint(Vs[vr1 + g]);
            unsigned v2 = __float_as_uint(Vs[vr0 + g + 8]);
            unsigned v3 = __float_as_uint(Vs[vr1 + g + 8]);
            mma_tf32(oA[0],oA[1],oA[2],oA[3], pa0,pa1,pa2,pa3, v0,v1);
            mma_tf32(oB[0],oB[1],oB[2],oB[3], pa0,pa1,pa2,pa3, v2,v3);
        }
        float inv0 = 1.f / l0, inv1 = 1.f / l1;
        int f0 = tile*16 + g, f1 = f0 + 8;
        if (f0 < FF) {
            float* op = g_fo + ((b*FF + f0)*TT + t)*DC;
            *(float2*)(op + 2*tig)     = make_float2(oA[0]*inv0, oA[1]*inv0);
            *(float2*)(op + 8 + 2*tig) = make_float2(oB[0]*inv0, oB[1]*inv0);
        }
        if (f1 < FF) {
            float* op = g_fo + ((b*FF + f1)*TT + t)*DC;
            *(float2*)(op + 2*tig)     = make_float2(oA[2]*inv1, oA[3]*inv1);
            *(float2*)(op + 8 + 2*tig) = make_float2(oB[2]*inv1, oB[3]*inv1);
        }
    }
}

// ---------------------------------------------------------------------------
// Kernel 3: causal time attention via tf32 mma, 16 warps x 2 tiles
// {w, 31-w}, cp.async fill, no-cvt passthrough + proj + residual.
// ---------------------------------------------------------------------------
extern __shared__ float sm3[];
__global__ __launch_bounds__(512) void asa_tattn(
    const float* __restrict__ inp,
    const float* __restrict__ pw, const float* __restrict__ pb,
    const float* __restrict__ pg, const float* __restrict__ pbe,
    const float* __restrict__ pm, const float* __restrict__ pv,
    const float* __restrict__ pa,
    float* __restrict__ out)
{
    float* Ks   = sm3;                    // 512*KSTR
    float* Vs   = Ks + 512*KSTR;          // 512*VSTR
    float* pws  = Vs + 512*VSTR;          // 64*16
    float* psh  = pws + 64*16;            // 64
    float* obuf = psh + 64;               // 16 warps * 16*17
    __shared__ float s_alpha;

    int bf = blockIdx.x;
    int b = bf / FF, f = bf % FF;
    int base = bf * TT * DC;
    int tid = threadIdx.x;

    for (int i = tid; i < 512*4; i += 512) {
        int row = i >> 2, j4e = (i & 3) * 4;
        if (row < TT) {
            cp16(Ks + row*KSTR + j4e, g_kt + base + row*DC + j4e);
            cp16(Vs + row*VSTR + j4e, g_fo + base + row*DC + j4e);
        } else {
            uint4 z = make_uint4(0,0,0,0);
            *(uint4*)(Ks + row*KSTR + j4e) = z;
            *(uint4*)(Vs + row*VSTR + j4e) = z;
        }
    }
    for (int i = tid; i < 64*16; i += 512) {
        int o = i >> 4;
        pws[i] = pw[i] * (pg[o] * rsqrtf(pv[o] + BN_EPS));
    }
    if (tid < 64) {
        int o = tid;
        psh[o] = (pb[o] - pm[o]) * (pg[o] * rsqrtf(pv[o] + BN_EPS)) + pbe[o];
    }
    if (tid == 0) s_alpha = pa[0];
    CP_WAIT();
    __syncthreads();

    int warp = tid >> 5, lane = tid & 31;
    int g = lane >> 2, tig = lane & 3;
    int qsel = lane & ~3;
    int src1 = qsel | (tig >> 1);
    int src2 = src1 + 2;
    float alpha = s_alpha;
    float* ob = obuf + warp * (16*17);

    int tiles[2] = { warp, 31 - warp };

#pragma unroll
    for (int ti = 0; ti < 2; ti++) {
        int tile = tiles[ti];
        int qt0 = tile * 16;
        int ta = qt0 + g;
        int tb = qt0 + g + 8;
        int tr0 = min(ta, TT-1), tr1 = min(tb, TT-1);
        const float* q0p = g_qt + base + tr0*DC;
        const float* q1p = g_qt + base + tr1*DC;
        unsigned qa[2][4];
#pragma unroll
        for (int ks = 0; ks < 2; ks++) {
            qa[ks][0] = __float_as_uint(q0p[ks*8 + tig]     * SCALE2);
            qa[ks][1] = __float_as_uint(q1p[ks*8 + tig]     * SCALE2);
            qa[ks][2] = __float_as_uint(q0p[ks*8 + tig + 4] * SCALE2);
            qa[ks][3] = __float_as_uint(q1p[ks*8 + tig + 4] * SCALE2);
        }
        float m0 = -3.0e38f, m1 = -3.0e38f, l0 = 0.f, l1 = 0.f;
        float oA[4] = {0,0,0,0}, oB[4] = {0,0,0,0};

        for (int kb = 0; kb <= tile; kb++) {
            int krA = (kb*16 + g)*KSTR;
            int krB = (kb*16 + 8 + g)*KSTR;
            unsigned k0 = __float_as_uint(Ks[krA + tig]);
            unsigned k1 = __float_as_uint(Ks[krA + tig + 4]);
            unsigned k2 = __float_as_uint(Ks[krA + tig + 8]);
            unsigned k3 = __float_as_uint(Ks[krA + tig + 12]);
            unsigned k4 = __float_as_uint(Ks[krB + tig]);
            unsigned k5 = __float_as_uint(Ks[krB + tig + 4]);
            unsigned k6 = __float_as_uint(Ks[krB + tig + 8]);
            unsigned k7 = __float_as_uint(Ks[krB + tig + 12]);
            float s0=0.f,s1=0.f,s2=0.f,s3=0.f, s4=0.f,s5=0.f,s6=0.f,s7=0.f;
            mma_tf32(s0,s1,s2,s3, qa[0][0],qa[0][1],qa[0][2],qa[0][3], k0,k1);
            mma_tf32(s0,s1,s2,s3, qa[1][0],qa[1][1],qa[1][2],qa[1][3], k2,k3);
            mma_tf32(s4,s5,s6,s7, qa[0][0],qa[0][1],qa[0][2],qa[0][3], k4,k5);
            mma_tf32(s4,s5,s6,s7, qa[1][0],qa[1][1],qa[1][2],qa[1][3], k6,k7);
            if (kb == tile) {
                int yA0 = kb*16 + 2*tig, yA1 = yA0 + 1;
                int yB0 = yA0 + 8,       yB1 = yA1 + 8;
                if (yA0 > ta) s0 = -3.0e38f;
                if (yA1 > ta) s1 = -3.0e38f;
                if (yA0 > tb) s2 = -3.0e38f;
                if (yA1 > tb) s3 = -3.0e38f;
                if (yB0 > ta) s4 = -3.0e38f;
                if (yB1 > ta) s5 = -3.0e38f;
                if (yB0 > tb) s6 = -3.0e38f;
                if (yB1 > tb) s7 = -3.0e38f;
            }
            float cm0 = fmaxf(fmaxf(s0,s1), fmaxf(s4,s5));
            float cm1 = fmaxf(fmaxf(s2,s3), fmaxf(s6,s7));
            cm0 = fmaxf(cm0, __shfl_xor_sync(0xffffffffu, cm0, 1));
            cm0 = fmaxf(cm0, __shfl_xor_sync(0xffffffffu, cm0, 2));
            cm1 = fmaxf(cm1, __shfl_xor_sync(0xffffffffu, cm1, 1));
            cm1 = fmaxf(cm1, __shfl_xor_sync(0xffffffffu, cm1, 2));
            float mn0 = fmaxf(m0, cm0), mn1 = fmaxf(m1, cm1);
            float c0 = exp2f(m0 - mn0), c1 = exp2f(m1 - mn1);
            m0 = mn0; m1 = mn1;
            float p0 = exp2f(s0 - mn0), p1 = exp2f(s1 - mn0);
            float p2 = exp2f(s2 - mn1), p3 = exp2f(s3 - mn1);
            float p4 = exp2f(s4 - mn0), p5 = exp2f(s5 - mn0);
            float p6 = exp2f(s6 - mn1), p7 = exp2f(s7 - mn1);
            float ps0 = (p0 + p1) + (p4 + p5);
            float ps1 = (p2 + p3) + (p6 + p7);
            ps0 += __shfl_xor_sync(0xffffffffu, ps0, 1);
            ps0 += __shfl_xor_sync(0xffffffffu, ps0, 2);
            ps1 += __shfl_xor_sync(0xffffffffu, ps1, 1);
            ps1 += __shfl_xor_sync(0xffffffffu, ps1, 2);
            l0 = l0*c0 + ps0; l1 = l1*c1 + ps1;
            oA[0] *= c0; oA[1] *= c0; oA[2] *= c1; oA[3] *= c1;
            oB[0] *= c0; oB[1] *= c0; oB[2] *= c1; oB[3] *= c1;

            unsigned paA0,paA1,paA2,paA3, paB0,paB1,paB2,paB3;
            redistribute_p(__float_as_uint(p0),__float_as_uint(p1),
                           __float_as_uint(p2),__float_as_uint(p3),
                           src1,src2,tig, paA0,paA1,paA2,paA3);
            redistribute_p(__float_as_uint(p4),__float_as_uint(p5),
                           __float_as_uint(p6),__float_as_uint(p7),
                           src1,src2,tig, paB0,paB1,paB2,paB3);

            int vrA0 = (kb*16 + tig)*VSTR,      vrA1 = (kb*16 + tig + 4)*VSTR;
            int vrB0 = (kb*16 + 8 + tig)*VSTR,  vrB1 = (kb*16 + 12 + tig)*VSTR;
            unsigned vA0 = __float_as_uint(Vs[vrA0 + g]);
            unsigned vA1 = __float_as_uint(Vs[vrA1 + g]);
            unsigned vA2 = __float_as_uint(Vs[vrA0 + g + 8]);
            unsigned vA3 = __float_as_uint(Vs[vrA1 + g + 8]);
            unsigned vB0 = __float_as_uint(Vs[vrB0 + g]);
            unsigned vB1 = __float_as_uint(Vs[vrB1 + g]);
            unsigned vB2 = __float_as_uint(Vs[vrB0 + g + 8]);
            unsigned vB3 = __float_as_uint(Vs[vrB1 + g + 8]);
            mma_tf32(oA[0],oA[1],oA[2],oA[3], paA0,paA1,paA2,paA3, vA0,vA1);
            mma_tf32(oA[0],oA[1],oA[2],oA[3], paB0,paB1,paB2,paB3, vB0,vB1);
            mma_tf32(oB[0],oB[1],oB[2],oB[3], paA0,paA1,paA2,paA3, vA2,vA3);
            mma_tf32(oB[0],oB[1],oB[2],oB[3], paB0,paB1,paB2,paB3, vB2,vB3);
        }
        float inv0 = 1.f / l0, inv1 = 1.f / l1;
        ob[g*17 + 2*tig]          = oA[0]*inv0;
        ob[g*17 + 2*tig + 1]      = oA[1]*inv0;
        ob[g*17 + 8 + 2*tig]      = oB[0]*inv0;
        ob[g*17 + 8 + 2*tig + 1]  = oB[1]*inv0;
        ob[(g+8)*17 + 2*tig]         = oA[2]*inv1;
        ob[(g+8)*17 + 2*tig + 1]     = oA[3]*inv1;
        ob[(g+8)*17 + 8 + 2*tig]     = oB[2]*inv1;
        ob[(g+8)*17 + 8 + 2*tig + 1] = oB[3]*inv1;
        __syncwarp();

        int qi = lane & 15;
        int t = qt0 + qi;
        if (t < TT) {
            const float* orow = ob + qi*17;
            u64 o2[8];
#pragma unroll
            for (int j = 0; j < 8; j++) o2[j] = pk2(orow[2*j], orow[2*j+1]);
            int c0 = (lane >> 4) * 32;
            int obase = b*CC*FTSZ + f*TT + t;
#pragma unroll 4
            for (int j = 0; j < 32; j++) {
                int co = c0 + j;
                const ulonglong2* wr = (const ulonglong2*)(pws + co*16);
                ulonglong2 wa = wr[0], wb = wr[1], wc = wr[2], wd = wr[3];
                u64 d0 = mul2(wa.x, o2[0]);
                u64 d1 = mul2(wa.y, o2[1]);
                d0 = fma2(wb.x, o2[2], d0);
                d1 = fma2(wb.y, o2[3], d1);
                d0 = fma2(wc.x, o2[4], d0);
                d1 = fma2(wc.y, o2[5], d1);
                d0 = fma2(wd.x, o2[6], d0);
                d1 = fma2(wd.y, o2[7], d1);
                float lo0,hi0,lo1,hi1;
                upk2(d0,lo0,hi0); upk2(d1,lo1,hi1);
                float r = psh[co] + (lo0+hi0) + (lo1+hi1);
                r = r >= 0.f ? r : alpha * r;
                int idx = obase + co*FTSZ;
                out[idx] = r + __ldg(&inp[idx]);
            }
        }
        __syncwarp();
    }
}

// ---------------------------------------------------------------------------
extern "C" void kernel_launch(void* const* d_in, const int* in_sizes, int n_in,
                              void* d_out, int out_size)
{
    const float* inp = (const float*)d_in[0];

    int smc_bytes = (64*PSTR + 64*WSTR + 80 + 2) * (int)sizeof(float);
    cudaFuncSetAttribute(asa_conv, cudaFuncAttributeMaxDynamicSharedMemorySize, smc_bytes);
    asa_conv<<<(NPIX + 127)/128, 256, smc_bytes>>>(
        inp,
        (const float*)d_in[1],  (const float*)d_in[2],  (const float*)d_in[3],
        (const float*)d_in[4],  (const float*)d_in[5],  (const float*)d_in[6],
        (const float*)d_in[7],
        (const float*)d_in[8],  (const float*)d_in[9],  (const float*)d_in[10],
        (const float*)d_in[11], (const float*)d_in[12], (const float*)d_in[13],
        (const float*)d_in[14]);

    asa_fattn<<<BB*TT, 544>>>();

    int sm3_bytes = (512*KSTR + 512*VSTR + 64*16 + 64 + 16*16*17) * (int)sizeof(float);
    cudaFuncSetAttribute(asa_tattn, cudaFuncAttributeMaxDynamicSharedMemorySize, sm3_bytes);
    asa_tattn<<<BB*FF, 512, sm3_bytes>>>(
        inp,
        (const float*)d_in[15], (const float*)d_in[16], (const float*)d_in[17],
        (const float*)d_in[18], (const float*)d_in[19], (const float*)d_in[20],
        (const float*)d_in[21],
        (float*)d_out);
}

// round 13
// speedup vs baseline: 3.6000x; 1.0793x over previous
#include <cuda_runtime.h>

#define BB 2
#define CC 64
#define FF 257
#define TT 500
#define DC 16
#define BN_EPS 1e-5f
#define SCALE2 0.36067376022224085f   /* 0.25 * log2(e) */
#define NPIX (BB*FF*TT)
#define FTSZ (FF*TT)

typedef unsigned long long u64;

__device__ __forceinline__ u64 pk2(float lo, float hi) {
    u64 r; asm("mov.b64 %0, {%1,%2};" : "=l"(r) : "f"(lo), "f"(hi)); return r;
}
__device__ __forceinline__ void upk2(u64 v, float& lo, float& hi) {
    asm("mov.b64 {%0,%1}, %2;" : "=f"(lo), "=f"(hi) : "l"(v));
}
__device__ __forceinline__ u64 fma2(u64 a, u64 b, u64 c) {
    u64 d; asm("fma.rn.f32x2 %0, %1, %2, %3;" : "=l"(d) : "l"(a), "l"(b), "l"(c)); return d;
}
__device__ __forceinline__ u64 mul2(u64 a, u64 b) {
    u64 d; asm("mul.rn.f32x2 %0, %1, %2;" : "=l"(d) : "l"(a), "l"(b)); return d;
}
__device__ __forceinline__ unsigned cvt_tf32(float x) {
    unsigned r; asm("cvt.rna.tf32.f32 %0, %1;" : "=r"(r) : "f"(x)); return r;
}
__device__ __forceinline__ void mma_tf32(
    float& d0, float& d1, float& d2, float& d3,
    unsigned a0, unsigned a1, unsigned a2, unsigned a3,
    unsigned b0, unsigned b1)
{
    asm("mma.sync.aligned.m16n8k8.row.col.f32.tf32.tf32.f32 "
        "{%0,%1,%2,%3},{%4,%5,%6,%7},{%8,%9},{%0,%1,%2,%3};"
        : "+f"(d0), "+f"(d1), "+f"(d2), "+f"(d3)
        : "r"(a0), "r"(a1), "r"(a2), "r"(a3), "r"(b0), "r"(b1));
}
__device__ __forceinline__ void cp16(void* dst, const void* src) {
    unsigned d = (unsigned)__cvta_generic_to_shared(dst);
    asm volatile("cp.async.ca.shared.global [%0], [%1], 16;" :: "r"(d), "l"(src));
}
#define CP_WAIT() asm volatile("cp.async.commit_group;\ncp.async.wait_group 0;" ::: "memory")

// Scratch (device globals; no allocation allowed)
__device__ float g_qf[BB*TT*FF*DC];   // [b][t][f][c]
__device__ float g_kf[BB*TT*FF*DC];   // [b][t][f][c]
__device__ float g_vv[BB*TT*FF*DC];   // [b][t][f][c]
__device__ float g_qt[BB*FF*TT*DC];   // [b][f][t][c]
__device__ float g_kt[BB*FF*TT*DC];   // [b][f][t][c]
__device__ float g_fo[BB*FF*TT*DC];   // [b][f][t][c]

// ---------------------------------------------------------------------------
// Kernel 1: fused 1x1 convs via tf32 MMA (cp.async fill, rna at frag load).
// ---------------------------------------------------------------------------
#define PSTR 136
#define WSTR 88

extern __shared__ float smc[];
__global__ __launch_bounds__(256) void asa_conv(
    const float* __restrict__ inp,
    const float* __restrict__ fw, const float* __restrict__ fb,
    const float* __restrict__ fg, const float* __restrict__ fbe,
    const float* __restrict__ fm, const float* __restrict__ fv,
    const float* __restrict__ fa,
    const float* __restrict__ tw, const float* __restrict__ tb,
    const float* __restrict__ tg, const float* __restrict__ tbe,
    const float* __restrict__ tm, const float* __restrict__ tv,
    const float* __restrict__ ta)
{
    float* xs = smc;                   // [64][PSTR]  raw fp32
    float* ws = smc + 64*PSTR;         // [64][WSTR]  tf32 (rna)
    float* sh = ws + 64*WSTR;          // [80]
    float* al = sh + 80;               // [2]

    int tid = threadIdx.x;

    for (int idx = tid; idx < 80*64; idx += 256) {
        int c = idx & 63, op = idx >> 6;
        int e = op >> 4, cc = op & 15;
        float w, g, vv;
        if (e < 3) { int o = 3*cc + e;      w = fw[o*64+c]; g = fg[o]; vv = fv[o]; }
        else       { int o2 = 2*cc + (e-3); w = tw[o2*64+c]; g = tg[o2]; vv = tv[o2]; }
        ws[c*WSTR + op] = __uint_as_float(cvt_tf32(w * (g * rsqrtf(vv + BN_EPS))));
    }
    if (tid < 80) {
        int op = tid, e = op >> 4, cc = op & 15;
        float g, vv, m, b, be;
        if (e < 3) { int o = 3*cc + e;      g=fg[o]; vv=fv[o]; m=fm[o]; b=fb[o]; be=fbe[o]; }
        else       { int o2 = 2*cc + (e-3); g=tg[o2]; vv=tv[o2]; m=tm[o2]; b=tb[o2]; be=tbe[o2]; }
        sh[op] = (b - m) * (g * rsqrtf(vv + BN_EPS)) + be;
    }
    if (tid == 0) { al[0] = fa[0]; al[1] = ta[0]; }

    int p0 = blockIdx.x * 128;
    int b0 = p0 / FTSZ;
    int bend = (p0 + 127) / FTSZ;
    if (b0 == bend && p0 + 127 < NPIX) {
        int ft0 = p0 - b0*FTSZ;
        const float* src = inp + b0*CC*FTSZ + ft0;
        for (int i = tid; i < 64*32; i += 256) {
            int c = i >> 5, l4 = i & 31;
            cp16(xs + c*PSTR + l4*4, src + c*FTSZ + l4*4);
        }
        CP_WAIT();
    } else {
        for (int i = tid; i < 64*128; i += 256) {
            int c = i >> 7, lp = i & 127;
            int p = p0 + lp;
            float v = 0.f;
            if (p < NPIX) {
                int b = p / FTSZ;
                int ft = p - b*FTSZ;
                v = inp[(b*CC + c)*FTSZ + ft];
            }
            xs[c*PSTR + lp] = v;
        }
    }
    __syncthreads();

    int warp = tid >> 5, lane = tid & 31;
    int g = lane >> 2, tig = lane & 3;
    int px0 = warp*16;

    float acc[10][4];
#pragma unroll
    for (int nt = 0; nt < 10; nt++)
#pragma unroll
        for (int j = 0; j < 4; j++) acc[nt][j] = 0.f;

#pragma unroll
    for (int k = 0; k < 8; k++) {
        int r0 = (8*k + tig)*PSTR, r1 = (8*k + tig + 4)*PSTR;
        unsigned a0 = cvt_tf32(xs[r0 + px0 + g]);
        unsigned a1 = cvt_tf32(xs[r0 + px0 + g + 8]);
        unsigned a2 = cvt_tf32(xs[r1 + px0 + g]);
        unsigned a3 = cvt_tf32(xs[r1 + px0 + g + 8]);
        int w0 = (8*k + tig)*WSTR + g, w1 = (8*k + tig + 4)*WSTR + g;
#pragma unroll
        for (int nt = 0; nt < 10; nt++) {
            unsigned bb0 = __float_as_uint(ws[w0 + nt*8]);
            unsigned bb1 = __float_as_uint(ws[w1 + nt*8]);
            mma_tf32(acc[nt][0], acc[nt][1], acc[nt][2], acc[nt][3],
                     a0, a1, a2, a3, bb0, bb1);
        }
    }

    float sh0[10], sh1[10];
#pragma unroll
    for (int nt = 0; nt < 10; nt++) {
        sh0[nt] = sh[nt*8 + 2*tig];
        sh1[nt] = sh[nt*8 + 2*tig + 1];
    }
    float a0v = al[0], a1v = al[1];

#pragma unroll
    for (int r = 0; r < 2; r++) {
        int px  = px0 + g + r*8;
        int off = r * 2;
        int p = p0 + px;
        if (p >= NPIX) continue;
        int b = p / FTSZ;
        int ft = p - b*FTSZ;
        int f = ft / TT;
        int t = ft - f*TT;
        int fidx = ((b*TT + t)*FF + f)*DC;
        int tidx = ((b*FF + f)*TT + t)*DC;
        float* dsts[5];
        dsts[0] = g_qf + fidx;
        dsts[1] = g_kf + fidx;
        dsts[2] = g_vv + fidx;
        dsts[3] = g_qt + tidx;
        dsts[4] = g_kt + tidx;
#pragma unroll
        for (int nt = 0; nt < 10; nt++) {
            int e = nt >> 1;
            float alpha = (e < 3) ? a0v : a1v;
            float v0 = acc[nt][off]     + sh0[nt];
            float v1 = acc[nt][off + 1] + sh1[nt];
            v0 = v0 >= 0.f ? v0 : alpha * v0;
            v1 = v1 >= 0.f ? v1 : alpha * v1;
            *(float2*)(dsts[e] + (nt & 1)*8 + 2*tig) = make_float2(v0, v1);
        }
    }
}

// ---------------------------------------------------------------------------
// Shared warp-level helpers for attention (tf32 MMA path).
// ---------------------------------------------------------------------------
#define KSTR 20
#define VSTR 24

__device__ __forceinline__ void redistribute_p(
    unsigned u0, unsigned u1, unsigned u2, unsigned u3,
    int src1, int src2, int tig,
    unsigned& pa0, unsigned& pa1, unsigned& pa2, unsigned& pa3)
{
    unsigned x0 = __shfl_sync(0xffffffffu, u0, src1);
    unsigned x1 = __shfl_sync(0xffffffffu, u1, src1);
    pa0 = (tig & 1) ? x1 : x0;
    unsigned y0 = __shfl_sync(0xffffffffu, u2, src1);
    unsigned y1 = __shfl_sync(0xffffffffu, u3, src1);
    pa1 = (tig & 1) ? y1 : y0;
    x0 = __shfl_sync(0xffffffffu, u0, src2);
    x1 = __shfl_sync(0xffffffffu, u1, src2);
    pa2 = (tig & 1) ? x1 : x0;
    y0 = __shfl_sync(0xffffffffu, u2, src2);
    y1 = __shfl_sync(0xffffffffu, u3, src2);
    pa3 = (tig & 1) ? y1 : y0;
}

// ---------------------------------------------------------------------------
// Kernel 2: frequency attention. tf32 mma, 17 warps, cp.async fill,
// NO online max (exp2 domain, scores bounded), per-lane l partials.
// ---------------------------------------------------------------------------
__global__ __launch_bounds__(544) void asa_fattn()
{
    __shared__ float Ks[264*KSTR];
    __shared__ float Vs[264*VSTR];
    int bt = blockIdx.x;
    int b = bt / TT, t = bt % TT;
    int base = (b*TT + t)*FF*DC;
    int tid = threadIdx.x;

    for (int i = tid; i < 264*4; i += 544) {
        int row = i >> 2, j4e = (i & 3) * 4;
        if (row < FF) {
            cp16(Ks + row*KSTR + j4e, g_kf + base + row*DC + j4e);
            cp16(Vs + row*VSTR + j4e, g_vv + base + row*DC + j4e);
        } else {
            uint4 z = make_uint4(0,0,0,0);
            *(uint4*)(Ks + row*KSTR + j4e) = z;
            *(uint4*)(Vs + row*VSTR + j4e) = z;
        }
    }
    CP_WAIT();
    __syncthreads();

    int warp = tid >> 5, lane = tid & 31;
    int g = lane >> 2, tig = lane & 3;
    int qsel = lane & ~3;
    int src1 = qsel | (tig >> 1);
    int src2 = src1 + 2;

    {
        int tile = warp;
        int fr0 = min(tile*16 + g, FF-1);
        int fr1 = min(tile*16 + g + 8, FF-1);
        const float* q0p = g_qf + base + fr0*DC;
        const float* q1p = g_qf + base + fr1*DC;
        unsigned qa[2][4];
#pragma unroll
        for (int ks = 0; ks < 2; ks++) {
            qa[ks][0] = cvt_tf32(q0p[ks*8 + tig]     * SCALE2);
            qa[ks][1] = cvt_tf32(q1p[ks*8 + tig]     * SCALE2);
            qa[ks][2] = cvt_tf32(q0p[ks*8 + tig + 4] * SCALE2);
            qa[ks][3] = cvt_tf32(q1p[ks*8 + tig + 4] * SCALE2);
        }
        float lp0 = 0.f, lp1 = 0.f;
        float oA[4] = {0,0,0,0}, oB[4] = {0,0,0,0};

        for (int kb = 0; kb < 16; kb++) {
            int krA = (kb*16 + g)*KSTR;
            int krB = (kb*16 + 8 + g)*KSTR;
            unsigned k0 = __float_as_uint(Ks[krA + tig]);
            unsigned k1 = __float_as_uint(Ks[krA + tig + 4]);
            unsigned k2 = __float_as_uint(Ks[krA + tig + 8]);
            unsigned k3 = __float_as_uint(Ks[krA + tig + 12]);
            unsigned k4 = __float_as_uint(Ks[krB + tig]);
            unsigned k5 = __float_as_uint(Ks[krB + tig + 4]);
            unsigned k6 = __float_as_uint(Ks[krB + tig + 8]);
            unsigned k7 = __float_as_uint(Ks[krB + tig + 12]);
            float s0=0.f,s1=0.f,s2=0.f,s3=0.f, s4=0.f,s5=0.f,s6=0.f,s7=0.f;
            mma_tf32(s0,s1,s2,s3, qa[0][0],qa[0][1],qa[0][2],qa[0][3], k0,k1);
            mma_tf32(s0,s1,s2,s3, qa[1][0],qa[1][1],qa[1][2],qa[1][3], k2,k3);
            mma_tf32(s4,s5,s6,s7, qa[0][0],qa[0][1],qa[0][2],qa[0][3], k4,k5);
            mma_tf32(s4,s5,s6,s7, qa[1][0],qa[1][1],qa[1][2],qa[1][3], k6,k7);

            float p0 = exp2f(s0), p1 = exp2f(s1);
            float p2 = exp2f(s2), p3 = exp2f(s3);
            float p4 = exp2f(s4), p5 = exp2f(s5);
            float p6 = exp2f(s6), p7 = exp2f(s7);
            lp0 += (p0 + p1) + (p4 + p5);
            lp1 += (p2 + p3) + (p6 + p7);

            unsigned paA0,paA1,paA2,paA3, paB0,paB1,paB2,paB3;
            redistribute_p(cvt_tf32(p0),cvt_tf32(p1),cvt_tf32(p2),cvt_tf32(p3),
                           src1,src2,tig, paA0,paA1,paA2,paA3);
            redistribute_p(cvt_tf32(p4),cvt_tf32(p5),cvt_tf32(p6),cvt_tf32(p7),
                           src1,src2,tig, paB0,paB1,paB2,paB3);

            int vrA0 = (kb*16 + tig)*VSTR,      vrA1 = (kb*16 + tig + 4)*VSTR;
            int vrB0 = (kb*16 + 8 + tig)*VSTR,  vrB1 = (kb*16 + 12 + tig)*VSTR;
            unsigned vA0 = __float_as_uint(Vs[vrA0 + g]);
            unsigned vA1 = __float_as_uint(Vs[vrA1 + g]);
            unsigned vA2 = __float_as_uint(Vs[vrA0 + g + 8]);
            unsigned vA3 = __float_as_uint(Vs[vrA1 + g + 8]);
            unsigned vB0 = __float_as_uint(Vs[vrB0 + g]);
            unsigned vB1 = __float_as_uint(Vs[vrB1 + g]);
            unsigned vB2 = __float_as_uint(Vs[vrB0 + g + 8]);
            unsigned vB3 = __float_as_uint(Vs[vrB1 + g + 8]);
            mma_tf32(oA[0],oA[1],oA[2],oA[3], paA0,paA1,paA2,paA3, vA0,vA1);
            mma_tf32(oA[0],oA[1],oA[2],oA[3], paB0,paB1,paB2,paB3, vB0,vB1);
            mma_tf32(oB[0],oB[1],oB[2],oB[3], paA0,paA1,paA2,paA3, vA2,vA3);
            mma_tf32(oB[0],oB[1],oB[2],oB[3], paB0,paB1,paB2,paB3, vB2,vB3);
        }
        // tail single block: key 256 (cols >0 masked)
        {
            int krow = (256 + g)*KSTR;
            unsigned k0 = __float_as_uint(Ks[krow + tig]);
            unsigned k1 = __float_as_uint(Ks[krow + tig + 4]);
            unsigned k2 = __float_as_uint(Ks[krow + tig + 8]);
            unsigned k3 = __float_as_uint(Ks[krow + tig + 12]);
            float s0=0.f,s1=0.f,s2=0.f,s3=0.f;
            mma_tf32(s0,s1,s2,s3, qa[0][0],qa[0][1],qa[0][2],qa[0][3], k0,k1);
            mma_tf32(s0,s1,s2,s3, qa[1][0],qa[1][1],qa[1][2],qa[1][3], k2,k3);
            float p0 = (tig == 0) ? exp2f(s0) : 0.f;
            float p2 = (tig == 0) ? exp2f(s2) : 0.f;
            lp0 += p0; lp1 += p2;
            unsigned pa0,pa1,pa2,pa3;
            redistribute_p(cvt_tf32(p0), 0u, cvt_tf32(p2), 0u,
                           src1,src2,tig, pa0,pa1,pa2,pa3);
            int vr0 = (256 + tig)*VSTR, vr1 = (256 + tig + 4)*VSTR;
            unsigned v0 = __float_as_uint(Vs[vr0 + g]);
            unsigned v1 = __float_as_uint(Vs[vr1 + g]);
            unsigned v2 = __float_as_uint(Vs[vr0 + g + 8]);
            unsigned v3 = __float_as_uint(Vs[vr1 + g + 8]);
            mma_tf32(oA[0],oA[1],oA[2],oA[3], pa0,pa1,pa2,pa3, v0,v1);
            mma_tf32(oB[0],oB[1],oB[2],oB[3], pa0,pa1,pa2,pa3, v2,v3);
        }
        // reduce l across the quad once
        lp0 += __shfl_xor_sync(0xffffffffu, lp0, 1);
        lp0 += __shfl_xor_sync(0xffffffffu, lp0, 2);
        lp1 += __shfl_xor_sync(0xffffffffu, lp1, 1);
        lp1 += __shfl_xor_sync(0xffffffffu, lp1, 2);
        float inv0 = 1.f / lp0, inv1 = 1.f / lp1;
        int f0 = tile*16 + g, f1 = f0 + 8;
        if (f0 < FF) {
            float* op = g_fo + ((b*FF + f0)*TT + t)*DC;
            *(float2*)(op + 2*tig)     = make_float2(oA[0]*inv0, oA[1]*inv0);
            *(float2*)(op + 8 + 2*tig) = make_float2(oB[0]*inv0, oB[1]*inv0);
        }
        if (f1 < FF) {
            float* op = g_fo + ((b*FF + f1)*TT + t)*DC;
            *(float2*)(op + 2*tig)     = make_float2(oA[2]*inv1, oA[3]*inv1);
            *(float2*)(op + 8 + 2*tig) = make_float2(oB[2]*inv1, oB[3]*inv1);
        }
    }
}

// ---------------------------------------------------------------------------
// Kernel 3: causal time attention. tf32 mma, 16 warps x 2 tiles {w, 31-w},
// NO online max, per-lane l partials, proj + residual.
// ---------------------------------------------------------------------------
extern __shared__ float sm3[];
__global__ __launch_bounds__(512) void asa_tattn(
    const float* __restrict__ inp,
    const float* __restrict__ pw, const float* __restrict__ pb,
    const float* __restrict__ pg, const float* __restrict__ pbe,
    const float* __restrict__ pm, const float* __restrict__ pv,
    const float* __restrict__ pa,
    float* __restrict__ out)
{
    float* Ks   = sm3;                    // 512*KSTR
    float* Vs   = Ks + 512*KSTR;          // 512*VSTR
    float* pws  = Vs + 512*VSTR;          // 64*16
    float* psh  = pws + 64*16;            // 64
    float* obuf = psh + 64;               // 16 warps * 16*17
    __shared__ float s_alpha;

    int bf = blockIdx.x;
    int b = bf / FF, f = bf % FF;
    int base = bf * TT * DC;
    int tid = threadIdx.x;

    for (int i = tid; i < 512*4; i += 512) {
        int row = i >> 2, j4e = (i & 3) * 4;
        if (row < TT) {
            cp16(Ks + row*KSTR + j4e, g_kt + base + row*DC + j4e);
            cp16(Vs + row*VSTR + j4e, g_fo + base + row*DC + j4e);
        } else {
            uint4 z = make_uint4(0,0,0,0);
            *(uint4*)(Ks + row*KSTR + j4e) = z;
            *(uint4*)(Vs + row*VSTR + j4e) = z;
        }
    }
    for (int i = tid; i < 64*16; i += 512) {
        int o = i >> 4;
        pws[i] = pw[i] * (pg[o] * rsqrtf(pv[o] + BN_EPS));
    }
    if (tid < 64) {
        int o = tid;
        psh[o] = (pb[o] - pm[o]) * (pg[o] * rsqrtf(pv[o] + BN_EPS)) + pbe[o];
    }
    if (tid == 0) s_alpha = pa[0];
    CP_WAIT();
    __syncthreads();

    int warp = tid >> 5, lane = tid & 31;
    int g = lane >> 2, tig = lane & 3;
    int qsel = lane & ~3;
    int src1 = qsel | (tig >> 1);
    int src2 = src1 + 2;
    float alpha = s_alpha;
    float* ob = obuf + warp * (16*17);

    int tiles[2] = { warp, 31 - warp };

#pragma unroll
    for (int ti = 0; ti < 2; ti++) {
        int tile = tiles[ti];
        int qt0 = tile * 16;
        int ta = qt0 + g;
        int tb = qt0 + g + 8;
        int tr0 = min(ta, TT-1), tr1 = min(tb, TT-1);
        const float* q0p = g_qt + base + tr0*DC;
        const float* q1p = g_qt + base + tr1*DC;
        unsigned qa[2][4];
#pragma unroll
        for (int ks = 0; ks < 2; ks++) {
            qa[ks][0] = cvt_tf32(q0p[ks*8 + tig]     * SCALE2);
            qa[ks][1] = cvt_tf32(q1p[ks*8 + tig]     * SCALE2);
            qa[ks][2] = cvt_tf32(q0p[ks*8 + tig + 4] * SCALE2);
            qa[ks][3] = cvt_tf32(q1p[ks*8 + tig + 4] * SCALE2);
        }
        float lp0 = 0.f, lp1 = 0.f;
        float oA[4] = {0,0,0,0}, oB[4] = {0,0,0,0};

        for (int kb = 0; kb <= tile; kb++) {
            int krA = (kb*16 + g)*KSTR;
            int krB = (kb*16 + 8 + g)*KSTR;
            unsigned k0 = __float_as_uint(Ks[krA + tig]);
            unsigned k1 = __float_as_uint(Ks[krA + tig + 4]);
            unsigned k2 = __float_as_uint(Ks[krA + tig + 8]);
            unsigned k3 = __float_as_uint(Ks[krA + tig + 12]);
            unsigned k4 = __float_as_uint(Ks[krB + tig]);
            unsigned k5 = __float_as_uint(Ks[krB + tig + 4]);
            unsigned k6 = __float_as_uint(Ks[krB + tig + 8]);
            unsigned k7 = __float_as_uint(Ks[krB + tig + 12]);
            float s0=0.f,s1=0.f,s2=0.f,s3=0.f, s4=0.f,s5=0.f,s6=0.f,s7=0.f;
            mma_tf32(s0,s1,s2,s3, qa[0][0],qa[0][1],qa[0][2],qa[0][3], k0,k1);
            mma_tf32(s0,s1,s2,s3, qa[1][0],qa[1][1],qa[1][2],qa[1][3], k2,k3);
            mma_tf32(s4,s5,s6,s7, qa[0][0],qa[0][1],qa[0][2],qa[0][3], k4,k5);
            mma_tf32(s4,s5,s6,s7, qa[1][0],qa[1][1],qa[1][2],qa[1][3], k6,k7);
            if (kb == tile) {
                int yA0 = kb*16 + 2*tig, yA1 = yA0 + 1;
                int yB0 = yA0 + 8,       yB1 = yA1 + 8;
                if (yA0 > ta) s0 = -3.0e38f;
                if (yA1 > ta) s1 = -3.0e38f;
                if (yA0 > tb) s2 = -3.0e38f;
                if (yA1 > tb) s3 = -3.0e38f;
                if (yB0 > ta) s4 = -3.0e38f;
                if (yB1 > ta) s5 = -3.0e38f;
                if (yB0 > tb) s6 = -3.0e38f;
                if (yB1 > tb) s7 = -3.0e38f;
            }
            float p0 = exp2f(s0), p1 = exp2f(s1);
            float p2 = exp2f(s2), p3 = exp2f(s3);
            float p4 = exp2f(s4), p5 = exp2f(s5);
            float p6 = exp2f(s6), p7 = exp2f(s7);
            lp0 += (p0 + p1) + (p4 + p5);
            lp1 += (p2 + p3) + (p6 + p7);

            unsigned paA0,paA1,paA2,paA3, paB0,paB1,paB2,paB3;
            redistribute_p(cvt_tf32(p0),cvt_tf32(p1),cvt_tf32(p2),cvt_tf32(p3),
                           src1,src2,tig, paA0,paA1,paA2,paA3);
            redistribute_p(cvt_tf32(p4),cvt_tf32(p5),cvt_tf32(p6),cvt_tf32(p7),
                           src1,src2,tig, paB0,paB1,paB2,paB3);

            int vrA0 = (kb*16 + tig)*VSTR,      vrA1 = (kb*16 + tig + 4)*VSTR;
            int vrB0 = (kb*16 + 8 + tig)*VSTR,  vrB1 = (kb*16 + 12 + tig)*VSTR;
            unsigned vA0 = __float_as_uint(Vs[vrA0 + g]);
            unsigned vA1 = __float_as_uint(Vs[vrA1 + g]);
            unsigned vA2 = __float_as_uint(Vs[vrA0 + g + 8]);
            unsigned vA3 = __float_as_uint(Vs[vrA1 + g + 8]);
            unsigned vB0 = __float_as_uint(Vs[vrB0 + g]);
            unsigned vB1 = __float_as_uint(Vs[vrB1 + g]);
            unsigned vB2 = __float_as_uint(Vs[vrB0 + g + 8]);
            unsigned vB3 = __float_as_uint(Vs[vrB1 + g + 8]);
            mma_tf32(oA[0],oA[1],oA[2],oA[3], paA0,paA1,paA2,paA3, vA0,vA1);
            mma_tf32(oA[0],oA[1],oA[2],oA[3], paB0,paB1,paB2,paB3, vB0,vB1);
            mma_tf32(oB[0],oB[1],oB[2],oB[3], paA0,paA1,paA2,paA3, vA2,vA3);
            mma_tf32(oB[0],oB[1],oB[2],oB[3], paB0,paB1,paB2,paB3, vB2,vB3);
        }
        lp0 += __shfl_xor_sync(0xffffffffu, lp0, 1);
        lp0 += __shfl_xor_sync(0xffffffffu, lp0, 2);
        lp1 += __shfl_xor_sync(0xffffffffu, lp1, 1);
        lp1 += __shfl_xor_sync(0xffffffffu, lp1, 2);
        float inv0 = 1.f / lp0, inv1 = 1.f / lp1;
        ob[g*17 + 2*tig]          = oA[0]*inv0;
        ob[g*17 + 2*tig + 1]      = oA[1]*inv0;
        ob[g*17 + 8 + 2*tig]      = oB[0]*inv0;
        ob[g*17 + 8 + 2*tig + 1]  = oB[1]*inv0;
        ob[(g+8)*17 + 2*tig]         = oA[2]*inv1;
        ob[(g+8)*17 + 2*tig + 1]     = oA[3]*inv1;
        ob[(g+8)*17 + 8 + 2*tig]     = oB[2]*inv1;
        ob[(g+8)*17 + 8 + 2*tig + 1] = oB[3]*inv1;
        __syncwarp();

        int qi = lane & 15;
        int t = qt0 + qi;
        if (t < TT) {
            const float* orow = ob + qi*17;
            u64 o2[8];
#pragma unroll
            for (int j = 0; j < 8; j++) o2[j] = pk2(orow[2*j], orow[2*j+1]);
            int c0 = (lane >> 4) * 32;
            int obase = b*CC*FTSZ + f*TT + t;
#pragma unroll 4
            for (int j = 0; j < 32; j++) {
                int co = c0 + j;
                const ulonglong2* wr = (const ulonglong2*)(pws + co*16);
                ulonglong2 wa = wr[0], wb = wr[1], wc = wr[2], wd = wr[3];
                u64 d0 = mul2(wa.x, o2[0]);
                u64 d1 = mul2(wa.y, o2[1]);
                d0 = fma2(wb.x, o2[2], d0);
                d1 = fma2(wb.y, o2[3], d1);
                d0 = fma2(wc.x, o2[4], d0);
                d1 = fma2(wc.y, o2[5], d1);
                d0 = fma2(wd.x, o2[6], d0);
                d1 = fma2(wd.y, o2[7], d1);
                float lo0,hi0,lo1,hi1;
                upk2(d0,lo0,hi0); upk2(d1,lo1,hi1);
                float r = psh[co] + (lo0+hi0) + (lo1+hi1);
                r = r >= 0.f ? r : alpha * r;
                int idx = obase + co*FTSZ;
                out[idx] = r + __ldg(&inp[idx]);
            }
        }
        __syncwarp();
    }
}

// ---------------------------------------------------------------------------
extern "C" void kernel_launch(void* const* d_in, const int* in_sizes, int n_in,
                              void* d_out, int out_size)
{
    const float* inp = (const float*)d_in[0];

    int smc_bytes = (64*PSTR + 64*WSTR + 80 + 2) * (int)sizeof(float);
    cudaFuncSetAttribute(asa_conv, cudaFuncAttributeMaxDynamicSharedMemorySize, smc_bytes);
    asa_conv<<<(NPIX + 127)/128, 256, smc_bytes>>>(
        inp,
        (const float*)d_in[1],  (const float*)d_in[2],  (const float*)d_in[3],
        (const float*)d_in[4],  (const float*)d_in[5],  (const float*)d_in[6],
        (const float*)d_in[7],
        (const float*)d_in[8],  (const float*)d_in[9],  (const float*)d_in[10],
        (const float*)d_in[11], (const float*)d_in[12], (const float*)d_in[13],
        (const float*)d_in[14]);

    asa_fattn<<<BB*TT, 544>>>();

    int sm3_bytes = (512*KSTR + 512*VSTR + 64*16 + 64 + 16*16*17) * (int)sizeof(float);
    cudaFuncSetAttribute(asa_tattn, cudaFuncAttributeMaxDynamicSharedMemorySize, sm3_bytes);
    asa_tattn<<<BB*FF, 512, sm3_bytes>>>(
        inp,
        (const float*)d_in[15], (const float*)d_in[16], (const float*)d_in[17],
        (const float*)d_in[18], (const float*)d_in[19], (const float*)d_in[20],
        (const float*)d_in[21],
        (float*)d_out);
}

// round 14
// speedup vs baseline: 4.5680x; 1.2689x over previous
#include <cuda_runtime.h>

#define BB 2
#define CC 64
#define FF 257
#define TT 500
#define DC 16
#define BN_EPS 1e-5f
#define SCALE2 0.36067376022224085f   /* 0.25 * log2(e) */
#define NPIX (BB*FF*TT)
#define FTSZ (FF*TT)

typedef unsigned long long u64;

__device__ __forceinline__ u64 pk2(float lo, float hi) {
    u64 r; asm("mov.b64 %0, {%1,%2};" : "=l"(r) : "f"(lo), "f"(hi)); return r;
}
__device__ __forceinline__ void upk2(u64 v, float& lo, float& hi) {
    asm("mov.b64 {%0,%1}, %2;" : "=f"(lo), "=f"(hi) : "l"(v));
}
__device__ __forceinline__ u64 fma2(u64 a, u64 b, u64 c) {
    u64 d; asm("fma.rn.f32x2 %0, %1, %2, %3;" : "=l"(d) : "l"(a), "l"(b), "l"(c)); return d;
}
__device__ __forceinline__ u64 mul2(u64 a, u64 b) {
    u64 d; asm("mul.rn.f32x2 %0, %1, %2;" : "=l"(d) : "l"(a), "l"(b)); return d;
}
__device__ __forceinline__ unsigned cvt_tf32(float x) {
    unsigned r; asm("cvt.rna.tf32.f32 %0, %1;" : "=r"(r) : "f"(x)); return r;
}
// pack {lo, hi} into half2 (first src -> upper 16 bits per PTX)
__device__ __forceinline__ unsigned h2pk(float lo, float hi) {
    unsigned r; asm("cvt.rn.f16x2.f32 %0, %1, %2;" : "=r"(r) : "f"(hi), "f"(lo)); return r;
}
__device__ __forceinline__ void mma_tf32(
    float& d0, float& d1, float& d2, float& d3,
    unsigned a0, unsigned a1, unsigned a2, unsigned a3,
    unsigned b0, unsigned b1)
{
    asm("mma.sync.aligned.m16n8k8.row.col.f32.tf32.tf32.f32 "
        "{%0,%1,%2,%3},{%4,%5,%6,%7},{%8,%9},{%0,%1,%2,%3};"
        : "+f"(d0), "+f"(d1), "+f"(d2), "+f"(d3)
        : "r"(a0), "r"(a1), "r"(a2), "r"(a3), "r"(b0), "r"(b1));
}
__device__ __forceinline__ void mma_f16(
    float& d0, float& d1, float& d2, float& d3,
    unsigned a0, unsigned a1, unsigned a2, unsigned a3,
    unsigned b0, unsigned b1)
{
    asm("mma.sync.aligned.m16n8k16.row.col.f32.f16.f16.f32 "
        "{%0,%1,%2,%3},{%4,%5,%6,%7},{%8,%9},{%0,%1,%2,%3};"
        : "+f"(d0), "+f"(d1), "+f"(d2), "+f"(d3)
        : "r"(a0), "r"(a1), "r"(a2), "r"(a3), "r"(b0), "r"(b1));
}
__device__ __forceinline__ void cp16(void* dst, const void* src) {
    unsigned d = (unsigned)__cvta_generic_to_shared(dst);
    asm volatile("cp.async.ca.shared.global [%0], [%1], 16;" :: "r"(d), "l"(src));
}
#define CP_WAIT() asm volatile("cp.async.commit_group;\ncp.async.wait_group 0;" ::: "memory")

// Scratch (device globals; no allocation allowed)
__device__ float g_qf[BB*TT*FF*DC];   // [b][t][f][c]
__device__ float g_kf[BB*TT*FF*DC];   // [b][t][f][c]
__device__ float g_vv[BB*TT*FF*DC];   // [b][t][f][c]
__device__ float g_qt[BB*FF*TT*DC];   // [b][f][t][c]
__device__ float g_kt[BB*FF*TT*DC];   // [b][f][t][c]
__device__ float g_fo[BB*FF*TT*DC];   // [b][f][t][c]

// ---------------------------------------------------------------------------
// Kernel 1: fused 1x1 convs via tf32 MMA (unchanged from R13).
// ---------------------------------------------------------------------------
#define PSTR 136
#define WSTR 88

extern __shared__ float smc[];
__global__ __launch_bounds__(256) void asa_conv(
    const float* __restrict__ inp,
    const float* __restrict__ fw, const float* __restrict__ fb,
    const float* __restrict__ fg, const float* __restrict__ fbe,
    const float* __restrict__ fm, const float* __restrict__ fv,
    const float* __restrict__ fa,
    const float* __restrict__ tw, const float* __restrict__ tb,
    const float* __restrict__ tg, const float* __restrict__ tbe,
    const float* __restrict__ tm, const float* __restrict__ tv,
    const float* __restrict__ ta)
{
    float* xs = smc;
    float* ws = smc + 64*PSTR;
    float* sh = ws + 64*WSTR;
    float* al = sh + 80;

    int tid = threadIdx.x;

    for (int idx = tid; idx < 80*64; idx += 256) {
        int c = idx & 63, op = idx >> 6;
        int e = op >> 4, cc = op & 15;
        float w, g, vv;
        if (e < 3) { int o = 3*cc + e;      w = fw[o*64+c]; g = fg[o]; vv = fv[o]; }
        else       { int o2 = 2*cc + (e-3); w = tw[o2*64+c]; g = tg[o2]; vv = tv[o2]; }
        ws[c*WSTR + op] = __uint_as_float(cvt_tf32(w * (g * rsqrtf(vv + BN_EPS))));
    }
    if (tid < 80) {
        int op = tid, e = op >> 4, cc = op & 15;
        float g, vv, m, b, be;
        if (e < 3) { int o = 3*cc + e;      g=fg[o]; vv=fv[o]; m=fm[o]; b=fb[o]; be=fbe[o]; }
        else       { int o2 = 2*cc + (e-3); g=tg[o2]; vv=tv[o2]; m=tm[o2]; b=tb[o2]; be=tbe[o2]; }
        sh[op] = (b - m) * (g * rsqrtf(vv + BN_EPS)) + be;
    }
    if (tid == 0) { al[0] = fa[0]; al[1] = ta[0]; }

    int p0 = blockIdx.x * 128;
    int b0 = p0 / FTSZ;
    int bend = (p0 + 127) / FTSZ;
    if (b0 == bend && p0 + 127 < NPIX) {
        int ft0 = p0 - b0*FTSZ;
        const float* src = inp + b0*CC*FTSZ + ft0;
        for (int i = tid; i < 64*32; i += 256) {
            int c = i >> 5, l4 = i & 31;
            cp16(xs + c*PSTR + l4*4, src + c*FTSZ + l4*4);
        }
        CP_WAIT();
    } else {
        for (int i = tid; i < 64*128; i += 256) {
            int c = i >> 7, lp = i & 127;
            int p = p0 + lp;
            float v = 0.f;
            if (p < NPIX) {
                int b = p / FTSZ;
                int ft = p - b*FTSZ;
                v = inp[(b*CC + c)*FTSZ + ft];
            }
            xs[c*PSTR + lp] = v;
        }
    }
    __syncthreads();

    int warp = tid >> 5, lane = tid & 31;
    int g = lane >> 2, tig = lane & 3;
    int px0 = warp*16;

    float acc[10][4];
#pragma unroll
    for (int nt = 0; nt < 10; nt++)
#pragma unroll
        for (int j = 0; j < 4; j++) acc[nt][j] = 0.f;

#pragma unroll
    for (int k = 0; k < 8; k++) {
        int r0 = (8*k + tig)*PSTR, r1 = (8*k + tig + 4)*PSTR;
        unsigned a0 = cvt_tf32(xs[r0 + px0 + g]);
        unsigned a1 = cvt_tf32(xs[r0 + px0 + g + 8]);
        unsigned a2 = cvt_tf32(xs[r1 + px0 + g]);
        unsigned a3 = cvt_tf32(xs[r1 + px0 + g + 8]);
        int w0 = (8*k + tig)*WSTR + g, w1 = (8*k + tig + 4)*WSTR + g;
#pragma unroll
        for (int nt = 0; nt < 10; nt++) {
            unsigned bb0 = __float_as_uint(ws[w0 + nt*8]);
            unsigned bb1 = __float_as_uint(ws[w1 + nt*8]);
            mma_tf32(acc[nt][0], acc[nt][1], acc[nt][2], acc[nt][3],
                     a0, a1, a2, a3, bb0, bb1);
        }
    }

    float sh0[10], sh1[10];
#pragma unroll
    for (int nt = 0; nt < 10; nt++) {
        sh0[nt] = sh[nt*8 + 2*tig];
        sh1[nt] = sh[nt*8 + 2*tig + 1];
    }
    float a0v = al[0], a1v = al[1];

#pragma unroll
    for (int r = 0; r < 2; r++) {
        int px  = px0 + g + r*8;
        int off = r * 2;
        int p = p0 + px;
        if (p >= NPIX) continue;
        int b = p / FTSZ;
        int ft = p - b*FTSZ;
        int f = ft / TT;
        int t = ft - f*TT;
        int fidx = ((b*TT + t)*FF + f)*DC;
        int tidx = ((b*FF + f)*TT + t)*DC;
        float* dsts[5];
        dsts[0] = g_qf + fidx;
        dsts[1] = g_kf + fidx;
        dsts[2] = g_vv + fidx;
        dsts[3] = g_qt + tidx;
        dsts[4] = g_kt + tidx;
#pragma unroll
        for (int nt = 0; nt < 10; nt++) {
            int e = nt >> 1;
            float alpha = (e < 3) ? a0v : a1v;
            float v0 = acc[nt][off]     + sh0[nt];
            float v1 = acc[nt][off + 1] + sh1[nt];
            v0 = v0 >= 0.f ? v0 : alpha * v0;
            v1 = v1 >= 0.f ? v1 : alpha * v1;
            *(float2*)(dsts[e] + (nt & 1)*8 + 2*tig) = make_float2(v0, v1);
        }
    }
}

// ---------------------------------------------------------------------------
// Kernel 2: frequency attention. fp16 m16n8k16 MMA, FA2 P-layout passthrough,
// no online max (clamped exp2), 17 warps x 1 tile.
// Kh[key][dcpair] stride 12; Vh[dc][keypair] stride 132.
// ---------------------------------------------------------------------------
#define FNR 264          // padded key rows
#define FNKP 132         // key pairs (stride, ==4 mod 32)

extern __shared__ unsigned smf[];
__global__ __launch_bounds__(544) void asa_fattn()
{
    unsigned* Kh = smf;                      // FNR*12
    unsigned* Vh = smf + FNR*12;             // 16*FNKP
    float* Kst = (float*)(Vh + 16*FNKP);     // FNR*16
    float* Vst = Kst + FNR*16;               // FNR*16

    int bt = blockIdx.x;
    int b = bt / TT, t = bt % TT;
    int base = (b*TT + t)*FF*DC;
    int tid = threadIdx.x;

    for (int i = tid; i < FNR*4; i += 544) {
        if (i < FF*4) {
            cp16(Kst + i*4, g_kf + base + i*4);
            cp16(Vst + i*4, g_vv + base + i*4);
        } else {
            uint4 z = make_uint4(0,0,0,0);
            *(uint4*)(Kst + i*4) = z;
            *(uint4*)(Vst + i*4) = z;
        }
    }
    CP_WAIT();
    __syncthreads();
    // convert: Kh[key][dp] and Vh[dc][kp]
    for (int i = tid; i < FNR*8; i += 544) {
        int key = i >> 3, dp = i & 7;
        float2 v = *(const float2*)(Kst + key*16 + 2*dp);
        Kh[key*12 + dp] = h2pk(v.x, v.y);
    }
    for (int i = tid; i < 16*FNKP; i += 544) {
        int dc = i & 15, kp = i >> 4;
        float lo = Vst[(2*kp)*16 + dc];
        float hi = Vst[(2*kp+1)*16 + dc];
        Vh[dc*FNKP + kp] = h2pk(lo, hi);
    }
    __syncthreads();

    int warp = tid >> 5, lane = tid & 31;
    int g = lane >> 2, tig = lane & 3;

    {
        int tile = warp;
        int fr0 = min(tile*16 + g, FF-1);
        int fr1 = min(tile*16 + g + 8, FF-1);
        const float* q0p = g_qf + base + fr0*DC;
        const float* q1p = g_qf + base + fr1*DC;
        float2 xa = *(const float2*)(q0p + 2*tig);
        float2 xb = *(const float2*)(q1p + 2*tig);
        float2 xc = *(const float2*)(q0p + 8 + 2*tig);
        float2 xd = *(const float2*)(q1p + 8 + 2*tig);
        unsigned qh0 = h2pk(xa.x*SCALE2, xa.y*SCALE2);
        unsigned qh1 = h2pk(xb.x*SCALE2, xb.y*SCALE2);
        unsigned qh2 = h2pk(xc.x*SCALE2, xc.y*SCALE2);
        unsigned qh3 = h2pk(xd.x*SCALE2, xd.y*SCALE2);

        float lp0 = 0.f, lp1 = 0.f;
        float oA[4] = {0,0,0,0}, oB[4] = {0,0,0,0};

        for (int kb = 0; kb < 16; kb++) {
            int kr0 = (kb*16 + g)*12;
            int kr1 = kr0 + 96;
            unsigned kA0 = Kh[kr0 + tig], kA1 = Kh[kr0 + tig + 4];
            unsigned kB0 = Kh[kr1 + tig], kB1 = Kh[kr1 + tig + 4];
            float s0=0.f,s1=0.f,s2=0.f,s3=0.f, s4=0.f,s5=0.f,s6=0.f,s7=0.f;
            mma_f16(s0,s1,s2,s3, qh0,qh1,qh2,qh3, kA0,kA1);
            mma_f16(s4,s5,s6,s7, qh0,qh1,qh2,qh3, kB0,kB1);

            float p0 = exp2f(fminf(s0,14.f)), p1 = exp2f(fminf(s1,14.f));
            float p2 = exp2f(fminf(s2,14.f)), p3 = exp2f(fminf(s3,14.f));
            float p4 = exp2f(fminf(s4,14.f)), p5 = exp2f(fminf(s5,14.f));
            float p6 = exp2f(fminf(s6,14.f)), p7 = exp2f(fminf(s7,14.f));
            lp0 += (p0 + p1) + (p4 + p5);
            lp1 += (p2 + p3) + (p6 + p7);

            unsigned pa0 = h2pk(p0,p1), pa1 = h2pk(p2,p3);
            unsigned pa2 = h2pk(p4,p5), pa3 = h2pk(p6,p7);

            int vb = kb*8 + tig;
            unsigned vA0 = Vh[g*FNKP + vb],       vA1 = Vh[g*FNKP + vb + 4];
            unsigned vB0 = Vh[(g+8)*FNKP + vb],   vB1 = Vh[(g+8)*FNKP + vb + 4];
            mma_f16(oA[0],oA[1],oA[2],oA[3], pa0,pa1,pa2,pa3, vA0,vA1);
            mma_f16(oB[0],oB[1],oB[2],oB[3], pa0,pa1,pa2,pa3, vB0,vB1);
        }
        // tail: key 256 only (keys 257+ masked / zero)
        {
            int kr = (256 + g)*12;
            unsigned kA0 = Kh[kr + tig], kA1 = Kh[kr + tig + 4];
            float s0=0.f,s1=0.f,s2=0.f,s3=0.f;
            mma_f16(s0,s1,s2,s3, qh0,qh1,qh2,qh3, kA0,kA1);
            float p0 = (tig == 0) ? exp2f(fminf(s0,14.f)) : 0.f;
            float p2 = (tig == 0) ? exp2f(fminf(s2,14.f)) : 0.f;
            lp0 += p0; lp1 += p2;
            unsigned pa0 = h2pk(p0, 0.f), pa1 = h2pk(p2, 0.f);
            unsigned vA0 = Vh[g*FNKP + 128 + tig];
            unsigned vB0 = Vh[(g+8)*FNKP + 128 + tig];
            mma_f16(oA[0],oA[1],oA[2],oA[3], pa0,pa1,0u,0u, vA0,0u);
            mma_f16(oB[0],oB[1],oB[2],oB[3], pa0,pa1,0u,0u, vB0,0u);
        }
        lp0 += __shfl_xor_sync(0xffffffffu, lp0, 1);
        lp0 += __shfl_xor_sync(0xffffffffu, lp0, 2);
        lp1 += __shfl_xor_sync(0xffffffffu, lp1, 1);
        lp1 += __shfl_xor_sync(0xffffffffu, lp1, 2);
        float inv0 = 1.f / lp0, inv1 = 1.f / lp1;
        int f0 = tile*16 + g, f1 = f0 + 8;
        if (f0 < FF) {
            float* op = g_fo + ((b*FF + f0)*TT + t)*DC;
            *(float2*)(op + 2*tig)     = make_float2(oA[0]*inv0, oA[1]*inv0);
            *(float2*)(op + 8 + 2*tig) = make_float2(oB[0]*inv0, oB[1]*inv0);
        }
        if (f1 < FF) {
            float* op = g_fo + ((b*FF + f1)*TT + t)*DC;
            *(float2*)(op + 2*tig)     = make_float2(oA[2]*inv1, oA[3]*inv1);
            *(float2*)(op + 8 + 2*tig) = make_float2(oB[2]*inv1, oB[3]*inv1);
        }
    }
}

// ---------------------------------------------------------------------------
// Kernel 3: causal time attention. fp16 MMA, FA2 passthrough, 16 warps x
// 2 tiles {w, 31-w}, two-phase staged fill + proj + residual.
// Kh[key][dcpair] stride 12; Vh[dc][keypair] stride 260.
// ---------------------------------------------------------------------------
#define TNR 512
#define TNKP 260        // 256 pairs padded to 260 (==4 mod 32)

extern __shared__ unsigned smt[];
__global__ __launch_bounds__(512) void asa_tattn(
    const float* __restrict__ inp,
    const float* __restrict__ pw, const float* __restrict__ pb,
    const float* __restrict__ pg, const float* __restrict__ pbe,
    const float* __restrict__ pm, const float* __restrict__ pv,
    const float* __restrict__ pa,
    float* __restrict__ out)
{
    unsigned* Kh  = smt;                         // TNR*12 = 6144 w
    unsigned* Vh  = smt + TNR*12;                // 16*TNKP = 4160 w
    float* pws    = (float*)(Vh + 16*TNKP);      // 1024
    float* psh    = pws + 1024;                  // 64
    float* obuf   = psh + 64;                    // 16*16*17 = 4352
    float* Sst    = obuf + 16*16*17;             // TNR*16 = 8192 w staging
    __shared__ float s_alpha;

    int bf = blockIdx.x;
    int b = bf / FF, f = bf % FF;
    int base = bf * TT * DC;
    int tid = threadIdx.x;

    // ---- phase 1: K ----
    for (int i = tid; i < TNR*4; i += 512) {
        if (i < TT*4) cp16(Sst + i*4, g_kt + base + i*4);
        else *(uint4*)(Sst + i*4) = make_uint4(0,0,0,0);
    }
    for (int i = tid; i < 64*16; i += 512) {
        int o = i >> 4;
        pws[i] = pw[i] * (pg[o] * rsqrtf(pv[o] + BN_EPS));
    }
    if (tid < 64) {
        int o = tid;
        psh[o] = (pb[o] - pm[o]) * (pg[o] * rsqrtf(pv[o] + BN_EPS)) + pbe[o];
    }
    if (tid == 0) s_alpha = pa[0];
    CP_WAIT();
    __syncthreads();
    for (int i = tid; i < TNR*8; i += 512) {
        int key = i >> 3, dp = i & 7;
        float2 v = *(const float2*)(Sst + key*16 + 2*dp);
        Kh[key*12 + dp] = h2pk(v.x, v.y);
    }
    __syncthreads();
    // ---- phase 2: V ----
    for (int i = tid; i < TNR*4; i += 512) {
        if (i < TT*4) cp16(Sst + i*4, g_fo + base + i*4);
        else *(uint4*)(Sst + i*4) = make_uint4(0,0,0,0);
    }
    CP_WAIT();
    __syncthreads();
    for (int i = tid; i < 16*256; i += 512) {
        int dc = i & 15, kp = i >> 4;
        float lo = Sst[(2*kp)*16 + dc];
        float hi = Sst[(2*kp+1)*16 + dc];
        Vh[dc*TNKP + kp] = h2pk(lo, hi);
    }
    __syncthreads();

    int warp = tid >> 5, lane = tid & 31;
    int g = lane >> 2, tig = lane & 3;
    float alpha = s_alpha;
    float* ob = obuf + warp * (16*17);

    int tiles[2] = { warp, 31 - warp };

#pragma unroll
    for (int ti = 0; ti < 2; ti++) {
        int tile = tiles[ti];
        int qt0 = tile * 16;
        int ta = qt0 + g;
        int tb = qt0 + g + 8;
        int tr0 = min(ta, TT-1), tr1 = min(tb, TT-1);
        const float* q0p = g_qt + base + tr0*DC;
        const float* q1p = g_qt + base + tr1*DC;
        float2 xa = *(const float2*)(q0p + 2*tig);
        float2 xb = *(const float2*)(q1p + 2*tig);
        float2 xc = *(const float2*)(q0p + 8 + 2*tig);
        float2 xd = *(const float2*)(q1p + 8 + 2*tig);
        unsigned qh0 = h2pk(xa.x*SCALE2, xa.y*SCALE2);
        unsigned qh1 = h2pk(xb.x*SCALE2, xb.y*SCALE2);
        unsigned qh2 = h2pk(xc.x*SCALE2, xc.y*SCALE2);
        unsigned qh3 = h2pk(xd.x*SCALE2, xd.y*SCALE2);

        float lp0 = 0.f, lp1 = 0.f;
        float oA[4] = {0,0,0,0}, oB[4] = {0,0,0,0};

        for (int kb = 0; kb <= tile; kb++) {
            int kr0 = (kb*16 + g)*12;
            int kr1 = kr0 + 96;
            unsigned kA0 = Kh[kr0 + tig], kA1 = Kh[kr0 + tig + 4];
            unsigned kB0 = Kh[kr1 + tig], kB1 = Kh[kr1 + tig + 4];
            float s0=0.f,s1=0.f,s2=0.f,s3=0.f, s4=0.f,s5=0.f,s6=0.f,s7=0.f;
            mma_f16(s0,s1,s2,s3, qh0,qh1,qh2,qh3, kA0,kA1);
            mma_f16(s4,s5,s6,s7, qh0,qh1,qh2,qh3, kB0,kB1);
            if (kb == tile) {
                int yA0 = kb*16 + 2*tig, yA1 = yA0 + 1;
                int yB0 = yA0 + 8,       yB1 = yA1 + 8;
                if (yA0 > ta) s0 = -3.0e38f;
                if (yA1 > ta) s1 = -3.0e38f;
                if (yA0 > tb) s2 = -3.0e38f;
                if (yA1 > tb) s3 = -3.0e38f;
                if (yB0 > ta) s4 = -3.0e38f;
                if (yB1 > ta) s5 = -3.0e38f;
                if (yB0 > tb) s6 = -3.0e38f;
                if (yB1 > tb) s7 = -3.0e38f;
            }
            float p0 = exp2f(fminf(s0,14.f)), p1 = exp2f(fminf(s1,14.f));
            float p2 = exp2f(fminf(s2,14.f)), p3 = exp2f(fminf(s3,14.f));
            float p4 = exp2f(fminf(s4,14.f)), p5 = exp2f(fminf(s5,14.f));
            float p6 = exp2f(fminf(s6,14.f)), p7 = exp2f(fminf(s7,14.f));
            lp0 += (p0 + p1) + (p4 + p5);
            lp1 += (p2 + p3) + (p6 + p7);

            unsigned pa0 = h2pk(p0,p1), pa1 = h2pk(p2,p3);
            unsigned pa2 = h2pk(p4,p5), pa3 = h2pk(p6,p7);

            int vb = kb*8 + tig;
            unsigned vA0 = Vh[g*TNKP + vb],       vA1 = Vh[g*TNKP + vb + 4];
            unsigned vB0 = Vh[(g+8)*TNKP + vb],   vB1 = Vh[(g+8)*TNKP + vb + 4];
            mma_f16(oA[0],oA[1],oA[2],oA[3], pa0,pa1,pa2,pa3, vA0,vA1);
            mma_f16(oB[0],oB[1],oB[2],oB[3], pa0,pa1,pa2,pa3, vB0,vB1);
        }
        lp0 += __shfl_xor_sync(0xffffffffu, lp0, 1);
        lp0 += __shfl_xor_sync(0xffffffffu, lp0, 2);
        lp1 += __shfl_xor_sync(0xffffffffu, lp1, 1);
        lp1 += __shfl_xor_sync(0xffffffffu, lp1, 2);
        float inv0 = 1.f / lp0, inv1 = 1.f / lp1;
        ob[g*17 + 2*tig]          = oA[0]*inv0;
        ob[g*17 + 2*tig + 1]      = oA[1]*inv0;
        ob[(g+8)*17 + 2*tig]      = oA[2]*inv1;
        ob[(g+8)*17 + 2*tig + 1]  = oA[3]*inv1;
        ob[g*17 + 8 + 2*tig]      = oB[0]*inv0;
        ob[g*17 + 8 + 2*tig + 1]  = oB[1]*inv0;
        ob[(g+8)*17 + 8 + 2*tig]     = oB[2]*inv1;
        ob[(g+8)*17 + 8 + 2*tig + 1] = oB[3]*inv1;
        __syncwarp();

        int qi = lane & 15;
        int t = qt0 + qi;
        if (t < TT) {
            const float* orow = ob + qi*17;
            u64 o2[8];
#pragma unroll
            for (int j = 0; j < 8; j++) o2[j] = pk2(orow[2*j], orow[2*j+1]);
            int c0 = (lane >> 4) * 32;
            int obase = b*CC*FTSZ + f*TT + t;
#pragma unroll 4
            for (int j = 0; j < 32; j++) {
                int co = c0 + j;
                const ulonglong2* wr = (const ulonglong2*)(pws + co*16);
                ulonglong2 wa = wr[0], wb = wr[1], wc = wr[2], wd = wr[3];
                u64 d0 = mul2(wa.x, o2[0]);
                u64 d1 = mul2(wa.y, o2[1]);
                d0 = fma2(wb.x, o2[2], d0);
                d1 = fma2(wb.y, o2[3], d1);
                d0 = fma2(wc.x, o2[4], d0);
                d1 = fma2(wc.y, o2[5], d1);
                d0 = fma2(wd.x, o2[6], d0);
                d1 = fma2(wd.y, o2[7], d1);
                float lo0,hi0,lo1,hi1;
                upk2(d0,lo0,hi0); upk2(d1,lo1,hi1);
                float r = psh[co] + (lo0+hi0) + (lo1+hi1);
                r = r >= 0.f ? r : alpha * r;
                int idx = obase + co*FTSZ;
                out[idx] = r + __ldg(&inp[idx]);
            }
        }
        __syncwarp();
    }
}

// ---------------------------------------------------------------------------
extern "C" void kernel_launch(void* const* d_in, const int* in_sizes, int n_in,
                              void* d_out, int out_size)
{
    const float* inp = (const float*)d_in[0];

    int smc_bytes = (64*PSTR + 64*WSTR + 80 + 2) * (int)sizeof(float);
    cudaFuncSetAttribute(asa_conv, cudaFuncAttributeMaxDynamicSharedMemorySize, smc_bytes);
    asa_conv<<<(NPIX + 127)/128, 256, smc_bytes>>>(
        inp,
        (const float*)d_in[1],  (const float*)d_in[2],  (const float*)d_in[3],
        (const float*)d_in[4],  (const float*)d_in[5],  (const float*)d_in[6],
        (const float*)d_in[7],
        (const float*)d_in[8],  (const float*)d_in[9],  (const float*)d_in[10],
        (const float*)d_in[11], (const float*)d_in[12], (const float*)d_in[13],
        (const float*)d_in[14]);

    int smf_bytes = (FNR*12 + 16*FNKP + FNR*16*2) * 4;
    cudaFuncSetAttribute(asa_fattn, cudaFuncAttributeMaxDynamicSharedMemorySize, smf_bytes);
    asa_fattn<<<BB*TT, 544, smf_bytes>>>();

    int smt_bytes = (TNR*12 + 16*TNKP + 1024 + 64 + 16*16*17 + TNR*16) * 4;
    cudaFuncSetAttribute(asa_tattn, cudaFuncAttributeMaxDynamicSharedMemorySize, smt_bytes);
    asa_tattn<<<BB*FF, 512, smt_bytes>>>(
        inp,
        (const float*)d_in[15], (const float*)d_in[16], (const float*)d_in[17],
        (const float*)d_in[18], (const float*)d_in[19], (const float*)d_in[20],
        (const float*)d_in[21],
        (float*)d_out);
}

// round 15
// speedup vs baseline: 5.0605x; 1.1078x over previous
#include <cuda_runtime.h>

#define BB 2
#define CC 64
#define FF 257
#define TT 500
#define DC 16
#define BN_EPS 1e-5f
#define SCALE2 0.36067376022224085f   /* 0.25 * log2(e) */
#define NPIX (BB*FF*TT)
#define FTSZ (FF*TT)

typedef unsigned long long u64;

__device__ __forceinline__ u64 pk2(float lo, float hi) {
    u64 r; asm("mov.b64 %0, {%1,%2};" : "=l"(r) : "f"(lo), "f"(hi)); return r;
}
__device__ __forceinline__ void upk2(u64 v, float& lo, float& hi) {
    asm("mov.b64 {%0,%1}, %2;" : "=f"(lo), "=f"(hi) : "l"(v));
}
__device__ __forceinline__ u64 fma2(u64 a, u64 b, u64 c) {
    u64 d; asm("fma.rn.f32x2 %0, %1, %2, %3;" : "=l"(d) : "l"(a), "l"(b), "l"(c)); return d;
}
__device__ __forceinline__ u64 mul2(u64 a, u64 b) {
    u64 d; asm("mul.rn.f32x2 %0, %1, %2;" : "=l"(d) : "l"(a), "l"(b)); return d;
}
// pack {lo, hi} into half2 (lo -> low 16 bits)
__device__ __forceinline__ unsigned h2pk(float lo, float hi) {
    unsigned r; asm("cvt.rn.f16x2.f32 %0, %1, %2;" : "=r"(r) : "f"(hi), "f"(lo)); return r;
}
__device__ __forceinline__ void mma_f16(
    float& d0, float& d1, float& d2, float& d3,
    unsigned a0, unsigned a1, unsigned a2, unsigned a3,
    unsigned b0, unsigned b1)
{
    asm("mma.sync.aligned.m16n8k16.row.col.f32.f16.f16.f32 "
        "{%0,%1,%2,%3},{%4,%5,%6,%7},{%8,%9},{%0,%1,%2,%3};"
        : "+f"(d0), "+f"(d1), "+f"(d2), "+f"(d3)
        : "r"(a0), "r"(a1), "r"(a2), "r"(a3), "r"(b0), "r"(b1));
}
__device__ __forceinline__ void cp16(void* dst, const void* src) {
    unsigned d = (unsigned)__cvta_generic_to_shared(dst);
    asm volatile("cp.async.ca.shared.global [%0], [%1], 16;" :: "r"(d), "l"(src));
}
#define CP_WAIT() asm volatile("cp.async.commit_group;\ncp.async.wait_group 0;" ::: "memory")

// Scratch (device globals; no allocation allowed)
__device__ float g_qf[BB*TT*FF*DC];   // [b][t][f][c]
__device__ float g_kf[BB*TT*FF*DC];   // [b][t][f][c]
__device__ float g_vv[BB*TT*FF*DC];   // [b][t][f][c]
__device__ float g_qt[BB*FF*TT*DC];   // [b][f][t][c]
__device__ float g_kt[BB*FF*TT*DC];   // [b][f][t][c]
__device__ float g_fo[BB*FF*TT*DC];   // [b][f][t][c]

// ---------------------------------------------------------------------------
// Kernel 1: fused 1x1 convs via fp16 MMA (m16n8k16).
// X fp32 smem [64][132]; W half2 [32 chpair][88 op]; A packed in-register.
// ---------------------------------------------------------------------------
#define PSTR 132
#define WSTR 88

extern __shared__ float smc[];
__global__ __launch_bounds__(256) void asa_conv(
    const float* __restrict__ inp,
    const float* __restrict__ fw, const float* __restrict__ fb,
    const float* __restrict__ fg, const float* __restrict__ fbe,
    const float* __restrict__ fm, const float* __restrict__ fv,
    const float* __restrict__ fa,
    const float* __restrict__ tw, const float* __restrict__ tb,
    const float* __restrict__ tg, const float* __restrict__ tbe,
    const float* __restrict__ tm, const float* __restrict__ tv,
    const float* __restrict__ ta)
{
    float* xs = smc;                             // [64][PSTR] fp32
    unsigned* Wh = (unsigned*)(smc + 64*PSTR);   // [32][WSTR] half2 (ch pairs)
    float* sh = (float*)(Wh + 32*WSTR);          // [80]
    float* al = sh + 80;                         // [2]

    int tid = threadIdx.x;

    // weights: fold BN scale, pack channel pairs to half2. op = e*16 + cc.
    for (int idx = tid; idx < 80*32; idx += 256) {
        int cp = idx & 31, op = idx >> 5;
        int e = op >> 4, cc = op & 15;
        float w0, w1, g, vv;
        if (e < 3) { int o = 3*cc + e;      w0 = fw[o*64+2*cp]; w1 = fw[o*64+2*cp+1]; g = fg[o]; vv = fv[o]; }
        else       { int o2 = 2*cc + (e-3); w0 = tw[o2*64+2*cp]; w1 = tw[o2*64+2*cp+1]; g = tg[o2]; vv = tv[o2]; }
        float s = g * rsqrtf(vv + BN_EPS);
        Wh[cp*WSTR + op] = h2pk(w0*s, w1*s);
    }
    if (tid < 80) {
        int op = tid, e = op >> 4, cc = op & 15;
        float g, vv, m, b, be;
        if (e < 3) { int o = 3*cc + e;      g=fg[o]; vv=fv[o]; m=fm[o]; b=fb[o]; be=fbe[o]; }
        else       { int o2 = 2*cc + (e-3); g=tg[o2]; vv=tv[o2]; m=tm[o2]; b=tb[o2]; be=tbe[o2]; }
        sh[op] = (b - m) * (g * rsqrtf(vv + BN_EPS)) + be;
    }
    if (tid == 0) { al[0] = fa[0]; al[1] = ta[0]; }

    int p0 = blockIdx.x * 128;
    int b0 = p0 / FTSZ;
    int bend = (p0 + 127) / FTSZ;
    if (b0 == bend && p0 + 127 < NPIX) {
        int ft0 = p0 - b0*FTSZ;
        const float* src = inp + b0*CC*FTSZ + ft0;
        for (int i = tid; i < 64*32; i += 256) {
            int c = i >> 5, l4 = i & 31;
            cp16(xs + c*PSTR + l4*4, src + c*FTSZ + l4*4);
        }
        CP_WAIT();
    } else {
        for (int i = tid; i < 64*128; i += 256) {
            int c = i >> 7, lp = i & 127;
            int p = p0 + lp;
            float v = 0.f;
            if (p < NPIX) {
                int b = p / FTSZ;
                int ft = p - b*FTSZ;
                v = inp[(b*CC + c)*FTSZ + ft];
            }
            xs[c*PSTR + lp] = v;
        }
    }
    __syncthreads();

    int warp = tid >> 5, lane = tid & 31;
    int g = lane >> 2, tig = lane & 3;
    int px0 = warp*16;
    int pxA = px0 + g, pxB = px0 + g + 8;

    float acc[10][4];
#pragma unroll
    for (int nt = 0; nt < 10; nt++)
#pragma unroll
        for (int j = 0; j < 4; j++) acc[nt][j] = 0.f;

#pragma unroll
    for (int k = 0; k < 4; k++) {
        int ch0 = 16*k + 2*tig;
        const float* r0 = xs + ch0*PSTR;
        const float* r1 = r0 + PSTR;
        const float* r2 = r0 + 8*PSTR;
        const float* r3 = r0 + 9*PSTR;
        unsigned a0 = h2pk(r0[pxA], r1[pxA]);
        unsigned a1 = h2pk(r0[pxB], r1[pxB]);
        unsigned a2 = h2pk(r2[pxA], r3[pxA]);
        unsigned a3 = h2pk(r2[pxB], r3[pxB]);
        int kp0 = (8*k + tig)*WSTR + g, kp1 = kp0 + 4*WSTR;
#pragma unroll
        for (int nt = 0; nt < 10; nt++) {
            unsigned bb0 = Wh[kp0 + nt*8];
            unsigned bb1 = Wh[kp1 + nt*8];
            mma_f16(acc[nt][0], acc[nt][1], acc[nt][2], acc[nt][3],
                    a0, a1, a2, a3, bb0, bb1);
        }
    }

    float sh0[10], sh1[10];
#pragma unroll
    for (int nt = 0; nt < 10; nt++) {
        sh0[nt] = sh[nt*8 + 2*tig];
        sh1[nt] = sh[nt*8 + 2*tig + 1];
    }
    float a0v = al[0], a1v = al[1];

#pragma unroll
    for (int r = 0; r < 2; r++) {
        int px  = px0 + g + r*8;
        int off = r * 2;
        int p = p0 + px;
        if (p >= NPIX) continue;
        int b = p / FTSZ;
        int ft = p - b*FTSZ;
        int f = ft / TT;
        int t = ft - f*TT;
        int fidx = ((b*TT + t)*FF + f)*DC;
        int tidx = ((b*FF + f)*TT + t)*DC;
        float* dsts[5];
        dsts[0] = g_qf + fidx;
        dsts[1] = g_kf + fidx;
        dsts[2] = g_vv + fidx;
        dsts[3] = g_qt + tidx;
        dsts[4] = g_kt + tidx;
#pragma unroll
        for (int nt = 0; nt < 10; nt++) {
            int e = nt >> 1;
            float alpha = (e < 3) ? a0v : a1v;
            float v0 = acc[nt][off]     + sh0[nt];
            float v1 = acc[nt][off + 1] + sh1[nt];
            v0 = v0 >= 0.f ? v0 : alpha * v0;
            v1 = v1 >= 0.f ? v1 : alpha * v1;
            *(float2*)(dsts[e] + (nt & 1)*8 + 2*tig) = make_float2(v0, v1);
        }
    }
}

// ---------------------------------------------------------------------------
// Kernel 2: frequency attention. fp16 m16n8k16 MMA, FA2 P passthrough,
// no online max (clamped exp2), 17 warps x 1 tile. (unchanged from R14)
// ---------------------------------------------------------------------------
#define FNR 264
#define FNKP 132

extern __shared__ unsigned smf[];
__global__ __launch_bounds__(544) void asa_fattn()
{
    unsigned* Kh = smf;                      // FNR*12
    unsigned* Vh = smf + FNR*12;             // 16*FNKP
    float* Kst = (float*)(Vh + 16*FNKP);     // FNR*16
    float* Vst = Kst + FNR*16;               // FNR*16

    int bt = blockIdx.x;
    int b = bt / TT, t = bt % TT;
    int base = (b*TT + t)*FF*DC;
    int tid = threadIdx.x;

    for (int i = tid; i < FNR*4; i += 544) {
        if (i < FF*4) {
            cp16(Kst + i*4, g_kf + base + i*4);
            cp16(Vst + i*4, g_vv + base + i*4);
        } else {
            uint4 z = make_uint4(0,0,0,0);
            *(uint4*)(Kst + i*4) = z;
            *(uint4*)(Vst + i*4) = z;
        }
    }
    CP_WAIT();
    __syncthreads();
    for (int i = tid; i < FNR*8; i += 544) {
        int key = i >> 3, dp = i & 7;
        float2 v = *(const float2*)(Kst + key*16 + 2*dp);
        Kh[key*12 + dp] = h2pk(v.x, v.y);
    }
    for (int i = tid; i < 16*FNKP; i += 544) {
        int dc = i & 15, kp = i >> 4;
        float lo = Vst[(2*kp)*16 + dc];
        float hi = Vst[(2*kp+1)*16 + dc];
        Vh[dc*FNKP + kp] = h2pk(lo, hi);
    }
    __syncthreads();

    int warp = tid >> 5, lane = tid & 31;
    int g = lane >> 2, tig = lane & 3;

    {
        int tile = warp;
        int fr0 = min(tile*16 + g, FF-1);
        int fr1 = min(tile*16 + g + 8, FF-1);
        const float* q0p = g_qf + base + fr0*DC;
        const float* q1p = g_qf + base + fr1*DC;
        float2 xa = *(const float2*)(q0p + 2*tig);
        float2 xb = *(const float2*)(q1p + 2*tig);
        float2 xc = *(const float2*)(q0p + 8 + 2*tig);
        float2 xd = *(const float2*)(q1p + 8 + 2*tig);
        unsigned qh0 = h2pk(xa.x*SCALE2, xa.y*SCALE2);
        unsigned qh1 = h2pk(xb.x*SCALE2, xb.y*SCALE2);
        unsigned qh2 = h2pk(xc.x*SCALE2, xc.y*SCALE2);
        unsigned qh3 = h2pk(xd.x*SCALE2, xd.y*SCALE2);

        float lp0 = 0.f, lp1 = 0.f;
        float oA[4] = {0,0,0,0}, oB[4] = {0,0,0,0};

        for (int kb = 0; kb < 16; kb++) {
            int kr0 = (kb*16 + g)*12;
            int kr1 = kr0 + 96;
            unsigned kA0 = Kh[kr0 + tig], kA1 = Kh[kr0 + tig + 4];
            unsigned kB0 = Kh[kr1 + tig], kB1 = Kh[kr1 + tig + 4];
            float s0=0.f,s1=0.f,s2=0.f,s3=0.f, s4=0.f,s5=0.f,s6=0.f,s7=0.f;
            mma_f16(s0,s1,s2,s3, qh0,qh1,qh2,qh3, kA0,kA1);
            mma_f16(s4,s5,s6,s7, qh0,qh1,qh2,qh3, kB0,kB1);

            float p0 = exp2f(fminf(s0,14.f)), p1 = exp2f(fminf(s1,14.f));
            float p2 = exp2f(fminf(s2,14.f)), p3 = exp2f(fminf(s3,14.f));
            float p4 = exp2f(fminf(s4,14.f)), p5 = exp2f(fminf(s5,14.f));
            float p6 = exp2f(fminf(s6,14.f)), p7 = exp2f(fminf(s7,14.f));
            lp0 += (p0 + p1) + (p4 + p5);
            lp1 += (p2 + p3) + (p6 + p7);

            unsigned pa0 = h2pk(p0,p1), pa1 = h2pk(p2,p3);
            unsigned pa2 = h2pk(p4,p5), pa3 = h2pk(p6,p7);

            int vb = kb*8 + tig;
            unsigned vA0 = Vh[g*FNKP + vb],       vA1 = Vh[g*FNKP + vb + 4];
            unsigned vB0 = Vh[(g+8)*FNKP + vb],   vB1 = Vh[(g+8)*FNKP + vb + 4];
            mma_f16(oA[0],oA[1],oA[2],oA[3], pa0,pa1,pa2,pa3, vA0,vA1);
            mma_f16(oB[0],oB[1],oB[2],oB[3], pa0,pa1,pa2,pa3, vB0,vB1);
        }
        {
            int kr = (256 + g)*12;
            unsigned kA0 = Kh[kr + tig], kA1 = Kh[kr + tig + 4];
            float s0=0.f,s1=0.f,s2=0.f,s3=0.f;
            mma_f16(s0,s1,s2,s3, qh0,qh1,qh2,qh3, kA0,kA1);
            float p0 = (tig == 0) ? exp2f(fminf(s0,14.f)) : 0.f;
            float p2 = (tig == 0) ? exp2f(fminf(s2,14.f)) : 0.f;
            lp0 += p0; lp1 += p2;
            unsigned pa0 = h2pk(p0, 0.f), pa1 = h2pk(p2, 0.f);
            unsigned vA0 = Vh[g*FNKP + 128 + tig];
            unsigned vB0 = Vh[(g+8)*FNKP + 128 + tig];
            mma_f16(oA[0],oA[1],oA[2],oA[3], pa0,pa1,0u,0u, vA0,0u);
            mma_f16(oB[0],oB[1],oB[2],oB[3], pa0,pa1,0u,0u, vB0,0u);
        }
        lp0 += __shfl_xor_sync(0xffffffffu, lp0, 1);
        lp0 += __shfl_xor_sync(0xffffffffu, lp0, 2);
        lp1 += __shfl_xor_sync(0xffffffffu, lp1, 1);
        lp1 += __shfl_xor_sync(0xffffffffu, lp1, 2);
        float inv0 = 1.f / lp0, inv1 = 1.f / lp1;
        int f0 = tile*16 + g, f1 = f0 + 8;
        if (f0 < FF) {
            float* op = g_fo + ((b*FF + f0)*TT + t)*DC;
            *(float2*)(op + 2*tig)     = make_float2(oA[0]*inv0, oA[1]*inv0);
            *(float2*)(op + 8 + 2*tig) = make_float2(oB[0]*inv0, oB[1]*inv0);
        }
        if (f1 < FF) {
            float* op = g_fo + ((b*FF + f1)*TT + t)*DC;
            *(float2*)(op + 2*tig)     = make_float2(oA[2]*inv1, oA[3]*inv1);
            *(float2*)(op + 8 + 2*tig) = make_float2(oB[2]*inv1, oB[3]*inv1);
        }
    }
}

// ---------------------------------------------------------------------------
// Kernel 3: causal time attention. fp16 MMA, FA2 passthrough, 16 warps x
// 2 tiles {w, 31-w}, two-phase staged fill + proj + residual. (unchanged)
// ---------------------------------------------------------------------------
#define TNR 512
#define TNKP 260

extern __shared__ unsigned smt[];
__global__ __launch_bounds__(512) void asa_tattn(
    const float* __restrict__ inp,
    const float* __restrict__ pw, const float* __restrict__ pb,
    const float* __restrict__ pg, const float* __restrict__ pbe,
    const float* __restrict__ pm, const float* __restrict__ pv,
    const float* __restrict__ pa,
    float* __restrict__ out)
{
    unsigned* Kh  = smt;
    unsigned* Vh  = smt + TNR*12;
    float* pws    = (float*)(Vh + 16*TNKP);
    float* psh    = pws + 1024;
    float* obuf   = psh + 64;
    float* Sst    = obuf + 16*16*17;
    __shared__ float s_alpha;

    int bf = blockIdx.x;
    int b = bf / FF, f = bf % FF;
    int base = bf * TT * DC;
    int tid = threadIdx.x;

    for (int i = tid; i < TNR*4; i += 512) {
        if (i < TT*4) cp16(Sst + i*4, g_kt + base + i*4);
        else *(uint4*)(Sst + i*4) = make_uint4(0,0,0,0);
    }
    for (int i = tid; i < 64*16; i += 512) {
        int o = i >> 4;
        pws[i] = pw[i] * (pg[o] * rsqrtf(pv[o] + BN_EPS));
    }
    if (tid < 64) {
        int o = tid;
        psh[o] = (pb[o] - pm[o]) * (pg[o] * rsqrtf(pv[o] + BN_EPS)) + pbe[o];
    }
    if (tid == 0) s_alpha = pa[0];
    CP_WAIT();
    __syncthreads();
    for (int i = tid; i < TNR*8; i += 512) {
        int key = i >> 3, dp = i & 7;
        float2 v = *(const float2*)(Sst + key*16 + 2*dp);
        Kh[key*12 + dp] = h2pk(v.x, v.y);
    }
    __syncthreads();
    for (int i = tid; i < TNR*4; i += 512) {
        if (i < TT*4) cp16(Sst + i*4, g_fo + base + i*4);
        else *(uint4*)(Sst + i*4) = make_uint4(0,0,0,0);
    }
    CP_WAIT();
    __syncthreads();
    for (int i = tid; i < 16*256; i += 512) {
        int dc = i & 15, kp = i >> 4;
        float lo = Sst[(2*kp)*16 + dc];
        float hi = Sst[(2*kp+1)*16 + dc];
        Vh[dc*TNKP + kp] = h2pk(lo, hi);
    }
    __syncthreads();

    int warp = tid >> 5, lane = tid & 31;
    int g = lane >> 2, tig = lane & 3;
    float alpha = s_alpha;
    float* ob = obuf + warp * (16*17);

    int tiles[2] = { warp, 31 - warp };

#pragma unroll
    for (int ti = 0; ti < 2; ti++) {
        int tile = tiles[ti];
        int qt0 = tile * 16;
        int ta = qt0 + g;
        int tb = qt0 + g + 8;
        int tr0 = min(ta, TT-1), tr1 = min(tb, TT-1);
        const float* q0p = g_qt + base + tr0*DC;
        const float* q1p = g_qt + base + tr1*DC;
        float2 xa = *(const float2*)(q0p + 2*tig);
        float2 xb = *(const float2*)(q1p + 2*tig);
        float2 xc = *(const float2*)(q0p + 8 + 2*tig);
        float2 xd = *(const float2*)(q1p + 8 + 2*tig);
        unsigned qh0 = h2pk(xa.x*SCALE2, xa.y*SCALE2);
        unsigned qh1 = h2pk(xb.x*SCALE2, xb.y*SCALE2);
        unsigned qh2 = h2pk(xc.x*SCALE2, xc.y*SCALE2);
        unsigned qh3 = h2pk(xd.x*SCALE2, xd.y*SCALE2);

        float lp0 = 0.f, lp1 = 0.f;
        float oA[4] = {0,0,0,0}, oB[4] = {0,0,0,0};

        for (int kb = 0; kb <= tile; kb++) {
            int kr0 = (kb*16 + g)*12;
            int kr1 = kr0 + 96;
            unsigned kA0 = Kh[kr0 + tig], kA1 = Kh[kr0 + tig + 4];
            unsigned kB0 = Kh[kr1 + tig], kB1 = Kh[kr1 + tig + 4];
            float s0=0.f,s1=0.f,s2=0.f,s3=0.f, s4=0.f,s5=0.f,s6=0.f,s7=0.f;
            mma_f16(s0,s1,s2,s3, qh0,qh1,qh2,qh3, kA0,kA1);
            mma_f16(s4,s5,s6,s7, qh0,qh1,qh2,qh3, kB0,kB1);
            if (kb == tile) {
                int yA0 = kb*16 + 2*tig, yA1 = yA0 + 1;
                int yB0 = yA0 + 8,       yB1 = yA1 + 8;
                if (yA0 > ta) s0 = -3.0e38f;
                if (yA1 > ta) s1 = -3.0e38f;
                if (yA0 > tb) s2 = -3.0e38f;
                if (yA1 > tb) s3 = -3.0e38f;
                if (yB0 > ta) s4 = -3.0e38f;
                if (yB1 > ta) s5 = -3.0e38f;
                if (yB0 > tb) s6 = -3.0e38f;
                if (yB1 > tb) s7 = -3.0e38f;
            }
            float p0 = exp2f(fminf(s0,14.f)), p1 = exp2f(fminf(s1,14.f));
            float p2 = exp2f(fminf(s2,14.f)), p3 = exp2f(fminf(s3,14.f));
            float p4 = exp2f(fminf(s4,14.f)), p5 = exp2f(fminf(s5,14.f));
            float p6 = exp2f(fminf(s6,14.f)), p7 = exp2f(fminf(s7,14.f));
            lp0 += (p0 + p1) + (p4 + p5);
            lp1 += (p2 + p3) + (p6 + p7);

            unsigned pa0 = h2pk(p0,p1), pa1 = h2pk(p2,p3);
            unsigned pa2 = h2pk(p4,p5), pa3 = h2pk(p6,p7);

            int vb = kb*8 + tig;
            unsigned vA0 = Vh[g*TNKP + vb],       vA1 = Vh[g*TNKP + vb + 4];
            unsigned vB0 = Vh[(g+8)*TNKP + vb],   vB1 = Vh[(g+8)*TNKP + vb + 4];
            mma_f16(oA[0],oA[1],oA[2],oA[3], pa0,pa1,pa2,pa3, vA0,vA1);
            mma_f16(oB[0],oB[1],oB[2],oB[3], pa0,pa1,pa2,pa3, vB0,vB1);
        }
        lp0 += __shfl_xor_sync(0xffffffffu, lp0, 1);
        lp0 += __shfl_xor_sync(0xffffffffu, lp0, 2);
        lp1 += __shfl_xor_sync(0xffffffffu, lp1, 1);
        lp1 += __shfl_xor_sync(0xffffffffu, lp1, 2);
        float inv0 = 1.f / lp0, inv1 = 1.f / lp1;
        ob[g*17 + 2*tig]          = oA[0]*inv0;
        ob[g*17 + 2*tig + 1]      = oA[1]*inv0;
        ob[(g+8)*17 + 2*tig]      = oA[2]*inv1;
        ob[(g+8)*17 + 2*tig + 1]  = oA[3]*inv1;
        ob[g*17 + 8 + 2*tig]      = oB[0]*inv0;
        ob[g*17 + 8 + 2*tig + 1]  = oB[1]*inv0;
        ob[(g+8)*17 + 8 + 2*tig]     = oB[2]*inv1;
        ob[(g+8)*17 + 8 + 2*tig + 1] = oB[3]*inv1;
        __syncwarp();

        int qi = lane & 15;
        int t = qt0 + qi;
        if (t < TT) {
            const float* orow = ob + qi*17;
            u64 o2[8];
#pragma unroll
            for (int j = 0; j < 8; j++) o2[j] = pk2(orow[2*j], orow[2*j+1]);
            int c0 = (lane >> 4) * 32;
            int obase = b*CC*FTSZ + f*TT + t;
#pragma unroll 4
            for (int j = 0; j < 32; j++) {
                int co = c0 + j;
                const ulonglong2* wr = (const ulonglong2*)(pws + co*16);
                ulonglong2 wa = wr[0], wb = wr[1], wc = wr[2], wd = wr[3];
                u64 d0 = mul2(wa.x, o2[0]);
                u64 d1 = mul2(wa.y, o2[1]);
                d0 = fma2(wb.x, o2[2], d0);
                d1 = fma2(wb.y, o2[3], d1);
                d0 = fma2(wc.x, o2[4], d0);
                d1 = fma2(wc.y, o2[5], d1);
                d0 = fma2(wd.x, o2[6], d0);
                d1 = fma2(wd.y, o2[7], d1);
                float lo0,hi0,lo1,hi1;
                upk2(d0,lo0,hi0); upk2(d1,lo1,hi1);
                float r = psh[co] + (lo0+hi0) + (lo1+hi1);
                r = r >= 0.f ? r : alpha * r;
                int idx = obase + co*FTSZ;
                out[idx] = r + __ldg(&inp[idx]);
            }
        }
        __syncwarp();
    }
}

// ---------------------------------------------------------------------------
extern "C" void kernel_launch(void* const* d_in, const int* in_sizes, int n_in,
                              void* d_out, int out_size)
{
    const float* inp = (const float*)d_in[0];

    int smc_bytes = (64*PSTR + 32*WSTR + 80 + 2) * (int)sizeof(float);
    cudaFuncSetAttribute(asa_conv, cudaFuncAttributeMaxDynamicSharedMemorySize, smc_bytes);
    asa_conv<<<(NPIX + 127)/128, 256, smc_bytes>>>(
        inp,
        (const float*)d_in[1],  (const float*)d_in[2],  (const float*)d_in[3],
        (const float*)d_in[4],  (const float*)d_in[5],  (const float*)d_in[6],
        (const float*)d_in[7],
        (const float*)d_in[8],  (const float*)d_in[9],  (const float*)d_in[10],
        (const float*)d_in[11], (const float*)d_in[12], (const float*)d_in[13],
        (const float*)d_in[14]);

    int smf_bytes = (FNR*12 + 16*FNKP + FNR*16*2) * 4;
    cudaFuncSetAttribute(asa_fattn, cudaFuncAttributeMaxDynamicSharedMemorySize, smf_bytes);
    asa_fattn<<<BB*TT, 544, smf_bytes>>>();

    int smt_bytes = (TNR*12 + 16*TNKP + 1024 + 64 + 16*16*17 + TNR*16) * 4;
    cudaFuncSetAttribute(asa_tattn, cudaFuncAttributeMaxDynamicSharedMemorySize, smt_bytes);
    asa_tattn<<<BB*FF, 512, smt_bytes>>>(
        inp,
        (const float*)d_in[15], (const float*)d_in[16], (const float*)d_in[17],
        (const float*)d_in[18], (const float*)d_in[19], (const float*)d_in[20],
        (const float*)d_in[21],
        (float*)d_out);
}

// round 16
// speedup vs baseline: 5.4759x; 1.0821x over previous
#include <cuda_runtime.h>
#include <cuda_fp16.h>

#define BB 2
#define CC 64
#define FF 257
#define TT 500
#define DC 16
#define BN_EPS 1e-5f
#define SCALE2 0.36067376022224085f   /* 0.25 * log2(e) */
#define NPIX (BB*FF*TT)
#define FTSZ (FF*TT)

typedef unsigned long long u64;

__device__ __forceinline__ u64 pk2(float lo, float hi) {
    u64 r; asm("mov.b64 %0, {%1,%2};" : "=l"(r) : "f"(lo), "f"(hi)); return r;
}
__device__ __forceinline__ void upk2(u64 v, float& lo, float& hi) {
    asm("mov.b64 {%0,%1}, %2;" : "=f"(lo), "=f"(hi) : "l"(v));
}
__device__ __forceinline__ u64 fma2(u64 a, u64 b, u64 c) {
    u64 d; asm("fma.rn.f32x2 %0, %1, %2, %3;" : "=l"(d) : "l"(a), "l"(b), "l"(c)); return d;
}
__device__ __forceinline__ u64 mul2(u64 a, u64 b) {
    u64 d; asm("mul.rn.f32x2 %0, %1, %2;" : "=l"(d) : "l"(a), "l"(b)); return d;
}
// pack {lo, hi} into half2 (lo -> low 16 bits)
__device__ __forceinline__ unsigned h2pk(float lo, float hi) {
    unsigned r; asm("cvt.rn.f16x2.f32 %0, %1, %2;" : "=r"(r) : "f"(hi), "f"(lo)); return r;
}
// unpack half2, scale in fp32, repack
__device__ __forceinline__ unsigned h2scale(unsigned h, float s) {
    __half2 v = *(__half2*)&h;
    float2 f = __half22float2(v);
    return h2pk(f.x*s, f.y*s);
}
__device__ __forceinline__ void mma_f16(
    float& d0, float& d1, float& d2, float& d3,
    unsigned a0, unsigned a1, unsigned a2, unsigned a3,
    unsigned b0, unsigned b1)
{
    asm("mma.sync.aligned.m16n8k16.row.col.f32.f16.f16.f32 "
        "{%0,%1,%2,%3},{%4,%5,%6,%7},{%8,%9},{%0,%1,%2,%3};"
        : "+f"(d0), "+f"(d1), "+f"(d2), "+f"(d3)
        : "r"(a0), "r"(a1), "r"(a2), "r"(a3), "r"(b0), "r"(b1));
}
__device__ __forceinline__ void cp16(void* dst, const void* src) {
    unsigned d = (unsigned)__cvta_generic_to_shared(dst);
    asm volatile("cp.async.ca.shared.global [%0], [%1], 16;" :: "r"(d), "l"(src));
}
#define CP_WAIT() asm volatile("cp.async.commit_group;\ncp.async.wait_group 0;" ::: "memory")

// Scratch (device globals; no allocation allowed). All half2-packed: 8 words/px.
__device__ __align__(16) unsigned gh_qf[BB*TT*FF*8];   // [b][t][f][8]
__device__ __align__(16) unsigned gh_kf[BB*TT*FF*8];
__device__ __align__(16) unsigned gh_vv[BB*TT*FF*8];
__device__ __align__(16) unsigned gh_qt[BB*FF*TT*8];   // [b][f][t][8]
__device__ __align__(16) unsigned gh_kt[BB*FF*TT*8];
__device__ __align__(16) unsigned gh_fo[BB*FF*TT*8];

// ---------------------------------------------------------------------------
// Kernel 1: fused 1x1 convs via fp16 MMA, half2 outputs.
// ---------------------------------------------------------------------------
#define PSTR 132
#define WSTR 88

extern __shared__ float smc[];
__global__ __launch_bounds__(256) void asa_conv(
    const float* __restrict__ inp,
    const float* __restrict__ fw, const float* __restrict__ fb,
    const float* __restrict__ fg, const float* __restrict__ fbe,
    const float* __restrict__ fm, const float* __restrict__ fv,
    const float* __restrict__ fa,
    const float* __restrict__ tw, const float* __restrict__ tb,
    const float* __restrict__ tg, const float* __restrict__ tbe,
    const float* __restrict__ tm, const float* __restrict__ tv,
    const float* __restrict__ ta)
{
    float* xs = smc;                             // [64][PSTR] fp32
    unsigned* Wh = (unsigned*)(smc + 64*PSTR);   // [32][WSTR] half2 (ch pairs)
    float* sh = (float*)(Wh + 32*WSTR);          // [80]
    float* al = sh + 80;                         // [2]

    int tid = threadIdx.x;

    for (int idx = tid; idx < 80*32; idx += 256) {
        int cp = idx & 31, op = idx >> 5;
        int e = op >> 4, cc = op & 15;
        float w0, w1, g, vv;
        if (e < 3) { int o = 3*cc + e;      w0 = fw[o*64+2*cp]; w1 = fw[o*64+2*cp+1]; g = fg[o]; vv = fv[o]; }
        else       { int o2 = 2*cc + (e-3); w0 = tw[o2*64+2*cp]; w1 = tw[o2*64+2*cp+1]; g = tg[o2]; vv = tv[o2]; }
        float s = g * rsqrtf(vv + BN_EPS);
        Wh[cp*WSTR + op] = h2pk(w0*s, w1*s);
    }
    if (tid < 80) {
        int op = tid, e = op >> 4, cc = op & 15;
        float g, vv, m, b, be;
        if (e < 3) { int o = 3*cc + e;      g=fg[o]; vv=fv[o]; m=fm[o]; b=fb[o]; be=fbe[o]; }
        else       { int o2 = 2*cc + (e-3); g=tg[o2]; vv=tv[o2]; m=tm[o2]; b=tb[o2]; be=tbe[o2]; }
        sh[op] = (b - m) * (g * rsqrtf(vv + BN_EPS)) + be;
    }
    if (tid == 0) { al[0] = fa[0]; al[1] = ta[0]; }

    int p0 = blockIdx.x * 128;
    int b0 = p0 / FTSZ;
    int bend = (p0 + 127) / FTSZ;
    if (b0 == bend && p0 + 127 < NPIX) {
        int ft0 = p0 - b0*FTSZ;
        const float* src = inp + b0*CC*FTSZ + ft0;
        for (int i = tid; i < 64*32; i += 256) {
            int c = i >> 5, l4 = i & 31;
            cp16(xs + c*PSTR + l4*4, src + c*FTSZ + l4*4);
        }
        CP_WAIT();
    } else {
        for (int i = tid; i < 64*128; i += 256) {
            int c = i >> 7, lp = i & 127;
            int p = p0 + lp;
            float v = 0.f;
            if (p < NPIX) {
                int b = p / FTSZ;
                int ft = p - b*FTSZ;
                v = inp[(b*CC + c)*FTSZ + ft];
            }
            xs[c*PSTR + lp] = v;
        }
    }
    __syncthreads();

    int warp = tid >> 5, lane = tid & 31;
    int g = lane >> 2, tig = lane & 3;
    int px0 = warp*16;
    int pxA = px0 + g, pxB = px0 + g + 8;

    float acc[10][4];
#pragma unroll
    for (int nt = 0; nt < 10; nt++)
#pragma unroll
        for (int j = 0; j < 4; j++) acc[nt][j] = 0.f;

#pragma unroll
    for (int k = 0; k < 4; k++) {
        int ch0 = 16*k + 2*tig;
        const float* r0 = xs + ch0*PSTR;
        const float* r1 = r0 + PSTR;
        const float* r2 = r0 + 8*PSTR;
        const float* r3 = r0 + 9*PSTR;
        unsigned a0 = h2pk(r0[pxA], r1[pxA]);
        unsigned a1 = h2pk(r0[pxB], r1[pxB]);
        unsigned a2 = h2pk(r2[pxA], r3[pxA]);
        unsigned a3 = h2pk(r2[pxB], r3[pxB]);
        int kp0 = (8*k + tig)*WSTR + g, kp1 = kp0 + 4*WSTR;
#pragma unroll
        for (int nt = 0; nt < 10; nt++) {
            unsigned bb0 = Wh[kp0 + nt*8];
            unsigned bb1 = Wh[kp1 + nt*8];
            mma_f16(acc[nt][0], acc[nt][1], acc[nt][2], acc[nt][3],
                    a0, a1, a2, a3, bb0, bb1);
        }
    }

    float sh0[10], sh1[10];
#pragma unroll
    for (int nt = 0; nt < 10; nt++) {
        sh0[nt] = sh[nt*8 + 2*tig];
        sh1[nt] = sh[nt*8 + 2*tig + 1];
    }
    float a0v = al[0], a1v = al[1];

#pragma unroll
    for (int r = 0; r < 2; r++) {
        int px  = px0 + g + r*8;
        int off = r * 2;
        int p = p0 + px;
        if (p >= NPIX) continue;
        int b = p / FTSZ;
        int ft = p - b*FTSZ;
        int f = ft / TT;
        int t = ft - f*TT;
        int fidx = ((b*TT + t)*FF + f)*8;
        int tidx = ((b*FF + f)*TT + t)*8;
        unsigned* dsts[5];
        dsts[0] = gh_qf + fidx;
        dsts[1] = gh_kf + fidx;
        dsts[2] = gh_vv + fidx;
        dsts[3] = gh_qt + tidx;
        dsts[4] = gh_kt + tidx;
#pragma unroll
        for (int nt = 0; nt < 10; nt++) {
            int e = nt >> 1;
            float alpha = (e < 3) ? a0v : a1v;
            float v0 = acc[nt][off]     + sh0[nt];
            float v1 = acc[nt][off + 1] + sh1[nt];
            v0 = v0 >= 0.f ? v0 : alpha * v0;
            v1 = v1 >= 0.f ? v1 : alpha * v1;
            dsts[e][(nt & 1)*4 + tig] = h2pk(v0, v1);
        }
    }
}

// ---------------------------------------------------------------------------
// Kernel 2: frequency attention. fp16 MMA, direct half K fill, half V stage.
// ---------------------------------------------------------------------------
#define FNR 264
#define FNKP 132

extern __shared__ unsigned smf[];
__global__ __launch_bounds__(544) void asa_fattn()
{
    unsigned* Kh  = smf;                     // FNR*12
    unsigned* Vh  = smf + FNR*12;            // 16*FNKP
    unsigned* Vst = Vh + 16*FNKP;            // FNR*8 (half rows)

    int bt = blockIdx.x;
    int b = bt / TT, t = bt % TT;
    int base8 = (b*TT + t)*FF*8;
    int tid = threadIdx.x;

    for (int i = tid; i < FNR*2; i += 544) {
        int row = i >> 1, hf = (i & 1) * 4;
        if (row < FF) {
            cp16(Kh + row*12 + hf, gh_kf + base8 + row*8 + hf);
            cp16(Vst + row*8 + hf, gh_vv + base8 + row*8 + hf);
        } else {
            uint4 z = make_uint4(0,0,0,0);
            *(uint4*)(Kh + row*12 + hf) = z;
            *(uint4*)(Vst + row*8 + hf) = z;
        }
    }
    CP_WAIT();
    __syncthreads();
    // transpose V: Vh[dc][kp]
    const unsigned short* Vsth = (const unsigned short*)Vst;
    for (int i = tid; i < 16*FNKP; i += 544) {
        int dc = i & 15, kp = i >> 4;
        unsigned lo = Vsth[(2*kp)*16 + dc];
        unsigned hi = Vsth[(2*kp+1)*16 + dc];
        Vh[dc*FNKP + kp] = lo | (hi << 16);
    }
    __syncthreads();

    int warp = tid >> 5, lane = tid & 31;
    int g = lane >> 2, tig = lane & 3;

    {
        int tile = warp;
        int fr0 = min(tile*16 + g, FF-1);
        int fr1 = min(tile*16 + g + 8, FF-1);
        const unsigned* q0h = gh_qf + base8 + fr0*8;
        const unsigned* q1h = gh_qf + base8 + fr1*8;
        unsigned qh0 = h2scale(q0h[tig],   SCALE2);
        unsigned qh1 = h2scale(q1h[tig],   SCALE2);
        unsigned qh2 = h2scale(q0h[4+tig], SCALE2);
        unsigned qh3 = h2scale(q1h[4+tig], SCALE2);

        float lp0 = 0.f, lp1 = 0.f;
        float oA[4] = {0,0,0,0}, oB[4] = {0,0,0,0};

        for (int kb = 0; kb < 16; kb++) {
            int kr0 = (kb*16 + g)*12;
            int kr1 = kr0 + 96;
            unsigned kA0 = Kh[kr0 + tig], kA1 = Kh[kr0 + tig + 4];
            unsigned kB0 = Kh[kr1 + tig], kB1 = Kh[kr1 + tig + 4];
            float s0=0.f,s1=0.f,s2=0.f,s3=0.f, s4=0.f,s5=0.f,s6=0.f,s7=0.f;
            mma_f16(s0,s1,s2,s3, qh0,qh1,qh2,qh3, kA0,kA1);
            mma_f16(s4,s5,s6,s7, qh0,qh1,qh2,qh3, kB0,kB1);

            float p0 = exp2f(fminf(s0,14.f)), p1 = exp2f(fminf(s1,14.f));
            float p2 = exp2f(fminf(s2,14.f)), p3 = exp2f(fminf(s3,14.f));
            float p4 = exp2f(fminf(s4,14.f)), p5 = exp2f(fminf(s5,14.f));
            float p6 = exp2f(fminf(s6,14.f)), p7 = exp2f(fminf(s7,14.f));
            lp0 += (p0 + p1) + (p4 + p5);
            lp1 += (p2 + p3) + (p6 + p7);

            unsigned pa0 = h2pk(p0,p1), pa1 = h2pk(p2,p3);
            unsigned pa2 = h2pk(p4,p5), pa3 = h2pk(p6,p7);

            int vb = kb*8 + tig;
            unsigned vA0 = Vh[g*FNKP + vb],       vA1 = Vh[g*FNKP + vb + 4];
            unsigned vB0 = Vh[(g+8)*FNKP + vb],   vB1 = Vh[(g+8)*FNKP + vb + 4];
            mma_f16(oA[0],oA[1],oA[2],oA[3], pa0,pa1,pa2,pa3, vA0,vA1);
            mma_f16(oB[0],oB[1],oB[2],oB[3], pa0,pa1,pa2,pa3, vB0,vB1);
        }
        { // tail: key 256 only
            int kr = (256 + g)*12;
            unsigned kA0 = Kh[kr + tig], kA1 = Kh[kr + tig + 4];
            float s0=0.f,s1=0.f,s2=0.f,s3=0.f;
            mma_f16(s0,s1,s2,s3, qh0,qh1,qh2,qh3, kA0,kA1);
            float p0 = (tig == 0) ? exp2f(fminf(s0,14.f)) : 0.f;
            float p2 = (tig == 0) ? exp2f(fminf(s2,14.f)) : 0.f;
            lp0 += p0; lp1 += p2;
            unsigned pa0 = h2pk(p0, 0.f), pa1 = h2pk(p2, 0.f);
            unsigned vA0 = Vh[g*FNKP + 128 + tig];
            unsigned vB0 = Vh[(g+8)*FNKP + 128 + tig];
            mma_f16(oA[0],oA[1],oA[2],oA[3], pa0,pa1,0u,0u, vA0,0u);
            mma_f16(oB[0],oB[1],oB[2],oB[3], pa0,pa1,0u,0u, vB0,0u);
        }
        lp0 += __shfl_xor_sync(0xffffffffu, lp0, 1);
        lp0 += __shfl_xor_sync(0xffffffffu, lp0, 2);
        lp1 += __shfl_xor_sync(0xffffffffu, lp1, 1);
        lp1 += __shfl_xor_sync(0xffffffffu, lp1, 2);
        float inv0 = 1.f / lp0, inv1 = 1.f / lp1;
        int f0 = tile*16 + g, f1 = f0 + 8;
        if (f0 < FF) {
            unsigned* op = gh_fo + ((b*FF + f0)*TT + t)*8;
            op[tig]   = h2pk(oA[0]*inv0, oA[1]*inv0);
            op[4+tig] = h2pk(oB[0]*inv0, oB[1]*inv0);
        }
        if (f1 < FF) {
            unsigned* op = gh_fo + ((b*FF + f1)*TT + t)*8;
            op[tig]   = h2pk(oA[2]*inv1, oA[3]*inv1);
            op[4+tig] = h2pk(oB[2]*inv1, oB[3]*inv1);
        }
    }
}

// ---------------------------------------------------------------------------
// Kernel 3: causal time attention. fp16 MMA, direct half K fill + half V
// stage (single phase), proj + residual.
// ---------------------------------------------------------------------------
#define TNR 512
#define TNKP 260

extern __shared__ unsigned smt[];
__global__ __launch_bounds__(512) void asa_tattn(
    const float* __restrict__ inp,
    const float* __restrict__ pw, const float* __restrict__ pb,
    const float* __restrict__ pg, const float* __restrict__ pbe,
    const float* __restrict__ pm, const float* __restrict__ pv,
    const float* __restrict__ pa,
    float* __restrict__ out)
{
    unsigned* Kh  = smt;                         // TNR*12
    unsigned* Vh  = smt + TNR*12;                // 16*TNKP
    float* pws    = (float*)(Vh + 16*TNKP);      // 1024
    float* psh    = pws + 1024;                  // 64
    float* obuf   = psh + 64;                    // 16*16*17
    unsigned* Vst = (unsigned*)(obuf + 16*16*17);// TNR*8
    __shared__ float s_alpha;

    int bf = blockIdx.x;
    int b = bf / FF, f = bf % FF;
    int base8 = bf * TT * 8;
    int tid = threadIdx.x;

    for (int i = tid; i < TNR*2; i += 512) {
        int row = i >> 1, hf = (i & 1) * 4;
        if (row < TT) {
            cp16(Kh + row*12 + hf, gh_kt + base8 + row*8 + hf);
            cp16(Vst + row*8 + hf, gh_fo + base8 + row*8 + hf);
        } else {
            uint4 z = make_uint4(0,0,0,0);
            *(uint4*)(Kh + row*12 + hf) = z;
            *(uint4*)(Vst + row*8 + hf) = z;
        }
    }
    for (int i = tid; i < 64*16; i += 512) {
        int o = i >> 4;
        pws[i] = pw[i] * (pg[o] * rsqrtf(pv[o] + BN_EPS));
    }
    if (tid < 64) {
        int o = tid;
        psh[o] = (pb[o] - pm[o]) * (pg[o] * rsqrtf(pv[o] + BN_EPS)) + pbe[o];
    }
    if (tid == 0) s_alpha = pa[0];
    CP_WAIT();
    __syncthreads();
    const unsigned short* Vsth = (const unsigned short*)Vst;
    for (int i = tid; i < 16*256; i += 512) {
        int dc = i & 15, kp = i >> 4;
        unsigned lo = Vsth[(2*kp)*16 + dc];
        unsigned hi = Vsth[(2*kp+1)*16 + dc];
        Vh[dc*TNKP + kp] = lo | (hi << 16);
    }
    __syncthreads();

    int warp = tid >> 5, lane = tid & 31;
    int g = lane >> 2, tig = lane & 3;
    float alpha = s_alpha;
    float* ob = obuf + warp * (16*17);

    int tiles[2] = { warp, 31 - warp };

#pragma unroll
    for (int ti = 0; ti < 2; ti++) {
        int tile = tiles[ti];
        int qt0 = tile * 16;
        int ta = qt0 + g;
        int tb = qt0 + g + 8;
        int tr0 = min(ta, TT-1), tr1 = min(tb, TT-1);
        const unsigned* q0h = gh_qt + base8 + tr0*8;
        const unsigned* q1h = gh_qt + base8 + tr1*8;
        unsigned qh0 = h2scale(q0h[tig],   SCALE2);
        unsigned qh1 = h2scale(q1h[tig],   SCALE2);
        unsigned qh2 = h2scale(q0h[4+tig], SCALE2);
        unsigned qh3 = h2scale(q1h[4+tig], SCALE2);

        float lp0 = 0.f, lp1 = 0.f;
        float oA[4] = {0,0,0,0}, oB[4] = {0,0,0,0};

        for (int kb = 0; kb <= tile; kb++) {
            int kr0 = (kb*16 + g)*12;
            int kr1 = kr0 + 96;
            unsigned kA0 = Kh[kr0 + tig], kA1 = Kh[kr0 + tig + 4];
            unsigned kB0 = Kh[kr1 + tig], kB1 = Kh[kr1 + tig + 4];
            float s0=0.f,s1=0.f,s2=0.f,s3=0.f, s4=0.f,s5=0.f,s6=0.f,s7=0.f;
            mma_f16(s0,s1,s2,s3, qh0,qh1,qh2,qh3, kA0,kA1);
            mma_f16(s4,s5,s6,s7, qh0,qh1,qh2,qh3, kB0,kB1);
            if (kb == tile) {
                int yA0 = kb*16 + 2*tig, yA1 = yA0 + 1;
                int yB0 = yA0 + 8,       yB1 = yA1 + 8;
                if (yA0 > ta) s0 = -3.0e38f;
                if (yA1 > ta) s1 = -3.0e38f;
                if (yA0 > tb) s2 = -3.0e38f;
                if (yA1 > tb) s3 = -3.0e38f;
                if (yB0 > ta) s4 = -3.0e38f;
                if (yB1 > ta) s5 = -3.0e38f;
                if (yB0 > tb) s6 = -3.0e38f;
                if (yB1 > tb) s7 = -3.0e38f;
            }
            float p0 = exp2f(fminf(s0,14.f)), p1 = exp2f(fminf(s1,14.f));
            float p2 = exp2f(fminf(s2,14.f)), p3 = exp2f(fminf(s3,14.f));
            float p4 = exp2f(fminf(s4,14.f)), p5 = exp2f(fminf(s5,14.f));
            float p6 = exp2f(fminf(s6,14.f)), p7 = exp2f(fminf(s7,14.f));
            lp0 += (p0 + p1) + (p4 + p5);
            lp1 += (p2 + p3) + (p6 + p7);

            unsigned pa0 = h2pk(p0,p1), pa1 = h2pk(p2,p3);
            unsigned pa2 = h2pk(p4,p5), pa3 = h2pk(p6,p7);

            int vb = kb*8 + tig;
            unsigned vA0 = Vh[g*TNKP + vb],       vA1 = Vh[g*TNKP + vb + 4];
            unsigned vB0 = Vh[(g+8)*TNKP + vb],   vB1 = Vh[(g+8)*TNKP + vb + 4];
            mma_f16(oA[0],oA[1],oA[2],oA[3], pa0,pa1,pa2,pa3, vA0,vA1);
            mma_f16(oB[0],oB[1],oB[2],oB[3], pa0,pa1,pa2,pa3, vB0,vB1);
        }
        lp0 += __shfl_xor_sync(0xffffffffu, lp0, 1);
        lp0 += __shfl_xor_sync(0xffffffffu, lp0, 2);
        lp1 += __shfl_xor_sync(0xffffffffu, lp1, 1);
        lp1 += __shfl_xor_sync(0xffffffffu, lp1, 2);
        float inv0 = 1.f / lp0, inv1 = 1.f / lp1;
        ob[g*17 + 2*tig]          = oA[0]*inv0;
        ob[g*17 + 2*tig + 1]      = oA[1]*inv0;
        ob[(g+8)*17 + 2*tig]      = oA[2]*inv1;
        ob[(g+8)*17 + 2*tig + 1]  = oA[3]*inv1;
        ob[g*17 + 8 + 2*tig]      = oB[0]*inv0;
        ob[g*17 + 8 + 2*tig + 1]  = oB[1]*inv0;
        ob[(g+8)*17 + 8 + 2*tig]     = oB[2]*inv1;
        ob[(g+8)*17 + 8 + 2*tig + 1] = oB[3]*inv1;
        __syncwarp();

        int qi = lane & 15;
        int t = qt0 + qi;
        if (t < TT) {
            const float* orow = ob + qi*17;
            u64 o2[8];
#pragma unroll
            for (int j = 0; j < 8; j++) o2[j] = pk2(orow[2*j], orow[2*j+1]);
            int c0 = (lane >> 4) * 32;
            int obase = b*CC*FTSZ + f*TT + t;
#pragma unroll 4
            for (int j = 0; j < 32; j++) {
                int co = c0 + j;
                const ulonglong2* wr = (const ulonglong2*)(pws + co*16);
                ulonglong2 wa = wr[0], wb = wr[1], wc = wr[2], wd = wr[3];
                u64 d0 = mul2(wa.x, o2[0]);
                u64 d1 = mul2(wa.y, o2[1]);
                d0 = fma2(wb.x, o2[2], d0);
                d1 = fma2(wb.y, o2[3], d1);
                d0 = fma2(wc.x, o2[4], d0);
                d1 = fma2(wc.y, o2[5], d1);
                d0 = fma2(wd.x, o2[6], d0);
                d1 = fma2(wd.y, o2[7], d1);
                float lo0,hi0,lo1,hi1;
                upk2(d0,lo0,hi0); upk2(d1,lo1,hi1);
                float r = psh[co] + (lo0+hi0) + (lo1+hi1);
                r = r >= 0.f ? r : alpha * r;
                int idx = obase + co*FTSZ;
                out[idx] = r + __ldg(&inp[idx]);
            }
        }
        __syncwarp();
    }
}

// ---------------------------------------------------------------------------
extern "C" void kernel_launch(void* const* d_in, const int* in_sizes, int n_in,
                              void* d_out, int out_size)
{
    const float* inp = (const float*)d_in[0];

    int smc_bytes = (64*PSTR + 32*WSTR + 80 + 2) * (int)sizeof(float);
    cudaFuncSetAttribute(asa_conv, cudaFuncAttributeMaxDynamicSharedMemorySize, smc_bytes);
    asa_conv<<<(NPIX + 127)/128, 256, smc_bytes>>>(
        inp,
        (const float*)d_in[1],  (const float*)d_in[2],  (const float*)d_in[3],
        (const float*)d_in[4],  (const float*)d_in[5],  (const float*)d_in[6],
        (const float*)d_in[7],
        (const float*)d_in[8],  (const float*)d_in[9],  (const float*)d_in[10],
        (const float*)d_in[11], (const float*)d_in[12], (const float*)d_in[13],
        (const float*)d_in[14]);

    int smf_bytes = (FNR*12 + 16*FNKP + FNR*8) * 4;
    cudaFuncSetAttribute(asa_fattn, cudaFuncAttributeMaxDynamicSharedMemorySize, smf_bytes);
    asa_fattn<<<BB*TT, 544, smf_bytes>>>();

    int smt_bytes = (TNR*12 + 16*TNKP + 1024 + 64 + 16*16*17 + TNR*8) * 4;
    cudaFuncSetAttribute(asa_tattn, cudaFuncAttributeMaxDynamicSharedMemorySize, smt_bytes);
    asa_tattn<<<BB*FF, 512, smt_bytes>>>(
        inp,
        (const float*)d_in[15], (const float*)d_in[16], (const float*)d_in[17],
        (const float*)d_in[18], (const float*)d_in[19], (const float*)d_in[20],
        (const float*)d_in[21],
        (float*)d_out);
}

// round 17
// speedup vs baseline: 5.9358x; 1.0840x over previous
#include <cuda_runtime.h>
#include <cuda_fp16.h>

#define BB 2
#define CC 64
#define FF 257
#define TT 500
#define DC 16
#define BN_EPS 1e-5f
#define SCALE2 0.36067376022224085f   /* 0.25 * log2(e) */
#define NPIX (BB*FF*TT)
#define FTSZ (FF*TT)

typedef unsigned long long u64;

__device__ __forceinline__ u64 pk2(float lo, float hi) {
    u64 r; asm("mov.b64 %0, {%1,%2};" : "=l"(r) : "f"(lo), "f"(hi)); return r;
}
__device__ __forceinline__ void upk2(u64 v, float& lo, float& hi) {
    asm("mov.b64 {%0,%1}, %2;" : "=f"(lo), "=f"(hi) : "l"(v));
}
__device__ __forceinline__ u64 fma2(u64 a, u64 b, u64 c) {
    u64 d; asm("fma.rn.f32x2 %0, %1, %2, %3;" : "=l"(d) : "l"(a), "l"(b), "l"(c)); return d;
}
__device__ __forceinline__ u64 mul2(u64 a, u64 b) {
    u64 d; asm("mul.rn.f32x2 %0, %1, %2;" : "=l"(d) : "l"(a), "l"(b)); return d;
}
// pack {lo, hi} into half2 (lo -> low 16 bits)
__device__ __forceinline__ unsigned h2pk(float lo, float hi) {
    unsigned r; asm("cvt.rn.f16x2.f32 %0, %1, %2;" : "=r"(r) : "f"(hi), "f"(lo)); return r;
}
__device__ __forceinline__ unsigned h2scale(unsigned h, float s) {
    __half2 v = *(__half2*)&h;
    float2 f = __half22float2(v);
    return h2pk(f.x*s, f.y*s);
}
// clamp to <=14 (fp16 14.0 = 0x4B00) then 2^x, both lanes, one MUFU op
__device__ __forceinline__ unsigned hexp2c(unsigned a) {
    unsigned r;
    asm("min.f16x2 %0, %1, %2;\n\tex2.approx.f16x2 %0, %0;"
        : "=r"(r) : "r"(a), "r"(0x4B004B00u));
    return r;
}
__device__ __forceinline__ unsigned hadd2(unsigned a, unsigned b) {
    unsigned r; asm("add.f16x2 %0, %1, %2;" : "=r"(r) : "r"(a), "r"(b)); return r;
}
__device__ __forceinline__ float2 h2unpack(unsigned h) {
    return __half22float2(*(__half2*)&h);
}
__device__ __forceinline__ void mma_f16(
    float& d0, float& d1, float& d2, float& d3,
    unsigned a0, unsigned a1, unsigned a2, unsigned a3,
    unsigned b0, unsigned b1)
{
    asm("mma.sync.aligned.m16n8k16.row.col.f32.f16.f16.f32 "
        "{%0,%1,%2,%3},{%4,%5,%6,%7},{%8,%9},{%0,%1,%2,%3};"
        : "+f"(d0), "+f"(d1), "+f"(d2), "+f"(d3)
        : "r"(a0), "r"(a1), "r"(a2), "r"(a3), "r"(b0), "r"(b1));
}
__device__ __forceinline__ void cp16(void* dst, const void* src) {
    unsigned d = (unsigned)__cvta_generic_to_shared(dst);
    asm volatile("cp.async.ca.shared.global [%0], [%1], 16;" :: "r"(d), "l"(src));
}
#define CP_WAIT() asm volatile("cp.async.commit_group;\ncp.async.wait_group 0;" ::: "memory")

// Scratch (device globals; no allocation allowed). All half2-packed: 8 words/px.
__device__ __align__(16) unsigned gh_qf[BB*TT*FF*8];   // [b][t][f][8]
__device__ __align__(16) unsigned gh_kf[BB*TT*FF*8];
__device__ __align__(16) unsigned gh_vv[BB*TT*FF*8];
__device__ __align__(16) unsigned gh_qt[BB*FF*TT*8];   // [b][f][t][8]
__device__ __align__(16) unsigned gh_kt[BB*FF*TT*8];
__device__ __align__(16) unsigned gh_fo[BB*FF*TT*8];

// ---------------------------------------------------------------------------
// Kernel 1: fused 1x1 convs via fp16 MMA, half2 outputs (unchanged from R16).
// ---------------------------------------------------------------------------
#define PSTR 132
#define WSTR 88

extern __shared__ float smc[];
__global__ __launch_bounds__(256) void asa_conv(
    const float* __restrict__ inp,
    const float* __restrict__ fw, const float* __restrict__ fb,
    const float* __restrict__ fg, const float* __restrict__ fbe,
    const float* __restrict__ fm, const float* __restrict__ fv,
    const float* __restrict__ fa,
    const float* __restrict__ tw, const float* __restrict__ tb,
    const float* __restrict__ tg, const float* __restrict__ tbe,
    const float* __restrict__ tm, const float* __restrict__ tv,
    const float* __restrict__ ta)
{
    float* xs = smc;                             // [64][PSTR] fp32
    unsigned* Wh = (unsigned*)(smc + 64*PSTR);   // [32][WSTR] half2 (ch pairs)
    float* sh = (float*)(Wh + 32*WSTR);          // [80]
    float* al = sh + 80;                         // [2]

    int tid = threadIdx.x;

    for (int idx = tid; idx < 80*32; idx += 256) {
        int cp = idx & 31, op = idx >> 5;
        int e = op >> 4, cc = op & 15;
        float w0, w1, g, vv;
        if (e < 3) { int o = 3*cc + e;      w0 = fw[o*64+2*cp]; w1 = fw[o*64+2*cp+1]; g = fg[o]; vv = fv[o]; }
        else       { int o2 = 2*cc + (e-3); w0 = tw[o2*64+2*cp]; w1 = tw[o2*64+2*cp+1]; g = tg[o2]; vv = tv[o2]; }
        float s = g * rsqrtf(vv + BN_EPS);
        Wh[cp*WSTR + op] = h2pk(w0*s, w1*s);
    }
    if (tid < 80) {
        int op = tid, e = op >> 4, cc = op & 15;
        float g, vv, m, b, be;
        if (e < 3) { int o = 3*cc + e;      g=fg[o]; vv=fv[o]; m=fm[o]; b=fb[o]; be=fbe[o]; }
        else       { int o2 = 2*cc + (e-3); g=tg[o2]; vv=tv[o2]; m=tm[o2]; b=tb[o2]; be=tbe[o2]; }
        sh[op] = (b - m) * (g * rsqrtf(vv + BN_EPS)) + be;
    }
    if (tid == 0) { al[0] = fa[0]; al[1] = ta[0]; }

    int p0 = blockIdx.x * 128;
    int b0 = p0 / FTSZ;
    int bend = (p0 + 127) / FTSZ;
    if (b0 == bend && p0 + 127 < NPIX) {
        int ft0 = p0 - b0*FTSZ;
        const float* src = inp + b0*CC*FTSZ + ft0;
        for (int i = tid; i < 64*32; i += 256) {
            int c = i >> 5, l4 = i & 31;
            cp16(xs + c*PSTR + l4*4, src + c*FTSZ + l4*4);
        }
        CP_WAIT();
    } else {
        for (int i = tid; i < 64*128; i += 256) {
            int c = i >> 7, lp = i & 127;
            int p = p0 + lp;
            float v = 0.f;
            if (p < NPIX) {
                int b = p / FTSZ;
                int ft = p - b*FTSZ;
                v = inp[(b*CC + c)*FTSZ + ft];
            }
            xs[c*PSTR + lp] = v;
        }
    }
    __syncthreads();

    int warp = tid >> 5, lane = tid & 31;
    int g = lane >> 2, tig = lane & 3;
    int px0 = warp*16;
    int pxA = px0 + g, pxB = px0 + g + 8;

    float acc[10][4];
#pragma unroll
    for (int nt = 0; nt < 10; nt++)
#pragma unroll
        for (int j = 0; j < 4; j++) acc[nt][j] = 0.f;

#pragma unroll
    for (int k = 0; k < 4; k++) {
        int ch0 = 16*k + 2*tig;
        const float* r0 = xs + ch0*PSTR;
        const float* r1 = r0 + PSTR;
        const float* r2 = r0 + 8*PSTR;
        const float* r3 = r0 + 9*PSTR;
        unsigned a0 = h2pk(r0[pxA], r1[pxA]);
        unsigned a1 = h2pk(r0[pxB], r1[pxB]);
        unsigned a2 = h2pk(r2[pxA], r3[pxA]);
        unsigned a3 = h2pk(r2[pxB], r3[pxB]);
        int kp0 = (8*k + tig)*WSTR + g, kp1 = kp0 + 4*WSTR;
#pragma unroll
        for (int nt = 0; nt < 10; nt++) {
            unsigned bb0 = Wh[kp0 + nt*8];
            unsigned bb1 = Wh[kp1 + nt*8];
            mma_f16(acc[nt][0], acc[nt][1], acc[nt][2], acc[nt][3],
                    a0, a1, a2, a3, bb0, bb1);
        }
    }

    float sh0[10], sh1[10];
#pragma unroll
    for (int nt = 0; nt < 10; nt++) {
        sh0[nt] = sh[nt*8 + 2*tig];
        sh1[nt] = sh[nt*8 + 2*tig + 1];
    }
    float a0v = al[0], a1v = al[1];

#pragma unroll
    for (int r = 0; r < 2; r++) {
        int px  = px0 + g + r*8;
        int off = r * 2;
        int p = p0 + px;
        if (p >= NPIX) continue;
        int b = p / FTSZ;
        int ft = p - b*FTSZ;
        int f = ft / TT;
        int t = ft - f*TT;
        int fidx = ((b*TT + t)*FF + f)*8;
        int tidx = ((b*FF + f)*TT + t)*8;
        unsigned* dsts[5];
        dsts[0] = gh_qf + fidx;
        dsts[1] = gh_kf + fidx;
        dsts[2] = gh_vv + fidx;
        dsts[3] = gh_qt + tidx;
        dsts[4] = gh_kt + tidx;
#pragma unroll
        for (int nt = 0; nt < 10; nt++) {
            int e = nt >> 1;
            float alpha = (e < 3) ? a0v : a1v;
            float v0 = acc[nt][off]     + sh0[nt];
            float v1 = acc[nt][off + 1] + sh1[nt];
            v0 = v0 >= 0.f ? v0 : alpha * v0;
            v1 = v1 >= 0.f ? v1 : alpha * v1;
            dsts[e][(nt & 1)*4 + tig] = h2pk(v0, v1);
        }
    }
}

// ---------------------------------------------------------------------------
// Kernel 2: frequency attention. fp16 MMA, half2 exp2 softmax.
// ---------------------------------------------------------------------------
#define FNR 264
#define FNKP 132

extern __shared__ unsigned smf[];
__global__ __launch_bounds__(544) void asa_fattn()
{
    unsigned* Kh  = smf;                     // FNR*12
    unsigned* Vh  = smf + FNR*12;            // 16*FNKP
    unsigned* Vst = Vh + 16*FNKP;            // FNR*8 (half rows)

    int bt = blockIdx.x;
    int b = bt / TT, t = bt % TT;
    int base8 = (b*TT + t)*FF*8;
    int tid = threadIdx.x;

    for (int i = tid; i < FNR*2; i += 544) {
        int row = i >> 1, hf = (i & 1) * 4;
        if (row < FF) {
            cp16(Kh + row*12 + hf, gh_kf + base8 + row*8 + hf);
            cp16(Vst + row*8 + hf, gh_vv + base8 + row*8 + hf);
        } else {
            uint4 z = make_uint4(0,0,0,0);
            *(uint4*)(Kh + row*12 + hf) = z;
            *(uint4*)(Vst + row*8 + hf) = z;
        }
    }
    CP_WAIT();
    __syncthreads();
    const unsigned short* Vsth = (const unsigned short*)Vst;
    for (int i = tid; i < 16*FNKP; i += 544) {
        int dc = i & 15, kp = i >> 4;
        unsigned lo = Vsth[(2*kp)*16 + dc];
        unsigned hi = Vsth[(2*kp+1)*16 + dc];
        Vh[dc*FNKP + kp] = lo | (hi << 16);
    }
    __syncthreads();

    int warp = tid >> 5, lane = tid & 31;
    int g = lane >> 2, tig = lane & 3;

    {
        int tile = warp;
        int fr0 = min(tile*16 + g, FF-1);
        int fr1 = min(tile*16 + g + 8, FF-1);
        const unsigned* q0h = gh_qf + base8 + fr0*8;
        const unsigned* q1h = gh_qf + base8 + fr1*8;
        unsigned qh0 = h2scale(q0h[tig],   SCALE2);
        unsigned qh1 = h2scale(q1h[tig],   SCALE2);
        unsigned qh2 = h2scale(q0h[4+tig], SCALE2);
        unsigned qh3 = h2scale(q1h[4+tig], SCALE2);

        float lp0 = 0.f, lp1 = 0.f;
        float oA[4] = {0,0,0,0}, oB[4] = {0,0,0,0};

        for (int kb = 0; kb < 16; kb++) {
            int kr0 = (kb*16 + g)*12;
            int kr1 = kr0 + 96;
            unsigned kA0 = Kh[kr0 + tig], kA1 = Kh[kr0 + tig + 4];
            unsigned kB0 = Kh[kr1 + tig], kB1 = Kh[kr1 + tig + 4];
            float s0=0.f,s1=0.f,s2=0.f,s3=0.f, s4=0.f,s5=0.f,s6=0.f,s7=0.f;
            mma_f16(s0,s1,s2,s3, qh0,qh1,qh2,qh3, kA0,kA1);
            mma_f16(s4,s5,s6,s7, qh0,qh1,qh2,qh3, kB0,kB1);

            unsigned pa0 = hexp2c(h2pk(s0,s1));
            unsigned pa1 = hexp2c(h2pk(s2,s3));
            unsigned pa2 = hexp2c(h2pk(s4,s5));
            unsigned pa3 = hexp2c(h2pk(s6,s7));
            float2 t0 = h2unpack(hadd2(pa0, pa2));
            float2 t1 = h2unpack(hadd2(pa1, pa3));
            lp0 += t0.x + t0.y;
            lp1 += t1.x + t1.y;

            int vb = kb*8 + tig;
            unsigned vA0 = Vh[g*FNKP + vb],       vA1 = Vh[g*FNKP + vb + 4];
            unsigned vB0 = Vh[(g+8)*FNKP + vb],   vB1 = Vh[(g+8)*FNKP + vb + 4];
            mma_f16(oA[0],oA[1],oA[2],oA[3], pa0,pa1,pa2,pa3, vA0,vA1);
            mma_f16(oB[0],oB[1],oB[2],oB[3], pa0,pa1,pa2,pa3, vB0,vB1);
        }
        { // tail: key 256 only
            int kr = (256 + g)*12;
            unsigned kA0 = Kh[kr + tig], kA1 = Kh[kr + tig + 4];
            float s0=0.f,s1=0.f,s2=0.f,s3=0.f;
            mma_f16(s0,s1,s2,s3, qh0,qh1,qh2,qh3, kA0,kA1);
            float p0 = (tig == 0) ? exp2f(fminf(s0,14.f)) : 0.f;
            float p2 = (tig == 0) ? exp2f(fminf(s2,14.f)) : 0.f;
            lp0 += p0; lp1 += p2;
            unsigned pa0 = h2pk(p0, 0.f), pa1 = h2pk(p2, 0.f);
            unsigned vA0 = Vh[g*FNKP + 128 + tig];
            unsigned vB0 = Vh[(g+8)*FNKP + 128 + tig];
            mma_f16(oA[0],oA[1],oA[2],oA[3], pa0,pa1,0u,0u, vA0,0u);
            mma_f16(oB[0],oB[1],oB[2],oB[3], pa0,pa1,0u,0u, vB0,0u);
        }
        lp0 += __shfl_xor_sync(0xffffffffu, lp0, 1);
        lp0 += __shfl_xor_sync(0xffffffffu, lp0, 2);
        lp1 += __shfl_xor_sync(0xffffffffu, lp1, 1);
        lp1 += __shfl_xor_sync(0xffffffffu, lp1, 2);
        float inv0 = 1.f / lp0, inv1 = 1.f / lp1;
        int f0 = tile*16 + g, f1 = f0 + 8;
        if (f0 < FF) {
            unsigned* op = gh_fo + ((b*FF + f0)*TT + t)*8;
            op[tig]   = h2pk(oA[0]*inv0, oA[1]*inv0);
            op[4+tig] = h2pk(oB[0]*inv0, oB[1]*inv0);
        }
        if (f1 < FF) {
            unsigned* op = gh_fo + ((b*FF + f1)*TT + t)*8;
            op[tig]   = h2pk(oA[2]*inv1, oA[3]*inv1);
            op[4+tig] = h2pk(oB[2]*inv1, oB[3]*inv1);
        }
    }
}

// ---------------------------------------------------------------------------
// Kernel 3: causal time attention. fp16 MMA, half2 exp2 softmax,
// proj + residual.
// ---------------------------------------------------------------------------
#define TNR 512
#define TNKP 260

extern __shared__ unsigned smt[];
__global__ __launch_bounds__(512) void asa_tattn(
    const float* __restrict__ inp,
    const float* __restrict__ pw, const float* __restrict__ pb,
    const float* __restrict__ pg, const float* __restrict__ pbe,
    const float* __restrict__ pm, const float* __restrict__ pv,
    const float* __restrict__ pa,
    float* __restrict__ out)
{
    unsigned* Kh  = smt;                         // TNR*12
    unsigned* Vh  = smt + TNR*12;                // 16*TNKP
    float* pws    = (float*)(Vh + 16*TNKP);      // 1024
    float* psh    = pws + 1024;                  // 64
    float* obuf   = psh + 64;                    // 16*16*17
    unsigned* Vst = (unsigned*)(obuf + 16*16*17);// TNR*8
    __shared__ float s_alpha;

    int bf = blockIdx.x;
    int b = bf / FF, f = bf % FF;
    int base8 = bf * TT * 8;
    int tid = threadIdx.x;

    for (int i = tid; i < TNR*2; i += 512) {
        int row = i >> 1, hf = (i & 1) * 4;
        if (row < TT) {
            cp16(Kh + row*12 + hf, gh_kt + base8 + row*8 + hf);
            cp16(Vst + row*8 + hf, gh_fo + base8 + row*8 + hf);
        } else {
            uint4 z = make_uint4(0,0,0,0);
            *(uint4*)(Kh + row*12 + hf) = z;
            *(uint4*)(Vst + row*8 + hf) = z;
        }
    }
    for (int i = tid; i < 64*16; i += 512) {
        int o = i >> 4;
        pws[i] = pw[i] * (pg[o] * rsqrtf(pv[o] + BN_EPS));
    }
    if (tid < 64) {
        int o = tid;
        psh[o] = (pb[o] - pm[o]) * (pg[o] * rsqrtf(pv[o] + BN_EPS)) + pbe[o];
    }
    if (tid == 0) s_alpha = pa[0];
    CP_WAIT();
    __syncthreads();
    const unsigned short* Vsth = (const unsigned short*)Vst;
    for (int i = tid; i < 16*256; i += 512) {
        int dc = i & 15, kp = i >> 4;
        unsigned lo = Vsth[(2*kp)*16 + dc];
        unsigned hi = Vsth[(2*kp+1)*16 + dc];
        Vh[dc*TNKP + kp] = lo | (hi << 16);
    }
    __syncthreads();

    int warp = tid >> 5, lane = tid & 31;
    int g = lane >> 2, tig = lane & 3;
    float alpha = s_alpha;
    float* ob = obuf + warp * (16*17);

    int tiles[2] = { warp, 31 - warp };

#pragma unroll
    for (int ti = 0; ti < 2; ti++) {
        int tile = tiles[ti];
        int qt0 = tile * 16;
        int ta = qt0 + g;
        int tb = qt0 + g + 8;
        int tr0 = min(ta, TT-1), tr1 = min(tb, TT-1);
        const unsigned* q0h = gh_qt + base8 + tr0*8;
        const unsigned* q1h = gh_qt + base8 + tr1*8;
        unsigned qh0 = h2scale(q0h[tig],   SCALE2);
        unsigned qh1 = h2scale(q1h[tig],   SCALE2);
        unsigned qh2 = h2scale(q0h[4+tig], SCALE2);
        unsigned qh3 = h2scale(q1h[4+tig], SCALE2);

        float lp0 = 0.f, lp1 = 0.f;
        float oA[4] = {0,0,0,0}, oB[4] = {0,0,0,0};

        for (int kb = 0; kb <= tile; kb++) {
            int kr0 = (kb*16 + g)*12;
            int kr1 = kr0 + 96;
            unsigned kA0 = Kh[kr0 + tig], kA1 = Kh[kr0 + tig + 4];
            unsigned kB0 = Kh[kr1 + tig], kB1 = Kh[kr1 + tig + 4];
            float s0=0.f,s1=0.f,s2=0.f,s3=0.f, s4=0.f,s5=0.f,s6=0.f,s7=0.f;
            mma_f16(s0,s1,s2,s3, qh0,qh1,qh2,qh3, kA0,kA1);
            mma_f16(s4,s5,s6,s7, qh0,qh1,qh2,qh3, kB0,kB1);
            if (kb == tile) {
                int yA0 = kb*16 + 2*tig, yA1 = yA0 + 1;
                int yB0 = yA0 + 8,       yB1 = yA1 + 8;
                if (yA0 > ta) s0 = -3.0e38f;
                if (yA1 > ta) s1 = -3.0e38f;
                if (yA0 > tb) s2 = -3.0e38f;
                if (yA1 > tb) s3 = -3.0e38f;
                if (yB0 > ta) s4 = -3.0e38f;
                if (yB1 > ta) s5 = -3.0e38f;
                if (yB0 > tb) s6 = -3.0e38f;
                if (yB1 > tb) s7 = -3.0e38f;
            }
            unsigned pa0 = hexp2c(h2pk(s0,s1));
            unsigned pa1 = hexp2c(h2pk(s2,s3));
            unsigned pa2 = hexp2c(h2pk(s4,s5));
            unsigned pa3 = hexp2c(h2pk(s6,s7));
            float2 t0 = h2unpack(hadd2(pa0, pa2));
            float2 t1 = h2unpack(hadd2(pa1, pa3));
            lp0 += t0.x + t0.y;
            lp1 += t1.x + t1.y;

            int vb = kb*8 + tig;
            unsigned vA0 = Vh[g*TNKP + vb],       vA1 = Vh[g*TNKP + vb + 4];
            unsigned vB0 = Vh[(g+8)*TNKP + vb],   vB1 = Vh[(g+8)*TNKP + vb + 4];
            mma_f16(oA[0],oA[1],oA[2],oA[3], pa0,pa1,pa2,pa3, vA0,vA1);
            mma_f16(oB[0],oB[1],oB[2],oB[3], pa0,pa1,pa2,pa3, vB0,vB1);
        }
        lp0 += __shfl_xor_sync(0xffffffffu, lp0, 1);
        lp0 += __shfl_xor_sync(0xffffffffu, lp0, 2);
        lp1 += __shfl_xor_sync(0xffffffffu, lp1, 1);
        lp1 += __shfl_xor_sync(0xffffffffu, lp1, 2);
        float inv0 = 1.f / lp0, inv1 = 1.f / lp1;
        ob[g*17 + 2*tig]          = oA[0]*inv0;
        ob[g*17 + 2*tig + 1]      = oA[1]*inv0;
        ob[(g+8)*17 + 2*tig]      = oA[2]*inv1;
        ob[(g+8)*17 + 2*tig + 1]  = oA[3]*inv1;
        ob[g*17 + 8 + 2*tig]      = oB[0]*inv0;
        ob[g*17 + 8 + 2*tig + 1]  = oB[1]*inv0;
        ob[(g+8)*17 + 8 + 2*tig]     = oB[2]*inv1;
        ob[(g+8)*17 + 8 + 2*tig + 1] = oB[3]*inv1;
        __syncwarp();

        int qi = lane & 15;
        int t = qt0 + qi;
        if (t < TT) {
            const float* orow = ob + qi*17;
            u64 o2[8];
#pragma unroll
            for (int j = 0; j < 8; j++) o2[j] = pk2(orow[2*j], orow[2*j+1]);
            int c0 = (lane >> 4) * 32;
            int obase = b*CC*FTSZ + f*TT + t;
#pragma unroll 4
            for (int j = 0; j < 32; j++) {
                int co = c0 + j;
                const ulonglong2* wr = (const ulonglong2*)(pws + co*16);
                ulonglong2 wa = wr[0], wb = wr[1], wc = wr[2], wd = wr[3];
                u64 d0 = mul2(wa.x, o2[0]);
                u64 d1 = mul2(wa.y, o2[1]);
                d0 = fma2(wb.x, o2[2], d0);
                d1 = fma2(wb.y, o2[3], d1);
                d0 = fma2(wc.x, o2[4], d0);
                d1 = fma2(wc.y, o2[5], d1);
                d0 = fma2(wd.x, o2[6], d0);
                d1 = fma2(wd.y, o2[7], d1);
                float lo0,hi0,lo1,hi1;
                upk2(d0,lo0,hi0); upk2(d1,lo1,hi1);
                float r = psh[co] + (lo0+hi0) + (lo1+hi1);
                r = r >= 0.f ? r : alpha * r;
                int idx = obase + co*FTSZ;
                out[idx] = r + __ldg(&inp[idx]);
            }
        }
        __syncwarp();
    }
}

// ---------------------------------------------------------------------------
extern "C" void kernel_launch(void* const* d_in, const int* in_sizes, int n_in,
                              void* d_out, int out_size)
{
    const float* inp = (const float*)d_in[0];

    int smc_bytes = (64*PSTR + 32*WSTR + 80 + 2) * (int)sizeof(float);
    cudaFuncSetAttribute(asa_conv, cudaFuncAttributeMaxDynamicSharedMemorySize, smc_bytes);
    asa_conv<<<(NPIX + 127)/128, 256, smc_bytes>>>(
        inp,
        (const float*)d_in[1],  (const float*)d_in[2],  (const float*)d_in[3],
        (const float*)d_in[4],  (const float*)d_in[5],  (const float*)d_in[6],
        (const float*)d_in[7],
        (const float*)d_in[8],  (const float*)d_in[9],  (const float*)d_in[10],
        (const float*)d_in[11], (const float*)d_in[12], (const float*)d_in[13],
        (const float*)d_in[14]);

    int smf_bytes = (FNR*12 + 16*FNKP + FNR*8) * 4;
    cudaFuncSetAttribute(asa_fattn, cudaFuncAttributeMaxDynamicSharedMemorySize, smf_bytes);
    asa_fattn<<<BB*TT, 544, smf_bytes>>>();

    int smt_bytes = (TNR*12 + 16*TNKP + 1024 + 64 + 16*16*17 + TNR*8) * 4;
    cudaFuncSetAttribute(asa_tattn, cudaFuncAttributeMaxDynamicSharedMemorySize, smt_bytes);
    asa_tattn<<<BB*FF, 512, smt_bytes>>>(
        inp,
        (const float*)d_in[15], (const float*)d_in[16], (const float*)d_in[17],
        (const float*)d_in[18], (const float*)d_in[19], (const float*)d_in[20],
        (const float*)d_in[21],
        (float*)d_out);
}